// round 1
// baseline (speedup 1.0000x reference)
#include <cuda_runtime.h>
#include <math.h>

#define NATOMS 4096
#define HDIM   128
#define BATCH  128
#define NHEAD  4
#define DHEAD  32
#define FDIM   259
#define H3     384

// -------- scratch (no allocations allowed) --------
__device__ float g_scratch[6850000];
__device__ int   g_bidx[NATOMS];

// ---------------- helpers ----------------
__device__ __forceinline__ float blocksum128(float v, float* sm) {
    #pragma unroll
    for (int off = 16; off > 0; off >>= 1)
        v += __shfl_xor_sync(0xffffffffu, v, off);
    int w = threadIdx.x >> 5;
    __syncthreads();
    if ((threadIdx.x & 31) == 0) sm[w] = v;
    __syncthreads();
    return sm[0] + sm[1] + sm[2] + sm[3];
}

__device__ __forceinline__ float blocksum256(float v, float* sm) {
    #pragma unroll
    for (int off = 16; off > 0; off >>= 1)
        v += __shfl_xor_sync(0xffffffffu, v, off);
    int w = threadIdx.x >> 5;
    __syncthreads();
    if ((threadIdx.x & 31) == 0) sm[w] = v;
    __syncthreads();
    float t = 0.f;
    #pragma unroll
    for (int i = 0; i < 8; i++) t += sm[i];
    return t;
}

__device__ __forceinline__ float silu_f(float x) {
    return x / (1.f + __expf(-x));
}

// ---------------- prep: bidx + clamp bounds ----------------
__global__ void prep_k(const int* __restrict__ num_atoms,
                       const float* __restrict__ cell,
                       float* __restrict__ bmin, float* __restrict__ bmax) {
    __shared__ int starts[BATCH + 1];
    int t = threadIdx.x;
    if (t == 0) {
        int acc = 0;
        for (int i = 0; i < BATCH; i++) { starts[i] = acc; acc += num_atoms[i]; }
        starts[BATCH] = acc;
    }
    __syncthreads();
    // pad semantics: positions past the last fill get the last batch index
    for (int i = t; i < NATOMS; i += 128) g_bidx[i] = BATCH - 1;
    __syncthreads();
    int s = starts[t], e = starts[t + 1];
    if (s > NATOMS) s = NATOMS;
    if (e > NATOMS) e = NATOMS;
    for (int i = s; i < e; i++) g_bidx[i] = t;
    #pragma unroll
    for (int i = 0; i < 3; i++) {
        float a = cell[(3 * t + i) * 3 + 0];
        float b = cell[(3 * t + i) * 3 + 1];
        float c = cell[(3 * t + i) * 3 + 2];
        bmin[t * 3 + i] = fminf(a, fminf(b, c)) + 1e-6f;
        bmax[t * 3 + i] = fmaxf(a, fmaxf(b, c)) - 1e-6f;
    }
}

// ---------------- embed + input LN ----------------
__global__ void embed_ln_k(const int* __restrict__ elems, const float* __restrict__ emb,
                           const float* __restrict__ g, const float* __restrict__ b,
                           float* __restrict__ xo) {
    __shared__ float sm[4];
    int r = blockIdx.x, t = threadIdx.x;
    float v = emb[elems[r] * HDIM + t];
    float mean = blocksum128(v, sm) * (1.f / 128.f);
    float d = v - mean;
    float var = blocksum128(d * d, sm) * (1.f / 128.f);
    xo[r * HDIM + t] = d * rsqrtf(var + 1e-5f) * g[t] + b[t];
}

// ---------------- row LN (width 128) with optional silu ----------------
__global__ void row_ln_k(const float* __restrict__ in, float* __restrict__ out,
                         const float* __restrict__ g, const float* __restrict__ b,
                         int dosilu) {
    __shared__ float sm[4];
    int r = blockIdx.x, t = threadIdx.x;
    float v = in[r * HDIM + t];
    float mean = blocksum128(v, sm) * (1.f / 128.f);
    float d = v - mean;
    float var = blocksum128(d * d, sm) * (1.f / 128.f);
    float y = d * rsqrtf(var + 1e-5f) * g[t] + b[t];
    if (dosilu) y = silu_f(y);
    out[r * HDIM + t] = y;
}

// ---------------- tiled SGEMM: C = A[M,K] @ W[K,N] + bias (+res) ----------------
// 256 threads, BM=BN=64, BK=16, 4x4 micro-tile. M,N multiples of 64; K arbitrary.
__global__ void sgemm_k(const float* __restrict__ A, const float* __restrict__ W,
                        const float* __restrict__ bias, const float* __restrict__ res,
                        float* __restrict__ C, int M, int N, int K) {
    __shared__ float As[16 * 68];
    __shared__ float Bs[16 * 64];
    int tid = threadIdx.x;
    int tx = tid & 15, ty = tid >> 4;
    int bn = blockIdx.x, bm = blockIdx.y;
    float acc[16];
    #pragma unroll
    for (int i = 0; i < 16; i++) acc[i] = 0.f;
    int ktiles = (K + 15) >> 4;
    for (int kt = 0; kt < ktiles; kt++) {
        int k0 = kt << 4;
        #pragma unroll
        for (int i = 0; i < 4; i++) {
            int flat = tid + i * 256;
            int r = flat >> 4, kk = flat & 15;
            int gk = k0 + kk;
            As[kk * 68 + r] = (gk < K) ? A[(bm * 64 + r) * K + gk] : 0.f;
        }
        #pragma unroll
        for (int i = 0; i < 4; i++) {
            int flat = tid + i * 256;
            int kk = flat >> 6, c = flat & 63;
            int gk = k0 + kk;
            Bs[kk * 64 + c] = (gk < K) ? W[gk * N + bn * 64 + c] : 0.f;
        }
        __syncthreads();
        #pragma unroll
        for (int kk = 0; kk < 16; kk++) {
            float4 a4 = *(const float4*)&As[kk * 68 + ty * 4];
            float4 b4 = *(const float4*)&Bs[kk * 64 + tx * 4];
            acc[0]  += a4.x * b4.x; acc[1]  += a4.x * b4.y; acc[2]  += a4.x * b4.z; acc[3]  += a4.x * b4.w;
            acc[4]  += a4.y * b4.x; acc[5]  += a4.y * b4.y; acc[6]  += a4.y * b4.z; acc[7]  += a4.y * b4.w;
            acc[8]  += a4.z * b4.x; acc[9]  += a4.z * b4.y; acc[10] += a4.z * b4.z; acc[11] += a4.z * b4.w;
            acc[12] += a4.w * b4.x; acc[13] += a4.w * b4.y; acc[14] += a4.w * b4.z; acc[15] += a4.w * b4.w;
        }
        __syncthreads();
    }
    #pragma unroll
    for (int i = 0; i < 4; i++) {
        int r = bm * 64 + ty * 4 + i;
        #pragma unroll
        for (int j = 0; j < 4; j++) {
            int c = bn * 64 + tx * 4 + j;
            float v = acc[i * 4 + j] + bias[c];
            if (res) v += res[r * N + c];
            C[r * N + c] = v;
        }
    }
}

// ---------------- flash attention (fp32, online softmax) ----------------
// grid (64 qblocks, 4 heads), 256 threads. Q chunk = 64 rows, K/V chunk = 64.
__global__ void flash_k(const float* __restrict__ qkv, float* __restrict__ ao) {
    __shared__ float sh[10880];
    float* Qt = sh;              // [32][64]  d-major, scaled Q
    float* Kt = sh + 2048;       // [32][64]  d-major
    float* Vs = sh + 4096;       // [64][34]
    float* Ps = sh + 6272;       // [64][72]
    int tid = threadIdx.x;
    int tx = tid & 15, ty = tid >> 4;
    int h = blockIdx.y, qb = blockIdx.x;
    const float scale = 0.17677669529663687f;   // 1/sqrt(32)

    #pragma unroll
    for (int i = 0; i < 8; i++) {
        int flat = tid + i * 256;
        int r = flat >> 5, d = flat & 31;
        Qt[d * 64 + r] = qkv[(qb * 64 + r) * H3 + h * DHEAD + d] * scale;
    }

    float m[4], l[4], o0[4], o1[4];
    #pragma unroll
    for (int i = 0; i < 4; i++) { m[i] = -1e30f; l[i] = 0.f; o0[i] = 0.f; o1[i] = 0.f; }

    for (int kb = 0; kb < 64; kb++) {
        __syncthreads();   // protect Kt/Vs reuse (and Qt fill on iter 0)
        #pragma unroll
        for (int i = 0; i < 8; i++) {
            int flat = tid + i * 256;
            int c = flat >> 5, d = flat & 31;
            int gbase = (kb * 64 + c) * H3 + h * DHEAD + d;
            Kt[d * 64 + c] = qkv[gbase + HDIM];
            Vs[c * 34 + d] = qkv[gbase + 2 * HDIM];
        }
        __syncthreads();

        float s[16];
        #pragma unroll
        for (int i = 0; i < 16; i++) s[i] = 0.f;
        #pragma unroll
        for (int d = 0; d < 32; d++) {
            float4 q4 = *(const float4*)&Qt[d * 64 + ty * 4];
            float4 k4 = *(const float4*)&Kt[d * 64 + tx * 4];
            s[0]  += q4.x * k4.x; s[1]  += q4.x * k4.y; s[2]  += q4.x * k4.z; s[3]  += q4.x * k4.w;
            s[4]  += q4.y * k4.x; s[5]  += q4.y * k4.y; s[6]  += q4.y * k4.z; s[7]  += q4.y * k4.w;
            s[8]  += q4.z * k4.x; s[9]  += q4.z * k4.y; s[10] += q4.z * k4.z; s[11] += q4.z * k4.w;
            s[12] += q4.w * k4.x; s[13] += q4.w * k4.y; s[14] += q4.w * k4.z; s[15] += q4.w * k4.w;
        }

        #pragma unroll
        for (int i = 0; i < 4; i++) {
            float mc = fmaxf(fmaxf(s[i * 4], s[i * 4 + 1]), fmaxf(s[i * 4 + 2], s[i * 4 + 3]));
            mc = fmaxf(mc, __shfl_xor_sync(0xffffffffu, mc, 8));
            mc = fmaxf(mc, __shfl_xor_sync(0xffffffffu, mc, 4));
            mc = fmaxf(mc, __shfl_xor_sync(0xffffffffu, mc, 2));
            mc = fmaxf(mc, __shfl_xor_sync(0xffffffffu, mc, 1));
            float mn = fmaxf(m[i], mc);
            float f = __expf(m[i] - mn);
            m[i] = mn;
            float p0 = __expf(s[i * 4 + 0] - mn);
            float p1 = __expf(s[i * 4 + 1] - mn);
            float p2 = __expf(s[i * 4 + 2] - mn);
            float p3 = __expf(s[i * 4 + 3] - mn);
            float rs = p0 + p1 + p2 + p3;
            rs += __shfl_xor_sync(0xffffffffu, rs, 8);
            rs += __shfl_xor_sync(0xffffffffu, rs, 4);
            rs += __shfl_xor_sync(0xffffffffu, rs, 2);
            rs += __shfl_xor_sync(0xffffffffu, rs, 1);
            l[i] = l[i] * f + rs;
            o0[i] *= f; o1[i] *= f;
            float4 pv = make_float4(p0, p1, p2, p3);
            *(float4*)&Ps[(ty * 4 + i) * 72 + tx * 4] = pv;
        }
        __syncthreads();

        #pragma unroll
        for (int c = 0; c < 64; c += 4) {
            float4 pa = *(const float4*)&Ps[(ty * 4 + 0) * 72 + c];
            float4 pb = *(const float4*)&Ps[(ty * 4 + 1) * 72 + c];
            float4 pc = *(const float4*)&Ps[(ty * 4 + 2) * 72 + c];
            float4 pd = *(const float4*)&Ps[(ty * 4 + 3) * 72 + c];
            float2 v0 = *(const float2*)&Vs[(c + 0) * 34 + tx * 2];
            float2 v1 = *(const float2*)&Vs[(c + 1) * 34 + tx * 2];
            float2 v2 = *(const float2*)&Vs[(c + 2) * 34 + tx * 2];
            float2 v3 = *(const float2*)&Vs[(c + 3) * 34 + tx * 2];
            o0[0] += pa.x * v0.x + pa.y * v1.x + pa.z * v2.x + pa.w * v3.x;
            o1[0] += pa.x * v0.y + pa.y * v1.y + pa.z * v2.y + pa.w * v3.y;
            o0[1] += pb.x * v0.x + pb.y * v1.x + pb.z * v2.x + pb.w * v3.x;
            o1[1] += pb.x * v0.y + pb.y * v1.y + pb.z * v2.y + pb.w * v3.y;
            o0[2] += pc.x * v0.x + pc.y * v1.x + pc.z * v2.x + pc.w * v3.x;
            o1[2] += pc.x * v0.y + pc.y * v1.y + pc.z * v2.y + pc.w * v3.y;
            o0[3] += pd.x * v0.x + pd.y * v1.x + pd.z * v2.x + pd.w * v3.x;
            o1[3] += pd.x * v0.y + pd.y * v1.y + pd.z * v2.y + pd.w * v3.y;
        }
    }

    #pragma unroll
    for (int i = 0; i < 4; i++) {
        int r = qb * 64 + ty * 4 + i;
        float inv = 1.f / l[i];
        float2 res = make_float2(o0[i] * inv, o1[i] * inv);
        *(float2*)&ao[r * HDIM + h * DHEAD + tx * 2] = res;
    }
}

// ---------------- cell encoder (rows 0..127 only are used) ----------------
__global__ void cellenc_k(const float* __restrict__ cell,
                          const float* __restrict__ w1, const float* __restrict__ b1,
                          const float* __restrict__ w2, const float* __restrict__ b2,
                          float* __restrict__ cf) {
    __shared__ float t1[128];
    int r = blockIdx.x, t = threadIdx.x;
    float c0 = cell[r * 3 + 0], c1 = cell[r * 3 + 1], c2 = cell[r * 3 + 2];
    float u = c0 * w1[0 * HDIM + t] + c1 * w1[1 * HDIM + t] + c2 * w1[2 * HDIM + t] + b1[t];
    t1[t] = silu_f(u);
    __syncthreads();
    float acc = b2[t];
    #pragma unroll 8
    for (int k = 0; k < 128; k++) acc += t1[k] * w2[k * HDIM + t];
    cf[r * HDIM + t] = acc;
}

// ---------------- build comb = LN(concat(xa, cf[bidx], coord)) over F=259 ----------------
__global__ void comb_k(const float* __restrict__ xa, const float* __restrict__ cf,
                       const float* __restrict__ coord, const int* __restrict__ bidx,
                       const float* __restrict__ g, const float* __restrict__ b,
                       float* __restrict__ comb) {
    __shared__ float sm[8];
    int r = blockIdx.x, t = threadIdx.x; // 256 threads
    int bi = bidx[r];
    float v0 = (t < 128) ? xa[r * HDIM + t] : cf[bi * HDIM + (t - 128)];
    bool has1 = (t < 3);
    float v1 = has1 ? coord[r * 3 + t] : 0.f;
    float total = blocksum256(v0 + v1, sm);
    float mean = total * (1.f / 259.f);
    float d0 = v0 - mean;
    float d1 = has1 ? (v1 - mean) : 0.f;
    float var = blocksum256(d0 * d0 + d1 * d1, sm) * (1.f / 259.f);
    float inv = rsqrtf(var + 1e-5f);
    comb[r * FDIM + t] = d0 * inv * g[t] + b[t];
    if (has1) comb[r * FDIM + 256 + t] = d1 * inv * g[256 + t] + b[256 + t];
}

// ---------------- final: out = clamp(coord + 0.01*tanh(hf @ w3 + b3)) ----------------
__global__ void final_k(const float* __restrict__ hf, const float* __restrict__ w3,
                        const float* __restrict__ b3, const float* __restrict__ coord,
                        const int* __restrict__ bidx,
                        const float* __restrict__ bmin, const float* __restrict__ bmax,
                        float* __restrict__ out) {
    __shared__ float ws[4][3];
    int r = blockIdx.x, t = threadIdx.x;
    float h = hf[r * HDIM + t];
    float p0 = h * w3[t * 3 + 0];
    float p1 = h * w3[t * 3 + 1];
    float p2 = h * w3[t * 3 + 2];
    #pragma unroll
    for (int off = 16; off > 0; off >>= 1) {
        p0 += __shfl_xor_sync(0xffffffffu, p0, off);
        p1 += __shfl_xor_sync(0xffffffffu, p1, off);
        p2 += __shfl_xor_sync(0xffffffffu, p2, off);
    }
    int w = t >> 5;
    if ((t & 31) == 0) { ws[w][0] = p0; ws[w][1] = p1; ws[w][2] = p2; }
    __syncthreads();
    if (t < 3) {
        float dot = ws[0][t] + ws[1][t] + ws[2][t] + ws[3][t] + b3[t];
        float val = coord[r * 3 + t] + 0.01f * tanhf(dot);
        int bi = bidx[r];
        out[r * 3 + t] = fminf(fmaxf(val, bmin[bi * 3 + t]), bmax[bi * 3 + t]);
    }
}

// ---------------- host ----------------
extern "C" void kernel_launch(void* const* d_in, const int* in_sizes, int n_in,
                              void* d_out, int out_size) {
    const int*   num_atoms  = (const int*)d_in[0];
    const int*   elems      = (const int*)d_in[1];
    const float* cell       = (const float*)d_in[2];
    const float* coord      = (const float*)d_in[3];
    const float* emb        = (const float*)d_in[4];
    const float* ln_in_g    = (const float*)d_in[5];
    const float* ln_in_b    = (const float*)d_in[6];
    const float* attn_in_w  = (const float*)d_in[7];
    const float* attn_in_b  = (const float*)d_in[8];
    const float* attn_out_w = (const float*)d_in[9];
    const float* attn_out_b = (const float*)d_in[10];
    const float* ce_w1      = (const float*)d_in[11];
    const float* ce_b1      = (const float*)d_in[12];
    const float* ce_w2      = (const float*)d_in[13];
    const float* ce_b2      = (const float*)d_in[14];
    const float* ln_feat_g  = (const float*)d_in[15];
    const float* ln_feat_b  = (const float*)d_in[16];
    const float* op_w1      = (const float*)d_in[17];
    const float* op_b1      = (const float*)d_in[18];
    const float* op_ln1_g   = (const float*)d_in[19];
    const float* op_ln1_b   = (const float*)d_in[20];
    const float* res_w1     = (const float*)d_in[21];
    const float* res_b1     = (const float*)d_in[22];
    const float* res_ln_g   = (const float*)d_in[23];
    const float* res_ln_b   = (const float*)d_in[24];
    const float* res_w2     = (const float*)d_in[25];
    const float* res_b2     = (const float*)d_in[26];
    const float* op_ln2_g   = (const float*)d_in[27];
    const float* op_ln2_b   = (const float*)d_in[28];
    const float* op_w3      = (const float*)d_in[29];
    const float* op_b3      = (const float*)d_in[30];
    float* out = (float*)d_out;

    float* S = nullptr;
    cudaGetSymbolAddress((void**)&S, g_scratch);
    int* bidx = nullptr;
    cudaGetSymbolAddress((void**)&bidx, g_bidx);

    float* x    = S;
    float* qkv  = x    + NATOMS * HDIM;
    float* ao   = qkv  + NATOMS * H3;
    float* xa   = ao   + NATOMS * HDIM;
    float* cf   = xa   + NATOMS * HDIM;
    float* comb = cf   + BATCH * HDIM;
    float* h0   = comb + NATOMS * FDIM;
    float* h1   = h0   + NATOMS * HDIM;
    float* tb   = h1   + NATOMS * HDIM;
    float* t2   = tb   + NATOMS * HDIM;
    float* hf   = t2   + NATOMS * HDIM;
    float* bmin = hf   + NATOMS * HDIM;
    float* bmax = bmin + BATCH * 3;

    prep_k<<<1, 128>>>(num_atoms, cell, bmin, bmax);
    embed_ln_k<<<NATOMS, 128>>>(elems, emb, ln_in_g, ln_in_b, x);
    sgemm_k<<<dim3(6, 64), 256>>>(x, attn_in_w, attn_in_b, nullptr, qkv, NATOMS, H3, HDIM);
    flash_k<<<dim3(64, NHEAD), 256>>>(qkv, ao);
    sgemm_k<<<dim3(2, 64), 256>>>(ao, attn_out_w, attn_out_b, nullptr, xa, NATOMS, HDIM, HDIM);
    cellenc_k<<<BATCH, 128>>>(cell, ce_w1, ce_b1, ce_w2, ce_b2, cf);
    comb_k<<<NATOMS, 256>>>(xa, cf, coord, bidx, ln_feat_g, ln_feat_b, comb);
    sgemm_k<<<dim3(2, 64), 256>>>(comb, op_w1, op_b1, nullptr, h0, NATOMS, HDIM, FDIM);
    row_ln_k<<<NATOMS, 128>>>(h0, h1, op_ln1_g, op_ln1_b, 1);
    sgemm_k<<<dim3(2, 64), 256>>>(h1, res_w1, res_b1, nullptr, tb, NATOMS, HDIM, HDIM);
    row_ln_k<<<NATOMS, 128>>>(tb, t2, res_ln_g, res_ln_b, 1);
    sgemm_k<<<dim3(2, 64), 256>>>(t2, res_w2, res_b2, h1, tb, NATOMS, HDIM, HDIM);
    row_ln_k<<<NATOMS, 128>>>(tb, hf, op_ln2_g, op_ln2_b, 0);
    final_k<<<NATOMS, 128>>>(hf, op_w3, op_b3, coord, bidx, bmin, bmax, out);
}

// round 2
// speedup vs baseline: 3.2461x; 3.2461x over previous
#include <cuda_runtime.h>
#include <cuda_bf16.h>
#include <math.h>
#include <stdint.h>

#define NATOMS 4096
#define HDIM   128
#define BATCH  128
#define NHEAD  4
#define DHEAD  32
#define FDIM   259
#define H3     384

// -------- scratch (no allocations allowed) --------
__device__ float g_scratch[8300000];
__device__ int   g_bidx[NATOMS];

// ---------------- helpers ----------------
__device__ __forceinline__ float blocksum128(float v, float* sm) {
    #pragma unroll
    for (int off = 16; off > 0; off >>= 1)
        v += __shfl_xor_sync(0xffffffffu, v, off);
    int w = threadIdx.x >> 5;
    __syncthreads();
    if ((threadIdx.x & 31) == 0) sm[w] = v;
    __syncthreads();
    return sm[0] + sm[1] + sm[2] + sm[3];
}

__device__ __forceinline__ float blocksum256(float v, float* sm) {
    #pragma unroll
    for (int off = 16; off > 0; off >>= 1)
        v += __shfl_xor_sync(0xffffffffu, v, off);
    int w = threadIdx.x >> 5;
    __syncthreads();
    if ((threadIdx.x & 31) == 0) sm[w] = v;
    __syncthreads();
    float t = 0.f;
    #pragma unroll
    for (int i = 0; i < 8; i++) t += sm[i];
    return t;
}

__device__ __forceinline__ float silu_f(float x) {
    return x / (1.f + __expf(-x));
}

// ---- mma / ldmatrix primitives ----
__device__ __forceinline__ void ldsm4(uint32_t& r0, uint32_t& r1, uint32_t& r2, uint32_t& r3, uint32_t addr) {
    asm volatile("ldmatrix.sync.aligned.m8n8.x4.shared.b16 {%0,%1,%2,%3}, [%4];"
                 : "=r"(r0), "=r"(r1), "=r"(r2), "=r"(r3) : "r"(addr));
}
__device__ __forceinline__ void ldsm4t(uint32_t& r0, uint32_t& r1, uint32_t& r2, uint32_t& r3, uint32_t addr) {
    asm volatile("ldmatrix.sync.aligned.m8n8.x4.trans.shared.b16 {%0,%1,%2,%3}, [%4];"
                 : "=r"(r0), "=r"(r1), "=r"(r2), "=r"(r3) : "r"(addr));
}
__device__ __forceinline__ void mma16816(float* d, const uint32_t* a, uint32_t b0, uint32_t b1) {
    asm volatile("mma.sync.aligned.m16n8k16.row.col.f32.bf16.bf16.f32 "
                 "{%0,%1,%2,%3}, {%4,%5,%6,%7}, {%8,%9}, {%0,%1,%2,%3};"
                 : "+f"(d[0]), "+f"(d[1]), "+f"(d[2]), "+f"(d[3])
                 : "r"(a[0]), "r"(a[1]), "r"(a[2]), "r"(a[3]), "r"(b0), "r"(b1));
}
__device__ __forceinline__ uint32_t packbf(float lo, float hi) {
    uint32_t r;
    asm volatile("cvt.rn.bf16x2.f32 %0, %1, %2;" : "=r"(r) : "f"(hi), "f"(lo));
    return r;
}

// ---------------- prep: bidx + clamp bounds ----------------
__global__ void prep_k(const int* __restrict__ num_atoms,
                       const float* __restrict__ cell,
                       float* __restrict__ bmin, float* __restrict__ bmax) {
    __shared__ int starts[BATCH + 1];
    int t = threadIdx.x;
    if (t == 0) {
        int acc = 0;
        for (int i = 0; i < BATCH; i++) { starts[i] = acc; acc += num_atoms[i]; }
        starts[BATCH] = acc;
    }
    __syncthreads();
    for (int i = t; i < NATOMS; i += 128) g_bidx[i] = BATCH - 1;
    __syncthreads();
    int s = starts[t], e = starts[t + 1];
    if (s > NATOMS) s = NATOMS;
    if (e > NATOMS) e = NATOMS;
    for (int i = s; i < e; i++) g_bidx[i] = t;
    #pragma unroll
    for (int i = 0; i < 3; i++) {
        float a = cell[(3 * t + i) * 3 + 0];
        float b = cell[(3 * t + i) * 3 + 1];
        float c = cell[(3 * t + i) * 3 + 2];
        bmin[t * 3 + i] = fminf(a, fminf(b, c)) + 1e-6f;
        bmax[t * 3 + i] = fmaxf(a, fmaxf(b, c)) - 1e-6f;
    }
}

// ---------------- embed + input LN ----------------
__global__ void embed_ln_k(const int* __restrict__ elems, const float* __restrict__ emb,
                           const float* __restrict__ g, const float* __restrict__ b,
                           float* __restrict__ xo) {
    __shared__ float sm[4];
    int r = blockIdx.x, t = threadIdx.x;
    float v = emb[elems[r] * HDIM + t];
    float mean = blocksum128(v, sm) * (1.f / 128.f);
    float d = v - mean;
    float var = blocksum128(d * d, sm) * (1.f / 128.f);
    xo[r * HDIM + t] = d * rsqrtf(var + 1e-5f) * g[t] + b[t];
}

// ---------------- row LN (width 128) with optional silu ----------------
__global__ void row_ln_k(const float* __restrict__ in, float* __restrict__ out,
                         const float* __restrict__ g, const float* __restrict__ b,
                         int dosilu) {
    __shared__ float sm[4];
    int r = blockIdx.x, t = threadIdx.x;
    float v = in[r * HDIM + t];
    float mean = blocksum128(v, sm) * (1.f / 128.f);
    float d = v - mean;
    float var = blocksum128(d * d, sm) * (1.f / 128.f);
    float y = d * rsqrtf(var + 1e-5f) * g[t] + b[t];
    if (dosilu) y = silu_f(y);
    out[r * HDIM + t] = y;
}

// ---------------- tiled SGEMM: C = A[M,K] @ W[K,N] + bias (+res) ----------------
__global__ void sgemm_k(const float* __restrict__ A, const float* __restrict__ W,
                        const float* __restrict__ bias, const float* __restrict__ res,
                        float* __restrict__ C, int M, int N, int K) {
    __shared__ float As[16 * 68];
    __shared__ float Bs[16 * 64];
    int tid = threadIdx.x;
    int tx = tid & 15, ty = tid >> 4;
    int bn = blockIdx.x, bm = blockIdx.y;
    float acc[16];
    #pragma unroll
    for (int i = 0; i < 16; i++) acc[i] = 0.f;
    int ktiles = (K + 15) >> 4;
    for (int kt = 0; kt < ktiles; kt++) {
        int k0 = kt << 4;
        #pragma unroll
        for (int i = 0; i < 4; i++) {
            int flat = tid + i * 256;
            int r = flat >> 4, kk = flat & 15;
            int gk = k0 + kk;
            As[kk * 68 + r] = (gk < K) ? A[(bm * 64 + r) * K + gk] : 0.f;
        }
        #pragma unroll
        for (int i = 0; i < 4; i++) {
            int flat = tid + i * 256;
            int kk = flat >> 6, c = flat & 63;
            int gk = k0 + kk;
            Bs[kk * 64 + c] = (gk < K) ? W[gk * N + bn * 64 + c] : 0.f;
        }
        __syncthreads();
        #pragma unroll
        for (int kk = 0; kk < 16; kk++) {
            float4 a4 = *(const float4*)&As[kk * 68 + ty * 4];
            float4 b4 = *(const float4*)&Bs[kk * 64 + tx * 4];
            acc[0]  += a4.x * b4.x; acc[1]  += a4.x * b4.y; acc[2]  += a4.x * b4.z; acc[3]  += a4.x * b4.w;
            acc[4]  += a4.y * b4.x; acc[5]  += a4.y * b4.y; acc[6]  += a4.y * b4.z; acc[7]  += a4.y * b4.w;
            acc[8]  += a4.z * b4.x; acc[9]  += a4.z * b4.y; acc[10] += a4.z * b4.z; acc[11] += a4.z * b4.w;
            acc[12] += a4.w * b4.x; acc[13] += a4.w * b4.y; acc[14] += a4.w * b4.z; acc[15] += a4.w * b4.w;
        }
        __syncthreads();
    }
    #pragma unroll
    for (int i = 0; i < 4; i++) {
        int r = bm * 64 + ty * 4 + i;
        #pragma unroll
        for (int j = 0; j < 4; j++) {
            int c = bn * 64 + tx * 4 + j;
            float v = acc[i * 4 + j] + bias[c];
            if (res) v += res[r * N + c];
            C[r * N + c] = v;
        }
    }
}

// ---------------- convert qkv (fp32 [N,384]) -> per-head bf16 Q,K,V [h][N][32] ----------------
__global__ void cvt_qkv_k(const float* __restrict__ qkv,
                          __nv_bfloat16* __restrict__ Qh,
                          __nv_bfloat16* __restrict__ Kh,
                          __nv_bfloat16* __restrict__ Vh) {
    int idx = blockIdx.x * 256 + threadIdx.x;
    int n = idx / H3, c = idx % H3;
    int type = c >> 7, cc = c & 127;
    int h = cc >> 5, d = cc & 31;
    float v = qkv[idx];
    int dst = ((h << 12) + n) * 32 + d;
    if (type == 0)      Qh[dst] = __float2bfloat16(v * 0.17677669529663687f);
    else if (type == 1) Kh[dst] = __float2bfloat16(v);
    else                Vh[dst] = __float2bfloat16(v);
}

// ---------------- bf16 tensor-core flash attention ----------------
// grid (64 qblocks, 4 heads), 128 threads (4 warps). 64 q rows/CTA, warp = 16 rows.
// SMEM: Q [64][40] bf16, double-buffered K/V [64][40] bf16 each.
#define KVSTRIDE 80   // bytes per row (32 bf16 + 8 pad)
#define KVBUF    5120 // 64 * 80

__device__ __forceinline__ void kv_load(const __nv_bfloat16* __restrict__ Kh,
                                        const __nv_bfloat16* __restrict__ Vh,
                                        int h, int kb, uint32_t sbase, int tid) {
    #pragma unroll
    for (int i = 0; i < 4; i++) {
        int s = tid + i * 128;
        int row = (s >> 2) & 63, seg = s & 3;
        const __nv_bfloat16* src = ((s < 256) ? Kh : Vh)
            + (((h << 12) + (kb << 6) + row) << 5) + seg * 8;
        uint32_t dst = sbase + ((s < 256) ? 0 : KVBUF) + row * KVSTRIDE + seg * 16;
        asm volatile("cp.async.ca.shared.global [%0], [%1], 16;" :: "r"(dst), "l"(src));
    }
    asm volatile("cp.async.commit_group;");
}

__global__ void __launch_bounds__(128) flashb_k(const __nv_bfloat16* __restrict__ Qh,
                                                const __nv_bfloat16* __restrict__ Kh,
                                                const __nv_bfloat16* __restrict__ Vh,
                                                float* __restrict__ ao) {
    __shared__ __align__(16) char smem[KVBUF + 4 * KVBUF];  // Q + 2x(K+V)
    const int tid = threadIdx.x, lane = tid & 31, warp = tid >> 5;
    const int h = blockIdx.y, qb = blockIdx.x;

    char* Qs = smem;
    uint32_t Qsa = (uint32_t)__cvta_generic_to_shared(Qs);
    uint32_t kva0 = Qsa + KVBUF;          // buf0: K then V
    uint32_t kva1 = Qsa + 3 * KVBUF;      // buf1

    // load Q tile (fp -> already bf16 w/ scale): 64 rows x 64B
    #pragma unroll
    for (int i = 0; i < 2; i++) {
        int s = tid + i * 128;
        int row = s >> 2, seg = s & 3;
        uint4 v = *(const uint4*)(Qh + (((h << 12) + (qb << 6) + row) << 5) + seg * 8);
        *(uint4*)(Qs + row * KVSTRIDE + seg * 16) = v;
    }
    kv_load(Kh, Vh, h, 0, kva0, tid);
    kv_load(Kh, Vh, h, 1, kva1, tid);
    __syncthreads();

    // Q fragments: 2 k-halves x 4 regs
    uint32_t qa[8];
    {
        int i = lane & 7, sel = lane >> 3;
        int row = warp * 16 + ((sel & 1) ? 8 : 0) + i;
        uint32_t a = Qsa + row * KVSTRIDE + ((sel >> 1) ? 16 : 0);
        ldsm4(qa[0], qa[1], qa[2], qa[3], a);
        ldsm4(qa[4], qa[5], qa[6], qa[7], a + 32);
    }

    float m0 = -1e30f, m1 = -1e30f, l0 = 0.f, l1 = 0.f;
    float o[4][4];
    #pragma unroll
    for (int j = 0; j < 4; j++)
        #pragma unroll
        for (int c = 0; c < 4; c++) o[j][c] = 0.f;

    const int i7 = lane & 7, sel = lane >> 3;
    const uint32_t krow = ((sel >= 2) ? 8 : 0) + i7;
    const uint32_t kcol = (sel & 1) ? 16 : 0;
    const uint32_t vrow = ((sel & 1) ? 8 : 0) + i7;
    const uint32_t vcol = (sel >= 2) ? 16 : 0;

    for (int kb = 0; kb < 64; kb++) {
        if (kb < 63) asm volatile("cp.async.wait_group 1;");
        else         asm volatile("cp.async.wait_group 0;");
        __syncthreads();
        uint32_t Kbase = (kb & 1) ? kva1 : kva0;
        uint32_t Vbase = Kbase + KVBUF;

        // ---- S = Q @ K^T : 8 n8-tiles ----
        float s[8][4];
        #pragma unroll
        for (int j = 0; j < 8; j++)
            #pragma unroll
            for (int c = 0; c < 4; c++) s[j][c] = 0.f;

        #pragma unroll
        for (int jp = 0; jp < 4; jp++) {
            uint32_t a = Kbase + (jp * 16 + krow) * KVSTRIDE + kcol;
            uint32_t b0, b1, b2, b3, c0, c1, c2, c3;
            ldsm4(b0, b1, b2, b3, a);        // k 0-15, tiles 2jp / 2jp+1
            ldsm4(c0, c1, c2, c3, a + 32);   // k 16-31
            mma16816(s[2 * jp],     qa,     b0, b1);
            mma16816(s[2 * jp],     qa + 4, c0, c1);
            mma16816(s[2 * jp + 1], qa,     b2, b3);
            mma16816(s[2 * jp + 1], qa + 4, c2, c3);
        }

        // ---- online softmax (rows g and g+8) ----
        float mx0 = -1e30f, mx1 = -1e30f;
        #pragma unroll
        for (int j = 0; j < 8; j++) {
            mx0 = fmaxf(mx0, fmaxf(s[j][0], s[j][1]));
            mx1 = fmaxf(mx1, fmaxf(s[j][2], s[j][3]));
        }
        mx0 = fmaxf(mx0, __shfl_xor_sync(0xffffffffu, mx0, 1));
        mx0 = fmaxf(mx0, __shfl_xor_sync(0xffffffffu, mx0, 2));
        mx1 = fmaxf(mx1, __shfl_xor_sync(0xffffffffu, mx1, 1));
        mx1 = fmaxf(mx1, __shfl_xor_sync(0xffffffffu, mx1, 2));
        float mn0 = fmaxf(m0, mx0), mn1 = fmaxf(m1, mx1);
        float f0 = __expf(m0 - mn0), f1 = __expf(m1 - mn1);
        m0 = mn0; m1 = mn1;
        float sum0 = 0.f, sum1 = 0.f;
        #pragma unroll
        for (int j = 0; j < 8; j++) {
            s[j][0] = __expf(s[j][0] - mn0);
            s[j][1] = __expf(s[j][1] - mn0);
            s[j][2] = __expf(s[j][2] - mn1);
            s[j][3] = __expf(s[j][3] - mn1);
            sum0 += s[j][0] + s[j][1];
            sum1 += s[j][2] + s[j][3];
        }
        sum0 += __shfl_xor_sync(0xffffffffu, sum0, 1);
        sum0 += __shfl_xor_sync(0xffffffffu, sum0, 2);
        sum1 += __shfl_xor_sync(0xffffffffu, sum1, 1);
        sum1 += __shfl_xor_sync(0xffffffffu, sum1, 2);
        l0 = l0 * f0 + sum0;
        l1 = l1 * f1 + sum1;
        #pragma unroll
        for (int j = 0; j < 4; j++) {
            o[j][0] *= f0; o[j][1] *= f0;
            o[j][2] *= f1; o[j][3] *= f1;
        }

        // ---- O += P @ V : 4 k-steps of 16 keys ----
        #pragma unroll
        for (int ks = 0; ks < 4; ks++) {
            uint32_t pa[4];
            pa[0] = packbf(s[2 * ks][0],     s[2 * ks][1]);
            pa[1] = packbf(s[2 * ks][2],     s[2 * ks][3]);
            pa[2] = packbf(s[2 * ks + 1][0], s[2 * ks + 1][1]);
            pa[3] = packbf(s[2 * ks + 1][2], s[2 * ks + 1][3]);
            uint32_t a = Vbase + (ks * 16 + vrow) * KVSTRIDE + vcol;
            uint32_t v0, v1, v2, v3, w0, w1, w2, w3;
            ldsm4t(v0, v1, v2, v3, a);        // d 0-15 (n-tiles 0,1)
            ldsm4t(w0, w1, w2, w3, a + 32);   // d 16-31 (n-tiles 2,3)
            mma16816(o[0], pa, v0, v1);
            mma16816(o[1], pa, v2, v3);
            mma16816(o[2], pa, w0, w1);
            mma16816(o[3], pa, w2, w3);
        }

        __syncthreads();
        if (kb < 62) kv_load(Kh, Vh, h, kb + 2, (kb & 1) ? kva1 : kva0, tid);
    }

    // ---- epilogue ----
    float inv0 = 1.f / l0, inv1 = 1.f / l1;
    int g = lane >> 2, l2 = (lane & 3) * 2;
    int row0 = (qb << 6) + warp * 16 + g;
    #pragma unroll
    for (int j = 0; j < 4; j++) {
        int col = (h << 5) + j * 8 + l2;
        *(float2*)&ao[row0 * HDIM + col]       = make_float2(o[j][0] * inv0, o[j][1] * inv0);
        *(float2*)&ao[(row0 + 8) * HDIM + col] = make_float2(o[j][2] * inv1, o[j][3] * inv1);
    }
}

// ---------------- cell encoder ----------------
__global__ void cellenc_k(const float* __restrict__ cell,
                          const float* __restrict__ w1, const float* __restrict__ b1,
                          const float* __restrict__ w2, const float* __restrict__ b2,
                          float* __restrict__ cf) {
    __shared__ float t1[128];
    int r = blockIdx.x, t = threadIdx.x;
    float c0 = cell[r * 3 + 0], c1 = cell[r * 3 + 1], c2 = cell[r * 3 + 2];
    float u = c0 * w1[0 * HDIM + t] + c1 * w1[1 * HDIM + t] + c2 * w1[2 * HDIM + t] + b1[t];
    t1[t] = silu_f(u);
    __syncthreads();
    float acc = b2[t];
    #pragma unroll 8
    for (int k = 0; k < 128; k++) acc += t1[k] * w2[k * HDIM + t];
    cf[r * HDIM + t] = acc;
}

// ---------------- comb = LN(concat(xa, cf[bidx], coord)) ----------------
__global__ void comb_k(const float* __restrict__ xa, const float* __restrict__ cf,
                       const float* __restrict__ coord, const int* __restrict__ bidx,
                       const float* __restrict__ g, const float* __restrict__ b,
                       float* __restrict__ comb) {
    __shared__ float sm[8];
    int r = blockIdx.x, t = threadIdx.x;
    int bi = bidx[r];
    float v0 = (t < 128) ? xa[r * HDIM + t] : cf[bi * HDIM + (t - 128)];
    bool has1 = (t < 3);
    float v1 = has1 ? coord[r * 3 + t] : 0.f;
    float total = blocksum256(v0 + v1, sm);
    float mean = total * (1.f / 259.f);
    float d0 = v0 - mean;
    float d1 = has1 ? (v1 - mean) : 0.f;
    float var = blocksum256(d0 * d0 + d1 * d1, sm) * (1.f / 259.f);
    float inv = rsqrtf(var + 1e-5f);
    comb[r * FDIM + t] = d0 * inv * g[t] + b[t];
    if (has1) comb[r * FDIM + 256 + t] = d1 * inv * g[256 + t] + b[256 + t];
}

// ---------------- final ----------------
__global__ void final_k(const float* __restrict__ hf, const float* __restrict__ w3,
                        const float* __restrict__ b3, const float* __restrict__ coord,
                        const int* __restrict__ bidx,
                        const float* __restrict__ bmin, const float* __restrict__ bmax,
                        float* __restrict__ out) {
    __shared__ float ws[4][3];
    int r = blockIdx.x, t = threadIdx.x;
    float h = hf[r * HDIM + t];
    float p0 = h * w3[t * 3 + 0];
    float p1 = h * w3[t * 3 + 1];
    float p2 = h * w3[t * 3 + 2];
    #pragma unroll
    for (int off = 16; off > 0; off >>= 1) {
        p0 += __shfl_xor_sync(0xffffffffu, p0, off);
        p1 += __shfl_xor_sync(0xffffffffu, p1, off);
        p2 += __shfl_xor_sync(0xffffffffu, p2, off);
    }
    int w = t >> 5;
    if ((t & 31) == 0) { ws[w][0] = p0; ws[w][1] = p1; ws[w][2] = p2; }
    __syncthreads();
    if (t < 3) {
        float dot = ws[0][t] + ws[1][t] + ws[2][t] + ws[3][t] + b3[t];
        float val = coord[r * 3 + t] + 0.01f * tanhf(dot);
        int bi = bidx[r];
        out[r * 3 + t] = fminf(fmaxf(val, bmin[bi * 3 + t]), bmax[bi * 3 + t]);
    }
}

// ---------------- host ----------------
extern "C" void kernel_launch(void* const* d_in, const int* in_sizes, int n_in,
                              void* d_out, int out_size) {
    const int*   num_atoms  = (const int*)d_in[0];
    const int*   elems      = (const int*)d_in[1];
    const float* cell       = (const float*)d_in[2];
    const float* coord      = (const float*)d_in[3];
    const float* emb        = (const float*)d_in[4];
    const float* ln_in_g    = (const float*)d_in[5];
    const float* ln_in_b    = (const float*)d_in[6];
    const float* attn_in_w  = (const float*)d_in[7];
    const float* attn_in_b  = (const float*)d_in[8];
    const float* attn_out_w = (const float*)d_in[9];
    const float* attn_out_b = (const float*)d_in[10];
    const float* ce_w1      = (const float*)d_in[11];
    const float* ce_b1      = (const float*)d_in[12];
    const float* ce_w2      = (const float*)d_in[13];
    const float* ce_b2      = (const float*)d_in[14];
    const float* ln_feat_g  = (const float*)d_in[15];
    const float* ln_feat_b  = (const float*)d_in[16];
    const float* op_w1      = (const float*)d_in[17];
    const float* op_b1      = (const float*)d_in[18];
    const float* op_ln1_g   = (const float*)d_in[19];
    const float* op_ln1_b   = (const float*)d_in[20];
    const float* res_w1     = (const float*)d_in[21];
    const float* res_b1     = (const float*)d_in[22];
    const float* res_ln_g   = (const float*)d_in[23];
    const float* res_ln_b   = (const float*)d_in[24];
    const float* res_w2     = (const float*)d_in[25];
    const float* res_b2     = (const float*)d_in[26];
    const float* op_ln2_g   = (const float*)d_in[27];
    const float* op_ln2_b   = (const float*)d_in[28];
    const float* op_w3      = (const float*)d_in[29];
    const float* op_b3      = (const float*)d_in[30];
    float* out = (float*)d_out;

    float* S = nullptr;
    cudaGetSymbolAddress((void**)&S, g_scratch);
    int* bidx = nullptr;
    cudaGetSymbolAddress((void**)&bidx, g_bidx);

    float* x    = S;
    float* qkv  = x    + NATOMS * HDIM;
    float* ao   = qkv  + NATOMS * H3;
    float* xa   = ao   + NATOMS * HDIM;
    float* cf   = xa   + NATOMS * HDIM;
    float* comb = cf   + BATCH * HDIM;
    float* h0   = comb + NATOMS * FDIM;
    float* h1   = h0   + NATOMS * HDIM;
    float* tb   = h1   + NATOMS * HDIM;
    float* t2   = tb   + NATOMS * HDIM;
    float* hf   = t2   + NATOMS * HDIM;
    float* bmin = hf   + NATOMS * HDIM;
    float* bmax = bmin + BATCH * 3;
    __nv_bfloat16* Qh = (__nv_bfloat16*)(bmax + BATCH * 3 + 16);
    __nv_bfloat16* Kh = Qh + NHEAD * NATOMS * DHEAD;
    __nv_bfloat16* Vh = Kh + NHEAD * NATOMS * DHEAD;

    prep_k<<<1, 128>>>(num_atoms, cell, bmin, bmax);
    embed_ln_k<<<NATOMS, 128>>>(elems, emb, ln_in_g, ln_in_b, x);
    sgemm_k<<<dim3(6, 64), 256>>>(x, attn_in_w, attn_in_b, nullptr, qkv, NATOMS, H3, HDIM);
    cvt_qkv_k<<<(NATOMS * H3) / 256, 256>>>(qkv, Qh, Kh, Vh);
    flashb_k<<<dim3(64, NHEAD), 128>>>(Qh, Kh, Vh, ao);
    sgemm_k<<<dim3(2, 64), 256>>>(ao, attn_out_w, attn_out_b, nullptr, xa, NATOMS, HDIM, HDIM);
    cellenc_k<<<BATCH, 128>>>(cell, ce_w1, ce_b1, ce_w2, ce_b2, cf);
    comb_k<<<NATOMS, 256>>>(xa, cf, coord, bidx, ln_feat_g, ln_feat_b, comb);
    sgemm_k<<<dim3(2, 64), 256>>>(comb, op_w1, op_b1, nullptr, h0, NATOMS, HDIM, FDIM);
    row_ln_k<<<NATOMS, 128>>>(h0, h1, op_ln1_g, op_ln1_b, 1);
    sgemm_k<<<dim3(2, 64), 256>>>(h1, res_w1, res_b1, nullptr, tb, NATOMS, HDIM, HDIM);
    row_ln_k<<<NATOMS, 128>>>(tb, t2, res_ln_g, res_ln_b, 1);
    sgemm_k<<<dim3(2, 64), 256>>>(t2, res_w2, res_b2, h1, tb, NATOMS, HDIM, HDIM);
    row_ln_k<<<NATOMS, 128>>>(tb, hf, op_ln2_g, op_ln2_b, 0);
    final_k<<<NATOMS, 128>>>(hf, op_w3, op_b3, coord, bidx, bmin, bmax, out);
}

// round 3
// speedup vs baseline: 4.8710x; 1.5006x over previous
#include <cuda_runtime.h>
#include <cuda_bf16.h>
#include <math.h>
#include <stdint.h>

#define NATOMS 4096
#define HDIM   128
#define BATCH  128
#define NHEAD  4
#define DHEAD  32
#define H3     384
#define FPAD   288   // padded feature dim for comb (259 -> 288)

// -------- scratch (no allocations allowed) --------
__device__ float g_scratch[8300000];
__device__ int   g_bidx[NATOMS];

// ---------------- helpers ----------------
__device__ __forceinline__ float blocksum128(float v, float* sm) {
    #pragma unroll
    for (int off = 16; off > 0; off >>= 1)
        v += __shfl_xor_sync(0xffffffffu, v, off);
    int w = threadIdx.x >> 5;
    __syncthreads();
    if ((threadIdx.x & 31) == 0) sm[w] = v;
    __syncthreads();
    return sm[0] + sm[1] + sm[2] + sm[3];
}

__device__ __forceinline__ float silu_f(float x) {
    return x / (1.f + __expf(-x));
}

// ---- mma / ldmatrix primitives ----
__device__ __forceinline__ void ldsm4(uint32_t& r0, uint32_t& r1, uint32_t& r2, uint32_t& r3, uint32_t addr) {
    asm volatile("ldmatrix.sync.aligned.m8n8.x4.shared.b16 {%0,%1,%2,%3}, [%4];"
                 : "=r"(r0), "=r"(r1), "=r"(r2), "=r"(r3) : "r"(addr));
}
__device__ __forceinline__ void ldsm4t(uint32_t& r0, uint32_t& r1, uint32_t& r2, uint32_t& r3, uint32_t addr) {
    asm volatile("ldmatrix.sync.aligned.m8n8.x4.trans.shared.b16 {%0,%1,%2,%3}, [%4];"
                 : "=r"(r0), "=r"(r1), "=r"(r2), "=r"(r3) : "r"(addr));
}
__device__ __forceinline__ void mma16816(float* d, const uint32_t* a, uint32_t b0, uint32_t b1) {
    asm volatile("mma.sync.aligned.m16n8k16.row.col.f32.bf16.bf16.f32 "
                 "{%0,%1,%2,%3}, {%4,%5,%6,%7}, {%8,%9}, {%0,%1,%2,%3};"
                 : "+f"(d[0]), "+f"(d[1]), "+f"(d[2]), "+f"(d[3])
                 : "r"(a[0]), "r"(a[1]), "r"(a[2]), "r"(a[3]), "r"(b0), "r"(b1));
}
__device__ __forceinline__ uint32_t packbf(float lo, float hi) {
    uint32_t r;
    asm volatile("cvt.rn.bf16x2.f32 %0, %1, %2;" : "=r"(r) : "f"(hi), "f"(lo));
    return r;
}
__device__ __forceinline__ void cpa16(uint32_t dst, const void* src) {
    asm volatile("cp.async.ca.shared.global [%0], [%1], 16;" :: "r"(dst), "l"(src));
}

// ---------------- prep: bidx + clamp bounds ----------------
__global__ void prep_k(const int* __restrict__ num_atoms,
                       const float* __restrict__ cell,
                       float* __restrict__ bmin, float* __restrict__ bmax) {
    __shared__ int starts[BATCH + 1];
    int t = threadIdx.x;
    if (t == 0) {
        int acc = 0;
        for (int i = 0; i < BATCH; i++) { starts[i] = acc; acc += num_atoms[i]; }
        starts[BATCH] = acc;
    }
    __syncthreads();
    for (int i = t; i < NATOMS; i += 128) g_bidx[i] = BATCH - 1;
    __syncthreads();
    int s = starts[t], e = starts[t + 1];
    if (s > NATOMS) s = NATOMS;
    if (e > NATOMS) e = NATOMS;
    for (int i = s; i < e; i++) g_bidx[i] = t;
    #pragma unroll
    for (int i = 0; i < 3; i++) {
        float a = cell[(3 * t + i) * 3 + 0];
        float b = cell[(3 * t + i) * 3 + 1];
        float c = cell[(3 * t + i) * 3 + 2];
        bmin[t * 3 + i] = fminf(a, fminf(b, c)) + 1e-6f;
        bmax[t * 3 + i] = fmaxf(a, fmaxf(b, c)) - 1e-6f;
    }
}

// ---------------- weight conversion to bf16 (op_w1 zero-padded to 288 rows) ----------------
__global__ void cvtw_k(const float* __restrict__ aiw, const float* __restrict__ aow,
                       const float* __restrict__ opw1, const float* __restrict__ rw1,
                       const float* __restrict__ rw2,
                       __nv_bfloat16* __restrict__ wqkv, __nv_bfloat16* __restrict__ wao,
                       __nv_bfloat16* __restrict__ wop1, __nv_bfloat16* __restrict__ wr1,
                       __nv_bfloat16* __restrict__ wr2) {
    int i = blockIdx.x * 256 + threadIdx.x;
    if (i < 49152) wqkv[i] = __float2bfloat16(aiw[i]);
    else if (i < 65536) { int j = i - 49152; wao[j] = __float2bfloat16(aow[j]); }
    else if (i < 102400) {
        int j = i - 65536; int r = j >> 7, c = j & 127;
        wop1[j] = __float2bfloat16(r < 259 ? opw1[r * 128 + c] : 0.f);
    }
    else if (i < 118784) { int j = i - 102400; wr1[j] = __float2bfloat16(rw1[j]); }
    else if (i < 135168) { int j = i - 118784; wr2[j] = __float2bfloat16(rw2[j]); }
}

// ---------------- embed + input LN -> bf16 ----------------
__global__ void embed_ln_k(const int* __restrict__ elems, const float* __restrict__ emb,
                           const float* __restrict__ g, const float* __restrict__ b,
                           __nv_bfloat16* __restrict__ xo) {
    __shared__ float sm[4];
    int r = blockIdx.x, t = threadIdx.x;
    float v = emb[elems[r] * HDIM + t];
    float mean = blocksum128(v, sm) * (1.f / 128.f);
    float d = v - mean;
    float var = blocksum128(d * d, sm) * (1.f / 128.f);
    xo[r * HDIM + t] = __float2bfloat16(d * rsqrtf(var + 1e-5f) * g[t] + b[t]);
}

// ---------------- cell encoder (fp32 cf) ----------------
__global__ void cellenc_k(const float* __restrict__ cell,
                          const float* __restrict__ w1, const float* __restrict__ b1,
                          const float* __restrict__ w2, const float* __restrict__ b2,
                          float* __restrict__ cf) {
    __shared__ float t1[128];
    int r = blockIdx.x, t = threadIdx.x;
    float c0 = cell[r * 3 + 0], c1 = cell[r * 3 + 1], c2 = cell[r * 3 + 2];
    float u = c0 * w1[0 * HDIM + t] + c1 * w1[1 * HDIM + t] + c2 * w1[2 * HDIM + t] + b1[t];
    t1[t] = silu_f(u);
    __syncthreads();
    float acc = b2[t];
    #pragma unroll 8
    for (int k = 0; k < 128; k++) acc += t1[k] * w2[k * HDIM + t];
    cf[r * HDIM + t] = acc;
}

// ============ bf16 tensor-core GEMM with fused epilogues ============
// 128 threads (4 warps in 2x2), BM=32, BN=128, BK=32, double-buffered cp.async.
// EPI 0: QKV  — write per-head bf16 Q(scaled)/K/V  (grid.x = 3 col blocks)
// EPI 1: COMB — xa + bias, then LN over [xa|cf[bidx]|coord] (259), write comb bf16 [M,288]
// EPI 2: LN(+g,b) + SiLU -> bf16 [M,128]
// EPI 3: +resid, LN, fused proj w3 + tanh + clamp -> fout [M,3]
template<int KSTEPS, int EPI>
__global__ void __launch_bounds__(128) gemmb_k(
    const __nv_bfloat16* __restrict__ A, int lda,
    const __nv_bfloat16* __restrict__ W, int ldw,
    const float* __restrict__ bias,
    const float* __restrict__ e_g, const float* __restrict__ e_b,
    const __nv_bfloat16* __restrict__ resid,
    const float* __restrict__ cf, const float* __restrict__ coordp,
    const int* __restrict__ bidx,
    const float* __restrict__ w3, const float* __restrict__ b3,
    const float* __restrict__ bmin, const float* __restrict__ bmax,
    __nv_bfloat16* __restrict__ o0, __nv_bfloat16* __restrict__ o1,
    __nv_bfloat16* __restrict__ o2, float* __restrict__ fout)
{
    __shared__ __align__(16) char sA[2 * 32 * 80];     // A tiles
    __shared__ __align__(16) char sW[2 * 32 * 272];    // W tiles
    __shared__ __align__(16) float sS[32 * 136];       // staging for LN epilogues
    const int tid = threadIdx.x, lane = tid & 31, warp = tid >> 5;
    const int wr = warp & 1, wc = warp >> 1;
    const int bm = blockIdx.y, nb = blockIdx.x;
    uint32_t aBase = (uint32_t)__cvta_generic_to_shared(sA);
    uint32_t wBase = (uint32_t)__cvta_generic_to_shared(sW);

    // ---- tile loaders ----
    {
        // preload steps 0 and 1
        #pragma unroll
        for (int p = 0; p < 2; p++) {
            int row = tid >> 2, seg = tid & 3;
            cpa16(aBase + p * 2560 + row * 80 + seg * 16,
                  A + (bm * 32 + row) * lda + p * 32 + seg * 8);
            #pragma unroll
            for (int i = 0; i < 4; i++) {
                int s = tid + i * 128;
                int wrow = s >> 4, wseg = s & 15;
                cpa16(wBase + p * 8704 + wrow * 272 + wseg * 16,
                      W + (p * 32 + wrow) * ldw + nb * 128 + wseg * 8);
            }
            asm volatile("cp.async.commit_group;");
        }
    }

    float acc[8][4];
    #pragma unroll
    for (int j = 0; j < 8; j++)
        #pragma unroll
        for (int c = 0; c < 4; c++) acc[j][c] = 0.f;

    const int i7 = lane & 7, sel = lane >> 3;
    const int arow = wr * 16 + ((sel & 1) ? 8 : 0) + i7;
    const int acol = (sel >> 1) ? 16 : 0;
    const int vrow = ((sel & 1) ? 8 : 0) + i7;
    const int vcol = (sel >= 2) ? 16 : 0;

    for (int ks = 0; ks < KSTEPS; ks++) {
        if (ks < KSTEPS - 1) asm volatile("cp.async.wait_group 1;");
        else                 asm volatile("cp.async.wait_group 0;");
        __syncthreads();
        uint32_t Ab = aBase + (ks & 1) * 2560;
        uint32_t Wb = wBase + (ks & 1) * 8704;
        #pragma unroll
        for (int kh = 0; kh < 2; kh++) {
            uint32_t qa[4];
            ldsm4(qa[0], qa[1], qa[2], qa[3], Ab + arow * 80 + acol + kh * 32);
            #pragma unroll
            for (int j = 0; j < 4; j++) {
                uint32_t r0, r1, r2, r3;
                ldsm4t(r0, r1, r2, r3, Wb + (kh * 16 + vrow) * 272 + wc * 128 + j * 32 + vcol);
                mma16816(acc[2 * j],     qa, r0, r1);
                mma16816(acc[2 * j + 1], qa, r2, r3);
            }
        }
        __syncthreads();
        if (ks + 2 < KSTEPS) {
            int p = ks + 2, buf = ks & 1;
            int row = tid >> 2, seg = tid & 3;
            cpa16(aBase + buf * 2560 + row * 80 + seg * 16,
                  A + (bm * 32 + row) * lda + p * 32 + seg * 8);
            #pragma unroll
            for (int i = 0; i < 4; i++) {
                int s = tid + i * 128;
                int wrow = s >> 4, wseg = s & 15;
                cpa16(wBase + buf * 8704 + wrow * 272 + wseg * 16,
                      W + (p * 32 + wrow) * ldw + nb * 128 + wseg * 8);
            }
            asm volatile("cp.async.commit_group;");
        }
    }

    const int g = lane >> 2, c2 = (lane & 3) * 2;

    if (EPI == 0) {
        // ---- QKV epilogue: direct per-head bf16 stores ----
        int r0 = bm * 32 + wr * 16 + g;
        __nv_bfloat16* outp = (nb == 0) ? o0 : (nb == 1) ? o1 : o2;
        float sc = (nb == 0) ? 0.17677669529663687f : 1.f;
        #pragma unroll
        for (int t = 0; t < 8; t++) {
            int col = wc * 64 + t * 8 + c2;
            float b0v = bias[nb * 128 + col], b1v = bias[nb * 128 + col + 1];
            int h = col >> 5, d = col & 31;
            *(uint32_t*)(outp + (((h << 12) + r0) << 5) + d) =
                packbf((acc[t][0] + b0v) * sc, (acc[t][1] + b1v) * sc);
            *(uint32_t*)(outp + (((h << 12) + r0 + 8) << 5) + d) =
                packbf((acc[t][2] + b0v) * sc, (acc[t][3] + b1v) * sc);
        }
        return;
    }

    // ---- stage tile (bias and optional residual added) ----
    {
        int sr0 = wr * 16 + g;
        #pragma unroll
        for (int t = 0; t < 8; t++) {
            int col = wc * 64 + t * 8 + c2;
            float a0 = bias[col], a1 = bias[col + 1];
            float v00 = acc[t][0] + a0, v01 = acc[t][1] + a1;
            float v10 = acc[t][2] + a0, v11 = acc[t][3] + a1;
            if (EPI == 3) {
                int gr0 = (bm * 32 + sr0) * 128 + col;
                int gr1 = (bm * 32 + sr0 + 8) * 128 + col;
                v00 += __bfloat162float(resid[gr0]);
                v01 += __bfloat162float(resid[gr0 + 1]);
                v10 += __bfloat162float(resid[gr1]);
                v11 += __bfloat162float(resid[gr1 + 1]);
            }
            sS[sr0 * 136 + col] = v00; sS[sr0 * 136 + col + 1] = v01;
            sS[(sr0 + 8) * 136 + col] = v10; sS[(sr0 + 8) * 136 + col + 1] = v11;
        }
    }
    __syncthreads();

    const int row = tid >> 2, q = tid & 3;
    const int grow = bm * 32 + row;

    if (EPI == 1) {
        // ---- comb: LN over [xa(128) | cf[bidx](128) | coord(3)] ----
        int bi = bidx[grow];
        float xv[32], cv[32];
        #pragma unroll
        for (int i = 0; i < 8; i++) {
            float4 f = *(const float4*)&sS[row * 136 + q * 32 + i * 4];
            xv[4 * i] = f.x; xv[4 * i + 1] = f.y; xv[4 * i + 2] = f.z; xv[4 * i + 3] = f.w;
            float4 c = *(const float4*)&cf[bi * 128 + q * 32 + i * 4];
            cv[4 * i] = c.x; cv[4 * i + 1] = c.y; cv[4 * i + 2] = c.z; cv[4 * i + 3] = c.w;
        }
        float c0 = 0.f, c1 = 0.f, c2v = 0.f;
        float s = 0.f;
        #pragma unroll
        for (int i = 0; i < 32; i++) s += xv[i] + cv[i];
        if (q == 0) {
            c0 = coordp[grow * 3 + 0]; c1 = coordp[grow * 3 + 1]; c2v = coordp[grow * 3 + 2];
            s += c0 + c1 + c2v;
        }
        s += __shfl_xor_sync(0xffffffffu, s, 1);
        s += __shfl_xor_sync(0xffffffffu, s, 2);
        float mean = s * (1.f / 259.f);
        float sq = 0.f;
        #pragma unroll
        for (int i = 0; i < 32; i++) {
            float d0 = xv[i] - mean, d1 = cv[i] - mean;
            sq += d0 * d0 + d1 * d1;
        }
        if (q == 0) {
            float d0 = c0 - mean, d1 = c1 - mean, d2 = c2v - mean;
            sq += d0 * d0 + d1 * d1 + d2 * d2;
        }
        sq += __shfl_xor_sync(0xffffffffu, sq, 1);
        sq += __shfl_xor_sync(0xffffffffu, sq, 2);
        float inv = rsqrtf(sq * (1.f / 259.f) + 1e-5f);

        uint32_t pk[16];
        #pragma unroll
        for (int i = 0; i < 16; i++) {
            int ca = q * 32 + 2 * i;
            float y0 = (xv[2 * i] - mean) * inv * e_g[ca] + e_b[ca];
            float y1 = (xv[2 * i + 1] - mean) * inv * e_g[ca + 1] + e_b[ca + 1];
            pk[i] = packbf(y0, y1);
        }
        uint4* dst = (uint4*)(o0 + grow * FPAD + q * 32);
        dst[0] = *(uint4*)&pk[0]; dst[1] = *(uint4*)&pk[4];
        dst[2] = *(uint4*)&pk[8]; dst[3] = *(uint4*)&pk[12];
        #pragma unroll
        for (int i = 0; i < 16; i++) {
            int ca = 128 + q * 32 + 2 * i;
            float y0 = (cv[2 * i] - mean) * inv * e_g[ca] + e_b[ca];
            float y1 = (cv[2 * i + 1] - mean) * inv * e_g[ca + 1] + e_b[ca + 1];
            pk[i] = packbf(y0, y1);
        }
        dst = (uint4*)(o0 + grow * FPAD + 128 + q * 32);
        dst[0] = *(uint4*)&pk[0]; dst[1] = *(uint4*)&pk[4];
        dst[2] = *(uint4*)&pk[8]; dst[3] = *(uint4*)&pk[12];
        // tail cols 256..287: coord features + zero pad
        #pragma unroll
        for (int jj = 0; jj < 8; jj++) {
            int c = 256 + q * 8 + jj;
            float val = 0.f;
            if (c < 259) {
                float raw = (jj == 0) ? c0 : (jj == 1) ? c1 : c2v;
                val = (raw - mean) * inv * e_g[c] + e_b[c];
            }
            o0[grow * FPAD + c] = __float2bfloat16(val);
        }
        return;
    }

    // EPI 2 / 3: row LN over 128
    float v[32];
    #pragma unroll
    for (int i = 0; i < 8; i++) {
        float4 f = *(const float4*)&sS[row * 136 + q * 32 + i * 4];
        v[4 * i] = f.x; v[4 * i + 1] = f.y; v[4 * i + 2] = f.z; v[4 * i + 3] = f.w;
    }
    float s = 0.f;
    #pragma unroll
    for (int i = 0; i < 32; i++) s += v[i];
    s += __shfl_xor_sync(0xffffffffu, s, 1);
    s += __shfl_xor_sync(0xffffffffu, s, 2);
    float mean = s * (1.f / 128.f);
    float sq = 0.f;
    #pragma unroll
    for (int i = 0; i < 32; i++) { float d = v[i] - mean; sq += d * d; }
    sq += __shfl_xor_sync(0xffffffffu, sq, 1);
    sq += __shfl_xor_sync(0xffffffffu, sq, 2);
    float inv = rsqrtf(sq * (1.f / 128.f) + 1e-5f);

    if (EPI == 2) {
        uint32_t pk[16];
        #pragma unroll
        for (int i = 0; i < 16; i++) {
            int ca = q * 32 + 2 * i;
            float y0 = silu_f((v[2 * i] - mean) * inv * e_g[ca] + e_b[ca]);
            float y1 = silu_f((v[2 * i + 1] - mean) * inv * e_g[ca + 1] + e_b[ca + 1]);
            pk[i] = packbf(y0, y1);
        }
        uint4* dst = (uint4*)(o0 + grow * 128 + q * 32);
        dst[0] = *(uint4*)&pk[0]; dst[1] = *(uint4*)&pk[4];
        dst[2] = *(uint4*)&pk[8]; dst[3] = *(uint4*)&pk[12];
        return;
    }

    // EPI 3: LN then fused 128->3 projection + tanh + clamp
    float p0 = 0.f, p1 = 0.f, p2 = 0.f;
    #pragma unroll
    for (int i = 0; i < 32; i++) {
        int ca = q * 32 + i;
        float y = (v[i] - mean) * inv * e_g[ca] + e_b[ca];
        p0 += y * w3[ca * 3 + 0];
        p1 += y * w3[ca * 3 + 1];
        p2 += y * w3[ca * 3 + 2];
    }
    p0 += __shfl_xor_sync(0xffffffffu, p0, 1);
    p0 += __shfl_xor_sync(0xffffffffu, p0, 2);
    p1 += __shfl_xor_sync(0xffffffffu, p1, 1);
    p1 += __shfl_xor_sync(0xffffffffu, p1, 2);
    p2 += __shfl_xor_sync(0xffffffffu, p2, 1);
    p2 += __shfl_xor_sync(0xffffffffu, p2, 2);
    if (q == 0) {
        int bi = bidx[grow];
        float dots[3] = {p0 + b3[0], p1 + b3[1], p2 + b3[2]};
        #pragma unroll
        for (int j = 0; j < 3; j++) {
            float val = coordp[grow * 3 + j] + 0.01f * tanhf(dots[j]);
            fout[grow * 3 + j] = fminf(fmaxf(val, bmin[bi * 3 + j]), bmax[bi * 3 + j]);
        }
    }
}

// ---------------- bf16 tensor-core flash attention (ao -> bf16) ----------------
#define KVSTRIDE 80
#define KVBUF    5120

__device__ __forceinline__ void kv_load(const __nv_bfloat16* __restrict__ Kh,
                                        const __nv_bfloat16* __restrict__ Vh,
                                        int h, int kb, uint32_t sbase, int tid) {
    #pragma unroll
    for (int i = 0; i < 4; i++) {
        int s = tid + i * 128;
        int row = (s >> 2) & 63, seg = s & 3;
        const __nv_bfloat16* src = ((s < 256) ? Kh : Vh)
            + (((h << 12) + (kb << 6) + row) << 5) + seg * 8;
        uint32_t dst = sbase + ((s < 256) ? 0 : KVBUF) + row * KVSTRIDE + seg * 16;
        cpa16(dst, src);
    }
    asm volatile("cp.async.commit_group;");
}

__global__ void __launch_bounds__(128) flashb_k(const __nv_bfloat16* __restrict__ Qh,
                                                const __nv_bfloat16* __restrict__ Kh,
                                                const __nv_bfloat16* __restrict__ Vh,
                                                __nv_bfloat16* __restrict__ ao) {
    __shared__ __align__(16) char smem[KVBUF + 4 * KVBUF];
    const int tid = threadIdx.x, lane = tid & 31, warp = tid >> 5;
    const int h = blockIdx.y, qb = blockIdx.x;

    char* Qs = smem;
    uint32_t Qsa = (uint32_t)__cvta_generic_to_shared(Qs);
    uint32_t kva0 = Qsa + KVBUF;
    uint32_t kva1 = Qsa + 3 * KVBUF;

    #pragma unroll
    for (int i = 0; i < 2; i++) {
        int s = tid + i * 128;
        int row = s >> 2, seg = s & 3;
        uint4 v = *(const uint4*)(Qh + (((h << 12) + (qb << 6) + row) << 5) + seg * 8);
        *(uint4*)(Qs + row * KVSTRIDE + seg * 16) = v;
    }
    kv_load(Kh, Vh, h, 0, kva0, tid);
    kv_load(Kh, Vh, h, 1, kva1, tid);
    __syncthreads();

    uint32_t qa[8];
    {
        int i = lane & 7, sl = lane >> 3;
        int row = warp * 16 + ((sl & 1) ? 8 : 0) + i;
        uint32_t a = Qsa + row * KVSTRIDE + ((sl >> 1) ? 16 : 0);
        ldsm4(qa[0], qa[1], qa[2], qa[3], a);
        ldsm4(qa[4], qa[5], qa[6], qa[7], a + 32);
    }

    float m0 = -1e30f, m1 = -1e30f, l0 = 0.f, l1 = 0.f;
    float o[4][4];
    #pragma unroll
    for (int j = 0; j < 4; j++)
        #pragma unroll
        for (int c = 0; c < 4; c++) o[j][c] = 0.f;

    const int i7 = lane & 7, sel = lane >> 3;
    const uint32_t krow = ((sel >= 2) ? 8 : 0) + i7;
    const uint32_t kcol = (sel & 1) ? 16 : 0;
    const uint32_t vrow = ((sel & 1) ? 8 : 0) + i7;
    const uint32_t vcol = (sel >= 2) ? 16 : 0;

    for (int kb = 0; kb < 64; kb++) {
        if (kb < 63) asm volatile("cp.async.wait_group 1;");
        else         asm volatile("cp.async.wait_group 0;");
        __syncthreads();
        uint32_t Kbase = (kb & 1) ? kva1 : kva0;
        uint32_t Vbase = Kbase + KVBUF;

        float s[8][4];
        #pragma unroll
        for (int j = 0; j < 8; j++)
            #pragma unroll
            for (int c = 0; c < 4; c++) s[j][c] = 0.f;

        #pragma unroll
        for (int jp = 0; jp < 4; jp++) {
            uint32_t a = Kbase + (jp * 16 + krow) * KVSTRIDE + kcol;
            uint32_t b0, b1, b2, b3, c0, c1, c2, c3;
            ldsm4(b0, b1, b2, b3, a);
            ldsm4(c0, c1, c2, c3, a + 32);
            mma16816(s[2 * jp],     qa,     b0, b1);
            mma16816(s[2 * jp],     qa + 4, c0, c1);
            mma16816(s[2 * jp + 1], qa,     b2, b3);
            mma16816(s[2 * jp + 1], qa + 4, c2, c3);
        }

        float mx0 = -1e30f, mx1 = -1e30f;
        #pragma unroll
        for (int j = 0; j < 8; j++) {
            mx0 = fmaxf(mx0, fmaxf(s[j][0], s[j][1]));
            mx1 = fmaxf(mx1, fmaxf(s[j][2], s[j][3]));
        }
        mx0 = fmaxf(mx0, __shfl_xor_sync(0xffffffffu, mx0, 1));
        mx0 = fmaxf(mx0, __shfl_xor_sync(0xffffffffu, mx0, 2));
        mx1 = fmaxf(mx1, __shfl_xor_sync(0xffffffffu, mx1, 1));
        mx1 = fmaxf(mx1, __shfl_xor_sync(0xffffffffu, mx1, 2));
        float mn0 = fmaxf(m0, mx0), mn1 = fmaxf(m1, mx1);
        float f0 = __expf(m0 - mn0), f1 = __expf(m1 - mn1);
        m0 = mn0; m1 = mn1;
        float sum0 = 0.f, sum1 = 0.f;
        #pragma unroll
        for (int j = 0; j < 8; j++) {
            s[j][0] = __expf(s[j][0] - mn0);
            s[j][1] = __expf(s[j][1] - mn0);
            s[j][2] = __expf(s[j][2] - mn1);
            s[j][3] = __expf(s[j][3] - mn1);
            sum0 += s[j][0] + s[j][1];
            sum1 += s[j][2] + s[j][3];
        }
        sum0 += __shfl_xor_sync(0xffffffffu, sum0, 1);
        sum0 += __shfl_xor_sync(0xffffffffu, sum0, 2);
        sum1 += __shfl_xor_sync(0xffffffffu, sum1, 1);
        sum1 += __shfl_xor_sync(0xffffffffu, sum1, 2);
        l0 = l0 * f0 + sum0;
        l1 = l1 * f1 + sum1;
        #pragma unroll
        for (int j = 0; j < 4; j++) {
            o[j][0] *= f0; o[j][1] *= f0;
            o[j][2] *= f1; o[j][3] *= f1;
        }

        #pragma unroll
        for (int ks = 0; ks < 4; ks++) {
            uint32_t pa[4];
            pa[0] = packbf(s[2 * ks][0],     s[2 * ks][1]);
            pa[1] = packbf(s[2 * ks][2],     s[2 * ks][3]);
            pa[2] = packbf(s[2 * ks + 1][0], s[2 * ks + 1][1]);
            pa[3] = packbf(s[2 * ks + 1][2], s[2 * ks + 1][3]);
            uint32_t a = Vbase + (ks * 16 + vrow) * KVSTRIDE + vcol;
            uint32_t v0, v1, v2, v3, w0, w1, w2, w3;
            ldsm4t(v0, v1, v2, v3, a);
            ldsm4t(w0, w1, w2, w3, a + 32);
            mma16816(o[0], pa, v0, v1);
            mma16816(o[1], pa, v2, v3);
            mma16816(o[2], pa, w0, w1);
            mma16816(o[3], pa, w2, w3);
        }

        __syncthreads();
        if (kb < 62) kv_load(Kh, Vh, h, kb + 2, (kb & 1) ? kva1 : kva0, tid);
    }

    float inv0 = 1.f / l0, inv1 = 1.f / l1;
    int g = lane >> 2, l2 = (lane & 3) * 2;
    int row0 = (qb << 6) + warp * 16 + g;
    #pragma unroll
    for (int j = 0; j < 4; j++) {
        int col = (h << 5) + j * 8 + l2;
        *(uint32_t*)&ao[row0 * HDIM + col]       = packbf(o[j][0] * inv0, o[j][1] * inv0);
        *(uint32_t*)&ao[(row0 + 8) * HDIM + col] = packbf(o[j][2] * inv1, o[j][3] * inv1);
    }
}

// ---------------- host ----------------
extern "C" void kernel_launch(void* const* d_in, const int* in_sizes, int n_in,
                              void* d_out, int out_size) {
    const int*   num_atoms  = (const int*)d_in[0];
    const int*   elems      = (const int*)d_in[1];
    const float* cell       = (const float*)d_in[2];
    const float* coord      = (const float*)d_in[3];
    const float* emb        = (const float*)d_in[4];
    const float* ln_in_g    = (const float*)d_in[5];
    const float* ln_in_b    = (const float*)d_in[6];
    const float* attn_in_w  = (const float*)d_in[7];
    const float* attn_in_b  = (const float*)d_in[8];
    const float* attn_out_w = (const float*)d_in[9];
    const float* attn_out_b = (const float*)d_in[10];
    const float* ce_w1      = (const float*)d_in[11];
    const float* ce_b1      = (const float*)d_in[12];
    const float* ce_w2      = (const float*)d_in[13];
    const float* ce_b2      = (const float*)d_in[14];
    const float* ln_feat_g  = (const float*)d_in[15];
    const float* ln_feat_b  = (const float*)d_in[16];
    const float* op_w1      = (const float*)d_in[17];
    const float* op_b1      = (const float*)d_in[18];
    const float* op_ln1_g   = (const float*)d_in[19];
    const float* op_ln1_b   = (const float*)d_in[20];
    const float* res_w1     = (const float*)d_in[21];
    const float* res_b1     = (const float*)d_in[22];
    const float* res_ln_g   = (const float*)d_in[23];
    const float* res_ln_b   = (const float*)d_in[24];
    const float* res_w2     = (const float*)d_in[25];
    const float* res_b2     = (const float*)d_in[26];
    const float* op_ln2_g   = (const float*)d_in[27];
    const float* op_ln2_b   = (const float*)d_in[28];
    const float* op_w3      = (const float*)d_in[29];
    const float* op_b3      = (const float*)d_in[30];
    float* out = (float*)d_out;

    float* S = nullptr;
    cudaGetSymbolAddress((void**)&S, g_scratch);
    int* bidx = nullptr;
    cudaGetSymbolAddress((void**)&bidx, g_bidx);

    __nv_bfloat16* P = (__nv_bfloat16*)S;
    __nv_bfloat16* xb    = P; P += NATOMS * HDIM;
    __nv_bfloat16* Qh    = P; P += NATOMS * HDIM;
    __nv_bfloat16* Kh    = P; P += NATOMS * HDIM;
    __nv_bfloat16* Vh    = P; P += NATOMS * HDIM;
    __nv_bfloat16* aob   = P; P += NATOMS * HDIM;
    __nv_bfloat16* combb = P; P += NATOMS * FPAD;
    __nv_bfloat16* h1b   = P; P += NATOMS * HDIM;
    __nv_bfloat16* t2b   = P; P += NATOMS * HDIM;
    __nv_bfloat16* wqkv  = P; P += 128 * 384;
    __nv_bfloat16* wao   = P; P += 128 * 128;
    __nv_bfloat16* wop1  = P; P += FPAD * 128;
    __nv_bfloat16* wr1   = P; P += 128 * 128;
    __nv_bfloat16* wr2   = P; P += 128 * 128;
    float* F = (float*)P;
    float* cf   = F; F += BATCH * HDIM;
    float* bmin = F; F += BATCH * 3;
    float* bmax = F; F += BATCH * 3;

    cvtw_k<<<528, 256>>>(attn_in_w, attn_out_w, op_w1, res_w1, res_w2,
                         wqkv, wao, wop1, wr1, wr2);
    prep_k<<<1, 128>>>(num_atoms, cell, bmin, bmax);
    embed_ln_k<<<NATOMS, 128>>>(elems, emb, ln_in_g, ln_in_b, xb);
    cellenc_k<<<BATCH, 128>>>(cell, ce_w1, ce_b1, ce_w2, ce_b2, cf);

    gemmb_k<4, 0><<<dim3(3, 128), 128>>>(xb, 128, wqkv, 384, attn_in_b,
        nullptr, nullptr, nullptr, nullptr, nullptr, nullptr, nullptr, nullptr,
        nullptr, nullptr, Qh, Kh, Vh, nullptr);

    flashb_k<<<dim3(64, NHEAD), 128>>>(Qh, Kh, Vh, aob);

    gemmb_k<4, 1><<<dim3(1, 128), 128>>>(aob, 128, wao, 128, attn_out_b,
        ln_feat_g, ln_feat_b, nullptr, cf, coord, bidx, nullptr, nullptr,
        nullptr, nullptr, combb, nullptr, nullptr, nullptr);

    gemmb_k<9, 2><<<dim3(1, 128), 128>>>(combb, FPAD, wop1, 128, op_b1,
        op_ln1_g, op_ln1_b, nullptr, nullptr, nullptr, nullptr, nullptr, nullptr,
        nullptr, nullptr, h1b, nullptr, nullptr, nullptr);

    gemmb_k<4, 2><<<dim3(1, 128), 128>>>(h1b, 128, wr1, 128, res_b1,
        res_ln_g, res_ln_b, nullptr, nullptr, nullptr, nullptr, nullptr, nullptr,
        nullptr, nullptr, t2b, nullptr, nullptr, nullptr);

    gemmb_k<4, 3><<<dim3(1, 128), 128>>>(t2b, 128, wr2, 128, res_b2,
        op_ln2_g, op_ln2_b, h1b, nullptr, coord, bidx, op_w3, op_b3,
        bmin, bmax, nullptr, nullptr, nullptr, out);
}

// round 4
// speedup vs baseline: 5.2598x; 1.0798x over previous
#include <cuda_runtime.h>
#include <cuda_bf16.h>
#include <math.h>
#include <stdint.h>

#define NATOMS 4096
#define HDIM   128
#define BATCH  128
#define NHEAD  4
#define DHEAD  32
#define H3     384
#define FPAD   288   // padded feature dim for comb (259 -> 288)

// -------- scratch (no allocations allowed) --------
__device__ float g_scratch[8300000];
__device__ int   g_bidx[NATOMS];

// ---------------- helpers ----------------
__device__ __forceinline__ float silu_f(float x) {
    return x / (1.f + __expf(-x));
}

// ---- mma / ldmatrix primitives ----
__device__ __forceinline__ void ldsm4(uint32_t& r0, uint32_t& r1, uint32_t& r2, uint32_t& r3, uint32_t addr) {
    asm volatile("ldmatrix.sync.aligned.m8n8.x4.shared.b16 {%0,%1,%2,%3}, [%4];"
                 : "=r"(r0), "=r"(r1), "=r"(r2), "=r"(r3) : "r"(addr));
}
__device__ __forceinline__ void ldsm4t(uint32_t& r0, uint32_t& r1, uint32_t& r2, uint32_t& r3, uint32_t addr) {
    asm volatile("ldmatrix.sync.aligned.m8n8.x4.trans.shared.b16 {%0,%1,%2,%3}, [%4];"
                 : "=r"(r0), "=r"(r1), "=r"(r2), "=r"(r3) : "r"(addr));
}
__device__ __forceinline__ void mma16816(float* d, const uint32_t* a, uint32_t b0, uint32_t b1) {
    asm volatile("mma.sync.aligned.m16n8k16.row.col.f32.bf16.bf16.f32 "
                 "{%0,%1,%2,%3}, {%4,%5,%6,%7}, {%8,%9}, {%0,%1,%2,%3};"
                 : "+f"(d[0]), "+f"(d[1]), "+f"(d[2]), "+f"(d[3])
                 : "r"(a[0]), "r"(a[1]), "r"(a[2]), "r"(a[3]), "r"(b0), "r"(b1));
}
__device__ __forceinline__ uint32_t packbf(float lo, float hi) {
    uint32_t r;
    asm volatile("cvt.rn.bf16x2.f32 %0, %1, %2;" : "=r"(r) : "f"(hi), "f"(lo));
    return r;
}
__device__ __forceinline__ void cpa16(uint32_t dst, const void* src) {
    asm volatile("cp.async.ca.shared.global [%0], [%1], 16;" :: "r"(dst), "l"(src));
}

// ================= fused setup kernel =================
// 256 threads. blocks: [0,512) embed_ln (8 rows, warp/row)
//                      [512,1040) weight cvt
//                      [1040,1048) cellenc (16 rows each)
//                      [1048] prep (bidx + clamp bounds)
__global__ void __launch_bounds__(256) setup_k(
    const int* __restrict__ elems, const float* __restrict__ emb,
    const float* __restrict__ ln_in_g, const float* __restrict__ ln_in_b,
    __nv_bfloat16* __restrict__ xo,
    const float* __restrict__ aiw, const float* __restrict__ aow,
    const float* __restrict__ opw1, const float* __restrict__ rw1,
    const float* __restrict__ rw2,
    __nv_bfloat16* __restrict__ wqkv, __nv_bfloat16* __restrict__ wao,
    __nv_bfloat16* __restrict__ wop1, __nv_bfloat16* __restrict__ wr1,
    __nv_bfloat16* __restrict__ wr2,
    const float* __restrict__ cell,
    const float* __restrict__ cw1, const float* __restrict__ cb1,
    const float* __restrict__ cw2, const float* __restrict__ cb2,
    float* __restrict__ cf,
    const int* __restrict__ num_atoms,
    float* __restrict__ bmin, float* __restrict__ bmax)
{
    const int b = blockIdx.x, tid = threadIdx.x;

    if (b < 512) {
        // ---- embed + input LN: warp per row ----
        int warp = tid >> 5, lane = tid & 31;
        int r = b * 8 + warp;
        int e = elems[r];
        float4 v = *(const float4*)&emb[e * HDIM + lane * 4];
        float s = v.x + v.y + v.z + v.w;
        #pragma unroll
        for (int off = 16; off > 0; off >>= 1) s += __shfl_xor_sync(0xffffffffu, s, off);
        float mean = s * (1.f / 128.f);
        float dx = v.x - mean, dy = v.y - mean, dz = v.z - mean, dw = v.w - mean;
        float sq = dx * dx + dy * dy + dz * dz + dw * dw;
        #pragma unroll
        for (int off = 16; off > 0; off >>= 1) sq += __shfl_xor_sync(0xffffffffu, sq, off);
        float inv = rsqrtf(sq * (1.f / 128.f) + 1e-5f);
        float4 gg = *(const float4*)&ln_in_g[lane * 4];
        float4 bb = *(const float4*)&ln_in_b[lane * 4];
        uint32_t p0 = packbf(dx * inv * gg.x + bb.x, dy * inv * gg.y + bb.y);
        uint32_t p1 = packbf(dz * inv * gg.z + bb.z, dw * inv * gg.w + bb.w);
        *(uint2*)(xo + r * HDIM + lane * 4) = make_uint2(p0, p1);
        return;
    }

    if (b < 1040) {
        // ---- weight conversion ----
        int i = (b - 512) * 256 + tid;
        if (i < 49152) wqkv[i] = __float2bfloat16(aiw[i]);
        else if (i < 65536) { int j = i - 49152; wao[j] = __float2bfloat16(aow[j]); }
        else if (i < 102400) {
            int j = i - 65536; int r = j >> 7, c = j & 127;
            wop1[j] = __float2bfloat16(r < 259 ? opw1[r * 128 + c] : 0.f);
        }
        else if (i < 118784) { int j = i - 102400; wr1[j] = __float2bfloat16(rw1[j]); }
        else { int j = i - 118784; wr2[j] = __float2bfloat16(rw2[j]); }
        return;
    }

    if (b < 1048) {
        // ---- cell encoder: 16 rows per block ----
        __shared__ float t1s[16][128];
        int r0 = (b - 1040) * 16;
        #pragma unroll
        for (int i = 0; i < 8; i++) {
            int idx = tid + i * 256;
            int rr = idx >> 7, k = idx & 127;
            int r = r0 + rr;
            float u = cell[r * 3 + 0] * cw1[k] + cell[r * 3 + 1] * cw1[128 + k]
                    + cell[r * 3 + 2] * cw1[256 + k] + cb1[k];
            t1s[rr][k] = silu_f(u);
        }
        __syncthreads();
        int t = tid & 127, half = tid >> 7;
        float acc[8];
        #pragma unroll
        for (int j = 0; j < 8; j++) acc[j] = cb2[t];
        #pragma unroll 4
        for (int k = 0; k < 128; k++) {
            float w = cw2[k * 128 + t];
            #pragma unroll
            for (int j = 0; j < 8; j++) acc[j] += t1s[half * 8 + j][k] * w;
        }
        #pragma unroll
        for (int j = 0; j < 8; j++) cf[(r0 + half * 8 + j) * 128 + t] = acc[j];
        return;
    }

    // ---- prep: bidx + clamp bounds (1 block) ----
    __shared__ int starts[BATCH + 1];
    if (tid == 0) {
        int acc = 0;
        for (int i = 0; i < BATCH; i++) { starts[i] = acc; acc += num_atoms[i]; }
        starts[BATCH] = acc;
    }
    __syncthreads();
    for (int i = tid; i < NATOMS; i += 256) g_bidx[i] = BATCH - 1;
    __syncthreads();
    if (tid < BATCH) {
        int s = starts[tid], e = starts[tid + 1];
        if (s > NATOMS) s = NATOMS;
        if (e > NATOMS) e = NATOMS;
        for (int i = s; i < e; i++) g_bidx[i] = tid;
        #pragma unroll
        for (int i = 0; i < 3; i++) {
            float a = cell[(3 * tid + i) * 3 + 0];
            float c1 = cell[(3 * tid + i) * 3 + 1];
            float c = cell[(3 * tid + i) * 3 + 2];
            bmin[tid * 3 + i] = fminf(a, fminf(c1, c)) + 1e-6f;
            bmax[tid * 3 + i] = fmaxf(a, fmaxf(c1, c)) - 1e-6f;
        }
    }
}

// ============ bf16 tensor-core GEMM with fused epilogues ============
// 128 threads (4 warps in 2x2), BM=32, BN=128, BK=32, double-buffered cp.async.
template<int KSTEPS, int EPI>
__global__ void __launch_bounds__(128) gemmb_k(
    const __nv_bfloat16* __restrict__ A, int lda,
    const __nv_bfloat16* __restrict__ W, int ldw,
    const float* __restrict__ bias,
    const float* __restrict__ e_g, const float* __restrict__ e_b,
    const __nv_bfloat16* __restrict__ resid,
    const float* __restrict__ cf, const float* __restrict__ coordp,
    const int* __restrict__ bidx,
    const float* __restrict__ w3, const float* __restrict__ b3,
    const float* __restrict__ bmin, const float* __restrict__ bmax,
    __nv_bfloat16* __restrict__ o0, __nv_bfloat16* __restrict__ o1,
    __nv_bfloat16* __restrict__ o2, float* __restrict__ fout)
{
    __shared__ __align__(16) char sA[2 * 32 * 80];
    __shared__ __align__(16) char sW[2 * 32 * 272];
    __shared__ __align__(16) float sS[32 * 136];
    const int tid = threadIdx.x, lane = tid & 31, warp = tid >> 5;
    const int wr = warp & 1, wc = warp >> 1;
    const int bm = blockIdx.y, nb = blockIdx.x;
    uint32_t aBase = (uint32_t)__cvta_generic_to_shared(sA);
    uint32_t wBase = (uint32_t)__cvta_generic_to_shared(sW);

    {
        #pragma unroll
        for (int p = 0; p < 2; p++) {
            int row = tid >> 2, seg = tid & 3;
            cpa16(aBase + p * 2560 + row * 80 + seg * 16,
                  A + (bm * 32 + row) * lda + p * 32 + seg * 8);
            #pragma unroll
            for (int i = 0; i < 4; i++) {
                int s = tid + i * 128;
                int wrow = s >> 4, wseg = s & 15;
                cpa16(wBase + p * 8704 + wrow * 272 + wseg * 16,
                      W + (p * 32 + wrow) * ldw + nb * 128 + wseg * 8);
            }
            asm volatile("cp.async.commit_group;");
        }
    }

    float acc[8][4];
    #pragma unroll
    for (int j = 0; j < 8; j++)
        #pragma unroll
        for (int c = 0; c < 4; c++) acc[j][c] = 0.f;

    const int i7 = lane & 7, sel = lane >> 3;
    const int arow = wr * 16 + ((sel & 1) ? 8 : 0) + i7;
    const int acol = (sel >> 1) ? 16 : 0;
    const int vrow = ((sel & 1) ? 8 : 0) + i7;
    const int vcol = (sel >= 2) ? 16 : 0;

    for (int ks = 0; ks < KSTEPS; ks++) {
        if (ks < KSTEPS - 1) asm volatile("cp.async.wait_group 1;");
        else                 asm volatile("cp.async.wait_group 0;");
        __syncthreads();
        uint32_t Ab = aBase + (ks & 1) * 2560;
        uint32_t Wb = wBase + (ks & 1) * 8704;
        #pragma unroll
        for (int kh = 0; kh < 2; kh++) {
            uint32_t qa[4];
            ldsm4(qa[0], qa[1], qa[2], qa[3], Ab + arow * 80 + acol + kh * 32);
            #pragma unroll
            for (int j = 0; j < 4; j++) {
                uint32_t r0, r1, r2, r3;
                ldsm4t(r0, r1, r2, r3, Wb + (kh * 16 + vrow) * 272 + wc * 128 + j * 32 + vcol);
                mma16816(acc[2 * j],     qa, r0, r1);
                mma16816(acc[2 * j + 1], qa, r2, r3);
            }
        }
        __syncthreads();
        if (ks + 2 < KSTEPS) {
            int p = ks + 2, buf = ks & 1;
            int row = tid >> 2, seg = tid & 3;
            cpa16(aBase + buf * 2560 + row * 80 + seg * 16,
                  A + (bm * 32 + row) * lda + p * 32 + seg * 8);
            #pragma unroll
            for (int i = 0; i < 4; i++) {
                int s = tid + i * 128;
                int wrow = s >> 4, wseg = s & 15;
                cpa16(wBase + buf * 8704 + wrow * 272 + wseg * 16,
                      W + (p * 32 + wrow) * ldw + nb * 128 + wseg * 8);
            }
            asm volatile("cp.async.commit_group;");
        }
    }

    const int g = lane >> 2, c2 = (lane & 3) * 2;

    if (EPI == 0) {
        int r0 = bm * 32 + wr * 16 + g;
        __nv_bfloat16* outp = (nb == 0) ? o0 : (nb == 1) ? o1 : o2;
        float sc = (nb == 0) ? 0.17677669529663687f : 1.f;
        #pragma unroll
        for (int t = 0; t < 8; t++) {
            int col = wc * 64 + t * 8 + c2;
            float b0v = bias[nb * 128 + col], b1v = bias[nb * 128 + col + 1];
            int h = col >> 5, d = col & 31;
            *(uint32_t*)(outp + (((h << 12) + r0) << 5) + d) =
                packbf((acc[t][0] + b0v) * sc, (acc[t][1] + b1v) * sc);
            *(uint32_t*)(outp + (((h << 12) + r0 + 8) << 5) + d) =
                packbf((acc[t][2] + b0v) * sc, (acc[t][3] + b1v) * sc);
        }
        return;
    }

    {
        int sr0 = wr * 16 + g;
        #pragma unroll
        for (int t = 0; t < 8; t++) {
            int col = wc * 64 + t * 8 + c2;
            float a0 = bias[col], a1 = bias[col + 1];
            float v00 = acc[t][0] + a0, v01 = acc[t][1] + a1;
            float v10 = acc[t][2] + a0, v11 = acc[t][3] + a1;
            if (EPI == 3) {
                int gr0 = (bm * 32 + sr0) * 128 + col;
                int gr1 = (bm * 32 + sr0 + 8) * 128 + col;
                v00 += __bfloat162float(resid[gr0]);
                v01 += __bfloat162float(resid[gr0 + 1]);
                v10 += __bfloat162float(resid[gr1]);
                v11 += __bfloat162float(resid[gr1 + 1]);
            }
            sS[sr0 * 136 + col] = v00; sS[sr0 * 136 + col + 1] = v01;
            sS[(sr0 + 8) * 136 + col] = v10; sS[(sr0 + 8) * 136 + col + 1] = v11;
        }
    }
    __syncthreads();

    const int row = tid >> 2, q = tid & 3;
    const int grow = bm * 32 + row;

    if (EPI == 1) {
        int bi = bidx[grow];
        float xv[32], cv[32];
        #pragma unroll
        for (int i = 0; i < 8; i++) {
            float4 f = *(const float4*)&sS[row * 136 + q * 32 + i * 4];
            xv[4 * i] = f.x; xv[4 * i + 1] = f.y; xv[4 * i + 2] = f.z; xv[4 * i + 3] = f.w;
            float4 c = *(const float4*)&cf[bi * 128 + q * 32 + i * 4];
            cv[4 * i] = c.x; cv[4 * i + 1] = c.y; cv[4 * i + 2] = c.z; cv[4 * i + 3] = c.w;
        }
        float c0 = 0.f, c1 = 0.f, c2v = 0.f;
        float s = 0.f;
        #pragma unroll
        for (int i = 0; i < 32; i++) s += xv[i] + cv[i];
        if (q == 0) {
            c0 = coordp[grow * 3 + 0]; c1 = coordp[grow * 3 + 1]; c2v = coordp[grow * 3 + 2];
            s += c0 + c1 + c2v;
        }
        s += __shfl_xor_sync(0xffffffffu, s, 1);
        s += __shfl_xor_sync(0xffffffffu, s, 2);
        float mean = s * (1.f / 259.f);
        float sq = 0.f;
        #pragma unroll
        for (int i = 0; i < 32; i++) {
            float d0 = xv[i] - mean, d1 = cv[i] - mean;
            sq += d0 * d0 + d1 * d1;
        }
        if (q == 0) {
            float d0 = c0 - mean, d1 = c1 - mean, d2 = c2v - mean;
            sq += d0 * d0 + d1 * d1 + d2 * d2;
        }
        sq += __shfl_xor_sync(0xffffffffu, sq, 1);
        sq += __shfl_xor_sync(0xffffffffu, sq, 2);
        float inv = rsqrtf(sq * (1.f / 259.f) + 1e-5f);

        uint32_t pk[16];
        #pragma unroll
        for (int i = 0; i < 16; i++) {
            int ca = q * 32 + 2 * i;
            float y0 = (xv[2 * i] - mean) * inv * e_g[ca] + e_b[ca];
            float y1 = (xv[2 * i + 1] - mean) * inv * e_g[ca + 1] + e_b[ca + 1];
            pk[i] = packbf(y0, y1);
        }
        uint4* dst = (uint4*)(o0 + grow * FPAD + q * 32);
        dst[0] = *(uint4*)&pk[0]; dst[1] = *(uint4*)&pk[4];
        dst[2] = *(uint4*)&pk[8]; dst[3] = *(uint4*)&pk[12];
        #pragma unroll
        for (int i = 0; i < 16; i++) {
            int ca = 128 + q * 32 + 2 * i;
            float y0 = (cv[2 * i] - mean) * inv * e_g[ca] + e_b[ca];
            float y1 = (cv[2 * i + 1] - mean) * inv * e_g[ca + 1] + e_b[ca + 1];
            pk[i] = packbf(y0, y1);
        }
        dst = (uint4*)(o0 + grow * FPAD + 128 + q * 32);
        dst[0] = *(uint4*)&pk[0]; dst[1] = *(uint4*)&pk[4];
        dst[2] = *(uint4*)&pk[8]; dst[3] = *(uint4*)&pk[12];
        #pragma unroll
        for (int jj = 0; jj < 8; jj++) {
            int c = 256 + q * 8 + jj;
            float val = 0.f;
            if (c < 259) {
                float raw = (jj == 0) ? c0 : (jj == 1) ? c1 : c2v;
                val = (raw - mean) * inv * e_g[c] + e_b[c];
            }
            o0[grow * FPAD + c] = __float2bfloat16(val);
        }
        return;
    }

    float v[32];
    #pragma unroll
    for (int i = 0; i < 8; i++) {
        float4 f = *(const float4*)&sS[row * 136 + q * 32 + i * 4];
        v[4 * i] = f.x; v[4 * i + 1] = f.y; v[4 * i + 2] = f.z; v[4 * i + 3] = f.w;
    }
    float s = 0.f;
    #pragma unroll
    for (int i = 0; i < 32; i++) s += v[i];
    s += __shfl_xor_sync(0xffffffffu, s, 1);
    s += __shfl_xor_sync(0xffffffffu, s, 2);
    float mean = s * (1.f / 128.f);
    float sq = 0.f;
    #pragma unroll
    for (int i = 0; i < 32; i++) { float d = v[i] - mean; sq += d * d; }
    sq += __shfl_xor_sync(0xffffffffu, sq, 1);
    sq += __shfl_xor_sync(0xffffffffu, sq, 2);
    float inv = rsqrtf(sq * (1.f / 128.f) + 1e-5f);

    if (EPI == 2) {
        uint32_t pk[16];
        #pragma unroll
        for (int i = 0; i < 16; i++) {
            int ca = q * 32 + 2 * i;
            float y0 = silu_f((v[2 * i] - mean) * inv * e_g[ca] + e_b[ca]);
            float y1 = silu_f((v[2 * i + 1] - mean) * inv * e_g[ca + 1] + e_b[ca + 1]);
            pk[i] = packbf(y0, y1);
        }
        uint4* dst = (uint4*)(o0 + grow * 128 + q * 32);
        dst[0] = *(uint4*)&pk[0]; dst[1] = *(uint4*)&pk[4];
        dst[2] = *(uint4*)&pk[8]; dst[3] = *(uint4*)&pk[12];
        return;
    }

    float p0 = 0.f, p1 = 0.f, p2 = 0.f;
    #pragma unroll
    for (int i = 0; i < 32; i++) {
        int ca = q * 32 + i;
        float y = (v[i] - mean) * inv * e_g[ca] + e_b[ca];
        p0 += y * w3[ca * 3 + 0];
        p1 += y * w3[ca * 3 + 1];
        p2 += y * w3[ca * 3 + 2];
    }
    p0 += __shfl_xor_sync(0xffffffffu, p0, 1);
    p0 += __shfl_xor_sync(0xffffffffu, p0, 2);
    p1 += __shfl_xor_sync(0xffffffffu, p1, 1);
    p1 += __shfl_xor_sync(0xffffffffu, p1, 2);
    p2 += __shfl_xor_sync(0xffffffffu, p2, 1);
    p2 += __shfl_xor_sync(0xffffffffu, p2, 2);
    if (q == 0) {
        int bi = bidx[grow];
        float dots[3] = {p0 + b3[0], p1 + b3[1], p2 + b3[2]};
        #pragma unroll
        for (int j = 0; j < 3; j++) {
            float val = coordp[grow * 3 + j] + 0.01f * tanhf(dots[j]);
            fout[grow * 3 + j] = fminf(fmaxf(val, bmin[bi * 3 + j]), bmax[bi * 3 + j]);
        }
    }
}

// ---------------- bf16 flash attention, 128-key chunks ----------------
#define CSTRIDE 80       // bytes per row (32 bf16 + pad)
#define QBUF    5120     // 64 rows
#define KVB     10240    // 128 rows

__device__ __forceinline__ void kv_load128(const __nv_bfloat16* __restrict__ Kh,
                                           const __nv_bfloat16* __restrict__ Vh,
                                           int h, int kb, uint32_t sbase, int tid) {
    #pragma unroll
    for (int i = 0; i < 8; i++) {
        int s = tid + i * 128;
        int row = (s >> 2) & 127, seg = s & 3;
        const __nv_bfloat16* src = ((s < 512) ? Kh : Vh)
            + (((h << 12) + (kb << 7) + row) << 5) + seg * 8;
        uint32_t dst = sbase + ((s < 512) ? 0 : KVB) + row * CSTRIDE + seg * 16;
        cpa16(dst, src);
    }
    asm volatile("cp.async.commit_group;");
}

__global__ void __launch_bounds__(128) flashb_k(const __nv_bfloat16* __restrict__ Qh,
                                                const __nv_bfloat16* __restrict__ Kh,
                                                const __nv_bfloat16* __restrict__ Vh,
                                                __nv_bfloat16* __restrict__ ao) {
    __shared__ __align__(16) char smem[QBUF + 4 * KVB];
    const int tid = threadIdx.x, lane = tid & 31, warp = tid >> 5;
    const int h = blockIdx.y, qb = blockIdx.x;

    char* Qs = smem;
    uint32_t Qsa = (uint32_t)__cvta_generic_to_shared(Qs);
    uint32_t kva0 = Qsa + QBUF;
    uint32_t kva1 = Qsa + QBUF + 2 * KVB;

    #pragma unroll
    for (int i = 0; i < 2; i++) {
        int s = tid + i * 128;
        int row = s >> 2, seg = s & 3;
        uint4 v = *(const uint4*)(Qh + (((h << 12) + (qb << 6) + row) << 5) + seg * 8);
        *(uint4*)(Qs + row * CSTRIDE + seg * 16) = v;
    }
    kv_load128(Kh, Vh, h, 0, kva0, tid);
    kv_load128(Kh, Vh, h, 1, kva1, tid);
    __syncthreads();

    uint32_t qa[8];
    {
        int i = lane & 7, sl = lane >> 3;
        int row = warp * 16 + ((sl & 1) ? 8 : 0) + i;
        uint32_t a = Qsa + row * CSTRIDE + ((sl >> 1) ? 16 : 0);
        ldsm4(qa[0], qa[1], qa[2], qa[3], a);
        ldsm4(qa[4], qa[5], qa[6], qa[7], a + 32);
    }

    float m0 = -1e30f, m1 = -1e30f, l0 = 0.f, l1 = 0.f;
    float o[4][4];
    #pragma unroll
    for (int j = 0; j < 4; j++)
        #pragma unroll
        for (int c = 0; c < 4; c++) o[j][c] = 0.f;

    const int i7 = lane & 7, sel = lane >> 3;
    const uint32_t krow = ((sel >= 2) ? 8 : 0) + i7;
    const uint32_t kcol = (sel & 1) ? 16 : 0;
    const uint32_t vrow = ((sel & 1) ? 8 : 0) + i7;
    const uint32_t vcol = (sel >= 2) ? 16 : 0;

    for (int kb = 0; kb < 32; kb++) {
        if (kb < 31) asm volatile("cp.async.wait_group 1;");
        else         asm volatile("cp.async.wait_group 0;");
        __syncthreads();
        uint32_t Kbase = (kb & 1) ? kva1 : kva0;
        uint32_t Vbase = Kbase + KVB;

        // ---- S = Q @ K^T : 16 n8-tiles ----
        float s[16][4];
        #pragma unroll
        for (int j = 0; j < 16; j++)
            #pragma unroll
            for (int c = 0; c < 4; c++) s[j][c] = 0.f;

        #pragma unroll
        for (int jp = 0; jp < 8; jp++) {
            uint32_t a = Kbase + (jp * 16 + krow) * CSTRIDE + kcol;
            uint32_t b0, b1, b2, b3, c0, c1, c2, c3;
            ldsm4(b0, b1, b2, b3, a);
            ldsm4(c0, c1, c2, c3, a + 32);
            mma16816(s[2 * jp],     qa,     b0, b1);
            mma16816(s[2 * jp],     qa + 4, c0, c1);
            mma16816(s[2 * jp + 1], qa,     b2, b3);
            mma16816(s[2 * jp + 1], qa + 4, c2, c3);
        }

        // ---- online softmax ----
        float mx0 = -1e30f, mx1 = -1e30f;
        #pragma unroll
        for (int j = 0; j < 16; j++) {
            mx0 = fmaxf(mx0, fmaxf(s[j][0], s[j][1]));
            mx1 = fmaxf(mx1, fmaxf(s[j][2], s[j][3]));
        }
        mx0 = fmaxf(mx0, __shfl_xor_sync(0xffffffffu, mx0, 1));
        mx0 = fmaxf(mx0, __shfl_xor_sync(0xffffffffu, mx0, 2));
        mx1 = fmaxf(mx1, __shfl_xor_sync(0xffffffffu, mx1, 1));
        mx1 = fmaxf(mx1, __shfl_xor_sync(0xffffffffu, mx1, 2));
        float mn0 = fmaxf(m0, mx0), mn1 = fmaxf(m1, mx1);
        float f0 = __expf(m0 - mn0), f1 = __expf(m1 - mn1);
        m0 = mn0; m1 = mn1;
        float sum0 = 0.f, sum1 = 0.f;
        #pragma unroll
        for (int j = 0; j < 16; j++) {
            s[j][0] = __expf(s[j][0] - mn0);
            s[j][1] = __expf(s[j][1] - mn0);
            s[j][2] = __expf(s[j][2] - mn1);
            s[j][3] = __expf(s[j][3] - mn1);
            sum0 += s[j][0] + s[j][1];
            sum1 += s[j][2] + s[j][3];
        }
        sum0 += __shfl_xor_sync(0xffffffffu, sum0, 1);
        sum0 += __shfl_xor_sync(0xffffffffu, sum0, 2);
        sum1 += __shfl_xor_sync(0xffffffffu, sum1, 1);
        sum1 += __shfl_xor_sync(0xffffffffu, sum1, 2);
        l0 = l0 * f0 + sum0;
        l1 = l1 * f1 + sum1;
        #pragma unroll
        for (int j = 0; j < 4; j++) {
            o[j][0] *= f0; o[j][1] *= f0;
            o[j][2] *= f1; o[j][3] *= f1;
        }

        // ---- O += P @ V : 8 k-steps of 16 keys ----
        #pragma unroll
        for (int ks = 0; ks < 8; ks++) {
            uint32_t pa[4];
            pa[0] = packbf(s[2 * ks][0],     s[2 * ks][1]);
            pa[1] = packbf(s[2 * ks][2],     s[2 * ks][3]);
            pa[2] = packbf(s[2 * ks + 1][0], s[2 * ks + 1][1]);
            pa[3] = packbf(s[2 * ks + 1][2], s[2 * ks + 1][3]);
            uint32_t a = Vbase + (ks * 16 + vrow) * CSTRIDE + vcol;
            uint32_t v0, v1, v2, v3, w0, w1, w2, w3;
            ldsm4t(v0, v1, v2, v3, a);
            ldsm4t(w0, w1, w2, w3, a + 32);
            mma16816(o[0], pa, v0, v1);
            mma16816(o[1], pa, v2, v3);
            mma16816(o[2], pa, w0, w1);
            mma16816(o[3], pa, w2, w3);
        }

        __syncthreads();
        if (kb < 30) kv_load128(Kh, Vh, h, kb + 2, (kb & 1) ? kva1 : kva0, tid);
    }

    float inv0 = 1.f / l0, inv1 = 1.f / l1;
    int g = lane >> 2, l2 = (lane & 3) * 2;
    int row0 = (qb << 6) + warp * 16 + g;
    #pragma unroll
    for (int j = 0; j < 4; j++) {
        int col = (h << 5) + j * 8 + l2;
        *(uint32_t*)&ao[row0 * HDIM + col]       = packbf(o[j][0] * inv0, o[j][1] * inv0);
        *(uint32_t*)&ao[(row0 + 8) * HDIM + col] = packbf(o[j][2] * inv1, o[j][3] * inv1);
    }
}

// ---------------- host ----------------
extern "C" void kernel_launch(void* const* d_in, const int* in_sizes, int n_in,
                              void* d_out, int out_size) {
    const int*   num_atoms  = (const int*)d_in[0];
    const int*   elems      = (const int*)d_in[1];
    const float* cell       = (const float*)d_in[2];
    const float* coord      = (const float*)d_in[3];
    const float* emb        = (const float*)d_in[4];
    const float* ln_in_g    = (const float*)d_in[5];
    const float* ln_in_b    = (const float*)d_in[6];
    const float* attn_in_w  = (const float*)d_in[7];
    const float* attn_in_b  = (const float*)d_in[8];
    const float* attn_out_w = (const float*)d_in[9];
    const float* attn_out_b = (const float*)d_in[10];
    const float* ce_w1      = (const float*)d_in[11];
    const float* ce_b1      = (const float*)d_in[12];
    const float* ce_w2      = (const float*)d_in[13];
    const float* ce_b2      = (const float*)d_in[14];
    const float* ln_feat_g  = (const float*)d_in[15];
    const float* ln_feat_b  = (const float*)d_in[16];
    const float* op_w1      = (const float*)d_in[17];
    const float* op_b1      = (const float*)d_in[18];
    const float* op_ln1_g   = (const float*)d_in[19];
    const float* op_ln1_b   = (const float*)d_in[20];
    const float* res_w1     = (const float*)d_in[21];
    const float* res_b1     = (const float*)d_in[22];
    const float* res_ln_g   = (const float*)d_in[23];
    const float* res_ln_b   = (const float*)d_in[24];
    const float* res_w2     = (const float*)d_in[25];
    const float* res_b2     = (const float*)d_in[26];
    const float* op_ln2_g   = (const float*)d_in[27];
    const float* op_ln2_b   = (const float*)d_in[28];
    const float* op_w3      = (const float*)d_in[29];
    const float* op_b3      = (const float*)d_in[30];
    float* out = (float*)d_out;

    float* S = nullptr;
    cudaGetSymbolAddress((void**)&S, g_scratch);
    int* bidx = nullptr;
    cudaGetSymbolAddress((void**)&bidx, g_bidx);

    __nv_bfloat16* P = (__nv_bfloat16*)S;
    __nv_bfloat16* xb    = P; P += NATOMS * HDIM;
    __nv_bfloat16* Qh    = P; P += NATOMS * HDIM;
    __nv_bfloat16* Kh    = P; P += NATOMS * HDIM;
    __nv_bfloat16* Vh    = P; P += NATOMS * HDIM;
    __nv_bfloat16* aob   = P; P += NATOMS * HDIM;
    __nv_bfloat16* combb = P; P += NATOMS * FPAD;
    __nv_bfloat16* h1b   = P; P += NATOMS * HDIM;
    __nv_bfloat16* t2b   = P; P += NATOMS * HDIM;
    __nv_bfloat16* wqkv  = P; P += 128 * 384;
    __nv_bfloat16* wao   = P; P += 128 * 128;
    __nv_bfloat16* wop1  = P; P += FPAD * 128;
    __nv_bfloat16* wr1   = P; P += 128 * 128;
    __nv_bfloat16* wr2   = P; P += 128 * 128;
    float* F = (float*)P;
    float* cf   = F; F += BATCH * HDIM;
    float* bmin = F; F += BATCH * 3;
    float* bmax = F; F += BATCH * 3;

    setup_k<<<1049, 256>>>(elems, emb, ln_in_g, ln_in_b, xb,
                           attn_in_w, attn_out_w, op_w1, res_w1, res_w2,
                           wqkv, wao, wop1, wr1, wr2,
                           cell, ce_w1, ce_b1, ce_w2, ce_b2, cf,
                           num_atoms, bmin, bmax);

    gemmb_k<4, 0><<<dim3(3, 128), 128>>>(xb, 128, wqkv, 384, attn_in_b,
        nullptr, nullptr, nullptr, nullptr, nullptr, nullptr, nullptr, nullptr,
        nullptr, nullptr, Qh, Kh, Vh, nullptr);

    flashb_k<<<dim3(64, NHEAD), 128>>>(Qh, Kh, Vh, aob);

    gemmb_k<4, 1><<<dim3(1, 128), 128>>>(aob, 128, wao, 128, attn_out_b,
        ln_feat_g, ln_feat_b, nullptr, cf, coord, bidx, nullptr, nullptr,
        nullptr, nullptr, combb, nullptr, nullptr, nullptr);

    gemmb_k<9, 2><<<dim3(1, 128), 128>>>(combb, FPAD, wop1, 128, op_b1,
        op_ln1_g, op_ln1_b, nullptr, nullptr, nullptr, nullptr, nullptr, nullptr,
        nullptr, nullptr, h1b, nullptr, nullptr, nullptr);

    gemmb_k<4, 2><<<dim3(1, 128), 128>>>(h1b, 128, wr1, 128, res_b1,
        res_ln_g, res_ln_b, nullptr, nullptr, nullptr, nullptr, nullptr, nullptr,
        nullptr, nullptr, t2b, nullptr, nullptr, nullptr);

    gemmb_k<4, 3><<<dim3(1, 128), 128>>>(t2b, 128, wr2, 128, res_b2,
        op_ln2_g, op_ln2_b, h1b, nullptr, coord, bidx, op_w3, op_b3,
        bmin, bmax, nullptr, nullptr, nullptr, out);
}

// round 5
// speedup vs baseline: 5.8811x; 1.1181x over previous
#include <cuda_runtime.h>
#include <cuda_bf16.h>
#include <math.h>
#include <stdint.h>

#define NATOMS 4096
#define HDIM   128
#define BATCH  128
#define NHEAD  4
#define DHEAD  32
#define H3     384
#define FPAD   288

// -------- scratch (no allocations allowed) --------
__device__ float g_scratch[8300000];
__device__ int   g_bidx[NATOMS];

// ---------------- helpers ----------------
__device__ __forceinline__ float silu_f(float x) {
    return x / (1.f + __expf(-x));
}
__device__ __forceinline__ void ldsm4(uint32_t& r0, uint32_t& r1, uint32_t& r2, uint32_t& r3, uint32_t addr) {
    asm volatile("ldmatrix.sync.aligned.m8n8.x4.shared.b16 {%0,%1,%2,%3}, [%4];"
                 : "=r"(r0), "=r"(r1), "=r"(r2), "=r"(r3) : "r"(addr));
}
__device__ __forceinline__ void ldsm4t(uint32_t& r0, uint32_t& r1, uint32_t& r2, uint32_t& r3, uint32_t addr) {
    asm volatile("ldmatrix.sync.aligned.m8n8.x4.trans.shared.b16 {%0,%1,%2,%3}, [%4];"
                 : "=r"(r0), "=r"(r1), "=r"(r2), "=r"(r3) : "r"(addr));
}
__device__ __forceinline__ void mma16816(float* d, const uint32_t* a, uint32_t b0, uint32_t b1) {
    asm volatile("mma.sync.aligned.m16n8k16.row.col.f32.bf16.bf16.f32 "
                 "{%0,%1,%2,%3}, {%4,%5,%6,%7}, {%8,%9}, {%0,%1,%2,%3};"
                 : "+f"(d[0]), "+f"(d[1]), "+f"(d[2]), "+f"(d[3])
                 : "r"(a[0]), "r"(a[1]), "r"(a[2]), "r"(a[3]), "r"(b0), "r"(b1));
}
__device__ __forceinline__ uint32_t packbf(float lo, float hi) {
    uint32_t r;
    asm volatile("cvt.rn.bf16x2.f32 %0, %1, %2;" : "=r"(r) : "f"(hi), "f"(lo));
    return r;
}
__device__ __forceinline__ void cpa16(uint32_t dst, const void* src) {
    asm volatile("cp.async.ca.shared.global [%0], [%1], 16;" :: "r"(dst), "l"(src));
}

// ================= fused setup kernel =================
__global__ void __launch_bounds__(256) setup_k(
    const int* __restrict__ elems, const float* __restrict__ emb,
    const float* __restrict__ ln_in_g, const float* __restrict__ ln_in_b,
    __nv_bfloat16* __restrict__ xo,
    const float* __restrict__ aiw, const float* __restrict__ aow,
    const float* __restrict__ opw1, const float* __restrict__ rw1,
    const float* __restrict__ rw2,
    __nv_bfloat16* __restrict__ wqkv, __nv_bfloat16* __restrict__ wao,
    __nv_bfloat16* __restrict__ wop1, __nv_bfloat16* __restrict__ wr1,
    __nv_bfloat16* __restrict__ wr2,
    const float* __restrict__ cell,
    const float* __restrict__ cw1, const float* __restrict__ cb1,
    const float* __restrict__ cw2, const float* __restrict__ cb2,
    float* __restrict__ cf,
    const int* __restrict__ num_atoms,
    float* __restrict__ bmin, float* __restrict__ bmax)
{
    const int b = blockIdx.x, tid = threadIdx.x;

    if (b < 512) {
        int warp = tid >> 5, lane = tid & 31;
        int r = b * 8 + warp;
        int e = elems[r];
        float4 v = *(const float4*)&emb[e * HDIM + lane * 4];
        float s = v.x + v.y + v.z + v.w;
        #pragma unroll
        for (int off = 16; off > 0; off >>= 1) s += __shfl_xor_sync(0xffffffffu, s, off);
        float mean = s * (1.f / 128.f);
        float dx = v.x - mean, dy = v.y - mean, dz = v.z - mean, dw = v.w - mean;
        float sq = dx * dx + dy * dy + dz * dz + dw * dw;
        #pragma unroll
        for (int off = 16; off > 0; off >>= 1) sq += __shfl_xor_sync(0xffffffffu, sq, off);
        float inv = rsqrtf(sq * (1.f / 128.f) + 1e-5f);
        float4 gg = *(const float4*)&ln_in_g[lane * 4];
        float4 bb = *(const float4*)&ln_in_b[lane * 4];
        uint32_t p0 = packbf(dx * inv * gg.x + bb.x, dy * inv * gg.y + bb.y);
        uint32_t p1 = packbf(dz * inv * gg.z + bb.z, dw * inv * gg.w + bb.w);
        *(uint2*)(xo + r * HDIM + lane * 4) = make_uint2(p0, p1);
        return;
    }

    if (b < 1040) {
        int i = (b - 512) * 256 + tid;
        if (i < 49152) wqkv[i] = __float2bfloat16(aiw[i]);
        else if (i < 65536) { int j = i - 49152; wao[j] = __float2bfloat16(aow[j]); }
        else if (i < 102400) {
            int j = i - 65536; int r = j >> 7, c = j & 127;
            wop1[j] = __float2bfloat16(r < 259 ? opw1[r * 128 + c] : 0.f);
        }
        else if (i < 118784) { int j = i - 102400; wr1[j] = __float2bfloat16(rw1[j]); }
        else { int j = i - 118784; wr2[j] = __float2bfloat16(rw2[j]); }
        return;
    }

    if (b < 1048) {
        __shared__ float t1s[16][128];
        int r0 = (b - 1040) * 16;
        #pragma unroll
        for (int i = 0; i < 8; i++) {
            int idx = tid + i * 256;
            int rr = idx >> 7, k = idx & 127;
            int r = r0 + rr;
            float u = cell[r * 3 + 0] * cw1[k] + cell[r * 3 + 1] * cw1[128 + k]
                    + cell[r * 3 + 2] * cw1[256 + k] + cb1[k];
            t1s[rr][k] = silu_f(u);
        }
        __syncthreads();
        int t = tid & 127, half = tid >> 7;
        float acc[8];
        #pragma unroll
        for (int j = 0; j < 8; j++) acc[j] = cb2[t];
        #pragma unroll 4
        for (int k = 0; k < 128; k++) {
            float w = cw2[k * 128 + t];
            #pragma unroll
            for (int j = 0; j < 8; j++) acc[j] += t1s[half * 8 + j][k] * w;
        }
        #pragma unroll
        for (int j = 0; j < 8; j++) cf[(r0 + half * 8 + j) * 128 + t] = acc[j];
        return;
    }

    __shared__ int starts[BATCH + 1];
    if (tid == 0) {
        int acc = 0;
        for (int i = 0; i < BATCH; i++) { starts[i] = acc; acc += num_atoms[i]; }
        starts[BATCH] = acc;
    }
    __syncthreads();
    for (int i = tid; i < NATOMS; i += 256) g_bidx[i] = BATCH - 1;
    __syncthreads();
    if (tid < BATCH) {
        int s = starts[tid], e = starts[tid + 1];
        if (s > NATOMS) s = NATOMS;
        if (e > NATOMS) e = NATOMS;
        for (int i = s; i < e; i++) g_bidx[i] = tid;
        #pragma unroll
        for (int i = 0; i < 3; i++) {
            float a = cell[(3 * tid + i) * 3 + 0];
            float c1 = cell[(3 * tid + i) * 3 + 1];
            float c = cell[(3 * tid + i) * 3 + 2];
            bmin[tid * 3 + i] = fminf(a, fminf(c1, c)) + 1e-6f;
            bmax[tid * 3 + i] = fmaxf(a, fmaxf(c1, c)) - 1e-6f;
        }
    }
}

// ================= QKV GEMM (BM=32, BN=128, BK=32, double-buffered) =================
__global__ void __launch_bounds__(128) qkv_k(
    const __nv_bfloat16* __restrict__ A, const __nv_bfloat16* __restrict__ W,
    const float* __restrict__ bias,
    __nv_bfloat16* __restrict__ Qh, __nv_bfloat16* __restrict__ Kh,
    __nv_bfloat16* __restrict__ Vh)
{
    __shared__ __align__(16) char sA[2 * 32 * 80];
    __shared__ __align__(16) char sW[2 * 32 * 272];
    const int tid = threadIdx.x, lane = tid & 31, warp = tid >> 5;
    const int wr = warp & 1, wc = warp >> 1;
    const int bm = blockIdx.y, nb = blockIdx.x;
    uint32_t aBase = (uint32_t)__cvta_generic_to_shared(sA);
    uint32_t wBase = (uint32_t)__cvta_generic_to_shared(sW);

    #pragma unroll
    for (int p = 0; p < 2; p++) {
        int row = tid >> 2, seg = tid & 3;
        cpa16(aBase + p * 2560 + row * 80 + seg * 16,
              A + (bm * 32 + row) * 128 + p * 32 + seg * 8);
        #pragma unroll
        for (int i = 0; i < 4; i++) {
            int s = tid + i * 128;
            int wrow = s >> 4, wseg = s & 15;
            cpa16(wBase + p * 8704 + wrow * 272 + wseg * 16,
                  W + (p * 32 + wrow) * H3 + nb * 128 + wseg * 8);
        }
        asm volatile("cp.async.commit_group;");
    }

    float acc[8][4];
    #pragma unroll
    for (int j = 0; j < 8; j++)
        #pragma unroll
        for (int c = 0; c < 4; c++) acc[j][c] = 0.f;

    const int i7 = lane & 7, sel = lane >> 3;
    const int arow = wr * 16 + ((sel & 1) ? 8 : 0) + i7;
    const int acol = (sel >> 1) ? 16 : 0;
    const int vrow = ((sel & 1) ? 8 : 0) + i7;
    const int vcol = (sel >= 2) ? 16 : 0;

    for (int ks = 0; ks < 4; ks++) {
        if (ks < 3) asm volatile("cp.async.wait_group 1;");
        else        asm volatile("cp.async.wait_group 0;");
        __syncthreads();
        uint32_t Ab = aBase + (ks & 1) * 2560;
        uint32_t Wb = wBase + (ks & 1) * 8704;
        #pragma unroll
        for (int kh = 0; kh < 2; kh++) {
            uint32_t qa[4];
            ldsm4(qa[0], qa[1], qa[2], qa[3], Ab + arow * 80 + acol + kh * 32);
            #pragma unroll
            for (int j = 0; j < 4; j++) {
                uint32_t r0, r1, r2, r3;
                ldsm4t(r0, r1, r2, r3, Wb + (kh * 16 + vrow) * 272 + wc * 128 + j * 32 + vcol);
                mma16816(acc[2 * j],     qa, r0, r1);
                mma16816(acc[2 * j + 1], qa, r2, r3);
            }
        }
        __syncthreads();
        if (ks + 2 < 4) {
            int p = ks + 2, buf = ks & 1;
            int row = tid >> 2, seg = tid & 3;
            cpa16(aBase + buf * 2560 + row * 80 + seg * 16,
                  A + (bm * 32 + row) * 128 + p * 32 + seg * 8);
            #pragma unroll
            for (int i = 0; i < 4; i++) {
                int s = tid + i * 128;
                int wrow = s >> 4, wseg = s & 15;
                cpa16(wBase + buf * 8704 + wrow * 272 + wseg * 16,
                      W + (p * 32 + wrow) * H3 + nb * 128 + wseg * 8);
            }
            asm volatile("cp.async.commit_group;");
        }
    }

    const int g = lane >> 2, c2 = (lane & 3) * 2;
    int r0 = bm * 32 + wr * 16 + g;
    __nv_bfloat16* outp = (nb == 0) ? Qh : (nb == 1) ? Kh : Vh;
    float sc = (nb == 0) ? 0.17677669529663687f : 1.f;
    #pragma unroll
    for (int t = 0; t < 8; t++) {
        int col = wc * 64 + t * 8 + c2;
        float b0v = bias[nb * 128 + col], b1v = bias[nb * 128 + col + 1];
        int h = col >> 5, d = col & 31;
        *(uint32_t*)(outp + (((h << 12) + r0) << 5) + d) =
            packbf((acc[t][0] + b0v) * sc, (acc[t][1] + b1v) * sc);
        *(uint32_t*)(outp + (((h << 12) + r0 + 8) << 5) + d) =
            packbf((acc[t][2] + b0v) * sc, (acc[t][3] + b1v) * sc);
    }
}

// ================= fused tail: 4 GEMMs + LNs + final, weights resident in smem ==========
#define WSTR 272
#define ASTR 592
#define SM_WAO   0
#define SM_WOP1  (128 * WSTR)                  // 34816
#define SM_WR1   (SM_WOP1 + 288 * WSTR)        // 113152
#define SM_WR2   (SM_WR1 + 128 * WSTR)         // 147968
#define SM_ACT   (SM_WR2 + 128 * WSTR)         // 182784
#define SM_STAGE (SM_ACT + 32 * ASTR)          // 201728
#define SMEM_TAIL (SM_STAGE + 32 * 136 * 4)    // 219136

__global__ void __launch_bounds__(128) tail_k(
    const __nv_bfloat16* __restrict__ aob,
    const __nv_bfloat16* __restrict__ wao, const float* __restrict__ aob_bias,
    const float* __restrict__ lnf_g, const float* __restrict__ lnf_b,
    const float* __restrict__ cf, const float* __restrict__ coordp,
    const int* __restrict__ bidx,
    const __nv_bfloat16* __restrict__ wop1, const float* __restrict__ op_b1,
    const float* __restrict__ ln1_g, const float* __restrict__ ln1_b,
    const __nv_bfloat16* __restrict__ wr1, const float* __restrict__ r_b1,
    const float* __restrict__ rln_g, const float* __restrict__ rln_b,
    const __nv_bfloat16* __restrict__ wr2, const float* __restrict__ r_b2,
    const float* __restrict__ ln2_g, const float* __restrict__ ln2_b,
    const float* __restrict__ w3, const float* __restrict__ b3,
    const float* __restrict__ bmin, const float* __restrict__ bmax,
    float* __restrict__ fout)
{
    extern __shared__ __align__(16) char dsm[];
    const int tid = threadIdx.x, lane = tid & 31, warp = tid >> 5;
    const int wr = warp & 1, wc = warp >> 1;
    const int bm = blockIdx.x;
    uint32_t base = (uint32_t)__cvta_generic_to_shared(dsm);
    uint32_t aAct = base + SM_ACT;
    float* sS = (float*)(dsm + SM_STAGE);

    // ---- group 0: activation tile + wao ----
    #pragma unroll
    for (int i = 0; i < 4; i++) {
        int s = tid + i * 128;
        int row = s >> 4, seg = s & 15;
        cpa16(aAct + row * ASTR + seg * 16, aob + (bm * 32 + row) * 128 + seg * 8);
    }
    #pragma unroll
    for (int i = 0; i < 16; i++) {
        int s = tid + i * 128;
        int row = s >> 4, seg = s & 15;
        cpa16(base + SM_WAO + row * WSTR + seg * 16, wao + row * 128 + seg * 8);
    }
    asm volatile("cp.async.commit_group;");
    // ---- group 1: wop1 (288 rows) ----
    #pragma unroll
    for (int i = 0; i < 36; i++) {
        int s = tid + i * 128;
        int row = s >> 4, seg = s & 15;
        cpa16(base + SM_WOP1 + row * WSTR + seg * 16, wop1 + row * 128 + seg * 8);
    }
    asm volatile("cp.async.commit_group;");
    // ---- group 2: wr1 ----
    #pragma unroll
    for (int i = 0; i < 16; i++) {
        int s = tid + i * 128;
        int row = s >> 4, seg = s & 15;
        cpa16(base + SM_WR1 + row * WSTR + seg * 16, wr1 + row * 128 + seg * 8);
    }
    asm volatile("cp.async.commit_group;");
    // ---- group 3: wr2 ----
    #pragma unroll
    for (int i = 0; i < 16; i++) {
        int s = tid + i * 128;
        int row = s >> 4, seg = s & 15;
        cpa16(base + SM_WR2 + row * WSTR + seg * 16, wr2 + row * 128 + seg * 8);
    }
    asm volatile("cp.async.commit_group;");

    const int i7 = lane & 7, sel = lane >> 3;
    const int arow = wr * 16 + ((sel & 1) ? 8 : 0) + i7;
    const int acol = (sel >> 1) ? 16 : 0;
    const int vrow = ((sel & 1) ? 8 : 0) + i7;
    const int vcol = (sel >= 2) ? 16 : 0;
    const int row = tid >> 2, q = tid & 3;
    const int grow = bm * 32 + row;
    const int sr0 = wr * 16 + (lane >> 2);
    const int c2 = (lane & 3) * 2;

    float acc[8][4];
    uint32_t hkeep[16];

    auto do_gemm = [&](int wOff, int ksteps) {
        #pragma unroll
        for (int j = 0; j < 8; j++)
            #pragma unroll
            for (int c = 0; c < 4; c++) acc[j][c] = 0.f;
        for (int ks = 0; ks < ksteps; ks++) {
            #pragma unroll
            for (int kh = 0; kh < 2; kh++) {
                uint32_t qa[4];
                ldsm4(qa[0], qa[1], qa[2], qa[3], aAct + arow * ASTR + ks * 64 + kh * 32 + acol);
                #pragma unroll
                for (int j = 0; j < 4; j++) {
                    uint32_t r0, r1, r2, r3;
                    ldsm4t(r0, r1, r2, r3,
                           base + wOff + (ks * 32 + kh * 16 + vrow) * WSTR + wc * 128 + j * 32 + vcol);
                    mma16816(acc[2 * j],     qa, r0, r1);
                    mma16816(acc[2 * j + 1], qa, r2, r3);
                }
            }
        }
    };

    auto stage = [&](const float* bias) {
        #pragma unroll
        for (int t = 0; t < 8; t++) {
            int col = wc * 64 + t * 8 + c2;
            float a0 = bias[col], a1 = bias[col + 1];
            sS[sr0 * 136 + col] = acc[t][0] + a0;       sS[sr0 * 136 + col + 1] = acc[t][1] + a1;
            sS[(sr0 + 8) * 136 + col] = acc[t][2] + a0; sS[(sr0 + 8) * 136 + col + 1] = acc[t][3] + a1;
        }
    };

    // ============ stage 0: xa = aob @ wao + b ; comb-LN(259) -> sA[32][288] ============
    asm volatile("cp.async.wait_group 3;");
    __syncthreads();
    do_gemm(SM_WAO, 4);
    stage(aob_bias);
    __syncthreads();
    {
        int bi = bidx[grow];
        float xv[32], cv[32];
        #pragma unroll
        for (int i = 0; i < 8; i++) {
            float4 f = *(const float4*)&sS[row * 136 + q * 32 + i * 4];
            xv[4 * i] = f.x; xv[4 * i + 1] = f.y; xv[4 * i + 2] = f.z; xv[4 * i + 3] = f.w;
            float4 c = *(const float4*)&cf[bi * 128 + q * 32 + i * 4];
            cv[4 * i] = c.x; cv[4 * i + 1] = c.y; cv[4 * i + 2] = c.z; cv[4 * i + 3] = c.w;
        }
        float c0 = 0.f, c1 = 0.f, c2v = 0.f;
        float s = 0.f;
        #pragma unroll
        for (int i = 0; i < 32; i++) s += xv[i] + cv[i];
        if (q == 0) {
            c0 = coordp[grow * 3 + 0]; c1 = coordp[grow * 3 + 1]; c2v = coordp[grow * 3 + 2];
            s += c0 + c1 + c2v;
        }
        s += __shfl_xor_sync(0xffffffffu, s, 1);
        s += __shfl_xor_sync(0xffffffffu, s, 2);
        float mean = s * (1.f / 259.f);
        float sq = 0.f;
        #pragma unroll
        for (int i = 0; i < 32; i++) {
            float d0 = xv[i] - mean, d1 = cv[i] - mean;
            sq += d0 * d0 + d1 * d1;
        }
        if (q == 0) {
            float d0 = c0 - mean, d1 = c1 - mean, d2 = c2v - mean;
            sq += d0 * d0 + d1 * d1 + d2 * d2;
        }
        sq += __shfl_xor_sync(0xffffffffu, sq, 1);
        sq += __shfl_xor_sync(0xffffffffu, sq, 2);
        float inv = rsqrtf(sq * (1.f / 259.f) + 1e-5f);

        uint32_t pk[16];
        #pragma unroll
        for (int i = 0; i < 16; i++) {
            int ca = q * 32 + 2 * i;
            pk[i] = packbf((xv[2 * i] - mean) * inv * lnf_g[ca] + lnf_b[ca],
                           (xv[2 * i + 1] - mean) * inv * lnf_g[ca + 1] + lnf_b[ca + 1]);
        }
        uint4* dst = (uint4*)(dsm + SM_ACT + row * ASTR + q * 64);
        dst[0] = *(uint4*)&pk[0]; dst[1] = *(uint4*)&pk[4];
        dst[2] = *(uint4*)&pk[8]; dst[3] = *(uint4*)&pk[12];
        #pragma unroll
        for (int i = 0; i < 16; i++) {
            int ca = 128 + q * 32 + 2 * i;
            pk[i] = packbf((cv[2 * i] - mean) * inv * lnf_g[ca] + lnf_b[ca],
                           (cv[2 * i + 1] - mean) * inv * lnf_g[ca + 1] + lnf_b[ca + 1]);
        }
        dst = (uint4*)(dsm + SM_ACT + row * ASTR + 256 + q * 64);
        dst[0] = *(uint4*)&pk[0]; dst[1] = *(uint4*)&pk[4];
        dst[2] = *(uint4*)&pk[8]; dst[3] = *(uint4*)&pk[12];
        // tail cols 256..287 (bytes 512..575)
        uint32_t tp0 = 0, tp1 = 0;
        if (q == 0) {
            tp0 = packbf((c0 - mean) * inv * lnf_g[256] + lnf_b[256],
                         (c1 - mean) * inv * lnf_g[257] + lnf_b[257]);
            tp1 = packbf((c2v - mean) * inv * lnf_g[258] + lnf_b[258], 0.f);
        }
        *(uint4*)(dsm + SM_ACT + row * ASTR + 512 + q * 16) = make_uint4(tp0, tp1, 0u, 0u);
    }

    // ============ stage 1: h0 = comb @ wop1 ; LN + SiLU -> sA + hkeep ============
    asm volatile("cp.async.wait_group 2;");
    __syncthreads();
    do_gemm(SM_WOP1, 9);
    stage(op_b1);
    __syncthreads();
    {
        float v[32];
        #pragma unroll
        for (int i = 0; i < 8; i++) {
            float4 f = *(const float4*)&sS[row * 136 + q * 32 + i * 4];
            v[4 * i] = f.x; v[4 * i + 1] = f.y; v[4 * i + 2] = f.z; v[4 * i + 3] = f.w;
        }
        float s = 0.f;
        #pragma unroll
        for (int i = 0; i < 32; i++) s += v[i];
        s += __shfl_xor_sync(0xffffffffu, s, 1);
        s += __shfl_xor_sync(0xffffffffu, s, 2);
        float mean = s * (1.f / 128.f);
        float sq = 0.f;
        #pragma unroll
        for (int i = 0; i < 32; i++) { float d = v[i] - mean; sq += d * d; }
        sq += __shfl_xor_sync(0xffffffffu, sq, 1);
        sq += __shfl_xor_sync(0xffffffffu, sq, 2);
        float inv = rsqrtf(sq * (1.f / 128.f) + 1e-5f);
        #pragma unroll
        for (int i = 0; i < 16; i++) {
            int ca = q * 32 + 2 * i;
            float y0 = silu_f((v[2 * i] - mean) * inv * ln1_g[ca] + ln1_b[ca]);
            float y1 = silu_f((v[2 * i + 1] - mean) * inv * ln1_g[ca + 1] + ln1_b[ca + 1]);
            hkeep[i] = packbf(y0, y1);
        }
        uint4* dst = (uint4*)(dsm + SM_ACT + row * ASTR + q * 64);
        dst[0] = *(uint4*)&hkeep[0]; dst[1] = *(uint4*)&hkeep[4];
        dst[2] = *(uint4*)&hkeep[8]; dst[3] = *(uint4*)&hkeep[12];
    }

    // ============ stage 2: t = h1 @ wr1 ; LN + SiLU -> sA ============
    asm volatile("cp.async.wait_group 1;");
    __syncthreads();
    do_gemm(SM_WR1, 4);
    stage(r_b1);
    __syncthreads();
    {
        float v[32];
        #pragma unroll
        for (int i = 0; i < 8; i++) {
            float4 f = *(const float4*)&sS[row * 136 + q * 32 + i * 4];
            v[4 * i] = f.x; v[4 * i + 1] = f.y; v[4 * i + 2] = f.z; v[4 * i + 3] = f.w;
        }
        float s = 0.f;
        #pragma unroll
        for (int i = 0; i < 32; i++) s += v[i];
        s += __shfl_xor_sync(0xffffffffu, s, 1);
        s += __shfl_xor_sync(0xffffffffu, s, 2);
        float mean = s * (1.f / 128.f);
        float sq = 0.f;
        #pragma unroll
        for (int i = 0; i < 32; i++) { float d = v[i] - mean; sq += d * d; }
        sq += __shfl_xor_sync(0xffffffffu, sq, 1);
        sq += __shfl_xor_sync(0xffffffffu, sq, 2);
        float inv = rsqrtf(sq * (1.f / 128.f) + 1e-5f);
        uint32_t pk[16];
        #pragma unroll
        for (int i = 0; i < 16; i++) {
            int ca = q * 32 + 2 * i;
            float y0 = silu_f((v[2 * i] - mean) * inv * rln_g[ca] + rln_b[ca]);
            float y1 = silu_f((v[2 * i + 1] - mean) * inv * rln_g[ca + 1] + rln_b[ca + 1]);
            pk[i] = packbf(y0, y1);
        }
        uint4* dst = (uint4*)(dsm + SM_ACT + row * ASTR + q * 64);
        dst[0] = *(uint4*)&pk[0]; dst[1] = *(uint4*)&pk[4];
        dst[2] = *(uint4*)&pk[8]; dst[3] = *(uint4*)&pk[12];
    }

    // ============ stage 3: hfin = t2 @ wr2 + b + h1 ; LN ; proj/tanh/clamp ============
    asm volatile("cp.async.wait_group 0;");
    __syncthreads();
    do_gemm(SM_WR2, 4);
    stage(r_b2);
    __syncthreads();
    {
        float v[32];
        #pragma unroll
        for (int i = 0; i < 8; i++) {
            float4 f = *(const float4*)&sS[row * 136 + q * 32 + i * 4];
            v[4 * i] = f.x; v[4 * i + 1] = f.y; v[4 * i + 2] = f.z; v[4 * i + 3] = f.w;
        }
        #pragma unroll
        for (int i = 0; i < 16; i++) {
            __nv_bfloat162 hh = *(__nv_bfloat162*)&hkeep[i];
            v[2 * i]     += __bfloat162float(hh.x);
            v[2 * i + 1] += __bfloat162float(hh.y);
        }
        float s = 0.f;
        #pragma unroll
        for (int i = 0; i < 32; i++) s += v[i];
        s += __shfl_xor_sync(0xffffffffu, s, 1);
        s += __shfl_xor_sync(0xffffffffu, s, 2);
        float mean = s * (1.f / 128.f);
        float sq = 0.f;
        #pragma unroll
        for (int i = 0; i < 32; i++) { float d = v[i] - mean; sq += d * d; }
        sq += __shfl_xor_sync(0xffffffffu, sq, 1);
        sq += __shfl_xor_sync(0xffffffffu, sq, 2);
        float inv = rsqrtf(sq * (1.f / 128.f) + 1e-5f);

        float p0 = 0.f, p1 = 0.f, p2 = 0.f;
        #pragma unroll
        for (int i = 0; i < 32; i++) {
            int ca = q * 32 + i;
            float y = (v[i] - mean) * inv * ln2_g[ca] + ln2_b[ca];
            p0 += y * w3[ca * 3 + 0];
            p1 += y * w3[ca * 3 + 1];
            p2 += y * w3[ca * 3 + 2];
        }
        p0 += __shfl_xor_sync(0xffffffffu, p0, 1);
        p0 += __shfl_xor_sync(0xffffffffu, p0, 2);
        p1 += __shfl_xor_sync(0xffffffffu, p1, 1);
        p1 += __shfl_xor_sync(0xffffffffu, p1, 2);
        p2 += __shfl_xor_sync(0xffffffffu, p2, 1);
        p2 += __shfl_xor_sync(0xffffffffu, p2, 2);
        if (q == 0) {
            int bi = bidx[grow];
            float dots[3] = {p0 + b3[0], p1 + b3[1], p2 + b3[2]};
            #pragma unroll
            for (int j = 0; j < 3; j++) {
                float val = coordp[grow * 3 + j] + 0.01f * tanhf(dots[j]);
                fout[grow * 3 + j] = fminf(fmaxf(val, bmin[bi * 3 + j]), bmax[bi * 3 + j]);
            }
        }
    }
}

// ---------------- bf16 flash attention, 128-key chunks ----------------
#define CSTRIDE 80
#define QBUF    5120
#define KVB     10240

__device__ __forceinline__ void kv_load128(const __nv_bfloat16* __restrict__ Kh,
                                           const __nv_bfloat16* __restrict__ Vh,
                                           int h, int kb, uint32_t sbase, int tid) {
    #pragma unroll
    for (int i = 0; i < 8; i++) {
        int s = tid + i * 128;
        int row = (s >> 2) & 127, seg = s & 3;
        const __nv_bfloat16* src = ((s < 512) ? Kh : Vh)
            + (((h << 12) + (kb << 7) + row) << 5) + seg * 8;
        uint32_t dst = sbase + ((s < 512) ? 0 : KVB) + row * CSTRIDE + seg * 16;
        cpa16(dst, src);
    }
    asm volatile("cp.async.commit_group;");
}

__global__ void __launch_bounds__(128) flashb_k(const __nv_bfloat16* __restrict__ Qh,
                                                const __nv_bfloat16* __restrict__ Kh,
                                                const __nv_bfloat16* __restrict__ Vh,
                                                __nv_bfloat16* __restrict__ ao) {
    __shared__ __align__(16) char smem[QBUF + 4 * KVB];
    const int tid = threadIdx.x, lane = tid & 31, warp = tid >> 5;
    const int h = blockIdx.y, qb = blockIdx.x;

    char* Qs = smem;
    uint32_t Qsa = (uint32_t)__cvta_generic_to_shared(Qs);
    uint32_t kva0 = Qsa + QBUF;
    uint32_t kva1 = Qsa + QBUF + 2 * KVB;

    #pragma unroll
    for (int i = 0; i < 2; i++) {
        int s = tid + i * 128;
        int row = s >> 2, seg = s & 3;
        uint4 v = *(const uint4*)(Qh + (((h << 12) + (qb << 6) + row) << 5) + seg * 8);
        *(uint4*)(Qs + row * CSTRIDE + seg * 16) = v;
    }
    kv_load128(Kh, Vh, h, 0, kva0, tid);
    kv_load128(Kh, Vh, h, 1, kva1, tid);
    __syncthreads();

    uint32_t qa[8];
    {
        int i = lane & 7, sl = lane >> 3;
        int row = warp * 16 + ((sl & 1) ? 8 : 0) + i;
        uint32_t a = Qsa + row * CSTRIDE + ((sl >> 1) ? 16 : 0);
        ldsm4(qa[0], qa[1], qa[2], qa[3], a);
        ldsm4(qa[4], qa[5], qa[6], qa[7], a + 32);
    }

    float m0 = -1e30f, m1 = -1e30f, l0 = 0.f, l1 = 0.f;
    float o[4][4];
    #pragma unroll
    for (int j = 0; j < 4; j++)
        #pragma unroll
        for (int c = 0; c < 4; c++) o[j][c] = 0.f;

    const int i7 = lane & 7, sel = lane >> 3;
    const uint32_t krow = ((sel >= 2) ? 8 : 0) + i7;
    const uint32_t kcol = (sel & 1) ? 16 : 0;
    const uint32_t vrow = ((sel & 1) ? 8 : 0) + i7;
    const uint32_t vcol = (sel >= 2) ? 16 : 0;

    for (int kb = 0; kb < 32; kb++) {
        if (kb < 31) asm volatile("cp.async.wait_group 1;");
        else         asm volatile("cp.async.wait_group 0;");
        __syncthreads();
        uint32_t Kbase = (kb & 1) ? kva1 : kva0;
        uint32_t Vbase = Kbase + KVB;

        float s[16][4];
        #pragma unroll
        for (int j = 0; j < 16; j++)
            #pragma unroll
            for (int c = 0; c < 4; c++) s[j][c] = 0.f;

        #pragma unroll
        for (int jp = 0; jp < 8; jp++) {
            uint32_t a = Kbase + (jp * 16 + krow) * CSTRIDE + kcol;
            uint32_t b0, b1, b2, b3, c0, c1, c2, c3;
            ldsm4(b0, b1, b2, b3, a);
            ldsm4(c0, c1, c2, c3, a + 32);
            mma16816(s[2 * jp],     qa,     b0, b1);
            mma16816(s[2 * jp],     qa + 4, c0, c1);
            mma16816(s[2 * jp + 1], qa,     b2, b3);
            mma16816(s[2 * jp + 1], qa + 4, c2, c3);
        }

        float mx0 = -1e30f, mx1 = -1e30f;
        #pragma unroll
        for (int j = 0; j < 16; j++) {
            mx0 = fmaxf(mx0, fmaxf(s[j][0], s[j][1]));
            mx1 = fmaxf(mx1, fmaxf(s[j][2], s[j][3]));
        }
        mx0 = fmaxf(mx0, __shfl_xor_sync(0xffffffffu, mx0, 1));
        mx0 = fmaxf(mx0, __shfl_xor_sync(0xffffffffu, mx0, 2));
        mx1 = fmaxf(mx1, __shfl_xor_sync(0xffffffffu, mx1, 1));
        mx1 = fmaxf(mx1, __shfl_xor_sync(0xffffffffu, mx1, 2));
        float mn0 = fmaxf(m0, mx0), mn1 = fmaxf(m1, mx1);
        float f0 = __expf(m0 - mn0), f1 = __expf(m1 - mn1);
        m0 = mn0; m1 = mn1;
        float sum0 = 0.f, sum1 = 0.f;
        #pragma unroll
        for (int j = 0; j < 16; j++) {
            s[j][0] = __expf(s[j][0] - mn0);
            s[j][1] = __expf(s[j][1] - mn0);
            s[j][2] = __expf(s[j][2] - mn1);
            s[j][3] = __expf(s[j][3] - mn1);
            sum0 += s[j][0] + s[j][1];
            sum1 += s[j][2] + s[j][3];
        }
        sum0 += __shfl_xor_sync(0xffffffffu, sum0, 1);
        sum0 += __shfl_xor_sync(0xffffffffu, sum0, 2);
        sum1 += __shfl_xor_sync(0xffffffffu, sum1, 1);
        sum1 += __shfl_xor_sync(0xffffffffu, sum1, 2);
        l0 = l0 * f0 + sum0;
        l1 = l1 * f1 + sum1;
        #pragma unroll
        for (int j = 0; j < 4; j++) {
            o[j][0] *= f0; o[j][1] *= f0;
            o[j][2] *= f1; o[j][3] *= f1;
        }

        #pragma unroll
        for (int ks = 0; ks < 8; ks++) {
            uint32_t pa[4];
            pa[0] = packbf(s[2 * ks][0],     s[2 * ks][1]);
            pa[1] = packbf(s[2 * ks][2],     s[2 * ks][3]);
            pa[2] = packbf(s[2 * ks + 1][0], s[2 * ks + 1][1]);
            pa[3] = packbf(s[2 * ks + 1][2], s[2 * ks + 1][3]);
            uint32_t a = Vbase + (ks * 16 + vrow) * CSTRIDE + vcol;
            uint32_t v0, v1, v2, v3, w0, w1, w2, w3;
            ldsm4t(v0, v1, v2, v3, a);
            ldsm4t(w0, w1, w2, w3, a + 32);
            mma16816(o[0], pa, v0, v1);
            mma16816(o[1], pa, v2, v3);
            mma16816(o[2], pa, w0, w1);
            mma16816(o[3], pa, w2, w3);
        }

        __syncthreads();
        if (kb < 30) kv_load128(Kh, Vh, h, kb + 2, (kb & 1) ? kva1 : kva0, tid);
    }

    float inv0 = 1.f / l0, inv1 = 1.f / l1;
    int g = lane >> 2, l2 = (lane & 3) * 2;
    int row0 = (qb << 6) + warp * 16 + g;
    #pragma unroll
    for (int j = 0; j < 4; j++) {
        int col = (h << 5) + j * 8 + l2;
        *(uint32_t*)&ao[row0 * HDIM + col]       = packbf(o[j][0] * inv0, o[j][1] * inv0);
        *(uint32_t*)&ao[(row0 + 8) * HDIM + col] = packbf(o[j][2] * inv1, o[j][3] * inv1);
    }
}

// ---------------- host ----------------
extern "C" void kernel_launch(void* const* d_in, const int* in_sizes, int n_in,
                              void* d_out, int out_size) {
    const int*   num_atoms  = (const int*)d_in[0];
    const int*   elems      = (const int*)d_in[1];
    const float* cell       = (const float*)d_in[2];
    const float* coord      = (const float*)d_in[3];
    const float* emb        = (const float*)d_in[4];
    const float* ln_in_g    = (const float*)d_in[5];
    const float* ln_in_b    = (const float*)d_in[6];
    const float* attn_in_w  = (const float*)d_in[7];
    const float* attn_in_b  = (const float*)d_in[8];
    const float* attn_out_w = (const float*)d_in[9];
    const float* attn_out_b = (const float*)d_in[10];
    const float* ce_w1      = (const float*)d_in[11];
    const float* ce_b1      = (const float*)d_in[12];
    const float* ce_w2      = (const float*)d_in[13];
    const float* ce_b2      = (const float*)d_in[14];
    const float* ln_feat_g  = (const float*)d_in[15];
    const float* ln_feat_b  = (const float*)d_in[16];
    const float* op_w1      = (const float*)d_in[17];
    const float* op_b1      = (const float*)d_in[18];
    const float* op_ln1_g   = (const float*)d_in[19];
    const float* op_ln1_b   = (const float*)d_in[20];
    const float* res_w1     = (const float*)d_in[21];
    const float* res_b1     = (const float*)d_in[22];
    const float* res_ln_g   = (const float*)d_in[23];
    const float* res_ln_b   = (const float*)d_in[24];
    const float* res_w2     = (const float*)d_in[25];
    const float* res_b2     = (const float*)d_in[26];
    const float* op_ln2_g   = (const float*)d_in[27];
    const float* op_ln2_b   = (const float*)d_in[28];
    const float* op_w3      = (const float*)d_in[29];
    const float* op_b3      = (const float*)d_in[30];
    float* out = (float*)d_out;

    float* S = nullptr;
    cudaGetSymbolAddress((void**)&S, g_scratch);
    int* bidx = nullptr;
    cudaGetSymbolAddress((void**)&bidx, g_bidx);

    __nv_bfloat16* P = (__nv_bfloat16*)S;
    __nv_bfloat16* xb    = P; P += NATOMS * HDIM;
    __nv_bfloat16* Qh    = P; P += NATOMS * HDIM;
    __nv_bfloat16* Kh    = P; P += NATOMS * HDIM;
    __nv_bfloat16* Vh    = P; P += NATOMS * HDIM;
    __nv_bfloat16* aob   = P; P += NATOMS * HDIM;
    __nv_bfloat16* wqkv  = P; P += 128 * 384;
    __nv_bfloat16* wao   = P; P += 128 * 128;
    __nv_bfloat16* wop1  = P; P += FPAD * 128;
    __nv_bfloat16* wr1   = P; P += 128 * 128;
    __nv_bfloat16* wr2   = P; P += 128 * 128;
    float* F = (float*)P;
    float* cf   = F; F += BATCH * HDIM;
    float* bmin = F; F += BATCH * 3;
    float* bmax = F; F += BATCH * 3;

    static bool attr_set = false;
    if (!attr_set) {
        cudaFuncSetAttribute(tail_k, cudaFuncAttributeMaxDynamicSharedMemorySize, SMEM_TAIL);
        attr_set = true;
    }

    setup_k<<<1049, 256>>>(elems, emb, ln_in_g, ln_in_b, xb,
                           attn_in_w, attn_out_w, op_w1, res_w1, res_w2,
                           wqkv, wao, wop1, wr1, wr2,
                           cell, ce_w1, ce_b1, ce_w2, ce_b2, cf,
                           num_atoms, bmin, bmax);

    qkv_k<<<dim3(3, 128), 128>>>(xb, wqkv, attn_in_b, Qh, Kh, Vh);

    flashb_k<<<dim3(64, NHEAD), 128>>>(Qh, Kh, Vh, aob);

    tail_k<<<128, 128, SMEM_TAIL>>>(aob,
        wao, attn_out_b, ln_feat_g, ln_feat_b, cf, coord, bidx,
        wop1, op_b1, op_ln1_g, op_ln1_b,
        wr1, res_b1, res_ln_g, res_ln_b,
        wr2, res_b2, op_ln2_g, op_ln2_b,
        op_w3, op_b3, bmin, bmax, out);
}

// round 6
// speedup vs baseline: 6.2975x; 1.0708x over previous
#include <cuda_runtime.h>
#include <cuda_bf16.h>
#include <math.h>
#include <stdint.h>

#define NATOMS 4096
#define HDIM   128
#define BATCH  128
#define NHEAD  4
#define DHEAD  32
#define H3     384
#define FPAD   288

// -------- scratch (no allocations allowed) --------
__device__ float g_scratch[8300000];
__device__ int   g_bidx[NATOMS];

// ---------------- helpers ----------------
__device__ __forceinline__ float silu_f(float x) {
    return x / (1.f + __expf(-x));
}
__device__ __forceinline__ void ldsm4(uint32_t& r0, uint32_t& r1, uint32_t& r2, uint32_t& r3, uint32_t addr) {
    asm volatile("ldmatrix.sync.aligned.m8n8.x4.shared.b16 {%0,%1,%2,%3}, [%4];"
                 : "=r"(r0), "=r"(r1), "=r"(r2), "=r"(r3) : "r"(addr));
}
__device__ __forceinline__ void ldsm4t(uint32_t& r0, uint32_t& r1, uint32_t& r2, uint32_t& r3, uint32_t addr) {
    asm volatile("ldmatrix.sync.aligned.m8n8.x4.trans.shared.b16 {%0,%1,%2,%3}, [%4];"
                 : "=r"(r0), "=r"(r1), "=r"(r2), "=r"(r3) : "r"(addr));
}
__device__ __forceinline__ void mma16816(float* d, const uint32_t* a, uint32_t b0, uint32_t b1) {
    asm volatile("mma.sync.aligned.m16n8k16.row.col.f32.bf16.bf16.f32 "
                 "{%0,%1,%2,%3}, {%4,%5,%6,%7}, {%8,%9}, {%0,%1,%2,%3};"
                 : "+f"(d[0]), "+f"(d[1]), "+f"(d[2]), "+f"(d[3])
                 : "r"(a[0]), "r"(a[1]), "r"(a[2]), "r"(a[3]), "r"(b0), "r"(b1));
}
__device__ __forceinline__ uint32_t packbf(float lo, float hi) {
    uint32_t r;
    asm volatile("cvt.rn.bf16x2.f32 %0, %1, %2;" : "=r"(r) : "f"(hi), "f"(lo));
    return r;
}
__device__ __forceinline__ void cpa16(uint32_t dst, const void* src) {
    asm volatile("cp.async.ca.shared.global [%0], [%1], 16;" :: "r"(dst), "l"(src));
}

// ================= fused setup kernel =================
__global__ void __launch_bounds__(256) setup_k(
    const int* __restrict__ elems, const float* __restrict__ emb,
    const float* __restrict__ ln_in_g, const float* __restrict__ ln_in_b,
    __nv_bfloat16* __restrict__ xo,
    const float* __restrict__ aiw, const float* __restrict__ aow,
    const float* __restrict__ opw1, const float* __restrict__ rw1,
    const float* __restrict__ rw2,
    __nv_bfloat16* __restrict__ wqkv, __nv_bfloat16* __restrict__ wao,
    __nv_bfloat16* __restrict__ wop1, __nv_bfloat16* __restrict__ wr1,
    __nv_bfloat16* __restrict__ wr2,
    const float* __restrict__ cell,
    const float* __restrict__ cw1, const float* __restrict__ cb1,
    const float* __restrict__ cw2, const float* __restrict__ cb2,
    float* __restrict__ cf,
    const int* __restrict__ num_atoms,
    float* __restrict__ bmin, float* __restrict__ bmax)
{
    const int b = blockIdx.x, tid = threadIdx.x;

    if (b < 512) {
        int warp = tid >> 5, lane = tid & 31;
        int r = b * 8 + warp;
        int e = elems[r];
        float4 v = *(const float4*)&emb[e * HDIM + lane * 4];
        float s = v.x + v.y + v.z + v.w;
        #pragma unroll
        for (int off = 16; off > 0; off >>= 1) s += __shfl_xor_sync(0xffffffffu, s, off);
        float mean = s * (1.f / 128.f);
        float dx = v.x - mean, dy = v.y - mean, dz = v.z - mean, dw = v.w - mean;
        float sq = dx * dx + dy * dy + dz * dz + dw * dw;
        #pragma unroll
        for (int off = 16; off > 0; off >>= 1) sq += __shfl_xor_sync(0xffffffffu, sq, off);
        float inv = rsqrtf(sq * (1.f / 128.f) + 1e-5f);
        float4 gg = *(const float4*)&ln_in_g[lane * 4];
        float4 bb = *(const float4*)&ln_in_b[lane * 4];
        uint32_t p0 = packbf(dx * inv * gg.x + bb.x, dy * inv * gg.y + bb.y);
        uint32_t p1 = packbf(dz * inv * gg.z + bb.z, dw * inv * gg.w + bb.w);
        *(uint2*)(xo + r * HDIM + lane * 4) = make_uint2(p0, p1);
        return;
    }

    if (b < 1040) {
        int i = (b - 512) * 256 + tid;
        if (i < 49152) wqkv[i] = __float2bfloat16(aiw[i]);
        else if (i < 65536) { int j = i - 49152; wao[j] = __float2bfloat16(aow[j]); }
        else if (i < 102400) {
            int j = i - 65536; int r = j >> 7, c = j & 127;
            wop1[j] = __float2bfloat16(r < 259 ? opw1[r * 128 + c] : 0.f);
        }
        else if (i < 118784) { int j = i - 102400; wr1[j] = __float2bfloat16(rw1[j]); }
        else { int j = i - 118784; wr2[j] = __float2bfloat16(rw2[j]); }
        return;
    }

    if (b < 1048) {
        __shared__ float t1s[16][128];
        int r0 = (b - 1040) * 16;
        #pragma unroll
        for (int i = 0; i < 8; i++) {
            int idx = tid + i * 256;
            int rr = idx >> 7, k = idx & 127;
            int r = r0 + rr;
            float u = cell[r * 3 + 0] * cw1[k] + cell[r * 3 + 1] * cw1[128 + k]
                    + cell[r * 3 + 2] * cw1[256 + k] + cb1[k];
            t1s[rr][k] = silu_f(u);
        }
        __syncthreads();
        int t = tid & 127, half = tid >> 7;
        float acc[8];
        #pragma unroll
        for (int j = 0; j < 8; j++) acc[j] = cb2[t];
        #pragma unroll 4
        for (int k = 0; k < 128; k++) {
            float w = cw2[k * 128 + t];
            #pragma unroll
            for (int j = 0; j < 8; j++) acc[j] += t1s[half * 8 + j][k] * w;
        }
        #pragma unroll
        for (int j = 0; j < 8; j++) cf[(r0 + half * 8 + j) * 128 + t] = acc[j];
        return;
    }

    __shared__ int starts[BATCH + 1];
    if (tid == 0) {
        int acc = 0;
        for (int i = 0; i < BATCH; i++) { starts[i] = acc; acc += num_atoms[i]; }
        starts[BATCH] = acc;
    }
    __syncthreads();
    for (int i = tid; i < NATOMS; i += 256) g_bidx[i] = BATCH - 1;
    __syncthreads();
    if (tid < BATCH) {
        int s = starts[tid], e = starts[tid + 1];
        if (s > NATOMS) s = NATOMS;
        if (e > NATOMS) e = NATOMS;
        for (int i = s; i < e; i++) g_bidx[i] = tid;
        #pragma unroll
        for (int i = 0; i < 3; i++) {
            float a = cell[(3 * tid + i) * 3 + 0];
            float c1 = cell[(3 * tid + i) * 3 + 1];
            float c = cell[(3 * tid + i) * 3 + 2];
            bmin[tid * 3 + i] = fminf(a, fminf(c1, c)) + 1e-6f;
            bmax[tid * 3 + i] = fmaxf(a, fmaxf(c1, c)) - 1e-6f;
        }
    }
}

// ================= QKV GEMM (BM=32, BN=128, BK=32, double-buffered) =================
__global__ void __launch_bounds__(128) qkv_k(
    const __nv_bfloat16* __restrict__ A, const __nv_bfloat16* __restrict__ W,
    const float* __restrict__ bias,
    __nv_bfloat16* __restrict__ Qh, __nv_bfloat16* __restrict__ Kh,
    __nv_bfloat16* __restrict__ Vh)
{
    __shared__ __align__(16) char sA[2 * 32 * 80];
    __shared__ __align__(16) char sW[2 * 32 * 272];
    const int tid = threadIdx.x, lane = tid & 31, warp = tid >> 5;
    const int wr = warp & 1, wc = warp >> 1;
    const int bm = blockIdx.y, nb = blockIdx.x;
    uint32_t aBase = (uint32_t)__cvta_generic_to_shared(sA);
    uint32_t wBase = (uint32_t)__cvta_generic_to_shared(sW);

    #pragma unroll
    for (int p = 0; p < 2; p++) {
        int row = tid >> 2, seg = tid & 3;
        cpa16(aBase + p * 2560 + row * 80 + seg * 16,
              A + (bm * 32 + row) * 128 + p * 32 + seg * 8);
        #pragma unroll
        for (int i = 0; i < 4; i++) {
            int s = tid + i * 128;
            int wrow = s >> 4, wseg = s & 15;
            cpa16(wBase + p * 8704 + wrow * 272 + wseg * 16,
                  W + (p * 32 + wrow) * H3 + nb * 128 + wseg * 8);
        }
        asm volatile("cp.async.commit_group;");
    }

    float acc[8][4];
    #pragma unroll
    for (int j = 0; j < 8; j++)
        #pragma unroll
        for (int c = 0; c < 4; c++) acc[j][c] = 0.f;

    const int i7 = lane & 7, sel = lane >> 3;
    const int arow = wr * 16 + ((sel & 1) ? 8 : 0) + i7;
    const int acol = (sel >> 1) ? 16 : 0;
    const int vrow = ((sel & 1) ? 8 : 0) + i7;
    const int vcol = (sel >= 2) ? 16 : 0;

    for (int ks = 0; ks < 4; ks++) {
        if (ks < 3) asm volatile("cp.async.wait_group 1;");
        else        asm volatile("cp.async.wait_group 0;");
        __syncthreads();
        uint32_t Ab = aBase + (ks & 1) * 2560;
        uint32_t Wb = wBase + (ks & 1) * 8704;
        #pragma unroll
        for (int kh = 0; kh < 2; kh++) {
            uint32_t qa[4];
            ldsm4(qa[0], qa[1], qa[2], qa[3], Ab + arow * 80 + acol + kh * 32);
            #pragma unroll
            for (int j = 0; j < 4; j++) {
                uint32_t r0, r1, r2, r3;
                ldsm4t(r0, r1, r2, r3, Wb + (kh * 16 + vrow) * 272 + wc * 128 + j * 32 + vcol);
                mma16816(acc[2 * j],     qa, r0, r1);
                mma16816(acc[2 * j + 1], qa, r2, r3);
            }
        }
        __syncthreads();
        if (ks + 2 < 4) {
            int p = ks + 2, buf = ks & 1;
            int row = tid >> 2, seg = tid & 3;
            cpa16(aBase + buf * 2560 + row * 80 + seg * 16,
                  A + (bm * 32 + row) * 128 + p * 32 + seg * 8);
            #pragma unroll
            for (int i = 0; i < 4; i++) {
                int s = tid + i * 128;
                int wrow = s >> 4, wseg = s & 15;
                cpa16(wBase + buf * 8704 + wrow * 272 + wseg * 16,
                      W + (p * 32 + wrow) * H3 + nb * 128 + wseg * 8);
            }
            asm volatile("cp.async.commit_group;");
        }
    }

    const int g = lane >> 2, c2 = (lane & 3) * 2;
    int r0 = bm * 32 + wr * 16 + g;
    __nv_bfloat16* outp = (nb == 0) ? Qh : (nb == 1) ? Kh : Vh;
    // fold log2(e) into Q scale so flash can use exp2f
    float sc = (nb == 0) ? (0.17677669529663687f * 1.4426950408889634f) : 1.f;
    #pragma unroll
    for (int t = 0; t < 8; t++) {
        int col = wc * 64 + t * 8 + c2;
        float b0v = bias[nb * 128 + col], b1v = bias[nb * 128 + col + 1];
        int h = col >> 5, d = col & 31;
        *(uint32_t*)(outp + (((h << 12) + r0) << 5) + d) =
            packbf((acc[t][0] + b0v) * sc, (acc[t][1] + b1v) * sc);
        *(uint32_t*)(outp + (((h << 12) + r0 + 8) << 5) + d) =
            packbf((acc[t][2] + b0v) * sc, (acc[t][3] + b1v) * sc);
    }
}

// ================= fused tail: 4 GEMMs + LNs + final (256 threads, 8 warps) ==========
#define WSTR 272
#define ASTR 592
#define SM_WAO   0
#define SM_WOP1  (128 * WSTR)
#define SM_WR1   (SM_WOP1 + 288 * WSTR)
#define SM_WR2   (SM_WR1 + 128 * WSTR)
#define SM_ACT   (SM_WR2 + 128 * WSTR)
#define SM_STAGE (SM_ACT + 32 * ASTR)
#define SMEM_TAIL (SM_STAGE + 32 * 136 * 4)

__global__ void __launch_bounds__(256) tail_k(
    const __nv_bfloat16* __restrict__ aob,
    const __nv_bfloat16* __restrict__ wao, const float* __restrict__ aob_bias,
    const float* __restrict__ lnf_g, const float* __restrict__ lnf_b,
    const float* __restrict__ cf, const float* __restrict__ coordp,
    const int* __restrict__ bidx,
    const __nv_bfloat16* __restrict__ wop1, const float* __restrict__ op_b1,
    const float* __restrict__ ln1_g, const float* __restrict__ ln1_b,
    const __nv_bfloat16* __restrict__ wr1, const float* __restrict__ r_b1,
    const float* __restrict__ rln_g, const float* __restrict__ rln_b,
    const __nv_bfloat16* __restrict__ wr2, const float* __restrict__ r_b2,
    const float* __restrict__ ln2_g, const float* __restrict__ ln2_b,
    const float* __restrict__ w3, const float* __restrict__ b3,
    const float* __restrict__ bmin, const float* __restrict__ bmax,
    float* __restrict__ fout)
{
    extern __shared__ __align__(16) char dsm[];
    const int tid = threadIdx.x, lane = tid & 31, warp = tid >> 5;
    const int wr = warp & 1, wc = warp >> 1;   // 2 x 4 warp grid
    const int bm = blockIdx.x;
    uint32_t base = (uint32_t)__cvta_generic_to_shared(dsm);
    uint32_t aAct = base + SM_ACT;
    float* sS = (float*)(dsm + SM_STAGE);

    // ---- group 0: activation tile + wao ----
    #pragma unroll
    for (int i = 0; i < 2; i++) {
        int s = tid + i * 256;
        int row = s >> 4, seg = s & 15;
        cpa16(aAct + row * ASTR + seg * 16, aob + (bm * 32 + row) * 128 + seg * 8);
    }
    #pragma unroll
    for (int i = 0; i < 8; i++) {
        int s = tid + i * 256;
        int row = s >> 4, seg = s & 15;
        cpa16(base + SM_WAO + row * WSTR + seg * 16, wao + row * 128 + seg * 8);
    }
    asm volatile("cp.async.commit_group;");
    // ---- group 1: wop1 (288 rows) ----
    #pragma unroll
    for (int i = 0; i < 18; i++) {
        int s = tid + i * 256;
        int row = s >> 4, seg = s & 15;
        cpa16(base + SM_WOP1 + row * WSTR + seg * 16, wop1 + row * 128 + seg * 8);
    }
    asm volatile("cp.async.commit_group;");
    // ---- group 2: wr1 ----
    #pragma unroll
    for (int i = 0; i < 8; i++) {
        int s = tid + i * 256;
        int row = s >> 4, seg = s & 15;
        cpa16(base + SM_WR1 + row * WSTR + seg * 16, wr1 + row * 128 + seg * 8);
    }
    asm volatile("cp.async.commit_group;");
    // ---- group 3: wr2 ----
    #pragma unroll
    for (int i = 0; i < 8; i++) {
        int s = tid + i * 256;
        int row = s >> 4, seg = s & 15;
        cpa16(base + SM_WR2 + row * WSTR + seg * 16, wr2 + row * 128 + seg * 8);
    }
    asm volatile("cp.async.commit_group;");

    const int i7 = lane & 7, sel = lane >> 3;
    const int arow = wr * 16 + ((sel & 1) ? 8 : 0) + i7;
    const int acol = (sel >> 1) ? 16 : 0;
    const int vrow = ((sel & 1) ? 8 : 0) + i7;
    const int vcol = (sel >= 2) ? 16 : 0;
    const int row = tid >> 3, q = tid & 7;     // LN: 8 threads per row
    const int grow = bm * 32 + row;
    const int sr0 = wr * 16 + (lane >> 2);
    const int c2 = (lane & 3) * 2;

    float acc[4][4];
    uint32_t hkeep[8];

    auto do_gemm = [&](int wOff, int ksteps) {
        #pragma unroll
        for (int j = 0; j < 4; j++)
            #pragma unroll
            for (int c = 0; c < 4; c++) acc[j][c] = 0.f;
        for (int ks = 0; ks < ksteps; ks++) {
            #pragma unroll
            for (int kh = 0; kh < 2; kh++) {
                uint32_t qa[4];
                ldsm4(qa[0], qa[1], qa[2], qa[3], aAct + arow * ASTR + ks * 64 + kh * 32 + acol);
                #pragma unroll
                for (int j = 0; j < 2; j++) {
                    uint32_t r0, r1, r2, r3;
                    ldsm4t(r0, r1, r2, r3,
                           base + wOff + (ks * 32 + kh * 16 + vrow) * WSTR + wc * 64 + j * 32 + vcol);
                    mma16816(acc[2 * j],     qa, r0, r1);
                    mma16816(acc[2 * j + 1], qa, r2, r3);
                }
            }
        }
    };

    auto stage = [&](const float* bias) {
        #pragma unroll
        for (int t = 0; t < 4; t++) {
            int col = wc * 32 + t * 8 + c2;
            float a0 = bias[col], a1 = bias[col + 1];
            sS[sr0 * 136 + col] = acc[t][0] + a0;       sS[sr0 * 136 + col + 1] = acc[t][1] + a1;
            sS[(sr0 + 8) * 136 + col] = acc[t][2] + a0; sS[(sr0 + 8) * 136 + col + 1] = acc[t][3] + a1;
        }
    };

    // ============ stage 0: xa = aob @ wao + b ; comb-LN(259) ============
    asm volatile("cp.async.wait_group 3;");
    __syncthreads();
    do_gemm(SM_WAO, 4);
    stage(aob_bias);
    __syncthreads();
    {
        int bi = bidx[grow];
        float xv[16], cv[16];
        #pragma unroll
        for (int i = 0; i < 4; i++) {
            float4 f = *(const float4*)&sS[row * 136 + q * 16 + i * 4];
            xv[4 * i] = f.x; xv[4 * i + 1] = f.y; xv[4 * i + 2] = f.z; xv[4 * i + 3] = f.w;
            float4 c = *(const float4*)&cf[bi * 128 + q * 16 + i * 4];
            cv[4 * i] = c.x; cv[4 * i + 1] = c.y; cv[4 * i + 2] = c.z; cv[4 * i + 3] = c.w;
        }
        float c0 = 0.f, c1 = 0.f, c2v = 0.f;
        float s = 0.f;
        #pragma unroll
        for (int i = 0; i < 16; i++) s += xv[i] + cv[i];
        if (q == 0) {
            c0 = coordp[grow * 3 + 0]; c1 = coordp[grow * 3 + 1]; c2v = coordp[grow * 3 + 2];
            s += c0 + c1 + c2v;
        }
        s += __shfl_xor_sync(0xffffffffu, s, 1);
        s += __shfl_xor_sync(0xffffffffu, s, 2);
        s += __shfl_xor_sync(0xffffffffu, s, 4);
        float mean = s * (1.f / 259.f);
        float sq = 0.f;
        #pragma unroll
        for (int i = 0; i < 16; i++) {
            float d0 = xv[i] - mean, d1 = cv[i] - mean;
            sq += d0 * d0 + d1 * d1;
        }
        if (q == 0) {
            float d0 = c0 - mean, d1 = c1 - mean, d2 = c2v - mean;
            sq += d0 * d0 + d1 * d1 + d2 * d2;
        }
        sq += __shfl_xor_sync(0xffffffffu, sq, 1);
        sq += __shfl_xor_sync(0xffffffffu, sq, 2);
        sq += __shfl_xor_sync(0xffffffffu, sq, 4);
        float inv = rsqrtf(sq * (1.f / 259.f) + 1e-5f);

        uint32_t pk[8];
        #pragma unroll
        for (int i = 0; i < 8; i++) {
            int ca = q * 16 + 2 * i;
            pk[i] = packbf((xv[2 * i] - mean) * inv * lnf_g[ca] + lnf_b[ca],
                           (xv[2 * i + 1] - mean) * inv * lnf_g[ca + 1] + lnf_b[ca + 1]);
        }
        uint4* dst = (uint4*)(dsm + SM_ACT + row * ASTR + q * 32);
        dst[0] = *(uint4*)&pk[0]; dst[1] = *(uint4*)&pk[4];
        #pragma unroll
        for (int i = 0; i < 8; i++) {
            int ca = 128 + q * 16 + 2 * i;
            pk[i] = packbf((cv[2 * i] - mean) * inv * lnf_g[ca] + lnf_b[ca],
                           (cv[2 * i + 1] - mean) * inv * lnf_g[ca + 1] + lnf_b[ca + 1]);
        }
        dst = (uint4*)(dsm + SM_ACT + row * ASTR + 256 + q * 32);
        dst[0] = *(uint4*)&pk[0]; dst[1] = *(uint4*)&pk[4];
        // tail cols 256..287 (bytes 512..575): 8 bytes per q-thread
        uint32_t tp0 = 0, tp1 = 0;
        if (q == 0) {
            tp0 = packbf((c0 - mean) * inv * lnf_g[256] + lnf_b[256],
                         (c1 - mean) * inv * lnf_g[257] + lnf_b[257]);
            tp1 = packbf((c2v - mean) * inv * lnf_g[258] + lnf_b[258], 0.f);
        }
        *(uint2*)(dsm + SM_ACT + row * ASTR + 512 + q * 8) = make_uint2(tp0, tp1);
    }

    // ============ stage 1: h0 = comb @ wop1 ; LN + SiLU ============
    asm volatile("cp.async.wait_group 2;");
    __syncthreads();
    do_gemm(SM_WOP1, 9);
    stage(op_b1);
    __syncthreads();
    {
        float v[16];
        #pragma unroll
        for (int i = 0; i < 4; i++) {
            float4 f = *(const float4*)&sS[row * 136 + q * 16 + i * 4];
            v[4 * i] = f.x; v[4 * i + 1] = f.y; v[4 * i + 2] = f.z; v[4 * i + 3] = f.w;
        }
        float s = 0.f;
        #pragma unroll
        for (int i = 0; i < 16; i++) s += v[i];
        s += __shfl_xor_sync(0xffffffffu, s, 1);
        s += __shfl_xor_sync(0xffffffffu, s, 2);
        s += __shfl_xor_sync(0xffffffffu, s, 4);
        float mean = s * (1.f / 128.f);
        float sq = 0.f;
        #pragma unroll
        for (int i = 0; i < 16; i++) { float d = v[i] - mean; sq += d * d; }
        sq += __shfl_xor_sync(0xffffffffu, sq, 1);
        sq += __shfl_xor_sync(0xffffffffu, sq, 2);
        sq += __shfl_xor_sync(0xffffffffu, sq, 4);
        float inv = rsqrtf(sq * (1.f / 128.f) + 1e-5f);
        #pragma unroll
        for (int i = 0; i < 8; i++) {
            int ca = q * 16 + 2 * i;
            float y0 = silu_f((v[2 * i] - mean) * inv * ln1_g[ca] + ln1_b[ca]);
            float y1 = silu_f((v[2 * i + 1] - mean) * inv * ln1_g[ca + 1] + ln1_b[ca + 1]);
            hkeep[i] = packbf(y0, y1);
        }
        uint4* dst = (uint4*)(dsm + SM_ACT + row * ASTR + q * 32);
        dst[0] = *(uint4*)&hkeep[0]; dst[1] = *(uint4*)&hkeep[4];
    }

    // ============ stage 2: t = h1 @ wr1 ; LN + SiLU ============
    asm volatile("cp.async.wait_group 1;");
    __syncthreads();
    do_gemm(SM_WR1, 4);
    stage(r_b1);
    __syncthreads();
    {
        float v[16];
        #pragma unroll
        for (int i = 0; i < 4; i++) {
            float4 f = *(const float4*)&sS[row * 136 + q * 16 + i * 4];
            v[4 * i] = f.x; v[4 * i + 1] = f.y; v[4 * i + 2] = f.z; v[4 * i + 3] = f.w;
        }
        float s = 0.f;
        #pragma unroll
        for (int i = 0; i < 16; i++) s += v[i];
        s += __shfl_xor_sync(0xffffffffu, s, 1);
        s += __shfl_xor_sync(0xffffffffu, s, 2);
        s += __shfl_xor_sync(0xffffffffu, s, 4);
        float mean = s * (1.f / 128.f);
        float sq = 0.f;
        #pragma unroll
        for (int i = 0; i < 16; i++) { float d = v[i] - mean; sq += d * d; }
        sq += __shfl_xor_sync(0xffffffffu, sq, 1);
        sq += __shfl_xor_sync(0xffffffffu, sq, 2);
        sq += __shfl_xor_sync(0xffffffffu, sq, 4);
        float inv = rsqrtf(sq * (1.f / 128.f) + 1e-5f);
        uint32_t pk[8];
        #pragma unroll
        for (int i = 0; i < 8; i++) {
            int ca = q * 16 + 2 * i;
            float y0 = silu_f((v[2 * i] - mean) * inv * rln_g[ca] + rln_b[ca]);
            float y1 = silu_f((v[2 * i + 1] - mean) * inv * rln_g[ca + 1] + rln_b[ca + 1]);
            pk[i] = packbf(y0, y1);
        }
        uint4* dst = (uint4*)(dsm + SM_ACT + row * ASTR + q * 32);
        dst[0] = *(uint4*)&pk[0]; dst[1] = *(uint4*)&pk[4];
    }

    // ============ stage 3: hfin = t2 @ wr2 + b + h1 ; LN ; proj/tanh/clamp ============
    asm volatile("cp.async.wait_group 0;");
    __syncthreads();
    do_gemm(SM_WR2, 4);
    stage(r_b2);
    __syncthreads();
    {
        float v[16];
        #pragma unroll
        for (int i = 0; i < 4; i++) {
            float4 f = *(const float4*)&sS[row * 136 + q * 16 + i * 4];
            v[4 * i] = f.x; v[4 * i + 1] = f.y; v[4 * i + 2] = f.z; v[4 * i + 3] = f.w;
        }
        #pragma unroll
        for (int i = 0; i < 8; i++) {
            __nv_bfloat162 hh = *(__nv_bfloat162*)&hkeep[i];
            v[2 * i]     += __bfloat162float(hh.x);
            v[2 * i + 1] += __bfloat162float(hh.y);
        }
        float s = 0.f;
        #pragma unroll
        for (int i = 0; i < 16; i++) s += v[i];
        s += __shfl_xor_sync(0xffffffffu, s, 1);
        s += __shfl_xor_sync(0xffffffffu, s, 2);
        s += __shfl_xor_sync(0xffffffffu, s, 4);
        float mean = s * (1.f / 128.f);
        float sq = 0.f;
        #pragma unroll
        for (int i = 0; i < 16; i++) { float d = v[i] - mean; sq += d * d; }
        sq += __shfl_xor_sync(0xffffffffu, sq, 1);
        sq += __shfl_xor_sync(0xffffffffu, sq, 2);
        sq += __shfl_xor_sync(0xffffffffu, sq, 4);
        float inv = rsqrtf(sq * (1.f / 128.f) + 1e-5f);

        float p0 = 0.f, p1 = 0.f, p2 = 0.f;
        #pragma unroll
        for (int i = 0; i < 16; i++) {
            int ca = q * 16 + i;
            float y = (v[i] - mean) * inv * ln2_g[ca] + ln2_b[ca];
            p0 += y * w3[ca * 3 + 0];
            p1 += y * w3[ca * 3 + 1];
            p2 += y * w3[ca * 3 + 2];
        }
        p0 += __shfl_xor_sync(0xffffffffu, p0, 1);
        p0 += __shfl_xor_sync(0xffffffffu, p0, 2);
        p0 += __shfl_xor_sync(0xffffffffu, p0, 4);
        p1 += __shfl_xor_sync(0xffffffffu, p1, 1);
        p1 += __shfl_xor_sync(0xffffffffu, p1, 2);
        p1 += __shfl_xor_sync(0xffffffffu, p1, 4);
        p2 += __shfl_xor_sync(0xffffffffu, p2, 1);
        p2 += __shfl_xor_sync(0xffffffffu, p2, 2);
        p2 += __shfl_xor_sync(0xffffffffu, p2, 4);
        if (q == 0) {
            int bi = bidx[grow];
            float dots[3] = {p0 + b3[0], p1 + b3[1], p2 + b3[2]};
            #pragma unroll
            for (int j = 0; j < 3; j++) {
                float val = coordp[grow * 3 + j] + 0.01f * tanhf(dots[j]);
                fout[grow * 3 + j] = fminf(fmaxf(val, bmin[bi * 3 + j]), bmax[bi * 3 + j]);
            }
        }
    }
}

// ---------------- bf16 flash attention, 128-key chunks, exp2-domain ----------------
#define CSTRIDE 80
#define QBUF    5120
#define KVB     10240

__device__ __forceinline__ void kv_load128(const __nv_bfloat16* __restrict__ Kh,
                                           const __nv_bfloat16* __restrict__ Vh,
                                           int h, int kb, uint32_t sbase, int tid) {
    #pragma unroll
    for (int i = 0; i < 8; i++) {
        int s = tid + i * 128;
        int row = (s >> 2) & 127, seg = s & 3;
        const __nv_bfloat16* src = ((s < 512) ? Kh : Vh)
            + (((h << 12) + (kb << 7) + row) << 5) + seg * 8;
        uint32_t dst = sbase + ((s < 512) ? 0 : KVB) + row * CSTRIDE + seg * 16;
        cpa16(dst, src);
    }
    asm volatile("cp.async.commit_group;");
}

__global__ void __launch_bounds__(128) flashb_k(const __nv_bfloat16* __restrict__ Qh,
                                                const __nv_bfloat16* __restrict__ Kh,
                                                const __nv_bfloat16* __restrict__ Vh,
                                                __nv_bfloat16* __restrict__ ao) {
    __shared__ __align__(16) char smem[QBUF + 4 * KVB];
    const int tid = threadIdx.x, lane = tid & 31, warp = tid >> 5;
    const int h = blockIdx.y, qb = blockIdx.x;

    char* Qs = smem;
    uint32_t Qsa = (uint32_t)__cvta_generic_to_shared(Qs);
    uint32_t kva0 = Qsa + QBUF;
    uint32_t kva1 = Qsa + QBUF + 2 * KVB;

    #pragma unroll
    for (int i = 0; i < 2; i++) {
        int s = tid + i * 128;
        int row = s >> 2, seg = s & 3;
        uint4 v = *(const uint4*)(Qh + (((h << 12) + (qb << 6) + row) << 5) + seg * 8);
        *(uint4*)(Qs + row * CSTRIDE + seg * 16) = v;
    }
    kv_load128(Kh, Vh, h, 0, kva0, tid);
    kv_load128(Kh, Vh, h, 1, kva1, tid);
    __syncthreads();

    uint32_t qa[8];
    {
        int i = lane & 7, sl = lane >> 3;
        int row = warp * 16 + ((sl & 1) ? 8 : 0) + i;
        uint32_t a = Qsa + row * CSTRIDE + ((sl >> 1) ? 16 : 0);
        ldsm4(qa[0], qa[1], qa[2], qa[3], a);
        ldsm4(qa[4], qa[5], qa[6], qa[7], a + 32);
    }

    float m0 = -1e30f, m1 = -1e30f, l0 = 0.f, l1 = 0.f;
    float o[4][4];
    #pragma unroll
    for (int j = 0; j < 4; j++)
        #pragma unroll
        for (int c = 0; c < 4; c++) o[j][c] = 0.f;

    const int i7 = lane & 7, sel = lane >> 3;
    const uint32_t krow = ((sel >= 2) ? 8 : 0) + i7;
    const uint32_t kcol = (sel & 1) ? 16 : 0;
    const uint32_t vrow = ((sel & 1) ? 8 : 0) + i7;
    const uint32_t vcol = (sel >= 2) ? 16 : 0;

    for (int kb = 0; kb < 32; kb++) {
        if (kb < 31) asm volatile("cp.async.wait_group 1;");
        else         asm volatile("cp.async.wait_group 0;");
        __syncthreads();
        uint32_t Kbase = (kb & 1) ? kva1 : kva0;
        uint32_t Vbase = Kbase + KVB;

        float s[16][4];
        #pragma unroll
        for (int j = 0; j < 16; j++)
            #pragma unroll
            for (int c = 0; c < 4; c++) s[j][c] = 0.f;

        #pragma unroll
        for (int jp = 0; jp < 8; jp++) {
            uint32_t a = Kbase + (jp * 16 + krow) * CSTRIDE + kcol;
            uint32_t b0, b1, b2, b3, c0, c1, c2, c3;
            ldsm4(b0, b1, b2, b3, a);
            ldsm4(c0, c1, c2, c3, a + 32);
            mma16816(s[2 * jp],     qa,     b0, b1);
            mma16816(s[2 * jp],     qa + 4, c0, c1);
            mma16816(s[2 * jp + 1], qa,     b2, b3);
            mma16816(s[2 * jp + 1], qa + 4, c2, c3);
        }

        float mx0 = -1e30f, mx1 = -1e30f;
        #pragma unroll
        for (int j = 0; j < 16; j++) {
            mx0 = fmaxf(mx0, fmaxf(s[j][0], s[j][1]));
            mx1 = fmaxf(mx1, fmaxf(s[j][2], s[j][3]));
        }
        mx0 = fmaxf(mx0, __shfl_xor_sync(0xffffffffu, mx0, 1));
        mx0 = fmaxf(mx0, __shfl_xor_sync(0xffffffffu, mx0, 2));
        mx1 = fmaxf(mx1, __shfl_xor_sync(0xffffffffu, mx1, 1));
        mx1 = fmaxf(mx1, __shfl_xor_sync(0xffffffffu, mx1, 2));
        float mn0 = fmaxf(m0, mx0), mn1 = fmaxf(m1, mx1);
        float f0 = exp2f(m0 - mn0), f1 = exp2f(m1 - mn1);
        m0 = mn0; m1 = mn1;
        float sum0 = 0.f, sum1 = 0.f;
        #pragma unroll
        for (int j = 0; j < 16; j++) {
            s[j][0] = exp2f(s[j][0] - mn0);
            s[j][1] = exp2f(s[j][1] - mn0);
            s[j][2] = exp2f(s[j][2] - mn1);
            s[j][3] = exp2f(s[j][3] - mn1);
            sum0 += s[j][0] + s[j][1];
            sum1 += s[j][2] + s[j][3];
        }
        sum0 += __shfl_xor_sync(0xffffffffu, sum0, 1);
        sum0 += __shfl_xor_sync(0xffffffffu, sum0, 2);
        sum1 += __shfl_xor_sync(0xffffffffu, sum1, 1);
        sum1 += __shfl_xor_sync(0xffffffffu, sum1, 2);
        l0 = l0 * f0 + sum0;
        l1 = l1 * f1 + sum1;
        #pragma unroll
        for (int j = 0; j < 4; j++) {
            o[j][0] *= f0; o[j][1] *= f0;
            o[j][2] *= f1; o[j][3] *= f1;
        }

        #pragma unroll
        for (int ks = 0; ks < 8; ks++) {
            uint32_t pa[4];
            pa[0] = packbf(s[2 * ks][0],     s[2 * ks][1]);
            pa[1] = packbf(s[2 * ks][2],     s[2 * ks][3]);
            pa[2] = packbf(s[2 * ks + 1][0], s[2 * ks + 1][1]);
            pa[3] = packbf(s[2 * ks + 1][2], s[2 * ks + 1][3]);
            uint32_t a = Vbase + (ks * 16 + vrow) * CSTRIDE + vcol;
            uint32_t v0, v1, v2, v3, w0, w1, w2, w3;
            ldsm4t(v0, v1, v2, v3, a);
            ldsm4t(w0, w1, w2, w3, a + 32);
            mma16816(o[0], pa, v0, v1);
            mma16816(o[1], pa, v2, v3);
            mma16816(o[2], pa, w0, w1);
            mma16816(o[3], pa, w2, w3);
        }

        __syncthreads();
        if (kb < 30) kv_load128(Kh, Vh, h, kb + 2, (kb & 1) ? kva1 : kva0, tid);
    }

    float inv0 = 1.f / l0, inv1 = 1.f / l1;
    int g = lane >> 2, l2 = (lane & 3) * 2;
    int row0 = (qb << 6) + warp * 16 + g;
    #pragma unroll
    for (int j = 0; j < 4; j++) {
        int col = (h << 5) + j * 8 + l2;
        *(uint32_t*)&ao[row0 * HDIM + col]       = packbf(o[j][0] * inv0, o[j][1] * inv0);
        *(uint32_t*)&ao[(row0 + 8) * HDIM + col] = packbf(o[j][2] * inv1, o[j][3] * inv1);
    }
}

// ---------------- host ----------------
extern "C" void kernel_launch(void* const* d_in, const int* in_sizes, int n_in,
                              void* d_out, int out_size) {
    const int*   num_atoms  = (const int*)d_in[0];
    const int*   elems      = (const int*)d_in[1];
    const float* cell       = (const float*)d_in[2];
    const float* coord      = (const float*)d_in[3];
    const float* emb        = (const float*)d_in[4];
    const float* ln_in_g    = (const float*)d_in[5];
    const float* ln_in_b    = (const float*)d_in[6];
    const float* attn_in_w  = (const float*)d_in[7];
    const float* attn_in_b  = (const float*)d_in[8];
    const float* attn_out_w = (const float*)d_in[9];
    const float* attn_out_b = (const float*)d_in[10];
    const float* ce_w1      = (const float*)d_in[11];
    const float* ce_b1      = (const float*)d_in[12];
    const float* ce_w2      = (const float*)d_in[13];
    const float* ce_b2      = (const float*)d_in[14];
    const float* ln_feat_g  = (const float*)d_in[15];
    const float* ln_feat_b  = (const float*)d_in[16];
    const float* op_w1      = (const float*)d_in[17];
    const float* op_b1      = (const float*)d_in[18];
    const float* op_ln1_g   = (const float*)d_in[19];
    const float* op_ln1_b   = (const float*)d_in[20];
    const float* res_w1     = (const float*)d_in[21];
    const float* res_b1     = (const float*)d_in[22];
    const float* res_ln_g   = (const float*)d_in[23];
    const float* res_ln_b   = (const float*)d_in[24];
    const float* res_w2     = (const float*)d_in[25];
    const float* res_b2     = (const float*)d_in[26];
    const float* op_ln2_g   = (const float*)d_in[27];
    const float* op_ln2_b   = (const float*)d_in[28];
    const float* op_w3      = (const float*)d_in[29];
    const float* op_b3      = (const float*)d_in[30];
    float* out = (float*)d_out;

    float* S = nullptr;
    cudaGetSymbolAddress((void**)&S, g_scratch);
    int* bidx = nullptr;
    cudaGetSymbolAddress((void**)&bidx, g_bidx);

    __nv_bfloat16* P = (__nv_bfloat16*)S;
    __nv_bfloat16* xb    = P; P += NATOMS * HDIM;
    __nv_bfloat16* Qh    = P; P += NATOMS * HDIM;
    __nv_bfloat16* Kh    = P; P += NATOMS * HDIM;
    __nv_bfloat16* Vh    = P; P += NATOMS * HDIM;
    __nv_bfloat16* aob   = P; P += NATOMS * HDIM;
    __nv_bfloat16* wqkv  = P; P += 128 * 384;
    __nv_bfloat16* wao   = P; P += 128 * 128;
    __nv_bfloat16* wop1  = P; P += FPAD * 128;
    __nv_bfloat16* wr1   = P; P += 128 * 128;
    __nv_bfloat16* wr2   = P; P += 128 * 128;
    float* F = (float*)P;
    float* cf   = F; F += BATCH * HDIM;
    float* bmin = F; F += BATCH * 3;
    float* bmax = F; F += BATCH * 3;

    static bool attr_set = false;
    if (!attr_set) {
        cudaFuncSetAttribute(tail_k, cudaFuncAttributeMaxDynamicSharedMemorySize, SMEM_TAIL);
        attr_set = true;
    }

    setup_k<<<1049, 256>>>(elems, emb, ln_in_g, ln_in_b, xb,
                           attn_in_w, attn_out_w, op_w1, res_w1, res_w2,
                           wqkv, wao, wop1, wr1, wr2,
                           cell, ce_w1, ce_b1, ce_w2, ce_b2, cf,
                           num_atoms, bmin, bmax);

    qkv_k<<<dim3(3, 128), 128>>>(xb, wqkv, attn_in_b, Qh, Kh, Vh);

    flashb_k<<<dim3(64, NHEAD), 128>>>(Qh, Kh, Vh, aob);

    tail_k<<<128, 256, SMEM_TAIL>>>(aob,
        wao, attn_out_b, ln_feat_g, ln_feat_b, cf, coord, bidx,
        wop1, op_b1, op_ln1_g, op_ln1_b,
        wr1, res_b1, res_ln_g, res_ln_b,
        wr2, res_b2, op_ln2_g, op_ln2_b,
        op_w3, op_b3, bmin, bmax, out);
}

// round 7
// speedup vs baseline: 6.8717x; 1.0912x over previous
#include <cuda_runtime.h>
#include <cuda_bf16.h>
#include <math.h>
#include <stdint.h>

#define NATOMS 4096
#define HDIM   128
#define BATCH  128
#define NHEAD  4
#define DHEAD  32
#define H3     384
#define FPAD   288

// -------- scratch (no allocations allowed) --------
__device__ float g_scratch[8300000];
__device__ int   g_bidx[NATOMS];

// ---------------- helpers ----------------
__device__ __forceinline__ float silu_f(float x) {
    return x / (1.f + __expf(-x));
}
__device__ __forceinline__ void ldsm4(uint32_t& r0, uint32_t& r1, uint32_t& r2, uint32_t& r3, uint32_t addr) {
    asm volatile("ldmatrix.sync.aligned.m8n8.x4.shared.b16 {%0,%1,%2,%3}, [%4];"
                 : "=r"(r0), "=r"(r1), "=r"(r2), "=r"(r3) : "r"(addr));
}
__device__ __forceinline__ void ldsm4t(uint32_t& r0, uint32_t& r1, uint32_t& r2, uint32_t& r3, uint32_t addr) {
    asm volatile("ldmatrix.sync.aligned.m8n8.x4.trans.shared.b16 {%0,%1,%2,%3}, [%4];"
                 : "=r"(r0), "=r"(r1), "=r"(r2), "=r"(r3) : "r"(addr));
}
__device__ __forceinline__ void mma16816(float* d, const uint32_t* a, uint32_t b0, uint32_t b1) {
    asm volatile("mma.sync.aligned.m16n8k16.row.col.f32.bf16.bf16.f32 "
                 "{%0,%1,%2,%3}, {%4,%5,%6,%7}, {%8,%9}, {%0,%1,%2,%3};"
                 : "+f"(d[0]), "+f"(d[1]), "+f"(d[2]), "+f"(d[3])
                 : "r"(a[0]), "r"(a[1]), "r"(a[2]), "r"(a[3]), "r"(b0), "r"(b1));
}
__device__ __forceinline__ uint32_t packbf(float lo, float hi) {
    uint32_t r;
    asm volatile("cvt.rn.bf16x2.f32 %0, %1, %2;" : "=r"(r) : "f"(hi), "f"(lo));
    return r;
}
__device__ __forceinline__ void cpa16(uint32_t dst, const void* src) {
    asm volatile("cp.async.ca.shared.global [%0], [%1], 16;" :: "r"(dst), "l"(src));
}
__device__ __forceinline__ void barh(int id) {
    asm volatile("bar.sync %0, 128;" :: "r"(id) : "memory");
}

// ================= fused setup kernel =================
__global__ void __launch_bounds__(256) setup_k(
    const int* __restrict__ elems, const float* __restrict__ emb,
    const float* __restrict__ ln_in_g, const float* __restrict__ ln_in_b,
    __nv_bfloat16* __restrict__ xo,
    const float* __restrict__ aiw, const float* __restrict__ aow,
    const float* __restrict__ opw1, const float* __restrict__ rw1,
    const float* __restrict__ rw2,
    __nv_bfloat16* __restrict__ wqkv, __nv_bfloat16* __restrict__ wao,
    __nv_bfloat16* __restrict__ wop1, __nv_bfloat16* __restrict__ wr1,
    __nv_bfloat16* __restrict__ wr2,
    const float* __restrict__ cell,
    const float* __restrict__ cw1, const float* __restrict__ cb1,
    const float* __restrict__ cw2, const float* __restrict__ cb2,
    float* __restrict__ cf,
    const int* __restrict__ num_atoms,
    float* __restrict__ bmin, float* __restrict__ bmax)
{
    const int b = blockIdx.x, tid = threadIdx.x;

    if (b < 512) {
        int warp = tid >> 5, lane = tid & 31;
        int r = b * 8 + warp;
        int e = elems[r];
        float4 v = *(const float4*)&emb[e * HDIM + lane * 4];
        float s = v.x + v.y + v.z + v.w;
        #pragma unroll
        for (int off = 16; off > 0; off >>= 1) s += __shfl_xor_sync(0xffffffffu, s, off);
        float mean = s * (1.f / 128.f);
        float dx = v.x - mean, dy = v.y - mean, dz = v.z - mean, dw = v.w - mean;
        float sq = dx * dx + dy * dy + dz * dz + dw * dw;
        #pragma unroll
        for (int off = 16; off > 0; off >>= 1) sq += __shfl_xor_sync(0xffffffffu, sq, off);
        float inv = rsqrtf(sq * (1.f / 128.f) + 1e-5f);
        float4 gg = *(const float4*)&ln_in_g[lane * 4];
        float4 bb = *(const float4*)&ln_in_b[lane * 4];
        uint32_t p0 = packbf(dx * inv * gg.x + bb.x, dy * inv * gg.y + bb.y);
        uint32_t p1 = packbf(dz * inv * gg.z + bb.z, dw * inv * gg.w + bb.w);
        *(uint2*)(xo + r * HDIM + lane * 4) = make_uint2(p0, p1);
        return;
    }

    if (b < 1040) {
        int i = (b - 512) * 256 + tid;
        if (i < 49152) wqkv[i] = __float2bfloat16(aiw[i]);
        else if (i < 65536) { int j = i - 49152; wao[j] = __float2bfloat16(aow[j]); }
        else if (i < 102400) {
            int j = i - 65536; int r = j >> 7, c = j & 127;
            wop1[j] = __float2bfloat16(r < 259 ? opw1[r * 128 + c] : 0.f);
        }
        else if (i < 118784) { int j = i - 102400; wr1[j] = __float2bfloat16(rw1[j]); }
        else { int j = i - 118784; wr2[j] = __float2bfloat16(rw2[j]); }
        return;
    }

    if (b < 1048) {
        __shared__ float t1s[16][128];
        int r0 = (b - 1040) * 16;
        #pragma unroll
        for (int i = 0; i < 8; i++) {
            int idx = tid + i * 256;
            int rr = idx >> 7, k = idx & 127;
            int r = r0 + rr;
            float u = cell[r * 3 + 0] * cw1[k] + cell[r * 3 + 1] * cw1[128 + k]
                    + cell[r * 3 + 2] * cw1[256 + k] + cb1[k];
            t1s[rr][k] = silu_f(u);
        }
        __syncthreads();
        int t = tid & 127, half = tid >> 7;
        float acc[8];
        #pragma unroll
        for (int j = 0; j < 8; j++) acc[j] = cb2[t];
        #pragma unroll 4
        for (int k = 0; k < 128; k++) {
            float w = cw2[k * 128 + t];
            #pragma unroll
            for (int j = 0; j < 8; j++) acc[j] += t1s[half * 8 + j][k] * w;
        }
        #pragma unroll
        for (int j = 0; j < 8; j++) cf[(r0 + half * 8 + j) * 128 + t] = acc[j];
        return;
    }

    __shared__ int starts[BATCH + 1];
    if (tid == 0) {
        int acc = 0;
        for (int i = 0; i < BATCH; i++) { starts[i] = acc; acc += num_atoms[i]; }
        starts[BATCH] = acc;
    }
    __syncthreads();
    for (int i = tid; i < NATOMS; i += 256) g_bidx[i] = BATCH - 1;
    __syncthreads();
    if (tid < BATCH) {
        int s = starts[tid], e = starts[tid + 1];
        if (s > NATOMS) s = NATOMS;
        if (e > NATOMS) e = NATOMS;
        for (int i = s; i < e; i++) g_bidx[i] = tid;
        #pragma unroll
        for (int i = 0; i < 3; i++) {
            float a = cell[(3 * tid + i) * 3 + 0];
            float c1 = cell[(3 * tid + i) * 3 + 1];
            float c = cell[(3 * tid + i) * 3 + 2];
            bmin[tid * 3 + i] = fminf(a, fminf(c1, c)) + 1e-6f;
            bmax[tid * 3 + i] = fmaxf(a, fmaxf(c1, c)) - 1e-6f;
        }
    }
}

// ================= QKV GEMM (BM=32, BN=128, BK=32, double-buffered) =================
__global__ void __launch_bounds__(128) qkv_k(
    const __nv_bfloat16* __restrict__ A, const __nv_bfloat16* __restrict__ W,
    const float* __restrict__ bias,
    __nv_bfloat16* __restrict__ Qh, __nv_bfloat16* __restrict__ Kh,
    __nv_bfloat16* __restrict__ Vh)
{
    __shared__ __align__(16) char sA[2 * 32 * 80];
    __shared__ __align__(16) char sW[2 * 32 * 272];
    const int tid = threadIdx.x, lane = tid & 31, warp = tid >> 5;
    const int wr = warp & 1, wc = warp >> 1;
    const int bm = blockIdx.y, nb = blockIdx.x;
    uint32_t aBase = (uint32_t)__cvta_generic_to_shared(sA);
    uint32_t wBase = (uint32_t)__cvta_generic_to_shared(sW);

    #pragma unroll
    for (int p = 0; p < 2; p++) {
        int row = tid >> 2, seg = tid & 3;
        cpa16(aBase + p * 2560 + row * 80 + seg * 16,
              A + (bm * 32 + row) * 128 + p * 32 + seg * 8);
        #pragma unroll
        for (int i = 0; i < 4; i++) {
            int s = tid + i * 128;
            int wrow = s >> 4, wseg = s & 15;
            cpa16(wBase + p * 8704 + wrow * 272 + wseg * 16,
                  W + (p * 32 + wrow) * H3 + nb * 128 + wseg * 8);
        }
        asm volatile("cp.async.commit_group;");
    }

    float acc[8][4];
    #pragma unroll
    for (int j = 0; j < 8; j++)
        #pragma unroll
        for (int c = 0; c < 4; c++) acc[j][c] = 0.f;

    const int i7 = lane & 7, sel = lane >> 3;
    const int arow = wr * 16 + ((sel & 1) ? 8 : 0) + i7;
    const int acol = (sel >> 1) ? 16 : 0;
    const int vrow = ((sel & 1) ? 8 : 0) + i7;
    const int vcol = (sel >= 2) ? 16 : 0;

    for (int ks = 0; ks < 4; ks++) {
        if (ks < 3) asm volatile("cp.async.wait_group 1;");
        else        asm volatile("cp.async.wait_group 0;");
        __syncthreads();
        uint32_t Ab = aBase + (ks & 1) * 2560;
        uint32_t Wb = wBase + (ks & 1) * 8704;
        #pragma unroll
        for (int kh = 0; kh < 2; kh++) {
            uint32_t qa[4];
            ldsm4(qa[0], qa[1], qa[2], qa[3], Ab + arow * 80 + acol + kh * 32);
            #pragma unroll
            for (int j = 0; j < 4; j++) {
                uint32_t r0, r1, r2, r3;
                ldsm4t(r0, r1, r2, r3, Wb + (kh * 16 + vrow) * 272 + wc * 128 + j * 32 + vcol);
                mma16816(acc[2 * j],     qa, r0, r1);
                mma16816(acc[2 * j + 1], qa, r2, r3);
            }
        }
        __syncthreads();
        if (ks + 2 < 4) {
            int p = ks + 2, buf = ks & 1;
            int row = tid >> 2, seg = tid & 3;
            cpa16(aBase + buf * 2560 + row * 80 + seg * 16,
                  A + (bm * 32 + row) * 128 + p * 32 + seg * 8);
            #pragma unroll
            for (int i = 0; i < 4; i++) {
                int s = tid + i * 128;
                int wrow = s >> 4, wseg = s & 15;
                cpa16(wBase + buf * 8704 + wrow * 272 + wseg * 16,
                      W + (p * 32 + wrow) * H3 + nb * 128 + wseg * 8);
            }
            asm volatile("cp.async.commit_group;");
        }
    }

    const int g = lane >> 2, c2 = (lane & 3) * 2;
    int r0 = bm * 32 + wr * 16 + g;
    __nv_bfloat16* outp = (nb == 0) ? Qh : (nb == 1) ? Kh : Vh;
    // fold log2(e) into Q scale so flash can use exp2f
    float sc = (nb == 0) ? (0.17677669529663687f * 1.4426950408889634f) : 1.f;
    #pragma unroll
    for (int t = 0; t < 8; t++) {
        int col = wc * 64 + t * 8 + c2;
        float b0v = bias[nb * 128 + col], b1v = bias[nb * 128 + col + 1];
        int h = col >> 5, d = col & 31;
        *(uint32_t*)(outp + (((h << 12) + r0) << 5) + d) =
            packbf((acc[t][0] + b0v) * sc, (acc[t][1] + b1v) * sc);
        *(uint32_t*)(outp + (((h << 12) + r0 + 8) << 5) + d) =
            packbf((acc[t][2] + b0v) * sc, (acc[t][3] + b1v) * sc);
    }
}

// ================= fused tail: two independent 16-row halves per CTA ==========
#define WSTR 272
#define ASTR 592
#define SM_WAO   0
#define SM_WOP1  (128 * WSTR)
#define SM_WR1   (SM_WOP1 + 288 * WSTR)
#define SM_WR2   (SM_WR1 + 128 * WSTR)
#define SM_ACT   (SM_WR2 + 128 * WSTR)
#define SM_STAGE (SM_ACT + 32 * ASTR)
#define SMEM_TAIL (SM_STAGE + 32 * 136 * 4)

__global__ void __launch_bounds__(256) tail_k(
    const __nv_bfloat16* __restrict__ aob,
    const __nv_bfloat16* __restrict__ wao, const float* __restrict__ aob_bias,
    const float* __restrict__ lnf_g, const float* __restrict__ lnf_b,
    const float* __restrict__ cf, const float* __restrict__ coordp,
    const int* __restrict__ bidx,
    const __nv_bfloat16* __restrict__ wop1, const float* __restrict__ op_b1,
    const float* __restrict__ ln1_g, const float* __restrict__ ln1_b,
    const __nv_bfloat16* __restrict__ wr1, const float* __restrict__ r_b1,
    const float* __restrict__ rln_g, const float* __restrict__ rln_b,
    const __nv_bfloat16* __restrict__ wr2, const float* __restrict__ r_b2,
    const float* __restrict__ ln2_g, const float* __restrict__ ln2_b,
    const float* __restrict__ w3, const float* __restrict__ b3,
    const float* __restrict__ bmin, const float* __restrict__ bmax,
    float* __restrict__ fout)
{
    extern __shared__ __align__(16) char dsm[];
    const int tid = threadIdx.x, lane = tid & 31, warp = tid >> 5;
    const int hb = warp >> 2;            // half: 0 or 1
    const int wc = warp & 3;             // 4 warps per half, n = 32 cols each
    const int bm = blockIdx.x;
    uint32_t base = (uint32_t)__cvta_generic_to_shared(dsm);
    uint32_t aAct = base + SM_ACT + hb * 16 * ASTR;    // this half's 16-row act buffer
    float* sSh = (float*)(dsm + SM_STAGE) + hb * 16 * 136;

    // ---- cooperative loads (all 256 threads): act tile + all 4 weight matrices ----
    #pragma unroll
    for (int i = 0; i < 2; i++) {
        int s = tid + i * 256;
        int row = s >> 4, seg = s & 15;
        cpa16(base + SM_ACT + row * ASTR + seg * 16, aob + (bm * 32 + row) * 128 + seg * 8);
    }
    #pragma unroll
    for (int i = 0; i < 8; i++) {
        int s = tid + i * 256;
        int row = s >> 4, seg = s & 15;
        cpa16(base + SM_WAO + row * WSTR + seg * 16, wao + row * 128 + seg * 8);
    }
    #pragma unroll
    for (int i = 0; i < 18; i++) {
        int s = tid + i * 256;
        int row = s >> 4, seg = s & 15;
        cpa16(base + SM_WOP1 + row * WSTR + seg * 16, wop1 + row * 128 + seg * 8);
    }
    #pragma unroll
    for (int i = 0; i < 8; i++) {
        int s = tid + i * 256;
        int row = s >> 4, seg = s & 15;
        cpa16(base + SM_WR1 + row * WSTR + seg * 16, wr1 + row * 128 + seg * 8);
    }
    #pragma unroll
    for (int i = 0; i < 8; i++) {
        int s = tid + i * 256;
        int row = s >> 4, seg = s & 15;
        cpa16(base + SM_WR2 + row * WSTR + seg * 16, wr2 + row * 128 + seg * 8);
    }
    asm volatile("cp.async.commit_group;");
    asm volatile("cp.async.wait_group 0;");
    __syncthreads();
    // from here the two halves run independently on named barriers 1 / 2

    const int i7 = lane & 7, sel = lane >> 3;
    const int arow = ((sel & 1) ? 8 : 0) + i7;     // m16 tile = the half's whole 16 rows
    const int acol = (sel >> 1) ? 16 : 0;
    const int vrow = ((sel & 1) ? 8 : 0) + i7;
    const int vcol = (sel >= 2) ? 16 : 0;
    const int htid = tid & 127;
    const int row = htid >> 3, q = htid & 7;       // LN: 8 threads per row, 16 rows
    const int grow = bm * 32 + hb * 16 + row;
    const int sr0 = lane >> 2;                      // rows sr0, sr0+8 of the half
    const int c2 = (lane & 3) * 2;
    const int barid = hb + 1;

    float acc[4][4];
    uint32_t hkeep[8];

    auto do_gemm = [&](int wOff, int ksteps) {
        #pragma unroll
        for (int j = 0; j < 4; j++)
            #pragma unroll
            for (int c = 0; c < 4; c++) acc[j][c] = 0.f;
        for (int ks = 0; ks < ksteps; ks++) {
            #pragma unroll
            for (int kh = 0; kh < 2; kh++) {
                uint32_t qa[4];
                ldsm4(qa[0], qa[1], qa[2], qa[3], aAct + arow * ASTR + ks * 64 + kh * 32 + acol);
                #pragma unroll
                for (int j = 0; j < 2; j++) {
                    uint32_t r0, r1, r2, r3;
                    ldsm4t(r0, r1, r2, r3,
                           base + wOff + (ks * 32 + kh * 16 + vrow) * WSTR + wc * 64 + j * 32 + vcol);
                    mma16816(acc[2 * j],     qa, r0, r1);
                    mma16816(acc[2 * j + 1], qa, r2, r3);
                }
            }
        }
    };

    auto stage = [&](const float* bias) {
        #pragma unroll
        for (int t = 0; t < 4; t++) {
            int col = wc * 32 + t * 8 + c2;
            float a0 = bias[col], a1 = bias[col + 1];
            sSh[sr0 * 136 + col] = acc[t][0] + a0;       sSh[sr0 * 136 + col + 1] = acc[t][1] + a1;
            sSh[(sr0 + 8) * 136 + col] = acc[t][2] + a0; sSh[(sr0 + 8) * 136 + col + 1] = acc[t][3] + a1;
        }
    };

    // ============ stage 0: xa = aob @ wao + b ; comb-LN(259) ============
    do_gemm(SM_WAO, 4);
    stage(aob_bias);
    barh(barid);
    {
        int bi = bidx[grow];
        float xv[16], cv[16];
        #pragma unroll
        for (int i = 0; i < 4; i++) {
            float4 f = *(const float4*)&sSh[row * 136 + q * 16 + i * 4];
            xv[4 * i] = f.x; xv[4 * i + 1] = f.y; xv[4 * i + 2] = f.z; xv[4 * i + 3] = f.w;
            float4 c = *(const float4*)&cf[bi * 128 + q * 16 + i * 4];
            cv[4 * i] = c.x; cv[4 * i + 1] = c.y; cv[4 * i + 2] = c.z; cv[4 * i + 3] = c.w;
        }
        float c0 = 0.f, c1 = 0.f, c2v = 0.f;
        float s = 0.f;
        #pragma unroll
        for (int i = 0; i < 16; i++) s += xv[i] + cv[i];
        if (q == 0) {
            c0 = coordp[grow * 3 + 0]; c1 = coordp[grow * 3 + 1]; c2v = coordp[grow * 3 + 2];
            s += c0 + c1 + c2v;
        }
        s += __shfl_xor_sync(0xffffffffu, s, 1);
        s += __shfl_xor_sync(0xffffffffu, s, 2);
        s += __shfl_xor_sync(0xffffffffu, s, 4);
        float mean = s * (1.f / 259.f);
        float sq = 0.f;
        #pragma unroll
        for (int i = 0; i < 16; i++) {
            float d0 = xv[i] - mean, d1 = cv[i] - mean;
            sq += d0 * d0 + d1 * d1;
        }
        if (q == 0) {
            float d0 = c0 - mean, d1 = c1 - mean, d2 = c2v - mean;
            sq += d0 * d0 + d1 * d1 + d2 * d2;
        }
        sq += __shfl_xor_sync(0xffffffffu, sq, 1);
        sq += __shfl_xor_sync(0xffffffffu, sq, 2);
        sq += __shfl_xor_sync(0xffffffffu, sq, 4);
        float inv = rsqrtf(sq * (1.f / 259.f) + 1e-5f);

        uint32_t pk[8];
        #pragma unroll
        for (int i = 0; i < 8; i++) {
            int ca = q * 16 + 2 * i;
            pk[i] = packbf((xv[2 * i] - mean) * inv * lnf_g[ca] + lnf_b[ca],
                           (xv[2 * i + 1] - mean) * inv * lnf_g[ca + 1] + lnf_b[ca + 1]);
        }
        uint4* dst = (uint4*)(dsm + SM_ACT + (hb * 16 + row) * ASTR + q * 32);
        dst[0] = *(uint4*)&pk[0]; dst[1] = *(uint4*)&pk[4];
        #pragma unroll
        for (int i = 0; i < 8; i++) {
            int ca = 128 + q * 16 + 2 * i;
            pk[i] = packbf((cv[2 * i] - mean) * inv * lnf_g[ca] + lnf_b[ca],
                           (cv[2 * i + 1] - mean) * inv * lnf_g[ca + 1] + lnf_b[ca + 1]);
        }
        dst = (uint4*)(dsm + SM_ACT + (hb * 16 + row) * ASTR + 256 + q * 32);
        dst[0] = *(uint4*)&pk[0]; dst[1] = *(uint4*)&pk[4];
        uint32_t tp0 = 0, tp1 = 0;
        if (q == 0) {
            tp0 = packbf((c0 - mean) * inv * lnf_g[256] + lnf_b[256],
                         (c1 - mean) * inv * lnf_g[257] + lnf_b[257]);
            tp1 = packbf((c2v - mean) * inv * lnf_g[258] + lnf_b[258], 0.f);
        }
        *(uint2*)(dsm + SM_ACT + (hb * 16 + row) * ASTR + 512 + q * 8) = make_uint2(tp0, tp1);
    }
    barh(barid);

    // ============ stage 1: h0 = comb @ wop1 ; LN + SiLU ============
    do_gemm(SM_WOP1, 9);
    stage(op_b1);
    barh(barid);
    {
        float v[16];
        #pragma unroll
        for (int i = 0; i < 4; i++) {
            float4 f = *(const float4*)&sSh[row * 136 + q * 16 + i * 4];
            v[4 * i] = f.x; v[4 * i + 1] = f.y; v[4 * i + 2] = f.z; v[4 * i + 3] = f.w;
        }
        float s = 0.f;
        #pragma unroll
        for (int i = 0; i < 16; i++) s += v[i];
        s += __shfl_xor_sync(0xffffffffu, s, 1);
        s += __shfl_xor_sync(0xffffffffu, s, 2);
        s += __shfl_xor_sync(0xffffffffu, s, 4);
        float mean = s * (1.f / 128.f);
        float sq = 0.f;
        #pragma unroll
        for (int i = 0; i < 16; i++) { float d = v[i] - mean; sq += d * d; }
        sq += __shfl_xor_sync(0xffffffffu, sq, 1);
        sq += __shfl_xor_sync(0xffffffffu, sq, 2);
        sq += __shfl_xor_sync(0xffffffffu, sq, 4);
        float inv = rsqrtf(sq * (1.f / 128.f) + 1e-5f);
        #pragma unroll
        for (int i = 0; i < 8; i++) {
            int ca = q * 16 + 2 * i;
            float y0 = silu_f((v[2 * i] - mean) * inv * ln1_g[ca] + ln1_b[ca]);
            float y1 = silu_f((v[2 * i + 1] - mean) * inv * ln1_g[ca + 1] + ln1_b[ca + 1]);
            hkeep[i] = packbf(y0, y1);
        }
        uint4* dst = (uint4*)(dsm + SM_ACT + (hb * 16 + row) * ASTR + q * 32);
        dst[0] = *(uint4*)&hkeep[0]; dst[1] = *(uint4*)&hkeep[4];
    }
    barh(barid);

    // ============ stage 2: t = h1 @ wr1 ; LN + SiLU ============
    do_gemm(SM_WR1, 4);
    stage(r_b1);
    barh(barid);
    {
        float v[16];
        #pragma unroll
        for (int i = 0; i < 4; i++) {
            float4 f = *(const float4*)&sSh[row * 136 + q * 16 + i * 4];
            v[4 * i] = f.x; v[4 * i + 1] = f.y; v[4 * i + 2] = f.z; v[4 * i + 3] = f.w;
        }
        float s = 0.f;
        #pragma unroll
        for (int i = 0; i < 16; i++) s += v[i];
        s += __shfl_xor_sync(0xffffffffu, s, 1);
        s += __shfl_xor_sync(0xffffffffu, s, 2);
        s += __shfl_xor_sync(0xffffffffu, s, 4);
        float mean = s * (1.f / 128.f);
        float sq = 0.f;
        #pragma unroll
        for (int i = 0; i < 16; i++) { float d = v[i] - mean; sq += d * d; }
        sq += __shfl_xor_sync(0xffffffffu, sq, 1);
        sq += __shfl_xor_sync(0xffffffffu, sq, 2);
        sq += __shfl_xor_sync(0xffffffffu, sq, 4);
        float inv = rsqrtf(sq * (1.f / 128.f) + 1e-5f);
        uint32_t pk[8];
        #pragma unroll
        for (int i = 0; i < 8; i++) {
            int ca = q * 16 + 2 * i;
            float y0 = silu_f((v[2 * i] - mean) * inv * rln_g[ca] + rln_b[ca]);
            float y1 = silu_f((v[2 * i + 1] - mean) * inv * rln_g[ca + 1] + rln_b[ca + 1]);
            pk[i] = packbf(y0, y1);
        }
        uint4* dst = (uint4*)(dsm + SM_ACT + (hb * 16 + row) * ASTR + q * 32);
        dst[0] = *(uint4*)&pk[0]; dst[1] = *(uint4*)&pk[4];
    }
    barh(barid);

    // ============ stage 3: hfin = t2 @ wr2 + b + h1 ; LN ; proj/tanh/clamp ============
    do_gemm(SM_WR2, 4);
    stage(r_b2);
    barh(barid);
    {
        float v[16];
        #pragma unroll
        for (int i = 0; i < 4; i++) {
            float4 f = *(const float4*)&sSh[row * 136 + q * 16 + i * 4];
            v[4 * i] = f.x; v[4 * i + 1] = f.y; v[4 * i + 2] = f.z; v[4 * i + 3] = f.w;
        }
        #pragma unroll
        for (int i = 0; i < 8; i++) {
            __nv_bfloat162 hh = *(__nv_bfloat162*)&hkeep[i];
            v[2 * i]     += __bfloat162float(hh.x);
            v[2 * i + 1] += __bfloat162float(hh.y);
        }
        float s = 0.f;
        #pragma unroll
        for (int i = 0; i < 16; i++) s += v[i];
        s += __shfl_xor_sync(0xffffffffu, s, 1);
        s += __shfl_xor_sync(0xffffffffu, s, 2);
        s += __shfl_xor_sync(0xffffffffu, s, 4);
        float mean = s * (1.f / 128.f);
        float sq = 0.f;
        #pragma unroll
        for (int i = 0; i < 16; i++) { float d = v[i] - mean; sq += d * d; }
        sq += __shfl_xor_sync(0xffffffffu, sq, 1);
        sq += __shfl_xor_sync(0xffffffffu, sq, 2);
        sq += __shfl_xor_sync(0xffffffffu, sq, 4);
        float inv = rsqrtf(sq * (1.f / 128.f) + 1e-5f);

        float p0 = 0.f, p1 = 0.f, p2 = 0.f;
        #pragma unroll
        for (int i = 0; i < 16; i++) {
            int ca = q * 16 + i;
            float y = (v[i] - mean) * inv * ln2_g[ca] + ln2_b[ca];
            p0 += y * w3[ca * 3 + 0];
            p1 += y * w3[ca * 3 + 1];
            p2 += y * w3[ca * 3 + 2];
        }
        p0 += __shfl_xor_sync(0xffffffffu, p0, 1);
        p0 += __shfl_xor_sync(0xffffffffu, p0, 2);
        p0 += __shfl_xor_sync(0xffffffffu, p0, 4);
        p1 += __shfl_xor_sync(0xffffffffu, p1, 1);
        p1 += __shfl_xor_sync(0xffffffffu, p1, 2);
        p1 += __shfl_xor_sync(0xffffffffu, p1, 4);
        p2 += __shfl_xor_sync(0xffffffffu, p2, 1);
        p2 += __shfl_xor_sync(0xffffffffu, p2, 2);
        p2 += __shfl_xor_sync(0xffffffffu, p2, 4);
        if (q == 0) {
            int bi = bidx[grow];
            float dots[3] = {p0 + b3[0], p1 + b3[1], p2 + b3[2]};
            #pragma unroll
            for (int j = 0; j < 3; j++) {
                float val = coordp[grow * 3 + j] + 0.01f * tanhf(dots[j]);
                fout[grow * 3 + j] = fminf(fmaxf(val, bmin[bi * 3 + j]), bmax[bi * 3 + j]);
            }
        }
    }
}

// ---------------- bf16 flash attention: fixed-max softmax, exp/PV interleaved ----------------
#define CSTRIDE 80
#define QBUF    5120
#define KVB     10240

__device__ __forceinline__ void kv_load128(const __nv_bfloat16* __restrict__ Kh,
                                           const __nv_bfloat16* __restrict__ Vh,
                                           int h, int kb, uint32_t sbase, int tid) {
    #pragma unroll
    for (int i = 0; i < 8; i++) {
        int s = tid + i * 128;
        int row = (s >> 2) & 127, seg = s & 3;
        const __nv_bfloat16* src = ((s < 512) ? Kh : Vh)
            + (((h << 12) + (kb << 7) + row) << 5) + seg * 8;
        uint32_t dst = sbase + ((s < 512) ? 0 : KVB) + row * CSTRIDE + seg * 16;
        cpa16(dst, src);
    }
    asm volatile("cp.async.commit_group;");
}

__global__ void __launch_bounds__(128) flashb_k(const __nv_bfloat16* __restrict__ Qh,
                                                const __nv_bfloat16* __restrict__ Kh,
                                                const __nv_bfloat16* __restrict__ Vh,
                                                __nv_bfloat16* __restrict__ ao) {
    __shared__ __align__(16) char smem[QBUF + 4 * KVB];
    const int tid = threadIdx.x, lane = tid & 31, warp = tid >> 5;
    const int h = blockIdx.y, qb = blockIdx.x;

    char* Qs = smem;
    uint32_t Qsa = (uint32_t)__cvta_generic_to_shared(Qs);
    uint32_t kva0 = Qsa + QBUF;
    uint32_t kva1 = Qsa + QBUF + 2 * KVB;

    #pragma unroll
    for (int i = 0; i < 2; i++) {
        int s = tid + i * 128;
        int row = s >> 2, seg = s & 3;
        uint4 v = *(const uint4*)(Qh + (((h << 12) + (qb << 6) + row) << 5) + seg * 8);
        *(uint4*)(Qs + row * CSTRIDE + seg * 16) = v;
    }
    kv_load128(Kh, Vh, h, 0, kva0, tid);
    kv_load128(Kh, Vh, h, 1, kva1, tid);
    __syncthreads();

    uint32_t qa[8];
    {
        int i = lane & 7, sl = lane >> 3;
        int row = warp * 16 + ((sl & 1) ? 8 : 0) + i;
        uint32_t a = Qsa + row * CSTRIDE + ((sl >> 1) ? 16 : 0);
        ldsm4(qa[0], qa[1], qa[2], qa[3], a);
        ldsm4(qa[4], qa[5], qa[6], qa[7], a + 32);
    }

    float l0 = 0.f, l1 = 0.f;   // per-thread partial sums, reduced at epilogue
    float o[4][4];
    #pragma unroll
    for (int j = 0; j < 4; j++)
        #pragma unroll
        for (int c = 0; c < 4; c++) o[j][c] = 0.f;

    const int i7 = lane & 7, sel = lane >> 3;
    const uint32_t krow = ((sel >= 2) ? 8 : 0) + i7;
    const uint32_t kcol = (sel & 1) ? 16 : 0;
    const uint32_t vrow = ((sel & 1) ? 8 : 0) + i7;
    const uint32_t vcol = (sel >= 2) ? 16 : 0;

    for (int kb = 0; kb < 32; kb++) {
        if (kb < 31) asm volatile("cp.async.wait_group 1;");
        else         asm volatile("cp.async.wait_group 0;");
        __syncthreads();
        uint32_t Kbase = (kb & 1) ? kva1 : kva0;
        uint32_t Vbase = Kbase + KVB;

        // ---- S = Q @ K^T : 16 n8-tiles ----
        float s[16][4];
        #pragma unroll
        for (int j = 0; j < 16; j++)
            #pragma unroll
            for (int c = 0; c < 4; c++) s[j][c] = 0.f;

        #pragma unroll
        for (int jp = 0; jp < 8; jp++) {
            uint32_t a = Kbase + (jp * 16 + krow) * CSTRIDE + kcol;
            uint32_t b0, b1, b2, b3, c0, c1, c2, c3;
            ldsm4(b0, b1, b2, b3, a);
            ldsm4(c0, c1, c2, c3, a + 32);
            mma16816(s[2 * jp],     qa,     b0, b1);
            mma16816(s[2 * jp],     qa + 4, c0, c1);
            mma16816(s[2 * jp + 1], qa,     b2, b3);
            mma16816(s[2 * jp + 1], qa + 4, c2, c3);
        }

        // ---- fixed-max softmax interleaved with PV mma (8 k-steps of 16 keys) ----
        #pragma unroll
        for (int ks = 0; ks < 8; ks++) {
            float e00 = exp2f(s[2 * ks][0]),     e01 = exp2f(s[2 * ks][1]);
            float e02 = exp2f(s[2 * ks][2]),     e03 = exp2f(s[2 * ks][3]);
            float e10 = exp2f(s[2 * ks + 1][0]), e11 = exp2f(s[2 * ks + 1][1]);
            float e12 = exp2f(s[2 * ks + 1][2]), e13 = exp2f(s[2 * ks + 1][3]);
            l0 += (e00 + e01) + (e10 + e11);
            l1 += (e02 + e03) + (e12 + e13);
            uint32_t pa[4];
            pa[0] = packbf(e00, e01);
            pa[1] = packbf(e02, e03);
            pa[2] = packbf(e10, e11);
            pa[3] = packbf(e12, e13);
            uint32_t a = Vbase + (ks * 16 + vrow) * CSTRIDE + vcol;
            uint32_t v0, v1, v2, v3, w0, w1, w2, w3;
            ldsm4t(v0, v1, v2, v3, a);
            ldsm4t(w0, w1, w2, w3, a + 32);
            mma16816(o[0], pa, v0, v1);
            mma16816(o[1], pa, v2, v3);
            mma16816(o[2], pa, w0, w1);
            mma16816(o[3], pa, w2, w3);
        }

        __syncthreads();
        if (kb < 30) kv_load128(Kh, Vh, h, kb + 2, (kb & 1) ? kva1 : kva0, tid);
    }

    // epilogue: reduce row sums across the quad, normalize, store bf16
    l0 += __shfl_xor_sync(0xffffffffu, l0, 1);
    l0 += __shfl_xor_sync(0xffffffffu, l0, 2);
    l1 += __shfl_xor_sync(0xffffffffu, l1, 1);
    l1 += __shfl_xor_sync(0xffffffffu, l1, 2);
    float inv0 = 1.f / l0, inv1 = 1.f / l1;
    int g = lane >> 2, l2 = (lane & 3) * 2;
    int row0 = (qb << 6) + warp * 16 + g;
    #pragma unroll
    for (int j = 0; j < 4; j++) {
        int col = (h << 5) + j * 8 + l2;
        *(uint32_t*)&ao[row0 * HDIM + col]       = packbf(o[j][0] * inv0, o[j][1] * inv0);
        *(uint32_t*)&ao[(row0 + 8) * HDIM + col] = packbf(o[j][2] * inv1, o[j][3] * inv1);
    }
}

// ---------------- host ----------------
extern "C" void kernel_launch(void* const* d_in, const int* in_sizes, int n_in,
                              void* d_out, int out_size) {
    const int*   num_atoms  = (const int*)d_in[0];
    const int*   elems      = (const int*)d_in[1];
    const float* cell       = (const float*)d_in[2];
    const float* coord      = (const float*)d_in[3];
    const float* emb        = (const float*)d_in[4];
    const float* ln_in_g    = (const float*)d_in[5];
    const float* ln_in_b    = (const float*)d_in[6];
    const float* attn_in_w  = (const float*)d_in[7];
    const float* attn_in_b  = (const float*)d_in[8];
    const float* attn_out_w = (const float*)d_in[9];
    const float* attn_out_b = (const float*)d_in[10];
    const float* ce_w1      = (const float*)d_in[11];
    const float* ce_b1      = (const float*)d_in[12];
    const float* ce_w2      = (const float*)d_in[13];
    const float* ce_b2      = (const float*)d_in[14];
    const float* ln_feat_g  = (const float*)d_in[15];
    const float* ln_feat_b  = (const float*)d_in[16];
    const float* op_w1      = (const float*)d_in[17];
    const float* op_b1      = (const float*)d_in[18];
    const float* op_ln1_g   = (const float*)d_in[19];
    const float* op_ln1_b   = (const float*)d_in[20];
    const float* res_w1     = (const float*)d_in[21];
    const float* res_b1     = (const float*)d_in[22];
    const float* res_ln_g   = (const float*)d_in[23];
    const float* res_ln_b   = (const float*)d_in[24];
    const float* res_w2     = (const float*)d_in[25];
    const float* res_b2     = (const float*)d_in[26];
    const float* op_ln2_g   = (const float*)d_in[27];
    const float* op_ln2_b   = (const float*)d_in[28];
    const float* op_w3      = (const float*)d_in[29];
    const float* op_b3      = (const float*)d_in[30];
    float* out = (float*)d_out;

    float* S = nullptr;
    cudaGetSymbolAddress((void**)&S, g_scratch);
    int* bidx = nullptr;
    cudaGetSymbolAddress((void**)&bidx, g_bidx);

    __nv_bfloat16* P = (__nv_bfloat16*)S;
    __nv_bfloat16* xb    = P; P += NATOMS * HDIM;
    __nv_bfloat16* Qh    = P; P += NATOMS * HDIM;
    __nv_bfloat16* Kh    = P; P += NATOMS * HDIM;
    __nv_bfloat16* Vh    = P; P += NATOMS * HDIM;
    __nv_bfloat16* aob   = P; P += NATOMS * HDIM;
    __nv_bfloat16* wqkv  = P; P += 128 * 384;
    __nv_bfloat16* wao   = P; P += 128 * 128;
    __nv_bfloat16* wop1  = P; P += FPAD * 128;
    __nv_bfloat16* wr1   = P; P += 128 * 128;
    __nv_bfloat16* wr2   = P; P += 128 * 128;
    float* F = (float*)P;
    float* cf   = F; F += BATCH * HDIM;
    float* bmin = F; F += BATCH * 3;
    float* bmax = F; F += BATCH * 3;

    static bool attr_set = false;
    if (!attr_set) {
        cudaFuncSetAttribute(tail_k, cudaFuncAttributeMaxDynamicSharedMemorySize, SMEM_TAIL);
        attr_set = true;
    }

    setup_k<<<1049, 256>>>(elems, emb, ln_in_g, ln_in_b, xb,
                           attn_in_w, attn_out_w, op_w1, res_w1, res_w2,
                           wqkv, wao, wop1, wr1, wr2,
                           cell, ce_w1, ce_b1, ce_w2, ce_b2, cf,
                           num_atoms, bmin, bmax);

    qkv_k<<<dim3(3, 128), 128>>>(xb, wqkv, attn_in_b, Qh, Kh, Vh);

    flashb_k<<<dim3(64, NHEAD), 128>>>(Qh, Kh, Vh, aob);

    tail_k<<<128, 256, SMEM_TAIL>>>(aob,
        wao, attn_out_b, ln_feat_g, ln_feat_b, cf, coord, bidx,
        wop1, op_b1, op_ln1_g, op_ln1_b,
        wr1, res_b1, res_ln_g, res_ln_b,
        wr2, res_b2, op_ln2_g, op_ln2_b,
        op_w3, op_b3, bmin, bmax, out);
}

// round 8
// speedup vs baseline: 7.2935x; 1.0614x over previous
#include <cuda_runtime.h>
#include <cuda_bf16.h>
#include <math.h>
#include <stdint.h>

#define NATOMS 4096
#define HDIM   128
#define BATCH  128
#define NHEAD  4
#define DHEAD  32
#define H3     384
#define FPAD   288
#define KSPLIT 2

// -------- scratch (no allocations allowed) --------
__device__ float g_scratch[8300000];
__device__ int   g_bidx[NATOMS];

// ---------------- helpers ----------------
__device__ __forceinline__ float silu_f(float x) {
    return x / (1.f + __expf(-x));
}
__device__ __forceinline__ void ldsm4(uint32_t& r0, uint32_t& r1, uint32_t& r2, uint32_t& r3, uint32_t addr) {
    asm volatile("ldmatrix.sync.aligned.m8n8.x4.shared.b16 {%0,%1,%2,%3}, [%4];"
                 : "=r"(r0), "=r"(r1), "=r"(r2), "=r"(r3) : "r"(addr));
}
__device__ __forceinline__ void ldsm4t(uint32_t& r0, uint32_t& r1, uint32_t& r2, uint32_t& r3, uint32_t addr) {
    asm volatile("ldmatrix.sync.aligned.m8n8.x4.trans.shared.b16 {%0,%1,%2,%3}, [%4];"
                 : "=r"(r0), "=r"(r1), "=r"(r2), "=r"(r3) : "r"(addr));
}
__device__ __forceinline__ void mma16816(float* d, const uint32_t* a, uint32_t b0, uint32_t b1) {
    asm volatile("mma.sync.aligned.m16n8k16.row.col.f32.bf16.bf16.f32 "
                 "{%0,%1,%2,%3}, {%4,%5,%6,%7}, {%8,%9}, {%0,%1,%2,%3};"
                 : "+f"(d[0]), "+f"(d[1]), "+f"(d[2]), "+f"(d[3])
                 : "r"(a[0]), "r"(a[1]), "r"(a[2]), "r"(a[3]), "r"(b0), "r"(b1));
}
__device__ __forceinline__ uint32_t packbf(float lo, float hi) {
    uint32_t r;
    asm volatile("cvt.rn.bf16x2.f32 %0, %1, %2;" : "=r"(r) : "f"(hi), "f"(lo));
    return r;
}
__device__ __forceinline__ void cpa16(uint32_t dst, const void* src) {
    asm volatile("cp.async.ca.shared.global [%0], [%1], 16;" :: "r"(dst), "l"(src));
}
__device__ __forceinline__ void barh(int id) {
    asm volatile("bar.sync %0, 128;" :: "r"(id) : "memory");
}

// ================= fused setup kernel =================
__global__ void __launch_bounds__(256) setup_k(
    const int* __restrict__ elems, const float* __restrict__ emb,
    const float* __restrict__ ln_in_g, const float* __restrict__ ln_in_b,
    __nv_bfloat16* __restrict__ xo,
    const float* __restrict__ aiw, const float* __restrict__ aow,
    const float* __restrict__ opw1, const float* __restrict__ rw1,
    const float* __restrict__ rw2,
    __nv_bfloat16* __restrict__ wqkv, __nv_bfloat16* __restrict__ wao,
    __nv_bfloat16* __restrict__ wop1, __nv_bfloat16* __restrict__ wr1,
    __nv_bfloat16* __restrict__ wr2,
    const float* __restrict__ cell,
    const float* __restrict__ cw1, const float* __restrict__ cb1,
    const float* __restrict__ cw2, const float* __restrict__ cb2,
    float* __restrict__ cf,
    const int* __restrict__ num_atoms,
    float* __restrict__ bmin, float* __restrict__ bmax)
{
    const int b = blockIdx.x, tid = threadIdx.x;

    if (b < 512) {
        int warp = tid >> 5, lane = tid & 31;
        int r = b * 8 + warp;
        int e = elems[r];
        float4 v = *(const float4*)&emb[e * HDIM + lane * 4];
        float s = v.x + v.y + v.z + v.w;
        #pragma unroll
        for (int off = 16; off > 0; off >>= 1) s += __shfl_xor_sync(0xffffffffu, s, off);
        float mean = s * (1.f / 128.f);
        float dx = v.x - mean, dy = v.y - mean, dz = v.z - mean, dw = v.w - mean;
        float sq = dx * dx + dy * dy + dz * dz + dw * dw;
        #pragma unroll
        for (int off = 16; off > 0; off >>= 1) sq += __shfl_xor_sync(0xffffffffu, sq, off);
        float inv = rsqrtf(sq * (1.f / 128.f) + 1e-5f);
        float4 gg = *(const float4*)&ln_in_g[lane * 4];
        float4 bb = *(const float4*)&ln_in_b[lane * 4];
        uint32_t p0 = packbf(dx * inv * gg.x + bb.x, dy * inv * gg.y + bb.y);
        uint32_t p1 = packbf(dz * inv * gg.z + bb.z, dw * inv * gg.w + bb.w);
        *(uint2*)(xo + r * HDIM + lane * 4) = make_uint2(p0, p1);
        return;
    }

    if (b < 1040) {
        int i = (b - 512) * 256 + tid;
        if (i < 49152) wqkv[i] = __float2bfloat16(aiw[i]);
        else if (i < 65536) { int j = i - 49152; wao[j] = __float2bfloat16(aow[j]); }
        else if (i < 102400) {
            int j = i - 65536; int r = j >> 7, c = j & 127;
            wop1[j] = __float2bfloat16(r < 259 ? opw1[r * 128 + c] : 0.f);
        }
        else if (i < 118784) { int j = i - 102400; wr1[j] = __float2bfloat16(rw1[j]); }
        else { int j = i - 118784; wr2[j] = __float2bfloat16(rw2[j]); }
        return;
    }

    if (b < 1048) {
        __shared__ float t1s[16][128];
        int r0 = (b - 1040) * 16;
        #pragma unroll
        for (int i = 0; i < 8; i++) {
            int idx = tid + i * 256;
            int rr = idx >> 7, k = idx & 127;
            int r = r0 + rr;
            float u = cell[r * 3 + 0] * cw1[k] + cell[r * 3 + 1] * cw1[128 + k]
                    + cell[r * 3 + 2] * cw1[256 + k] + cb1[k];
            t1s[rr][k] = silu_f(u);
        }
        __syncthreads();
        int t = tid & 127, half = tid >> 7;
        float acc[8];
        #pragma unroll
        for (int j = 0; j < 8; j++) acc[j] = cb2[t];
        #pragma unroll 4
        for (int k = 0; k < 128; k++) {
            float w = cw2[k * 128 + t];
            #pragma unroll
            for (int j = 0; j < 8; j++) acc[j] += t1s[half * 8 + j][k] * w;
        }
        #pragma unroll
        for (int j = 0; j < 8; j++) cf[(r0 + half * 8 + j) * 128 + t] = acc[j];
        return;
    }

    __shared__ int starts[BATCH + 1];
    if (tid == 0) {
        int acc = 0;
        for (int i = 0; i < BATCH; i++) { starts[i] = acc; acc += num_atoms[i]; }
        starts[BATCH] = acc;
    }
    __syncthreads();
    for (int i = tid; i < NATOMS; i += 256) g_bidx[i] = BATCH - 1;
    __syncthreads();
    if (tid < BATCH) {
        int s = starts[tid], e = starts[tid + 1];
        if (s > NATOMS) s = NATOMS;
        if (e > NATOMS) e = NATOMS;
        for (int i = s; i < e; i++) g_bidx[i] = tid;
        #pragma unroll
        for (int i = 0; i < 3; i++) {
            float a = cell[(3 * tid + i) * 3 + 0];
            float c1 = cell[(3 * tid + i) * 3 + 1];
            float c = cell[(3 * tid + i) * 3 + 2];
            bmin[tid * 3 + i] = fminf(a, fminf(c1, c)) + 1e-6f;
            bmax[tid * 3 + i] = fmaxf(a, fmaxf(c1, c)) - 1e-6f;
        }
    }
}

// ================= QKV GEMM (BM=32, BN=128, BK=32, double-buffered) =================
__global__ void __launch_bounds__(128) qkv_k(
    const __nv_bfloat16* __restrict__ A, const __nv_bfloat16* __restrict__ W,
    const float* __restrict__ bias,
    __nv_bfloat16* __restrict__ Qh, __nv_bfloat16* __restrict__ Kh,
    __nv_bfloat16* __restrict__ Vh)
{
    __shared__ __align__(16) char sA[2 * 32 * 80];
    __shared__ __align__(16) char sW[2 * 32 * 272];
    const int tid = threadIdx.x, lane = tid & 31, warp = tid >> 5;
    const int wr = warp & 1, wc = warp >> 1;
    const int bm = blockIdx.y, nb = blockIdx.x;
    uint32_t aBase = (uint32_t)__cvta_generic_to_shared(sA);
    uint32_t wBase = (uint32_t)__cvta_generic_to_shared(sW);

    #pragma unroll
    for (int p = 0; p < 2; p++) {
        int row = tid >> 2, seg = tid & 3;
        cpa16(aBase + p * 2560 + row * 80 + seg * 16,
              A + (bm * 32 + row) * 128 + p * 32 + seg * 8);
        #pragma unroll
        for (int i = 0; i < 4; i++) {
            int s = tid + i * 128;
            int wrow = s >> 4, wseg = s & 15;
            cpa16(wBase + p * 8704 + wrow * 272 + wseg * 16,
                  W + (p * 32 + wrow) * H3 + nb * 128 + wseg * 8);
        }
        asm volatile("cp.async.commit_group;");
    }

    float acc[8][4];
    #pragma unroll
    for (int j = 0; j < 8; j++)
        #pragma unroll
        for (int c = 0; c < 4; c++) acc[j][c] = 0.f;

    const int i7 = lane & 7, sel = lane >> 3;
    const int arow = wr * 16 + ((sel & 1) ? 8 : 0) + i7;
    const int acol = (sel >> 1) ? 16 : 0;
    const int vrow = ((sel & 1) ? 8 : 0) + i7;
    const int vcol = (sel >= 2) ? 16 : 0;

    for (int ks = 0; ks < 4; ks++) {
        if (ks < 3) asm volatile("cp.async.wait_group 1;");
        else        asm volatile("cp.async.wait_group 0;");
        __syncthreads();
        uint32_t Ab = aBase + (ks & 1) * 2560;
        uint32_t Wb = wBase + (ks & 1) * 8704;
        #pragma unroll
        for (int kh = 0; kh < 2; kh++) {
            uint32_t qa[4];
            ldsm4(qa[0], qa[1], qa[2], qa[3], Ab + arow * 80 + acol + kh * 32);
            #pragma unroll
            for (int j = 0; j < 4; j++) {
                uint32_t r0, r1, r2, r3;
                ldsm4t(r0, r1, r2, r3, Wb + (kh * 16 + vrow) * 272 + wc * 128 + j * 32 + vcol);
                mma16816(acc[2 * j],     qa, r0, r1);
                mma16816(acc[2 * j + 1], qa, r2, r3);
            }
        }
        __syncthreads();
        if (ks + 2 < 4) {
            int p = ks + 2, buf = ks & 1;
            int row = tid >> 2, seg = tid & 3;
            cpa16(aBase + buf * 2560 + row * 80 + seg * 16,
                  A + (bm * 32 + row) * 128 + p * 32 + seg * 8);
            #pragma unroll
            for (int i = 0; i < 4; i++) {
                int s = tid + i * 128;
                int wrow = s >> 4, wseg = s & 15;
                cpa16(wBase + buf * 8704 + wrow * 272 + wseg * 16,
                      W + (p * 32 + wrow) * H3 + nb * 128 + wseg * 8);
            }
            asm volatile("cp.async.commit_group;");
        }
    }

    const int g = lane >> 2, c2 = (lane & 3) * 2;
    int r0 = bm * 32 + wr * 16 + g;
    __nv_bfloat16* outp = (nb == 0) ? Qh : (nb == 1) ? Kh : Vh;
    float sc = (nb == 0) ? (0.17677669529663687f * 1.4426950408889634f) : 1.f;
    #pragma unroll
    for (int t = 0; t < 8; t++) {
        int col = wc * 64 + t * 8 + c2;
        float b0v = bias[nb * 128 + col], b1v = bias[nb * 128 + col + 1];
        int h = col >> 5, d = col & 31;
        *(uint32_t*)(outp + (((h << 12) + r0) << 5) + d) =
            packbf((acc[t][0] + b0v) * sc, (acc[t][1] + b1v) * sc);
        *(uint32_t*)(outp + (((h << 12) + r0 + 8) << 5) + d) =
            packbf((acc[t][2] + b0v) * sc, (acc[t][3] + b1v) * sc);
    }
}

// ================= fused tail: combine flash partials + 4 GEMMs + LNs + final ==========
#define WSTR 272
#define ASTR 592
#define SM_WAO   0
#define SM_WOP1  (128 * WSTR)
#define SM_WR1   (SM_WOP1 + 288 * WSTR)
#define SM_WR2   (SM_WR1 + 128 * WSTR)
#define SM_ACT   (SM_WR2 + 128 * WSTR)
#define SM_STAGE (SM_ACT + 32 * ASTR)
#define SMEM_TAIL (SM_STAGE + 32 * 136 * 4)

__global__ void __launch_bounds__(256) tail_k(
    const float* __restrict__ opart, const float* __restrict__ lpart,
    const __nv_bfloat16* __restrict__ wao, const float* __restrict__ aob_bias,
    const float* __restrict__ lnf_g, const float* __restrict__ lnf_b,
    const float* __restrict__ cf, const float* __restrict__ coordp,
    const int* __restrict__ bidx,
    const __nv_bfloat16* __restrict__ wop1, const float* __restrict__ op_b1,
    const float* __restrict__ ln1_g, const float* __restrict__ ln1_b,
    const __nv_bfloat16* __restrict__ wr1, const float* __restrict__ r_b1,
    const float* __restrict__ rln_g, const float* __restrict__ rln_b,
    const __nv_bfloat16* __restrict__ wr2, const float* __restrict__ r_b2,
    const float* __restrict__ ln2_g, const float* __restrict__ ln2_b,
    const float* __restrict__ w3, const float* __restrict__ b3,
    const float* __restrict__ bmin, const float* __restrict__ bmax,
    float* __restrict__ fout)
{
    extern __shared__ __align__(16) char dsm[];
    const int tid = threadIdx.x, lane = tid & 31, warp = tid >> 5;
    const int hb = warp >> 2;
    const int wc = warp & 3;
    const int bm = blockIdx.x;
    uint32_t base = (uint32_t)__cvta_generic_to_shared(dsm);
    uint32_t aAct = base + SM_ACT + hb * 16 * ASTR;
    float* sSh = (float*)(dsm + SM_STAGE) + hb * 16 * 136;

    // ---- issue all weight loads first (one group) ----
    #pragma unroll
    for (int i = 0; i < 8; i++) {
        int s = tid + i * 256;
        int row = s >> 4, seg = s & 15;
        cpa16(base + SM_WAO + row * WSTR + seg * 16, wao + row * 128 + seg * 8);
    }
    #pragma unroll
    for (int i = 0; i < 18; i++) {
        int s = tid + i * 256;
        int row = s >> 4, seg = s & 15;
        cpa16(base + SM_WOP1 + row * WSTR + seg * 16, wop1 + row * 128 + seg * 8);
    }
    #pragma unroll
    for (int i = 0; i < 8; i++) {
        int s = tid + i * 256;
        int row = s >> 4, seg = s & 15;
        cpa16(base + SM_WR1 + row * WSTR + seg * 16, wr1 + row * 128 + seg * 8);
    }
    #pragma unroll
    for (int i = 0; i < 8; i++) {
        int s = tid + i * 256;
        int row = s >> 4, seg = s & 15;
        cpa16(base + SM_WR2 + row * WSTR + seg * 16, wr2 + row * 128 + seg * 8);
    }
    asm volatile("cp.async.commit_group;");

    // ---- combine flash K-split partials into bf16 act tile (overlaps weight streaming) ----
    {
        int r = tid >> 3, q = tid & 7;          // 32 rows x 8 threads, 16 cols each
        int grow = bm * 32 + r;
        int h = q >> 1;
        float L = lpart[h * NATOMS + grow] + lpart[NHEAD * NATOMS + h * NATOMS + grow];
        float inv = 1.f / L;
        const float* o0p = opart + grow * 128 + q * 16;
        const float* o1p = o0p + NATOMS * HDIM;
        uint32_t pk[8];
        #pragma unroll
        for (int i = 0; i < 4; i++) {
            float4 a = *(const float4*)&o0p[4 * i];
            float4 b = *(const float4*)&o1p[4 * i];
            pk[2 * i]     = packbf((a.x + b.x) * inv, (a.y + b.y) * inv);
            pk[2 * i + 1] = packbf((a.z + b.z) * inv, (a.w + b.w) * inv);
        }
        uint4* dst = (uint4*)(dsm + SM_ACT + r * ASTR + q * 32);
        dst[0] = *(uint4*)&pk[0];
        dst[1] = *(uint4*)&pk[4];
    }

    asm volatile("cp.async.wait_group 0;");
    __syncthreads();
    // from here the two halves run independently on named barriers 1 / 2

    const int i7 = lane & 7, sel = lane >> 3;
    const int arow = ((sel & 1) ? 8 : 0) + i7;
    const int acol = (sel >> 1) ? 16 : 0;
    const int vrow = ((sel & 1) ? 8 : 0) + i7;
    const int vcol = (sel >= 2) ? 16 : 0;
    const int htid = tid & 127;
    const int row = htid >> 3, q = htid & 7;
    const int grow = bm * 32 + hb * 16 + row;
    const int sr0 = lane >> 2;
    const int c2 = (lane & 3) * 2;
    const int barid = hb + 1;

    float acc[4][4];
    uint32_t hkeep[8];

    auto do_gemm = [&](int wOff, int ksteps) {
        #pragma unroll
        for (int j = 0; j < 4; j++)
            #pragma unroll
            for (int c = 0; c < 4; c++) acc[j][c] = 0.f;
        for (int ks = 0; ks < ksteps; ks++) {
            #pragma unroll
            for (int kh = 0; kh < 2; kh++) {
                uint32_t qa[4];
                ldsm4(qa[0], qa[1], qa[2], qa[3], aAct + arow * ASTR + ks * 64 + kh * 32 + acol);
                #pragma unroll
                for (int j = 0; j < 2; j++) {
                    uint32_t r0, r1, r2, r3;
                    ldsm4t(r0, r1, r2, r3,
                           base + wOff + (ks * 32 + kh * 16 + vrow) * WSTR + wc * 64 + j * 32 + vcol);
                    mma16816(acc[2 * j],     qa, r0, r1);
                    mma16816(acc[2 * j + 1], qa, r2, r3);
                }
            }
        }
    };

    auto stage = [&](const float* bias) {
        #pragma unroll
        for (int t = 0; t < 4; t++) {
            int col = wc * 32 + t * 8 + c2;
            float a0 = bias[col], a1 = bias[col + 1];
            sSh[sr0 * 136 + col] = acc[t][0] + a0;       sSh[sr0 * 136 + col + 1] = acc[t][1] + a1;
            sSh[(sr0 + 8) * 136 + col] = acc[t][2] + a0; sSh[(sr0 + 8) * 136 + col + 1] = acc[t][3] + a1;
        }
    };

    // ============ stage 0: xa = aob @ wao + b ; comb-LN(259) ============
    do_gemm(SM_WAO, 4);
    stage(aob_bias);
    barh(barid);
    {
        int bi = bidx[grow];
        float xv[16], cv[16];
        #pragma unroll
        for (int i = 0; i < 4; i++) {
            float4 f = *(const float4*)&sSh[row * 136 + q * 16 + i * 4];
            xv[4 * i] = f.x; xv[4 * i + 1] = f.y; xv[4 * i + 2] = f.z; xv[4 * i + 3] = f.w;
            float4 c = *(const float4*)&cf[bi * 128 + q * 16 + i * 4];
            cv[4 * i] = c.x; cv[4 * i + 1] = c.y; cv[4 * i + 2] = c.z; cv[4 * i + 3] = c.w;
        }
        float c0 = 0.f, c1 = 0.f, c2v = 0.f;
        float s = 0.f;
        #pragma unroll
        for (int i = 0; i < 16; i++) s += xv[i] + cv[i];
        if (q == 0) {
            c0 = coordp[grow * 3 + 0]; c1 = coordp[grow * 3 + 1]; c2v = coordp[grow * 3 + 2];
            s += c0 + c1 + c2v;
        }
        s += __shfl_xor_sync(0xffffffffu, s, 1);
        s += __shfl_xor_sync(0xffffffffu, s, 2);
        s += __shfl_xor_sync(0xffffffffu, s, 4);
        float mean = s * (1.f / 259.f);
        float sq = 0.f;
        #pragma unroll
        for (int i = 0; i < 16; i++) {
            float d0 = xv[i] - mean, d1 = cv[i] - mean;
            sq += d0 * d0 + d1 * d1;
        }
        if (q == 0) {
            float d0 = c0 - mean, d1 = c1 - mean, d2 = c2v - mean;
            sq += d0 * d0 + d1 * d1 + d2 * d2;
        }
        sq += __shfl_xor_sync(0xffffffffu, sq, 1);
        sq += __shfl_xor_sync(0xffffffffu, sq, 2);
        sq += __shfl_xor_sync(0xffffffffu, sq, 4);
        float inv = rsqrtf(sq * (1.f / 259.f) + 1e-5f);

        uint32_t pk[8];
        #pragma unroll
        for (int i = 0; i < 8; i++) {
            int ca = q * 16 + 2 * i;
            pk[i] = packbf((xv[2 * i] - mean) * inv * lnf_g[ca] + lnf_b[ca],
                           (xv[2 * i + 1] - mean) * inv * lnf_g[ca + 1] + lnf_b[ca + 1]);
        }
        uint4* dst = (uint4*)(dsm + SM_ACT + (hb * 16 + row) * ASTR + q * 32);
        dst[0] = *(uint4*)&pk[0]; dst[1] = *(uint4*)&pk[4];
        #pragma unroll
        for (int i = 0; i < 8; i++) {
            int ca = 128 + q * 16 + 2 * i;
            pk[i] = packbf((cv[2 * i] - mean) * inv * lnf_g[ca] + lnf_b[ca],
                           (cv[2 * i + 1] - mean) * inv * lnf_g[ca + 1] + lnf_b[ca + 1]);
        }
        dst = (uint4*)(dsm + SM_ACT + (hb * 16 + row) * ASTR + 256 + q * 32);
        dst[0] = *(uint4*)&pk[0]; dst[1] = *(uint4*)&pk[4];
        uint32_t tp0 = 0, tp1 = 0;
        if (q == 0) {
            tp0 = packbf((c0 - mean) * inv * lnf_g[256] + lnf_b[256],
                         (c1 - mean) * inv * lnf_g[257] + lnf_b[257]);
            tp1 = packbf((c2v - mean) * inv * lnf_g[258] + lnf_b[258], 0.f);
        }
        *(uint2*)(dsm + SM_ACT + (hb * 16 + row) * ASTR + 512 + q * 8) = make_uint2(tp0, tp1);
    }
    barh(barid);

    // ============ stage 1: h0 = comb @ wop1 ; LN + SiLU ============
    do_gemm(SM_WOP1, 9);
    stage(op_b1);
    barh(barid);
    {
        float v[16];
        #pragma unroll
        for (int i = 0; i < 4; i++) {
            float4 f = *(const float4*)&sSh[row * 136 + q * 16 + i * 4];
            v[4 * i] = f.x; v[4 * i + 1] = f.y; v[4 * i + 2] = f.z; v[4 * i + 3] = f.w;
        }
        float s = 0.f;
        #pragma unroll
        for (int i = 0; i < 16; i++) s += v[i];
        s += __shfl_xor_sync(0xffffffffu, s, 1);
        s += __shfl_xor_sync(0xffffffffu, s, 2);
        s += __shfl_xor_sync(0xffffffffu, s, 4);
        float mean = s * (1.f / 128.f);
        float sq = 0.f;
        #pragma unroll
        for (int i = 0; i < 16; i++) { float d = v[i] - mean; sq += d * d; }
        sq += __shfl_xor_sync(0xffffffffu, sq, 1);
        sq += __shfl_xor_sync(0xffffffffu, sq, 2);
        sq += __shfl_xor_sync(0xffffffffu, sq, 4);
        float inv = rsqrtf(sq * (1.f / 128.f) + 1e-5f);
        #pragma unroll
        for (int i = 0; i < 8; i++) {
            int ca = q * 16 + 2 * i;
            float y0 = silu_f((v[2 * i] - mean) * inv * ln1_g[ca] + ln1_b[ca]);
            float y1 = silu_f((v[2 * i + 1] - mean) * inv * ln1_g[ca + 1] + ln1_b[ca + 1]);
            hkeep[i] = packbf(y0, y1);
        }
        uint4* dst = (uint4*)(dsm + SM_ACT + (hb * 16 + row) * ASTR + q * 32);
        dst[0] = *(uint4*)&hkeep[0]; dst[1] = *(uint4*)&hkeep[4];
    }
    barh(barid);

    // ============ stage 2: t = h1 @ wr1 ; LN + SiLU ============
    do_gemm(SM_WR1, 4);
    stage(r_b1);
    barh(barid);
    {
        float v[16];
        #pragma unroll
        for (int i = 0; i < 4; i++) {
            float4 f = *(const float4*)&sSh[row * 136 + q * 16 + i * 4];
            v[4 * i] = f.x; v[4 * i + 1] = f.y; v[4 * i + 2] = f.z; v[4 * i + 3] = f.w;
        }
        float s = 0.f;
        #pragma unroll
        for (int i = 0; i < 16; i++) s += v[i];
        s += __shfl_xor_sync(0xffffffffu, s, 1);
        s += __shfl_xor_sync(0xffffffffu, s, 2);
        s += __shfl_xor_sync(0xffffffffu, s, 4);
        float mean = s * (1.f / 128.f);
        float sq = 0.f;
        #pragma unroll
        for (int i = 0; i < 16; i++) { float d = v[i] - mean; sq += d * d; }
        sq += __shfl_xor_sync(0xffffffffu, sq, 1);
        sq += __shfl_xor_sync(0xffffffffu, sq, 2);
        sq += __shfl_xor_sync(0xffffffffu, sq, 4);
        float inv = rsqrtf(sq * (1.f / 128.f) + 1e-5f);
        uint32_t pk[8];
        #pragma unroll
        for (int i = 0; i < 8; i++) {
            int ca = q * 16 + 2 * i;
            float y0 = silu_f((v[2 * i] - mean) * inv * rln_g[ca] + rln_b[ca]);
            float y1 = silu_f((v[2 * i + 1] - mean) * inv * rln_g[ca + 1] + rln_b[ca + 1]);
            pk[i] = packbf(y0, y1);
        }
        uint4* dst = (uint4*)(dsm + SM_ACT + (hb * 16 + row) * ASTR + q * 32);
        dst[0] = *(uint4*)&pk[0]; dst[1] = *(uint4*)&pk[4];
    }
    barh(barid);

    // ============ stage 3: hfin = t2 @ wr2 + b + h1 ; LN ; proj/tanh/clamp ============
    do_gemm(SM_WR2, 4);
    stage(r_b2);
    barh(barid);
    {
        float v[16];
        #pragma unroll
        for (int i = 0; i < 4; i++) {
            float4 f = *(const float4*)&sSh[row * 136 + q * 16 + i * 4];
            v[4 * i] = f.x; v[4 * i + 1] = f.y; v[4 * i + 2] = f.z; v[4 * i + 3] = f.w;
        }
        #pragma unroll
        for (int i = 0; i < 8; i++) {
            __nv_bfloat162 hh = *(__nv_bfloat162*)&hkeep[i];
            v[2 * i]     += __bfloat162float(hh.x);
            v[2 * i + 1] += __bfloat162float(hh.y);
        }
        float s = 0.f;
        #pragma unroll
        for (int i = 0; i < 16; i++) s += v[i];
        s += __shfl_xor_sync(0xffffffffu, s, 1);
        s += __shfl_xor_sync(0xffffffffu, s, 2);
        s += __shfl_xor_sync(0xffffffffu, s, 4);
        float mean = s * (1.f / 128.f);
        float sq = 0.f;
        #pragma unroll
        for (int i = 0; i < 16; i++) { float d = v[i] - mean; sq += d * d; }
        sq += __shfl_xor_sync(0xffffffffu, sq, 1);
        sq += __shfl_xor_sync(0xffffffffu, sq, 2);
        sq += __shfl_xor_sync(0xffffffffu, sq, 4);
        float inv = rsqrtf(sq * (1.f / 128.f) + 1e-5f);

        float p0 = 0.f, p1 = 0.f, p2 = 0.f;
        #pragma unroll
        for (int i = 0; i < 16; i++) {
            int ca = q * 16 + i;
            float y = (v[i] - mean) * inv * ln2_g[ca] + ln2_b[ca];
            p0 += y * w3[ca * 3 + 0];
            p1 += y * w3[ca * 3 + 1];
            p2 += y * w3[ca * 3 + 2];
        }
        p0 += __shfl_xor_sync(0xffffffffu, p0, 1);
        p0 += __shfl_xor_sync(0xffffffffu, p0, 2);
        p0 += __shfl_xor_sync(0xffffffffu, p0, 4);
        p1 += __shfl_xor_sync(0xffffffffu, p1, 1);
        p1 += __shfl_xor_sync(0xffffffffu, p1, 2);
        p1 += __shfl_xor_sync(0xffffffffu, p1, 4);
        p2 += __shfl_xor_sync(0xffffffffu, p2, 1);
        p2 += __shfl_xor_sync(0xffffffffu, p2, 2);
        p2 += __shfl_xor_sync(0xffffffffu, p2, 4);
        if (q == 0) {
            int bi = bidx[grow];
            float dots[3] = {p0 + b3[0], p1 + b3[1], p2 + b3[2]};
            #pragma unroll
            for (int j = 0; j < 3; j++) {
                float val = coordp[grow * 3 + j] + 0.01f * tanhf(dots[j]);
                fout[grow * 3 + j] = fminf(fmaxf(val, bmin[bi * 3 + j]), bmax[bi * 3 + j]);
            }
        }
    }
}

// ---------------- bf16 flash attention: K-split, fixed-max softmax ----------------
#define CSTRIDE 80
#define QBUF    5120
#define KVB     10240
#define NITER   (32 / KSPLIT)

__device__ __forceinline__ void kv_load128(const __nv_bfloat16* __restrict__ Kh,
                                           const __nv_bfloat16* __restrict__ Vh,
                                           int h, int kb, uint32_t sbase, int tid) {
    #pragma unroll
    for (int i = 0; i < 8; i++) {
        int s = tid + i * 128;
        int row = (s >> 2) & 127, seg = s & 3;
        const __nv_bfloat16* src = ((s < 512) ? Kh : Vh)
            + (((h << 12) + (kb << 7) + row) << 5) + seg * 8;
        uint32_t dst = sbase + ((s < 512) ? 0 : KVB) + row * CSTRIDE + seg * 16;
        cpa16(dst, src);
    }
    asm volatile("cp.async.commit_group;");
}

__global__ void __launch_bounds__(128) flashb_k(const __nv_bfloat16* __restrict__ Qh,
                                                const __nv_bfloat16* __restrict__ Kh,
                                                const __nv_bfloat16* __restrict__ Vh,
                                                float* __restrict__ opart,
                                                float* __restrict__ lpart) {
    __shared__ __align__(16) char smem[QBUF + 4 * KVB];
    const int tid = threadIdx.x, lane = tid & 31, warp = tid >> 5;
    const int h = blockIdx.y, qb = blockIdx.x, sp = blockIdx.z;
    const int kb0 = sp * NITER;

    char* Qs = smem;
    uint32_t Qsa = (uint32_t)__cvta_generic_to_shared(Qs);
    uint32_t kva0 = Qsa + QBUF;
    uint32_t kva1 = Qsa + QBUF + 2 * KVB;

    #pragma unroll
    for (int i = 0; i < 2; i++) {
        int s = tid + i * 128;
        int row = s >> 2, seg = s & 3;
        uint4 v = *(const uint4*)(Qh + (((h << 12) + (qb << 6) + row) << 5) + seg * 8);
        *(uint4*)(Qs + row * CSTRIDE + seg * 16) = v;
    }
    kv_load128(Kh, Vh, h, kb0 + 0, kva0, tid);
    kv_load128(Kh, Vh, h, kb0 + 1, kva1, tid);
    __syncthreads();

    uint32_t qa[8];
    {
        int i = lane & 7, sl = lane >> 3;
        int row = warp * 16 + ((sl & 1) ? 8 : 0) + i;
        uint32_t a = Qsa + row * CSTRIDE + ((sl >> 1) ? 16 : 0);
        ldsm4(qa[0], qa[1], qa[2], qa[3], a);
        ldsm4(qa[4], qa[5], qa[6], qa[7], a + 32);
    }

    float l0 = 0.f, l1 = 0.f;
    float o[4][4];
    #pragma unroll
    for (int j = 0; j < 4; j++)
        #pragma unroll
        for (int c = 0; c < 4; c++) o[j][c] = 0.f;

    const int i7 = lane & 7, sel = lane >> 3;
    const uint32_t krow = ((sel >= 2) ? 8 : 0) + i7;
    const uint32_t kcol = (sel & 1) ? 16 : 0;
    const uint32_t vrow = ((sel & 1) ? 8 : 0) + i7;
    const uint32_t vcol = (sel >= 2) ? 16 : 0;

    for (int kb = 0; kb < NITER; kb++) {
        if (kb < NITER - 1) asm volatile("cp.async.wait_group 1;");
        else                asm volatile("cp.async.wait_group 0;");
        __syncthreads();
        uint32_t Kbase = (kb & 1) ? kva1 : kva0;
        uint32_t Vbase = Kbase + KVB;

        float s[16][4];
        #pragma unroll
        for (int j = 0; j < 16; j++)
            #pragma unroll
            for (int c = 0; c < 4; c++) s[j][c] = 0.f;

        #pragma unroll
        for (int jp = 0; jp < 8; jp++) {
            uint32_t a = Kbase + (jp * 16 + krow) * CSTRIDE + kcol;
            uint32_t b0, b1, b2, b3, c0, c1, c2, c3;
            ldsm4(b0, b1, b2, b3, a);
            ldsm4(c0, c1, c2, c3, a + 32);
            mma16816(s[2 * jp],     qa,     b0, b1);
            mma16816(s[2 * jp],     qa + 4, c0, c1);
            mma16816(s[2 * jp + 1], qa,     b2, b3);
            mma16816(s[2 * jp + 1], qa + 4, c2, c3);
        }

        #pragma unroll
        for (int ks = 0; ks < 8; ks++) {
            float e00 = exp2f(s[2 * ks][0]),     e01 = exp2f(s[2 * ks][1]);
            float e02 = exp2f(s[2 * ks][2]),     e03 = exp2f(s[2 * ks][3]);
            float e10 = exp2f(s[2 * ks + 1][0]), e11 = exp2f(s[2 * ks + 1][1]);
            float e12 = exp2f(s[2 * ks + 1][2]), e13 = exp2f(s[2 * ks + 1][3]);
            l0 += (e00 + e01) + (e10 + e11);
            l1 += (e02 + e03) + (e12 + e13);
            uint32_t pa[4];
            pa[0] = packbf(e00, e01);
            pa[1] = packbf(e02, e03);
            pa[2] = packbf(e10, e11);
            pa[3] = packbf(e12, e13);
            uint32_t a = Vbase + (ks * 16 + vrow) * CSTRIDE + vcol;
            uint32_t v0, v1, v2, v3, w0, w1, w2, w3;
            ldsm4t(v0, v1, v2, v3, a);
            ldsm4t(w0, w1, w2, w3, a + 32);
            mma16816(o[0], pa, v0, v1);
            mma16816(o[1], pa, v2, v3);
            mma16816(o[2], pa, w0, w1);
            mma16816(o[3], pa, w2, w3);
        }

        __syncthreads();
        if (kb < NITER - 2) kv_load128(Kh, Vh, h, kb0 + kb + 2, (kb & 1) ? kva1 : kva0, tid);
    }

    // epilogue: quad-reduce l, write UNNORMALIZED fp32 partials
    l0 += __shfl_xor_sync(0xffffffffu, l0, 1);
    l0 += __shfl_xor_sync(0xffffffffu, l0, 2);
    l1 += __shfl_xor_sync(0xffffffffu, l1, 1);
    l1 += __shfl_xor_sync(0xffffffffu, l1, 2);
    int g = lane >> 2, l2 = (lane & 3) * 2;
    int row0 = (qb << 6) + warp * 16 + g;
    float* op = opart + sp * NATOMS * HDIM;
    #pragma unroll
    for (int j = 0; j < 4; j++) {
        int col = (h << 5) + j * 8 + l2;
        *(float2*)&op[row0 * HDIM + col]       = make_float2(o[j][0], o[j][1]);
        *(float2*)&op[(row0 + 8) * HDIM + col] = make_float2(o[j][2], o[j][3]);
    }
    if ((lane & 3) == 0) {
        lpart[sp * NHEAD * NATOMS + h * NATOMS + row0]     = l0;
        lpart[sp * NHEAD * NATOMS + h * NATOMS + row0 + 8] = l1;
    }
}

// ---------------- host ----------------
extern "C" void kernel_launch(void* const* d_in, const int* in_sizes, int n_in,
                              void* d_out, int out_size) {
    const int*   num_atoms  = (const int*)d_in[0];
    const int*   elems      = (const int*)d_in[1];
    const float* cell       = (const float*)d_in[2];
    const float* coord      = (const float*)d_in[3];
    const float* emb        = (const float*)d_in[4];
    const float* ln_in_g    = (const float*)d_in[5];
    const float* ln_in_b    = (const float*)d_in[6];
    const float* attn_in_w  = (const float*)d_in[7];
    const float* attn_in_b  = (const float*)d_in[8];
    const float* attn_out_w = (const float*)d_in[9];
    const float* attn_out_b = (const float*)d_in[10];
    const float* ce_w1      = (const float*)d_in[11];
    const float* ce_b1      = (const float*)d_in[12];
    const float* ce_w2      = (const float*)d_in[13];
    const float* ce_b2      = (const float*)d_in[14];
    const float* ln_feat_g  = (const float*)d_in[15];
    const float* ln_feat_b  = (const float*)d_in[16];
    const float* op_w1      = (const float*)d_in[17];
    const float* op_b1      = (const float*)d_in[18];
    const float* op_ln1_g   = (const float*)d_in[19];
    const float* op_ln1_b   = (const float*)d_in[20];
    const float* res_w1     = (const float*)d_in[21];
    const float* res_b1     = (const float*)d_in[22];
    const float* res_ln_g   = (const float*)d_in[23];
    const float* res_ln_b   = (const float*)d_in[24];
    const float* res_w2     = (const float*)d_in[25];
    const float* res_b2     = (const float*)d_in[26];
    const float* op_ln2_g   = (const float*)d_in[27];
    const float* op_ln2_b   = (const float*)d_in[28];
    const float* op_w3      = (const float*)d_in[29];
    const float* op_b3      = (const float*)d_in[30];
    float* out = (float*)d_out;

    float* S = nullptr;
    cudaGetSymbolAddress((void**)&S, g_scratch);
    int* bidx = nullptr;
    cudaGetSymbolAddress((void**)&bidx, g_bidx);

    __nv_bfloat16* P = (__nv_bfloat16*)S;
    __nv_bfloat16* xb    = P; P += NATOMS * HDIM;
    __nv_bfloat16* Qh    = P; P += NATOMS * HDIM;
    __nv_bfloat16* Kh    = P; P += NATOMS * HDIM;
    __nv_bfloat16* Vh    = P; P += NATOMS * HDIM;
    __nv_bfloat16* wqkv  = P; P += 128 * 384;
    __nv_bfloat16* wao   = P; P += 128 * 128;
    __nv_bfloat16* wop1  = P; P += FPAD * 128;
    __nv_bfloat16* wr1   = P; P += 128 * 128;
    __nv_bfloat16* wr2   = P; P += 128 * 128;
    float* F = (float*)P;
    float* opart = F; F += KSPLIT * NATOMS * HDIM;
    float* lpart = F; F += KSPLIT * NHEAD * NATOMS;
    float* cf    = F; F += BATCH * HDIM;
    float* bmin  = F; F += BATCH * 3;
    float* bmax  = F; F += BATCH * 3;

    static bool attr_set = false;
    if (!attr_set) {
        cudaFuncSetAttribute(tail_k, cudaFuncAttributeMaxDynamicSharedMemorySize, SMEM_TAIL);
        attr_set = true;
    }

    setup_k<<<1049, 256>>>(elems, emb, ln_in_g, ln_in_b, xb,
                           attn_in_w, attn_out_w, op_w1, res_w1, res_w2,
                           wqkv, wao, wop1, wr1, wr2,
                           cell, ce_w1, ce_b1, ce_w2, ce_b2, cf,
                           num_atoms, bmin, bmax);

    qkv_k<<<dim3(3, 128), 128>>>(xb, wqkv, attn_in_b, Qh, Kh, Vh);

    flashb_k<<<dim3(64, NHEAD, KSPLIT), 128>>>(Qh, Kh, Vh, opart, lpart);

    tail_k<<<128, 256, SMEM_TAIL>>>(opart, lpart,
        wao, attn_out_b, ln_feat_g, ln_feat_b, cf, coord, bidx,
        wop1, op_b1, op_ln1_g, op_ln1_b,
        wr1, res_b1, res_ln_g, res_ln_b,
        wr2, res_b2, op_ln2_g, op_ln2_b,
        op_w3, op_b3, bmin, bmax, out);
}

// round 9
// speedup vs baseline: 7.4266x; 1.0182x over previous
#include <cuda_runtime.h>
#include <cuda_bf16.h>
#include <math.h>
#include <stdint.h>

#define NATOMS 4096
#define HDIM   128
#define BATCH  128
#define NHEAD  4
#define DHEAD  32
#define H3     384
#define FPAD   288
#define KSPLIT 2

// -------- scratch (no allocations allowed) --------
__device__ float g_scratch[8300000];
__device__ int   g_bidx[NATOMS];

// ---------------- helpers ----------------
__device__ __forceinline__ float silu_f(float x) {
    return x / (1.f + __expf(-x));
}
__device__ __forceinline__ void ldsm4(uint32_t& r0, uint32_t& r1, uint32_t& r2, uint32_t& r3, uint32_t addr) {
    asm volatile("ldmatrix.sync.aligned.m8n8.x4.shared.b16 {%0,%1,%2,%3}, [%4];"
                 : "=r"(r0), "=r"(r1), "=r"(r2), "=r"(r3) : "r"(addr));
}
__device__ __forceinline__ void ldsm4t(uint32_t& r0, uint32_t& r1, uint32_t& r2, uint32_t& r3, uint32_t addr) {
    asm volatile("ldmatrix.sync.aligned.m8n8.x4.trans.shared.b16 {%0,%1,%2,%3}, [%4];"
                 : "=r"(r0), "=r"(r1), "=r"(r2), "=r"(r3) : "r"(addr));
}
__device__ __forceinline__ void mma16816(float* d, const uint32_t* a, uint32_t b0, uint32_t b1) {
    asm volatile("mma.sync.aligned.m16n8k16.row.col.f32.bf16.bf16.f32 "
                 "{%0,%1,%2,%3}, {%4,%5,%6,%7}, {%8,%9}, {%0,%1,%2,%3};"
                 : "+f"(d[0]), "+f"(d[1]), "+f"(d[2]), "+f"(d[3])
                 : "r"(a[0]), "r"(a[1]), "r"(a[2]), "r"(a[3]), "r"(b0), "r"(b1));
}
__device__ __forceinline__ uint32_t packbf(float lo, float hi) {
    uint32_t r;
    asm volatile("cvt.rn.bf16x2.f32 %0, %1, %2;" : "=r"(r) : "f"(hi), "f"(lo));
    return r;
}
__device__ __forceinline__ void cpa16(uint32_t dst, const void* src) {
    asm volatile("cp.async.ca.shared.global [%0], [%1], 16;" :: "r"(dst), "l"(src));
}
__device__ __forceinline__ void cpa4(uint32_t dst, const void* src) {
    asm volatile("cp.async.ca.shared.global [%0], [%1], 4;" :: "r"(dst), "l"(src));
}
__device__ __forceinline__ void barh(int id) {
    asm volatile("bar.sync %0, 128;" :: "r"(id) : "memory");
}
// Schraudolph exp2 in fp32 bit space: exp2(x) ~ bits (int)(x*2^23 + C)
// C = 127*2^23 - 509211(centered) + 32768(bf16 round) ~ 1064876800
__device__ __forceinline__ uint32_t schexp(float x) {
    int i;
    asm("cvt.rni.s32.f32 %0, %1;" : "=r"(i) : "f"(fmaf(x, 8388608.f, 1064876800.f)));
    return (uint32_t)i;
}
__device__ __forceinline__ uint32_t prmt16(uint32_t a, uint32_t b) {
    uint32_t r;
    asm("prmt.b32 %0,%1,%2,0x7632;" : "=r"(r) : "r"(a), "r"(b));
    return r;
}

// ================= fused setup kernel =================
__global__ void __launch_bounds__(256) setup_k(
    const int* __restrict__ elems, const float* __restrict__ emb,
    const float* __restrict__ ln_in_g, const float* __restrict__ ln_in_b,
    __nv_bfloat16* __restrict__ xo,
    const float* __restrict__ aiw, const float* __restrict__ aow,
    const float* __restrict__ opw1, const float* __restrict__ rw1,
    const float* __restrict__ rw2,
    __nv_bfloat16* __restrict__ wqkv, __nv_bfloat16* __restrict__ wao,
    __nv_bfloat16* __restrict__ wop1, __nv_bfloat16* __restrict__ wr1,
    __nv_bfloat16* __restrict__ wr2,
    const float* __restrict__ cell,
    const float* __restrict__ cw1, const float* __restrict__ cb1,
    const float* __restrict__ cw2, const float* __restrict__ cb2,
    float* __restrict__ cf,
    const int* __restrict__ num_atoms,
    float* __restrict__ bmin, float* __restrict__ bmax)
{
    const int b = blockIdx.x, tid = threadIdx.x;

    if (b < 512) {
        int warp = tid >> 5, lane = tid & 31;
        int r = b * 8 + warp;
        int e = elems[r];
        float4 v = *(const float4*)&emb[e * HDIM + lane * 4];
        float s = v.x + v.y + v.z + v.w;
        #pragma unroll
        for (int off = 16; off > 0; off >>= 1) s += __shfl_xor_sync(0xffffffffu, s, off);
        float mean = s * (1.f / 128.f);
        float dx = v.x - mean, dy = v.y - mean, dz = v.z - mean, dw = v.w - mean;
        float sq = dx * dx + dy * dy + dz * dz + dw * dw;
        #pragma unroll
        for (int off = 16; off > 0; off >>= 1) sq += __shfl_xor_sync(0xffffffffu, sq, off);
        float inv = rsqrtf(sq * (1.f / 128.f) + 1e-5f);
        float4 gg = *(const float4*)&ln_in_g[lane * 4];
        float4 bb = *(const float4*)&ln_in_b[lane * 4];
        uint32_t p0 = packbf(dx * inv * gg.x + bb.x, dy * inv * gg.y + bb.y);
        uint32_t p1 = packbf(dz * inv * gg.z + bb.z, dw * inv * gg.w + bb.w);
        *(uint2*)(xo + r * HDIM + lane * 4) = make_uint2(p0, p1);
        return;
    }

    if (b < 1040) {
        int i = (b - 512) * 256 + tid;
        if (i < 49152) wqkv[i] = __float2bfloat16(aiw[i]);
        else if (i < 65536) { int j = i - 49152; wao[j] = __float2bfloat16(aow[j]); }
        else if (i < 102400) {
            int j = i - 65536; int r = j >> 7, c = j & 127;
            wop1[j] = __float2bfloat16(r < 259 ? opw1[r * 128 + c] : 0.f);
        }
        else if (i < 118784) { int j = i - 102400; wr1[j] = __float2bfloat16(rw1[j]); }
        else { int j = i - 118784; wr2[j] = __float2bfloat16(rw2[j]); }
        return;
    }

    if (b < 1048) {
        __shared__ float t1s[16][128];
        int r0 = (b - 1040) * 16;
        #pragma unroll
        for (int i = 0; i < 8; i++) {
            int idx = tid + i * 256;
            int rr = idx >> 7, k = idx & 127;
            int r = r0 + rr;
            float u = cell[r * 3 + 0] * cw1[k] + cell[r * 3 + 1] * cw1[128 + k]
                    + cell[r * 3 + 2] * cw1[256 + k] + cb1[k];
            t1s[rr][k] = silu_f(u);
        }
        __syncthreads();
        int t = tid & 127, half = tid >> 7;
        float acc[8];
        #pragma unroll
        for (int j = 0; j < 8; j++) acc[j] = cb2[t];
        #pragma unroll 4
        for (int k = 0; k < 128; k++) {
            float w = cw2[k * 128 + t];
            #pragma unroll
            for (int j = 0; j < 8; j++) acc[j] += t1s[half * 8 + j][k] * w;
        }
        #pragma unroll
        for (int j = 0; j < 8; j++) cf[(r0 + half * 8 + j) * 128 + t] = acc[j];
        return;
    }

    __shared__ int starts[BATCH + 1];
    if (tid == 0) {
        int acc = 0;
        for (int i = 0; i < BATCH; i++) { starts[i] = acc; acc += num_atoms[i]; }
        starts[BATCH] = acc;
    }
    __syncthreads();
    for (int i = tid; i < NATOMS; i += 256) g_bidx[i] = BATCH - 1;
    __syncthreads();
    if (tid < BATCH) {
        int s = starts[tid], e = starts[tid + 1];
        if (s > NATOMS) s = NATOMS;
        if (e > NATOMS) e = NATOMS;
        for (int i = s; i < e; i++) g_bidx[i] = tid;
        #pragma unroll
        for (int i = 0; i < 3; i++) {
            float a = cell[(3 * tid + i) * 3 + 0];
            float c1 = cell[(3 * tid + i) * 3 + 1];
            float c = cell[(3 * tid + i) * 3 + 2];
            bmin[tid * 3 + i] = fminf(a, fminf(c1, c)) + 1e-6f;
            bmax[tid * 3 + i] = fmaxf(a, fmaxf(c1, c)) - 1e-6f;
        }
    }
}

// ================= QKV GEMM (BM=32, BN=128, BK=32, double-buffered) =================
__global__ void __launch_bounds__(128) qkv_k(
    const __nv_bfloat16* __restrict__ A, const __nv_bfloat16* __restrict__ W,
    const float* __restrict__ bias,
    __nv_bfloat16* __restrict__ Qh, __nv_bfloat16* __restrict__ Kh,
    __nv_bfloat16* __restrict__ Vh)
{
    __shared__ __align__(16) char sA[2 * 32 * 80];
    __shared__ __align__(16) char sW[2 * 32 * 272];
    const int tid = threadIdx.x, lane = tid & 31, warp = tid >> 5;
    const int wr = warp & 1, wc = warp >> 1;
    const int bm = blockIdx.y, nb = blockIdx.x;
    uint32_t aBase = (uint32_t)__cvta_generic_to_shared(sA);
    uint32_t wBase = (uint32_t)__cvta_generic_to_shared(sW);

    #pragma unroll
    for (int p = 0; p < 2; p++) {
        int row = tid >> 2, seg = tid & 3;
        cpa16(aBase + p * 2560 + row * 80 + seg * 16,
              A + (bm * 32 + row) * 128 + p * 32 + seg * 8);
        #pragma unroll
        for (int i = 0; i < 4; i++) {
            int s = tid + i * 128;
            int wrow = s >> 4, wseg = s & 15;
            cpa16(wBase + p * 8704 + wrow * 272 + wseg * 16,
                  W + (p * 32 + wrow) * H3 + nb * 128 + wseg * 8);
        }
        asm volatile("cp.async.commit_group;");
    }

    float acc[8][4];
    #pragma unroll
    for (int j = 0; j < 8; j++)
        #pragma unroll
        for (int c = 0; c < 4; c++) acc[j][c] = 0.f;

    const int i7 = lane & 7, sel = lane >> 3;
    const int arow = wr * 16 + ((sel & 1) ? 8 : 0) + i7;
    const int acol = (sel >> 1) ? 16 : 0;
    const int vrow = ((sel & 1) ? 8 : 0) + i7;
    const int vcol = (sel >= 2) ? 16 : 0;

    for (int ks = 0; ks < 4; ks++) {
        if (ks < 3) asm volatile("cp.async.wait_group 1;");
        else        asm volatile("cp.async.wait_group 0;");
        __syncthreads();
        uint32_t Ab = aBase + (ks & 1) * 2560;
        uint32_t Wb = wBase + (ks & 1) * 8704;
        #pragma unroll
        for (int kh = 0; kh < 2; kh++) {
            uint32_t qa[4];
            ldsm4(qa[0], qa[1], qa[2], qa[3], Ab + arow * 80 + acol + kh * 32);
            #pragma unroll
            for (int j = 0; j < 4; j++) {
                uint32_t r0, r1, r2, r3;
                ldsm4t(r0, r1, r2, r3, Wb + (kh * 16 + vrow) * 272 + wc * 128 + j * 32 + vcol);
                mma16816(acc[2 * j],     qa, r0, r1);
                mma16816(acc[2 * j + 1], qa, r2, r3);
            }
        }
        __syncthreads();
        if (ks + 2 < 4) {
            int p = ks + 2, buf = ks & 1;
            int row = tid >> 2, seg = tid & 3;
            cpa16(aBase + buf * 2560 + row * 80 + seg * 16,
                  A + (bm * 32 + row) * 128 + p * 32 + seg * 8);
            #pragma unroll
            for (int i = 0; i < 4; i++) {
                int s = tid + i * 128;
                int wrow = s >> 4, wseg = s & 15;
                cpa16(wBase + buf * 8704 + wrow * 272 + wseg * 16,
                      W + (p * 32 + wrow) * H3 + nb * 128 + wseg * 8);
            }
            asm volatile("cp.async.commit_group;");
        }
    }

    const int g = lane >> 2, c2 = (lane & 3) * 2;
    int r0 = bm * 32 + wr * 16 + g;
    __nv_bfloat16* outp = (nb == 0) ? Qh : (nb == 1) ? Kh : Vh;
    float sc = (nb == 0) ? (0.17677669529663687f * 1.4426950408889634f) : 1.f;
    #pragma unroll
    for (int t = 0; t < 8; t++) {
        int col = wc * 64 + t * 8 + c2;
        float b0v = bias[nb * 128 + col], b1v = bias[nb * 128 + col + 1];
        int h = col >> 5, d = col & 31;
        *(uint32_t*)(outp + (((h << 12) + r0) << 5) + d) =
            packbf((acc[t][0] + b0v) * sc, (acc[t][1] + b1v) * sc);
        *(uint32_t*)(outp + (((h << 12) + r0 + 8) << 5) + d) =
            packbf((acc[t][2] + b0v) * sc, (acc[t][3] + b1v) * sc);
    }
}

// ================= fused tail: combine + 4 GEMMs + LNs + final, params in smem ==========
#define WSTR 272
#define ASTR 592
#define SM_WAO   0
#define SM_WOP1  (128 * WSTR)
#define SM_WR1   (SM_WOP1 + 288 * WSTR)
#define SM_WR2   (SM_WR1 + 128 * WSTR)
#define SM_ACT   (SM_WR2 + 128 * WSTR)
#define SM_STAGE (SM_ACT + 32 * ASTR)
#define SM_PAR   (SM_STAGE + 32 * 136 * 4)    // 219136 bytes
// parameter block offsets (in floats)
#define PAR_AOBB 0
#define PAR_OPB1 128
#define PAR_RB1  256
#define PAR_RB2  384
#define PAR_LNFG 512
#define PAR_LNFB 772
#define PAR_LN1G 1032
#define PAR_LN1B 1160
#define PAR_RLNG 1288
#define PAR_RLNB 1416
#define PAR_LN2G 1544
#define PAR_LN2B 1672
#define PAR_W3   1800
#define PAR_B3   2184
#define SMEM_TAIL (SM_PAR + 2192 * 4)          // 227904 bytes

__global__ void __launch_bounds__(256) tail_k(
    const float* __restrict__ opart, const float* __restrict__ lpart,
    const __nv_bfloat16* __restrict__ wao, const float* __restrict__ aob_bias,
    const float* __restrict__ lnf_g, const float* __restrict__ lnf_b,
    const float* __restrict__ cf, const float* __restrict__ coordp,
    const int* __restrict__ bidx,
    const __nv_bfloat16* __restrict__ wop1, const float* __restrict__ op_b1,
    const float* __restrict__ ln1_g, const float* __restrict__ ln1_b,
    const __nv_bfloat16* __restrict__ wr1, const float* __restrict__ r_b1,
    const float* __restrict__ rln_g, const float* __restrict__ rln_b,
    const __nv_bfloat16* __restrict__ wr2, const float* __restrict__ r_b2,
    const float* __restrict__ ln2_g, const float* __restrict__ ln2_b,
    const float* __restrict__ w3, const float* __restrict__ b3,
    const float* __restrict__ bmin, const float* __restrict__ bmax,
    float* __restrict__ fout)
{
    extern __shared__ __align__(16) char dsm[];
    const int tid = threadIdx.x, lane = tid & 31, warp = tid >> 5;
    const int hb = warp >> 2;
    const int wc = warp & 3;
    const int bm = blockIdx.x;
    uint32_t base = (uint32_t)__cvta_generic_to_shared(dsm);
    uint32_t aAct = base + SM_ACT + hb * 16 * ASTR;
    float* sSh = (float*)(dsm + SM_STAGE) + hb * 16 * 136;
    const float* par = (const float*)(dsm + SM_PAR);

    // ---- issue all weight loads ----
    #pragma unroll
    for (int i = 0; i < 8; i++) {
        int s = tid + i * 256;
        int row = s >> 4, seg = s & 15;
        cpa16(base + SM_WAO + row * WSTR + seg * 16, wao + row * 128 + seg * 8);
    }
    #pragma unroll
    for (int i = 0; i < 18; i++) {
        int s = tid + i * 256;
        int row = s >> 4, seg = s & 15;
        cpa16(base + SM_WOP1 + row * WSTR + seg * 16, wop1 + row * 128 + seg * 8);
    }
    #pragma unroll
    for (int i = 0; i < 8; i++) {
        int s = tid + i * 256;
        int row = s >> 4, seg = s & 15;
        cpa16(base + SM_WR1 + row * WSTR + seg * 16, wr1 + row * 128 + seg * 8);
    }
    #pragma unroll
    for (int i = 0; i < 8; i++) {
        int s = tid + i * 256;
        int row = s >> 4, seg = s & 15;
        cpa16(base + SM_WR2 + row * WSTR + seg * 16, wr2 + row * 128 + seg * 8);
    }
    // ---- parameter block (LN gamma/beta, biases, w3/b3) ----
    {
        int t = tid;
        if (t < 32)       cpa16(base + SM_PAR + (PAR_AOBB + t * 4) * 4,         aob_bias + t * 4);
        else if (t < 64)  cpa16(base + SM_PAR + (PAR_OPB1 + (t - 32) * 4) * 4,  op_b1 + (t - 32) * 4);
        else if (t < 96)  cpa16(base + SM_PAR + (PAR_RB1 + (t - 64) * 4) * 4,   r_b1 + (t - 64) * 4);
        else if (t < 128) cpa16(base + SM_PAR + (PAR_RB2 + (t - 96) * 4) * 4,   r_b2 + (t - 96) * 4);
        else if (t < 160) cpa16(base + SM_PAR + (PAR_LN1G + (t - 128) * 4) * 4, ln1_g + (t - 128) * 4);
        else if (t < 192) cpa16(base + SM_PAR + (PAR_LN1B + (t - 160) * 4) * 4, ln1_b + (t - 160) * 4);
        else if (t < 224) cpa16(base + SM_PAR + (PAR_RLNG + (t - 192) * 4) * 4, rln_g + (t - 192) * 4);
        else              cpa16(base + SM_PAR + (PAR_RLNB + (t - 224) * 4) * 4, rln_b + (t - 224) * 4);

        if (t < 32)       cpa16(base + SM_PAR + (PAR_LN2G + t * 4) * 4,          ln2_g + t * 4);
        else if (t < 64)  cpa16(base + SM_PAR + (PAR_LN2B + (t - 32) * 4) * 4,   ln2_b + (t - 32) * 4);
        else if (t < 160) cpa16(base + SM_PAR + (PAR_W3 + (t - 64) * 4) * 4,     w3 + (t - 64) * 4);
        else if (t < 224) cpa16(base + SM_PAR + (PAR_LNFG + (t - 160) * 4) * 4,  lnf_g + (t - 160) * 4);

        if (t < 64)       cpa16(base + SM_PAR + (PAR_LNFB + t * 4) * 4,          lnf_b + t * 4);
        else if (t < 67)  cpa4(base + SM_PAR + (PAR_LNFG + 256 + (t - 64)) * 4,  lnf_g + 256 + (t - 64));
        else if (t < 70)  cpa4(base + SM_PAR + (PAR_LNFB + 256 + (t - 67)) * 4,  lnf_b + 256 + (t - 67));
        else if (t < 73)  cpa4(base + SM_PAR + (PAR_B3 + (t - 70)) * 4,          b3 + (t - 70));
    }
    asm volatile("cp.async.commit_group;");

    // ---- combine flash K-split partials into bf16 act tile (overlaps weight streaming) ----
    {
        int r = tid >> 3, q = tid & 7;
        int grow = bm * 32 + r;
        int h = q >> 1;
        float L = lpart[h * NATOMS + grow] + lpart[NHEAD * NATOMS + h * NATOMS + grow];
        float inv = 1.f / L;
        const float* o0p = opart + grow * 128 + q * 16;
        const float* o1p = o0p + NATOMS * HDIM;
        uint32_t pk[8];
        #pragma unroll
        for (int i = 0; i < 4; i++) {
            float4 a = *(const float4*)&o0p[4 * i];
            float4 b = *(const float4*)&o1p[4 * i];
            pk[2 * i]     = packbf((a.x + b.x) * inv, (a.y + b.y) * inv);
            pk[2 * i + 1] = packbf((a.z + b.z) * inv, (a.w + b.w) * inv);
        }
        uint4* dst = (uint4*)(dsm + SM_ACT + r * ASTR + q * 32);
        dst[0] = *(uint4*)&pk[0];
        dst[1] = *(uint4*)&pk[4];
    }

    asm volatile("cp.async.wait_group 0;");
    __syncthreads();

    const int i7 = lane & 7, sel = lane >> 3;
    const int arow = ((sel & 1) ? 8 : 0) + i7;
    const int acol = (sel >> 1) ? 16 : 0;
    const int vrow = ((sel & 1) ? 8 : 0) + i7;
    const int vcol = (sel >= 2) ? 16 : 0;
    const int htid = tid & 127;
    const int row = htid >> 3, q = htid & 7;
    const int grow = bm * 32 + hb * 16 + row;
    const int sr0 = lane >> 2;
    const int c2 = (lane & 3) * 2;
    const int barid = hb + 1;

    float acc[4][4];
    uint32_t hkeep[8];

    auto do_gemm = [&](int wOff, int ksteps) {
        #pragma unroll
        for (int j = 0; j < 4; j++)
            #pragma unroll
            for (int c = 0; c < 4; c++) acc[j][c] = 0.f;
        for (int ks = 0; ks < ksteps; ks++) {
            #pragma unroll
            for (int kh = 0; kh < 2; kh++) {
                uint32_t qa[4];
                ldsm4(qa[0], qa[1], qa[2], qa[3], aAct + arow * ASTR + ks * 64 + kh * 32 + acol);
                #pragma unroll
                for (int j = 0; j < 2; j++) {
                    uint32_t r0, r1, r2, r3;
                    ldsm4t(r0, r1, r2, r3,
                           base + wOff + (ks * 32 + kh * 16 + vrow) * WSTR + wc * 64 + j * 32 + vcol);
                    mma16816(acc[2 * j],     qa, r0, r1);
                    mma16816(acc[2 * j + 1], qa, r2, r3);
                }
            }
        }
    };

    auto stage = [&](const float* bias) {
        #pragma unroll
        for (int t = 0; t < 4; t++) {
            int col = wc * 32 + t * 8 + c2;
            float a0 = bias[col], a1 = bias[col + 1];
            sSh[sr0 * 136 + col] = acc[t][0] + a0;       sSh[sr0 * 136 + col + 1] = acc[t][1] + a1;
            sSh[(sr0 + 8) * 136 + col] = acc[t][2] + a0; sSh[(sr0 + 8) * 136 + col + 1] = acc[t][3] + a1;
        }
    };

    // ============ stage 0: xa = aob @ wao + b ; comb-LN(259) ============
    do_gemm(SM_WAO, 4);
    stage(par + PAR_AOBB);
    barh(barid);
    {
        int bi = bidx[grow];
        float xv[16], cv[16];
        #pragma unroll
        for (int i = 0; i < 4; i++) {
            float4 f = *(const float4*)&sSh[row * 136 + q * 16 + i * 4];
            xv[4 * i] = f.x; xv[4 * i + 1] = f.y; xv[4 * i + 2] = f.z; xv[4 * i + 3] = f.w;
            float4 c = *(const float4*)&cf[bi * 128 + q * 16 + i * 4];
            cv[4 * i] = c.x; cv[4 * i + 1] = c.y; cv[4 * i + 2] = c.z; cv[4 * i + 3] = c.w;
        }
        float c0 = 0.f, c1 = 0.f, c2v = 0.f;
        float s = 0.f;
        #pragma unroll
        for (int i = 0; i < 16; i++) s += xv[i] + cv[i];
        if (q == 0) {
            c0 = coordp[grow * 3 + 0]; c1 = coordp[grow * 3 + 1]; c2v = coordp[grow * 3 + 2];
            s += c0 + c1 + c2v;
        }
        s += __shfl_xor_sync(0xffffffffu, s, 1);
        s += __shfl_xor_sync(0xffffffffu, s, 2);
        s += __shfl_xor_sync(0xffffffffu, s, 4);
        float mean = s * (1.f / 259.f);
        float sq = 0.f;
        #pragma unroll
        for (int i = 0; i < 16; i++) {
            float d0 = xv[i] - mean, d1 = cv[i] - mean;
            sq += d0 * d0 + d1 * d1;
        }
        if (q == 0) {
            float d0 = c0 - mean, d1 = c1 - mean, d2 = c2v - mean;
            sq += d0 * d0 + d1 * d1 + d2 * d2;
        }
        sq += __shfl_xor_sync(0xffffffffu, sq, 1);
        sq += __shfl_xor_sync(0xffffffffu, sq, 2);
        sq += __shfl_xor_sync(0xffffffffu, sq, 4);
        float inv = rsqrtf(sq * (1.f / 259.f) + 1e-5f);

        uint32_t pk[8];
        #pragma unroll
        for (int i = 0; i < 8; i++) {
            int ca = q * 16 + 2 * i;
            pk[i] = packbf((xv[2 * i] - mean) * inv * par[PAR_LNFG + ca] + par[PAR_LNFB + ca],
                           (xv[2 * i + 1] - mean) * inv * par[PAR_LNFG + ca + 1] + par[PAR_LNFB + ca + 1]);
        }
        uint4* dst = (uint4*)(dsm + SM_ACT + (hb * 16 + row) * ASTR + q * 32);
        dst[0] = *(uint4*)&pk[0]; dst[1] = *(uint4*)&pk[4];
        #pragma unroll
        for (int i = 0; i < 8; i++) {
            int ca = 128 + q * 16 + 2 * i;
            pk[i] = packbf((cv[2 * i] - mean) * inv * par[PAR_LNFG + ca] + par[PAR_LNFB + ca],
                           (cv[2 * i + 1] - mean) * inv * par[PAR_LNFG + ca + 1] + par[PAR_LNFB + ca + 1]);
        }
        dst = (uint4*)(dsm + SM_ACT + (hb * 16 + row) * ASTR + 256 + q * 32);
        dst[0] = *(uint4*)&pk[0]; dst[1] = *(uint4*)&pk[4];
        uint32_t tp0 = 0, tp1 = 0;
        if (q == 0) {
            tp0 = packbf((c0 - mean) * inv * par[PAR_LNFG + 256] + par[PAR_LNFB + 256],
                         (c1 - mean) * inv * par[PAR_LNFG + 257] + par[PAR_LNFB + 257]);
            tp1 = packbf((c2v - mean) * inv * par[PAR_LNFG + 258] + par[PAR_LNFB + 258], 0.f);
        }
        *(uint2*)(dsm + SM_ACT + (hb * 16 + row) * ASTR + 512 + q * 8) = make_uint2(tp0, tp1);
    }
    barh(barid);

    // ============ stage 1: h0 = comb @ wop1 ; LN + SiLU ============
    do_gemm(SM_WOP1, 9);
    stage(par + PAR_OPB1);
    barh(barid);
    {
        float v[16];
        #pragma unroll
        for (int i = 0; i < 4; i++) {
            float4 f = *(const float4*)&sSh[row * 136 + q * 16 + i * 4];
            v[4 * i] = f.x; v[4 * i + 1] = f.y; v[4 * i + 2] = f.z; v[4 * i + 3] = f.w;
        }
        float s = 0.f;
        #pragma unroll
        for (int i = 0; i < 16; i++) s += v[i];
        s += __shfl_xor_sync(0xffffffffu, s, 1);
        s += __shfl_xor_sync(0xffffffffu, s, 2);
        s += __shfl_xor_sync(0xffffffffu, s, 4);
        float mean = s * (1.f / 128.f);
        float sq = 0.f;
        #pragma unroll
        for (int i = 0; i < 16; i++) { float d = v[i] - mean; sq += d * d; }
        sq += __shfl_xor_sync(0xffffffffu, sq, 1);
        sq += __shfl_xor_sync(0xffffffffu, sq, 2);
        sq += __shfl_xor_sync(0xffffffffu, sq, 4);
        float inv = rsqrtf(sq * (1.f / 128.f) + 1e-5f);
        #pragma unroll
        for (int i = 0; i < 8; i++) {
            int ca = q * 16 + 2 * i;
            float y0 = silu_f((v[2 * i] - mean) * inv * par[PAR_LN1G + ca] + par[PAR_LN1B + ca]);
            float y1 = silu_f((v[2 * i + 1] - mean) * inv * par[PAR_LN1G + ca + 1] + par[PAR_LN1B + ca + 1]);
            hkeep[i] = packbf(y0, y1);
        }
        uint4* dst = (uint4*)(dsm + SM_ACT + (hb * 16 + row) * ASTR + q * 32);
        dst[0] = *(uint4*)&hkeep[0]; dst[1] = *(uint4*)&hkeep[4];
    }
    barh(barid);

    // ============ stage 2: t = h1 @ wr1 ; LN + SiLU ============
    do_gemm(SM_WR1, 4);
    stage(par + PAR_RB1);
    barh(barid);
    {
        float v[16];
        #pragma unroll
        for (int i = 0; i < 4; i++) {
            float4 f = *(const float4*)&sSh[row * 136 + q * 16 + i * 4];
            v[4 * i] = f.x; v[4 * i + 1] = f.y; v[4 * i + 2] = f.z; v[4 * i + 3] = f.w;
        }
        float s = 0.f;
        #pragma unroll
        for (int i = 0; i < 16; i++) s += v[i];
        s += __shfl_xor_sync(0xffffffffu, s, 1);
        s += __shfl_xor_sync(0xffffffffu, s, 2);
        s += __shfl_xor_sync(0xffffffffu, s, 4);
        float mean = s * (1.f / 128.f);
        float sq = 0.f;
        #pragma unroll
        for (int i = 0; i < 16; i++) { float d = v[i] - mean; sq += d * d; }
        sq += __shfl_xor_sync(0xffffffffu, sq, 1);
        sq += __shfl_xor_sync(0xffffffffu, sq, 2);
        sq += __shfl_xor_sync(0xffffffffu, sq, 4);
        float inv = rsqrtf(sq * (1.f / 128.f) + 1e-5f);
        uint32_t pk[8];
        #pragma unroll
        for (int i = 0; i < 8; i++) {
            int ca = q * 16 + 2 * i;
            float y0 = silu_f((v[2 * i] - mean) * inv * par[PAR_RLNG + ca] + par[PAR_RLNB + ca]);
            float y1 = silu_f((v[2 * i + 1] - mean) * inv * par[PAR_RLNG + ca + 1] + par[PAR_RLNB + ca + 1]);
            pk[i] = packbf(y0, y1);
        }
        uint4* dst = (uint4*)(dsm + SM_ACT + (hb * 16 + row) * ASTR + q * 32);
        dst[0] = *(uint4*)&pk[0]; dst[1] = *(uint4*)&pk[4];
    }
    barh(barid);

    // ============ stage 3: hfin = t2 @ wr2 + b + h1 ; LN ; proj/tanh/clamp ============
    do_gemm(SM_WR2, 4);
    stage(par + PAR_RB2);
    barh(barid);
    {
        float v[16];
        #pragma unroll
        for (int i = 0; i < 4; i++) {
            float4 f = *(const float4*)&sSh[row * 136 + q * 16 + i * 4];
            v[4 * i] = f.x; v[4 * i + 1] = f.y; v[4 * i + 2] = f.z; v[4 * i + 3] = f.w;
        }
        #pragma unroll
        for (int i = 0; i < 8; i++) {
            __nv_bfloat162 hh = *(__nv_bfloat162*)&hkeep[i];
            v[2 * i]     += __bfloat162float(hh.x);
            v[2 * i + 1] += __bfloat162float(hh.y);
        }
        float s = 0.f;
        #pragma unroll
        for (int i = 0; i < 16; i++) s += v[i];
        s += __shfl_xor_sync(0xffffffffu, s, 1);
        s += __shfl_xor_sync(0xffffffffu, s, 2);
        s += __shfl_xor_sync(0xffffffffu, s, 4);
        float mean = s * (1.f / 128.f);
        float sq = 0.f;
        #pragma unroll
        for (int i = 0; i < 16; i++) { float d = v[i] - mean; sq += d * d; }
        sq += __shfl_xor_sync(0xffffffffu, sq, 1);
        sq += __shfl_xor_sync(0xffffffffu, sq, 2);
        sq += __shfl_xor_sync(0xffffffffu, sq, 4);
        float inv = rsqrtf(sq * (1.f / 128.f) + 1e-5f);

        float p0 = 0.f, p1 = 0.f, p2 = 0.f;
        #pragma unroll
        for (int i = 0; i < 16; i++) {
            int ca = q * 16 + i;
            float y = (v[i] - mean) * inv * par[PAR_LN2G + ca] + par[PAR_LN2B + ca];
            p0 += y * par[PAR_W3 + ca * 3 + 0];
            p1 += y * par[PAR_W3 + ca * 3 + 1];
            p2 += y * par[PAR_W3 + ca * 3 + 2];
        }
        p0 += __shfl_xor_sync(0xffffffffu, p0, 1);
        p0 += __shfl_xor_sync(0xffffffffu, p0, 2);
        p0 += __shfl_xor_sync(0xffffffffu, p0, 4);
        p1 += __shfl_xor_sync(0xffffffffu, p1, 1);
        p1 += __shfl_xor_sync(0xffffffffu, p1, 2);
        p1 += __shfl_xor_sync(0xffffffffu, p1, 4);
        p2 += __shfl_xor_sync(0xffffffffu, p2, 1);
        p2 += __shfl_xor_sync(0xffffffffu, p2, 2);
        p2 += __shfl_xor_sync(0xffffffffu, p2, 4);
        if (q == 0) {
            int bi = bidx[grow];
            float dots[3] = {p0 + par[PAR_B3 + 0], p1 + par[PAR_B3 + 1], p2 + par[PAR_B3 + 2]};
            #pragma unroll
            for (int j = 0; j < 3; j++) {
                float val = coordp[grow * 3 + j] + 0.01f * tanhf(dots[j]);
                fout[grow * 3 + j] = fminf(fmaxf(val, bmin[bi * 3 + j]), bmax[bi * 3 + j]);
            }
        }
    }
}

// ---------------- bf16 flash attention: K-split, Schraudolph exp on FMA/ALU pipe ----------------
#define CSTRIDE 80
#define QBUF    5120
#define KVB     10240
#define NITER   (32 / KSPLIT)

__device__ __forceinline__ void kv_load128(const __nv_bfloat16* __restrict__ Kh,
                                           const __nv_bfloat16* __restrict__ Vh,
                                           int h, int kb, uint32_t sbase, int tid) {
    #pragma unroll
    for (int i = 0; i < 8; i++) {
        int s = tid + i * 128;
        int row = (s >> 2) & 127, seg = s & 3;
        const __nv_bfloat16* src = ((s < 512) ? Kh : Vh)
            + (((h << 12) + (kb << 7) + row) << 5) + seg * 8;
        uint32_t dst = sbase + ((s < 512) ? 0 : KVB) + row * CSTRIDE + seg * 16;
        cpa16(dst, src);
    }
    asm volatile("cp.async.commit_group;");
}

__global__ void __launch_bounds__(128) flashb_k(const __nv_bfloat16* __restrict__ Qh,
                                                const __nv_bfloat16* __restrict__ Kh,
                                                const __nv_bfloat16* __restrict__ Vh,
                                                float* __restrict__ opart,
                                                float* __restrict__ lpart) {
    __shared__ __align__(16) char smem[QBUF + 4 * KVB];
    const int tid = threadIdx.x, lane = tid & 31, warp = tid >> 5;
    const int h = blockIdx.y, qb = blockIdx.x, sp = blockIdx.z;
    const int kb0 = sp * NITER;

    char* Qs = smem;
    uint32_t Qsa = (uint32_t)__cvta_generic_to_shared(Qs);
    uint32_t kva0 = Qsa + QBUF;
    uint32_t kva1 = Qsa + QBUF + 2 * KVB;

    #pragma unroll
    for (int i = 0; i < 2; i++) {
        int s = tid + i * 128;
        int row = s >> 2, seg = s & 3;
        uint4 v = *(const uint4*)(Qh + (((h << 12) + (qb << 6) + row) << 5) + seg * 8);
        *(uint4*)(Qs + row * CSTRIDE + seg * 16) = v;
    }
    kv_load128(Kh, Vh, h, kb0 + 0, kva0, tid);
    kv_load128(Kh, Vh, h, kb0 + 1, kva1, tid);
    __syncthreads();

    uint32_t qa[8];
    {
        int i = lane & 7, sl = lane >> 3;
        int row = warp * 16 + ((sl & 1) ? 8 : 0) + i;
        uint32_t a = Qsa + row * CSTRIDE + ((sl >> 1) ? 16 : 0);
        ldsm4(qa[0], qa[1], qa[2], qa[3], a);
        ldsm4(qa[4], qa[5], qa[6], qa[7], a + 32);
    }

    float l0 = 0.f, l1 = 0.f;
    float o[4][4];
    #pragma unroll
    for (int j = 0; j < 4; j++)
        #pragma unroll
        for (int c = 0; c < 4; c++) o[j][c] = 0.f;

    const int i7 = lane & 7, sel = lane >> 3;
    const uint32_t krow = ((sel >= 2) ? 8 : 0) + i7;
    const uint32_t kcol = (sel & 1) ? 16 : 0;
    const uint32_t vrow = ((sel & 1) ? 8 : 0) + i7;
    const uint32_t vcol = (sel >= 2) ? 16 : 0;

    for (int kb = 0; kb < NITER; kb++) {
        if (kb < NITER - 1) asm volatile("cp.async.wait_group 1;");
        else                asm volatile("cp.async.wait_group 0;");
        __syncthreads();
        uint32_t Kbase = (kb & 1) ? kva1 : kva0;
        uint32_t Vbase = Kbase + KVB;

        float s[16][4];
        #pragma unroll
        for (int j = 0; j < 16; j++)
            #pragma unroll
            for (int c = 0; c < 4; c++) s[j][c] = 0.f;

        #pragma unroll
        for (int jp = 0; jp < 8; jp++) {
            uint32_t a = Kbase + (jp * 16 + krow) * CSTRIDE + kcol;
            uint32_t b0, b1, b2, b3, c0, c1, c2, c3;
            ldsm4(b0, b1, b2, b3, a);
            ldsm4(c0, c1, c2, c3, a + 32);
            mma16816(s[2 * jp],     qa,     b0, b1);
            mma16816(s[2 * jp],     qa + 4, c0, c1);
            mma16816(s[2 * jp + 1], qa,     b2, b3);
            mma16816(s[2 * jp + 1], qa + 4, c2, c3);
        }

        // exp2 via Schraudolph (FMA + F2I), bf16 pack via PRMT — zero MUFU
        #pragma unroll
        for (int ks = 0; ks < 8; ks++) {
            uint32_t i00 = schexp(s[2 * ks][0]),     i01 = schexp(s[2 * ks][1]);
            uint32_t i02 = schexp(s[2 * ks][2]),     i03 = schexp(s[2 * ks][3]);
            uint32_t i10 = schexp(s[2 * ks + 1][0]), i11 = schexp(s[2 * ks + 1][1]);
            uint32_t i12 = schexp(s[2 * ks + 1][2]), i13 = schexp(s[2 * ks + 1][3]);
            l0 += (__int_as_float(i00) + __int_as_float(i01))
                + (__int_as_float(i10) + __int_as_float(i11));
            l1 += (__int_as_float(i02) + __int_as_float(i03))
                + (__int_as_float(i12) + __int_as_float(i13));
            uint32_t pa[4];
            pa[0] = prmt16(i00, i01);
            pa[1] = prmt16(i02, i03);
            pa[2] = prmt16(i10, i11);
            pa[3] = prmt16(i12, i13);
            uint32_t a = Vbase + (ks * 16 + vrow) * CSTRIDE + vcol;
            uint32_t v0, v1, v2, v3, w0, w1, w2, w3;
            ldsm4t(v0, v1, v2, v3, a);
            ldsm4t(w0, w1, w2, w3, a + 32);
            mma16816(o[0], pa, v0, v1);
            mma16816(o[1], pa, v2, v3);
            mma16816(o[2], pa, w0, w1);
            mma16816(o[3], pa, w2, w3);
        }

        __syncthreads();
        if (kb < NITER - 2) kv_load128(Kh, Vh, h, kb0 + kb + 2, (kb & 1) ? kva1 : kva0, tid);
    }

    l0 += __shfl_xor_sync(0xffffffffu, l0, 1);
    l0 += __shfl_xor_sync(0xffffffffu, l0, 2);
    l1 += __shfl_xor_sync(0xffffffffu, l1, 1);
    l1 += __shfl_xor_sync(0xffffffffu, l1, 2);
    int g = lane >> 2, l2 = (lane & 3) * 2;
    int row0 = (qb << 6) + warp * 16 + g;
    float* op = opart + sp * NATOMS * HDIM;
    #pragma unroll
    for (int j = 0; j < 4; j++) {
        int col = (h << 5) + j * 8 + l2;
        *(float2*)&op[row0 * HDIM + col]       = make_float2(o[j][0], o[j][1]);
        *(float2*)&op[(row0 + 8) * HDIM + col] = make_float2(o[j][2], o[j][3]);
    }
    if ((lane & 3) == 0) {
        lpart[sp * NHEAD * NATOMS + h * NATOMS + row0]     = l0;
        lpart[sp * NHEAD * NATOMS + h * NATOMS + row0 + 8] = l1;
    }
}

// ---------------- host ----------------
extern "C" void kernel_launch(void* const* d_in, const int* in_sizes, int n_in,
                              void* d_out, int out_size) {
    const int*   num_atoms  = (const int*)d_in[0];
    const int*   elems      = (const int*)d_in[1];
    const float* cell       = (const float*)d_in[2];
    const float* coord      = (const float*)d_in[3];
    const float* emb        = (const float*)d_in[4];
    const float* ln_in_g    = (const float*)d_in[5];
    const float* ln_in_b    = (const float*)d_in[6];
    const float* attn_in_w  = (const float*)d_in[7];
    const float* attn_in_b  = (const float*)d_in[8];
    const float* attn_out_w = (const float*)d_in[9];
    const float* attn_out_b = (const float*)d_in[10];
    const float* ce_w1      = (const float*)d_in[11];
    const float* ce_b1      = (const float*)d_in[12];
    const float* ce_w2      = (const float*)d_in[13];
    const float* ce_b2      = (const float*)d_in[14];
    const float* ln_feat_g  = (const float*)d_in[15];
    const float* ln_feat_b  = (const float*)d_in[16];
    const float* op_w1      = (const float*)d_in[17];
    const float* op_b1      = (const float*)d_in[18];
    const float* op_ln1_g   = (const float*)d_in[19];
    const float* op_ln1_b   = (const float*)d_in[20];
    const float* res_w1     = (const float*)d_in[21];
    const float* res_b1     = (const float*)d_in[22];
    const float* res_ln_g   = (const float*)d_in[23];
    const float* res_ln_b   = (const float*)d_in[24];
    const float* res_w2     = (const float*)d_in[25];
    const float* res_b2     = (const float*)d_in[26];
    const float* op_ln2_g   = (const float*)d_in[27];
    const float* op_ln2_b   = (const float*)d_in[28];
    const float* op_w3      = (const float*)d_in[29];
    const float* op_b3      = (const float*)d_in[30];
    float* out = (float*)d_out;

    float* S = nullptr;
    cudaGetSymbolAddress((void**)&S, g_scratch);
    int* bidx = nullptr;
    cudaGetSymbolAddress((void**)&bidx, g_bidx);

    __nv_bfloat16* P = (__nv_bfloat16*)S;
    __nv_bfloat16* xb    = P; P += NATOMS * HDIM;
    __nv_bfloat16* Qh    = P; P += NATOMS * HDIM;
    __nv_bfloat16* Kh    = P; P += NATOMS * HDIM;
    __nv_bfloat16* Vh    = P; P += NATOMS * HDIM;
    __nv_bfloat16* wqkv  = P; P += 128 * 384;
    __nv_bfloat16* wao   = P; P += 128 * 128;
    __nv_bfloat16* wop1  = P; P += FPAD * 128;
    __nv_bfloat16* wr1   = P; P += 128 * 128;
    __nv_bfloat16* wr2   = P; P += 128 * 128;
    float* F = (float*)P;
    float* opart = F; F += KSPLIT * NATOMS * HDIM;
    float* lpart = F; F += KSPLIT * NHEAD * NATOMS;
    float* cf    = F; F += BATCH * HDIM;
    float* bmin  = F; F += BATCH * 3;
    float* bmax  = F; F += BATCH * 3;

    static bool attr_set = false;
    if (!attr_set) {
        cudaFuncSetAttribute(tail_k, cudaFuncAttributeMaxDynamicSharedMemorySize, SMEM_TAIL);
        attr_set = true;
    }

    setup_k<<<1049, 256>>>(elems, emb, ln_in_g, ln_in_b, xb,
                           attn_in_w, attn_out_w, op_w1, res_w1, res_w2,
                           wqkv, wao, wop1, wr1, wr2,
                           cell, ce_w1, ce_b1, ce_w2, ce_b2, cf,
                           num_atoms, bmin, bmax);

    qkv_k<<<dim3(3, 128), 128>>>(xb, wqkv, attn_in_b, Qh, Kh, Vh);

    flashb_k<<<dim3(64, NHEAD, KSPLIT), 128>>>(Qh, Kh, Vh, opart, lpart);

    tail_k<<<128, 256, SMEM_TAIL>>>(opart, lpart,
        wao, attn_out_b, ln_feat_g, ln_feat_b, cf, coord, bidx,
        wop1, op_b1, op_ln1_g, op_ln1_b,
        wr1, res_b1, res_ln_g, res_ln_b,
        wr2, res_b2, op_ln2_g, op_ln2_b,
        op_w3, op_b3, bmin, bmax, out);
}

// round 10
// speedup vs baseline: 7.4333x; 1.0009x over previous
#include <cuda_runtime.h>
#include <cuda_bf16.h>
#include <math.h>
#include <stdint.h>

#define NATOMS 4096
#define HDIM   128
#define BATCH  128
#define NHEAD  4
#define DHEAD  32
#define H3     384
#define FPAD   288
#define KSPLIT 4

// -------- scratch (no allocations allowed) --------
__device__ float g_scratch[8300000];
__device__ int   g_bidx[NATOMS];

// ---------------- helpers ----------------
__device__ __forceinline__ float silu_f(float x) {
    return x / (1.f + __expf(-x));
}
__device__ __forceinline__ void ldsm4(uint32_t& r0, uint32_t& r1, uint32_t& r2, uint32_t& r3, uint32_t addr) {
    asm volatile("ldmatrix.sync.aligned.m8n8.x4.shared.b16 {%0,%1,%2,%3}, [%4];"
                 : "=r"(r0), "=r"(r1), "=r"(r2), "=r"(r3) : "r"(addr));
}
__device__ __forceinline__ void ldsm4t(uint32_t& r0, uint32_t& r1, uint32_t& r2, uint32_t& r3, uint32_t addr) {
    asm volatile("ldmatrix.sync.aligned.m8n8.x4.trans.shared.b16 {%0,%1,%2,%3}, [%4];"
                 : "=r"(r0), "=r"(r1), "=r"(r2), "=r"(r3) : "r"(addr));
}
__device__ __forceinline__ void mma16816(float* d, const uint32_t* a, uint32_t b0, uint32_t b1) {
    asm volatile("mma.sync.aligned.m16n8k16.row.col.f32.bf16.bf16.f32 "
                 "{%0,%1,%2,%3}, {%4,%5,%6,%7}, {%8,%9}, {%0,%1,%2,%3};"
                 : "+f"(d[0]), "+f"(d[1]), "+f"(d[2]), "+f"(d[3])
                 : "r"(a[0]), "r"(a[1]), "r"(a[2]), "r"(a[3]), "r"(b0), "r"(b1));
}
__device__ __forceinline__ uint32_t packbf(float lo, float hi) {
    uint32_t r;
    asm volatile("cvt.rn.bf16x2.f32 %0, %1, %2;" : "=r"(r) : "f"(hi), "f"(lo));
    return r;
}
__device__ __forceinline__ void cpa16(uint32_t dst, const void* src) {
    asm volatile("cp.async.ca.shared.global [%0], [%1], 16;" :: "r"(dst), "l"(src));
}
__device__ __forceinline__ void cpa4(uint32_t dst, const void* src) {
    asm volatile("cp.async.ca.shared.global [%0], [%1], 4;" :: "r"(dst), "l"(src));
}
__device__ __forceinline__ void barh(int id) {
    asm volatile("bar.sync %0, 128;" :: "r"(id) : "memory");
}
// Schraudolph exp2: exp2(x) ~ bits (int)(x*2^23 + C)
__device__ __forceinline__ uint32_t schexp(float x) {
    int i;
    asm("cvt.rni.s32.f32 %0, %1;" : "=r"(i) : "f"(fmaf(x, 8388608.f, 1064876800.f)));
    return (uint32_t)i;
}
__device__ __forceinline__ uint32_t prmt16(uint32_t a, uint32_t b) {
    uint32_t r;
    asm("prmt.b32 %0,%1,%2,0x7632;" : "=r"(r) : "r"(a), "r"(b));
    return r;
}

// ================= fused setup kernel =================
__global__ void __launch_bounds__(256) setup_k(
    const int* __restrict__ elems, const float* __restrict__ emb,
    const float* __restrict__ ln_in_g, const float* __restrict__ ln_in_b,
    __nv_bfloat16* __restrict__ xo,
    const float* __restrict__ aiw, const float* __restrict__ aow,
    const float* __restrict__ opw1, const float* __restrict__ rw1,
    const float* __restrict__ rw2,
    __nv_bfloat16* __restrict__ wqkv, __nv_bfloat16* __restrict__ wao,
    __nv_bfloat16* __restrict__ wop1, __nv_bfloat16* __restrict__ wr1,
    __nv_bfloat16* __restrict__ wr2,
    const float* __restrict__ cell,
    const float* __restrict__ cw1, const float* __restrict__ cb1,
    const float* __restrict__ cw2, const float* __restrict__ cb2,
    float* __restrict__ cf,
    const int* __restrict__ num_atoms,
    float* __restrict__ bmin, float* __restrict__ bmax)
{
    const int b = blockIdx.x, tid = threadIdx.x;

    if (b < 512) {
        int warp = tid >> 5, lane = tid & 31;
        int r = b * 8 + warp;
        int e = elems[r];
        float4 v = *(const float4*)&emb[e * HDIM + lane * 4];
        float s = v.x + v.y + v.z + v.w;
        #pragma unroll
        for (int off = 16; off > 0; off >>= 1) s += __shfl_xor_sync(0xffffffffu, s, off);
        float mean = s * (1.f / 128.f);
        float dx = v.x - mean, dy = v.y - mean, dz = v.z - mean, dw = v.w - mean;
        float sq = dx * dx + dy * dy + dz * dz + dw * dw;
        #pragma unroll
        for (int off = 16; off > 0; off >>= 1) sq += __shfl_xor_sync(0xffffffffu, sq, off);
        float inv = rsqrtf(sq * (1.f / 128.f) + 1e-5f);
        float4 gg = *(const float4*)&ln_in_g[lane * 4];
        float4 bb = *(const float4*)&ln_in_b[lane * 4];
        uint32_t p0 = packbf(dx * inv * gg.x + bb.x, dy * inv * gg.y + bb.y);
        uint32_t p1 = packbf(dz * inv * gg.z + bb.z, dw * inv * gg.w + bb.w);
        *(uint2*)(xo + r * HDIM + lane * 4) = make_uint2(p0, p1);
        return;
    }

    if (b < 1040) {
        int i = (b - 512) * 256 + tid;
        if (i < 49152) wqkv[i] = __float2bfloat16(aiw[i]);
        else if (i < 65536) { int j = i - 49152; wao[j] = __float2bfloat16(aow[j]); }
        else if (i < 102400) {
            int j = i - 65536; int r = j >> 7, c = j & 127;
            wop1[j] = __float2bfloat16(r < 259 ? opw1[r * 128 + c] : 0.f);
        }
        else if (i < 118784) { int j = i - 102400; wr1[j] = __float2bfloat16(rw1[j]); }
        else { int j = i - 118784; wr2[j] = __float2bfloat16(rw2[j]); }
        return;
    }

    if (b < 1048) {
        __shared__ float t1s[16][128];
        int r0 = (b - 1040) * 16;
        #pragma unroll
        for (int i = 0; i < 8; i++) {
            int idx = tid + i * 256;
            int rr = idx >> 7, k = idx & 127;
            int r = r0 + rr;
            float u = cell[r * 3 + 0] * cw1[k] + cell[r * 3 + 1] * cw1[128 + k]
                    + cell[r * 3 + 2] * cw1[256 + k] + cb1[k];
            t1s[rr][k] = silu_f(u);
        }
        __syncthreads();
        int t = tid & 127, half = tid >> 7;
        float acc[8];
        #pragma unroll
        for (int j = 0; j < 8; j++) acc[j] = cb2[t];
        #pragma unroll 4
        for (int k = 0; k < 128; k++) {
            float w = cw2[k * 128 + t];
            #pragma unroll
            for (int j = 0; j < 8; j++) acc[j] += t1s[half * 8 + j][k] * w;
        }
        #pragma unroll
        for (int j = 0; j < 8; j++) cf[(r0 + half * 8 + j) * 128 + t] = acc[j];
        return;
    }

    __shared__ int starts[BATCH + 1];
    if (tid == 0) {
        int acc = 0;
        for (int i = 0; i < BATCH; i++) { starts[i] = acc; acc += num_atoms[i]; }
        starts[BATCH] = acc;
    }
    __syncthreads();
    for (int i = tid; i < NATOMS; i += 256) g_bidx[i] = BATCH - 1;
    __syncthreads();
    if (tid < BATCH) {
        int s = starts[tid], e = starts[tid + 1];
        if (s > NATOMS) s = NATOMS;
        if (e > NATOMS) e = NATOMS;
        for (int i = s; i < e; i++) g_bidx[i] = tid;
        #pragma unroll
        for (int i = 0; i < 3; i++) {
            float a = cell[(3 * tid + i) * 3 + 0];
            float c1 = cell[(3 * tid + i) * 3 + 1];
            float c = cell[(3 * tid + i) * 3 + 2];
            bmin[tid * 3 + i] = fminf(a, fminf(c1, c)) + 1e-6f;
            bmax[tid * 3 + i] = fmaxf(a, fmaxf(c1, c)) - 1e-6f;
        }
    }
}

// ================= QKV GEMM (BM=32, BN=128, BK=32, double-buffered) =================
__global__ void __launch_bounds__(128) qkv_k(
    const __nv_bfloat16* __restrict__ A, const __nv_bfloat16* __restrict__ W,
    const float* __restrict__ bias,
    __nv_bfloat16* __restrict__ Qh, __nv_bfloat16* __restrict__ Kh,
    __nv_bfloat16* __restrict__ Vh)
{
    __shared__ __align__(16) char sA[2 * 32 * 80];
    __shared__ __align__(16) char sW[2 * 32 * 272];
    const int tid = threadIdx.x, lane = tid & 31, warp = tid >> 5;
    const int wr = warp & 1, wc = warp >> 1;
    const int bm = blockIdx.y, nb = blockIdx.x;
    uint32_t aBase = (uint32_t)__cvta_generic_to_shared(sA);
    uint32_t wBase = (uint32_t)__cvta_generic_to_shared(sW);

    #pragma unroll
    for (int p = 0; p < 2; p++) {
        int row = tid >> 2, seg = tid & 3;
        cpa16(aBase + p * 2560 + row * 80 + seg * 16,
              A + (bm * 32 + row) * 128 + p * 32 + seg * 8);
        #pragma unroll
        for (int i = 0; i < 4; i++) {
            int s = tid + i * 128;
            int wrow = s >> 4, wseg = s & 15;
            cpa16(wBase + p * 8704 + wrow * 272 + wseg * 16,
                  W + (p * 32 + wrow) * H3 + nb * 128 + wseg * 8);
        }
        asm volatile("cp.async.commit_group;");
    }

    float acc[8][4];
    #pragma unroll
    for (int j = 0; j < 8; j++)
        #pragma unroll
        for (int c = 0; c < 4; c++) acc[j][c] = 0.f;

    const int i7 = lane & 7, sel = lane >> 3;
    const int arow = wr * 16 + ((sel & 1) ? 8 : 0) + i7;
    const int acol = (sel >> 1) ? 16 : 0;
    const int vrow = ((sel & 1) ? 8 : 0) + i7;
    const int vcol = (sel >= 2) ? 16 : 0;

    for (int ks = 0; ks < 4; ks++) {
        if (ks < 3) asm volatile("cp.async.wait_group 1;");
        else        asm volatile("cp.async.wait_group 0;");
        __syncthreads();
        uint32_t Ab = aBase + (ks & 1) * 2560;
        uint32_t Wb = wBase + (ks & 1) * 8704;
        #pragma unroll
        for (int kh = 0; kh < 2; kh++) {
            uint32_t qa[4];
            ldsm4(qa[0], qa[1], qa[2], qa[3], Ab + arow * 80 + acol + kh * 32);
            #pragma unroll
            for (int j = 0; j < 4; j++) {
                uint32_t r0, r1, r2, r3;
                ldsm4t(r0, r1, r2, r3, Wb + (kh * 16 + vrow) * 272 + wc * 128 + j * 32 + vcol);
                mma16816(acc[2 * j],     qa, r0, r1);
                mma16816(acc[2 * j + 1], qa, r2, r3);
            }
        }
        __syncthreads();
        if (ks + 2 < 4) {
            int p = ks + 2, buf = ks & 1;
            int row = tid >> 2, seg = tid & 3;
            cpa16(aBase + buf * 2560 + row * 80 + seg * 16,
                  A + (bm * 32 + row) * 128 + p * 32 + seg * 8);
            #pragma unroll
            for (int i = 0; i < 4; i++) {
                int s = tid + i * 128;
                int wrow = s >> 4, wseg = s & 15;
                cpa16(wBase + buf * 8704 + wrow * 272 + wseg * 16,
                      W + (p * 32 + wrow) * H3 + nb * 128 + wseg * 8);
            }
            asm volatile("cp.async.commit_group;");
        }
    }

    const int g = lane >> 2, c2 = (lane & 3) * 2;
    int r0 = bm * 32 + wr * 16 + g;
    __nv_bfloat16* outp = (nb == 0) ? Qh : (nb == 1) ? Kh : Vh;
    float sc = (nb == 0) ? (0.17677669529663687f * 1.4426950408889634f) : 1.f;
    #pragma unroll
    for (int t = 0; t < 8; t++) {
        int col = wc * 64 + t * 8 + c2;
        float b0v = bias[nb * 128 + col], b1v = bias[nb * 128 + col + 1];
        int h = col >> 5, d = col & 31;
        *(uint32_t*)(outp + (((h << 12) + r0) << 5) + d) =
            packbf((acc[t][0] + b0v) * sc, (acc[t][1] + b1v) * sc);
        *(uint32_t*)(outp + (((h << 12) + r0 + 8) << 5) + d) =
            packbf((acc[t][2] + b0v) * sc, (acc[t][3] + b1v) * sc);
    }
}

// ================= fused tail: combine + 4 GEMMs + LNs + final, params in smem ==========
#define WSTR 272
#define ASTR 592
#define SM_WAO   0
#define SM_WOP1  (128 * WSTR)
#define SM_WR1   (SM_WOP1 + 288 * WSTR)
#define SM_WR2   (SM_WR1 + 128 * WSTR)
#define SM_ACT   (SM_WR2 + 128 * WSTR)
#define SM_STAGE (SM_ACT + 32 * ASTR)
#define SM_PAR   (SM_STAGE + 32 * 136 * 4)
#define PAR_AOBB 0
#define PAR_OPB1 128
#define PAR_RB1  256
#define PAR_RB2  384
#define PAR_LNFG 512
#define PAR_LNFB 772
#define PAR_LN1G 1032
#define PAR_LN1B 1160
#define PAR_RLNG 1288
#define PAR_RLNB 1416
#define PAR_LN2G 1544
#define PAR_LN2B 1672
#define PAR_W3   1800
#define PAR_B3   2184
#define SMEM_TAIL (SM_PAR + 2192 * 4)

__global__ void __launch_bounds__(256) tail_k(
    const float* __restrict__ opart, const float* __restrict__ lpart,
    const __nv_bfloat16* __restrict__ wao, const float* __restrict__ aob_bias,
    const float* __restrict__ lnf_g, const float* __restrict__ lnf_b,
    const float* __restrict__ cf, const float* __restrict__ coordp,
    const int* __restrict__ bidx,
    const __nv_bfloat16* __restrict__ wop1, const float* __restrict__ op_b1,
    const float* __restrict__ ln1_g, const float* __restrict__ ln1_b,
    const __nv_bfloat16* __restrict__ wr1, const float* __restrict__ r_b1,
    const float* __restrict__ rln_g, const float* __restrict__ rln_b,
    const __nv_bfloat16* __restrict__ wr2, const float* __restrict__ r_b2,
    const float* __restrict__ ln2_g, const float* __restrict__ ln2_b,
    const float* __restrict__ w3, const float* __restrict__ b3,
    const float* __restrict__ bmin, const float* __restrict__ bmax,
    float* __restrict__ fout)
{
    extern __shared__ __align__(16) char dsm[];
    const int tid = threadIdx.x, lane = tid & 31, warp = tid >> 5;
    const int hb = warp >> 2;
    const int wc = warp & 3;
    const int bm = blockIdx.x;
    uint32_t base = (uint32_t)__cvta_generic_to_shared(dsm);
    uint32_t aAct = base + SM_ACT + hb * 16 * ASTR;
    float* sSh = (float*)(dsm + SM_STAGE) + hb * 16 * 136;
    const float* par = (const float*)(dsm + SM_PAR);

    #pragma unroll
    for (int i = 0; i < 8; i++) {
        int s = tid + i * 256;
        int row = s >> 4, seg = s & 15;
        cpa16(base + SM_WAO + row * WSTR + seg * 16, wao + row * 128 + seg * 8);
    }
    #pragma unroll
    for (int i = 0; i < 18; i++) {
        int s = tid + i * 256;
        int row = s >> 4, seg = s & 15;
        cpa16(base + SM_WOP1 + row * WSTR + seg * 16, wop1 + row * 128 + seg * 8);
    }
    #pragma unroll
    for (int i = 0; i < 8; i++) {
        int s = tid + i * 256;
        int row = s >> 4, seg = s & 15;
        cpa16(base + SM_WR1 + row * WSTR + seg * 16, wr1 + row * 128 + seg * 8);
    }
    #pragma unroll
    for (int i = 0; i < 8; i++) {
        int s = tid + i * 256;
        int row = s >> 4, seg = s & 15;
        cpa16(base + SM_WR2 + row * WSTR + seg * 16, wr2 + row * 128 + seg * 8);
    }
    {
        int t = tid;
        if (t < 32)       cpa16(base + SM_PAR + (PAR_AOBB + t * 4) * 4,         aob_bias + t * 4);
        else if (t < 64)  cpa16(base + SM_PAR + (PAR_OPB1 + (t - 32) * 4) * 4,  op_b1 + (t - 32) * 4);
        else if (t < 96)  cpa16(base + SM_PAR + (PAR_RB1 + (t - 64) * 4) * 4,   r_b1 + (t - 64) * 4);
        else if (t < 128) cpa16(base + SM_PAR + (PAR_RB2 + (t - 96) * 4) * 4,   r_b2 + (t - 96) * 4);
        else if (t < 160) cpa16(base + SM_PAR + (PAR_LN1G + (t - 128) * 4) * 4, ln1_g + (t - 128) * 4);
        else if (t < 192) cpa16(base + SM_PAR + (PAR_LN1B + (t - 160) * 4) * 4, ln1_b + (t - 160) * 4);
        else if (t < 224) cpa16(base + SM_PAR + (PAR_RLNG + (t - 192) * 4) * 4, rln_g + (t - 192) * 4);
        else              cpa16(base + SM_PAR + (PAR_RLNB + (t - 224) * 4) * 4, rln_b + (t - 224) * 4);

        if (t < 32)       cpa16(base + SM_PAR + (PAR_LN2G + t * 4) * 4,          ln2_g + t * 4);
        else if (t < 64)  cpa16(base + SM_PAR + (PAR_LN2B + (t - 32) * 4) * 4,   ln2_b + (t - 32) * 4);
        else if (t < 160) cpa16(base + SM_PAR + (PAR_W3 + (t - 64) * 4) * 4,     w3 + (t - 64) * 4);
        else if (t < 224) cpa16(base + SM_PAR + (PAR_LNFG + (t - 160) * 4) * 4,  lnf_g + (t - 160) * 4);

        if (t < 64)       cpa16(base + SM_PAR + (PAR_LNFB + t * 4) * 4,          lnf_b + t * 4);
        else if (t < 67)  cpa4(base + SM_PAR + (PAR_LNFG + 256 + (t - 64)) * 4,  lnf_g + 256 + (t - 64));
        else if (t < 70)  cpa4(base + SM_PAR + (PAR_LNFB + 256 + (t - 67)) * 4,  lnf_b + 256 + (t - 67));
        else if (t < 73)  cpa4(base + SM_PAR + (PAR_B3 + (t - 70)) * 4,          b3 + (t - 70));
    }
    asm volatile("cp.async.commit_group;");

    // ---- combine flash K-split partials (4 slices) into bf16 act tile ----
    {
        int r = tid >> 3, q = tid & 7;
        int grow = bm * 32 + r;
        int h = q >> 1;
        float L = 0.f;
        #pragma unroll
        for (int sp = 0; sp < KSPLIT; sp++)
            L += lpart[sp * NHEAD * NATOMS + h * NATOMS + grow];
        float inv = 1.f / L;
        const float* o0p = opart + grow * 128 + q * 16;
        uint32_t pk[8];
        #pragma unroll
        for (int i = 0; i < 4; i++) {
            float4 a = *(const float4*)&o0p[4 * i];
            #pragma unroll
            for (int sp = 1; sp < KSPLIT; sp++) {
                float4 b = *(const float4*)&o0p[sp * NATOMS * HDIM + 4 * i];
                a.x += b.x; a.y += b.y; a.z += b.z; a.w += b.w;
            }
            pk[2 * i]     = packbf(a.x * inv, a.y * inv);
            pk[2 * i + 1] = packbf(a.z * inv, a.w * inv);
        }
        uint4* dst = (uint4*)(dsm + SM_ACT + r * ASTR + q * 32);
        dst[0] = *(uint4*)&pk[0];
        dst[1] = *(uint4*)&pk[4];
    }

    asm volatile("cp.async.wait_group 0;");
    __syncthreads();

    const int i7 = lane & 7, sel = lane >> 3;
    const int arow = ((sel & 1) ? 8 : 0) + i7;
    const int acol = (sel >> 1) ? 16 : 0;
    const int vrow = ((sel & 1) ? 8 : 0) + i7;
    const int vcol = (sel >= 2) ? 16 : 0;
    const int htid = tid & 127;
    const int row = htid >> 3, q = htid & 7;
    const int grow = bm * 32 + hb * 16 + row;
    const int sr0 = lane >> 2;
    const int c2 = (lane & 3) * 2;
    const int barid = hb + 1;

    float acc[4][4];
    uint32_t hkeep[8];

    auto do_gemm = [&](int wOff, int ksteps) {
        #pragma unroll
        for (int j = 0; j < 4; j++)
            #pragma unroll
            for (int c = 0; c < 4; c++) acc[j][c] = 0.f;
        for (int ks = 0; ks < ksteps; ks++) {
            #pragma unroll
            for (int kh = 0; kh < 2; kh++) {
                uint32_t qa[4];
                ldsm4(qa[0], qa[1], qa[2], qa[3], aAct + arow * ASTR + ks * 64 + kh * 32 + acol);
                #pragma unroll
                for (int j = 0; j < 2; j++) {
                    uint32_t r0, r1, r2, r3;
                    ldsm4t(r0, r1, r2, r3,
                           base + wOff + (ks * 32 + kh * 16 + vrow) * WSTR + wc * 64 + j * 32 + vcol);
                    mma16816(acc[2 * j],     qa, r0, r1);
                    mma16816(acc[2 * j + 1], qa, r2, r3);
                }
            }
        }
    };

    auto stage = [&](const float* bias) {
        #pragma unroll
        for (int t = 0; t < 4; t++) {
            int col = wc * 32 + t * 8 + c2;
            float a0 = bias[col], a1 = bias[col + 1];
            sSh[sr0 * 136 + col] = acc[t][0] + a0;       sSh[sr0 * 136 + col + 1] = acc[t][1] + a1;
            sSh[(sr0 + 8) * 136 + col] = acc[t][2] + a0; sSh[(sr0 + 8) * 136 + col + 1] = acc[t][3] + a1;
        }
    };

    // ============ stage 0 ============
    do_gemm(SM_WAO, 4);
    stage(par + PAR_AOBB);
    barh(barid);
    {
        int bi = bidx[grow];
        float xv[16], cv[16];
        #pragma unroll
        for (int i = 0; i < 4; i++) {
            float4 f = *(const float4*)&sSh[row * 136 + q * 16 + i * 4];
            xv[4 * i] = f.x; xv[4 * i + 1] = f.y; xv[4 * i + 2] = f.z; xv[4 * i + 3] = f.w;
            float4 c = *(const float4*)&cf[bi * 128 + q * 16 + i * 4];
            cv[4 * i] = c.x; cv[4 * i + 1] = c.y; cv[4 * i + 2] = c.z; cv[4 * i + 3] = c.w;
        }
        float c0 = 0.f, c1 = 0.f, c2v = 0.f;
        float s = 0.f;
        #pragma unroll
        for (int i = 0; i < 16; i++) s += xv[i] + cv[i];
        if (q == 0) {
            c0 = coordp[grow * 3 + 0]; c1 = coordp[grow * 3 + 1]; c2v = coordp[grow * 3 + 2];
            s += c0 + c1 + c2v;
        }
        s += __shfl_xor_sync(0xffffffffu, s, 1);
        s += __shfl_xor_sync(0xffffffffu, s, 2);
        s += __shfl_xor_sync(0xffffffffu, s, 4);
        float mean = s * (1.f / 259.f);
        float sq = 0.f;
        #pragma unroll
        for (int i = 0; i < 16; i++) {
            float d0 = xv[i] - mean, d1 = cv[i] - mean;
            sq += d0 * d0 + d1 * d1;
        }
        if (q == 0) {
            float d0 = c0 - mean, d1 = c1 - mean, d2 = c2v - mean;
            sq += d0 * d0 + d1 * d1 + d2 * d2;
        }
        sq += __shfl_xor_sync(0xffffffffu, sq, 1);
        sq += __shfl_xor_sync(0xffffffffu, sq, 2);
        sq += __shfl_xor_sync(0xffffffffu, sq, 4);
        float inv = rsqrtf(sq * (1.f / 259.f) + 1e-5f);

        uint32_t pk[8];
        #pragma unroll
        for (int i = 0; i < 8; i++) {
            int ca = q * 16 + 2 * i;
            pk[i] = packbf((xv[2 * i] - mean) * inv * par[PAR_LNFG + ca] + par[PAR_LNFB + ca],
                           (xv[2 * i + 1] - mean) * inv * par[PAR_LNFG + ca + 1] + par[PAR_LNFB + ca + 1]);
        }
        uint4* dst = (uint4*)(dsm + SM_ACT + (hb * 16 + row) * ASTR + q * 32);
        dst[0] = *(uint4*)&pk[0]; dst[1] = *(uint4*)&pk[4];
        #pragma unroll
        for (int i = 0; i < 8; i++) {
            int ca = 128 + q * 16 + 2 * i;
            pk[i] = packbf((cv[2 * i] - mean) * inv * par[PAR_LNFG + ca] + par[PAR_LNFB + ca],
                           (cv[2 * i + 1] - mean) * inv * par[PAR_LNFG + ca + 1] + par[PAR_LNFB + ca + 1]);
        }
        dst = (uint4*)(dsm + SM_ACT + (hb * 16 + row) * ASTR + 256 + q * 32);
        dst[0] = *(uint4*)&pk[0]; dst[1] = *(uint4*)&pk[4];
        uint32_t tp0 = 0, tp1 = 0;
        if (q == 0) {
            tp0 = packbf((c0 - mean) * inv * par[PAR_LNFG + 256] + par[PAR_LNFB + 256],
                         (c1 - mean) * inv * par[PAR_LNFG + 257] + par[PAR_LNFB + 257]);
            tp1 = packbf((c2v - mean) * inv * par[PAR_LNFG + 258] + par[PAR_LNFB + 258], 0.f);
        }
        *(uint2*)(dsm + SM_ACT + (hb * 16 + row) * ASTR + 512 + q * 8) = make_uint2(tp0, tp1);
    }
    barh(barid);

    // ============ stage 1 ============
    do_gemm(SM_WOP1, 9);
    stage(par + PAR_OPB1);
    barh(barid);
    {
        float v[16];
        #pragma unroll
        for (int i = 0; i < 4; i++) {
            float4 f = *(const float4*)&sSh[row * 136 + q * 16 + i * 4];
            v[4 * i] = f.x; v[4 * i + 1] = f.y; v[4 * i + 2] = f.z; v[4 * i + 3] = f.w;
        }
        float s = 0.f;
        #pragma unroll
        for (int i = 0; i < 16; i++) s += v[i];
        s += __shfl_xor_sync(0xffffffffu, s, 1);
        s += __shfl_xor_sync(0xffffffffu, s, 2);
        s += __shfl_xor_sync(0xffffffffu, s, 4);
        float mean = s * (1.f / 128.f);
        float sq = 0.f;
        #pragma unroll
        for (int i = 0; i < 16; i++) { float d = v[i] - mean; sq += d * d; }
        sq += __shfl_xor_sync(0xffffffffu, sq, 1);
        sq += __shfl_xor_sync(0xffffffffu, sq, 2);
        sq += __shfl_xor_sync(0xffffffffu, sq, 4);
        float inv = rsqrtf(sq * (1.f / 128.f) + 1e-5f);
        #pragma unroll
        for (int i = 0; i < 8; i++) {
            int ca = q * 16 + 2 * i;
            float y0 = silu_f((v[2 * i] - mean) * inv * par[PAR_LN1G + ca] + par[PAR_LN1B + ca]);
            float y1 = silu_f((v[2 * i + 1] - mean) * inv * par[PAR_LN1G + ca + 1] + par[PAR_LN1B + ca + 1]);
            hkeep[i] = packbf(y0, y1);
        }
        uint4* dst = (uint4*)(dsm + SM_ACT + (hb * 16 + row) * ASTR + q * 32);
        dst[0] = *(uint4*)&hkeep[0]; dst[1] = *(uint4*)&hkeep[4];
    }
    barh(barid);

    // ============ stage 2 ============
    do_gemm(SM_WR1, 4);
    stage(par + PAR_RB1);
    barh(barid);
    {
        float v[16];
        #pragma unroll
        for (int i = 0; i < 4; i++) {
            float4 f = *(const float4*)&sSh[row * 136 + q * 16 + i * 4];
            v[4 * i] = f.x; v[4 * i + 1] = f.y; v[4 * i + 2] = f.z; v[4 * i + 3] = f.w;
        }
        float s = 0.f;
        #pragma unroll
        for (int i = 0; i < 16; i++) s += v[i];
        s += __shfl_xor_sync(0xffffffffu, s, 1);
        s += __shfl_xor_sync(0xffffffffu, s, 2);
        s += __shfl_xor_sync(0xffffffffu, s, 4);
        float mean = s * (1.f / 128.f);
        float sq = 0.f;
        #pragma unroll
        for (int i = 0; i < 16; i++) { float d = v[i] - mean; sq += d * d; }
        sq += __shfl_xor_sync(0xffffffffu, sq, 1);
        sq += __shfl_xor_sync(0xffffffffu, sq, 2);
        sq += __shfl_xor_sync(0xffffffffu, sq, 4);
        float inv = rsqrtf(sq * (1.f / 128.f) + 1e-5f);
        uint32_t pk[8];
        #pragma unroll
        for (int i = 0; i < 8; i++) {
            int ca = q * 16 + 2 * i;
            float y0 = silu_f((v[2 * i] - mean) * inv * par[PAR_RLNG + ca] + par[PAR_RLNB + ca]);
            float y1 = silu_f((v[2 * i + 1] - mean) * inv * par[PAR_RLNG + ca + 1] + par[PAR_RLNB + ca + 1]);
            pk[i] = packbf(y0, y1);
        }
        uint4* dst = (uint4*)(dsm + SM_ACT + (hb * 16 + row) * ASTR + q * 32);
        dst[0] = *(uint4*)&pk[0]; dst[1] = *(uint4*)&pk[4];
    }
    barh(barid);

    // ============ stage 3 ============
    do_gemm(SM_WR2, 4);
    stage(par + PAR_RB2);
    barh(barid);
    {
        float v[16];
        #pragma unroll
        for (int i = 0; i < 4; i++) {
            float4 f = *(const float4*)&sSh[row * 136 + q * 16 + i * 4];
            v[4 * i] = f.x; v[4 * i + 1] = f.y; v[4 * i + 2] = f.z; v[4 * i + 3] = f.w;
        }
        #pragma unroll
        for (int i = 0; i < 8; i++) {
            __nv_bfloat162 hh = *(__nv_bfloat162*)&hkeep[i];
            v[2 * i]     += __bfloat162float(hh.x);
            v[2 * i + 1] += __bfloat162float(hh.y);
        }
        float s = 0.f;
        #pragma unroll
        for (int i = 0; i < 16; i++) s += v[i];
        s += __shfl_xor_sync(0xffffffffu, s, 1);
        s += __shfl_xor_sync(0xffffffffu, s, 2);
        s += __shfl_xor_sync(0xffffffffu, s, 4);
        float mean = s * (1.f / 128.f);
        float sq = 0.f;
        #pragma unroll
        for (int i = 0; i < 16; i++) { float d = v[i] - mean; sq += d * d; }
        sq += __shfl_xor_sync(0xffffffffu, sq, 1);
        sq += __shfl_xor_sync(0xffffffffu, sq, 2);
        sq += __shfl_xor_sync(0xffffffffu, sq, 4);
        float inv = rsqrtf(sq * (1.f / 128.f) + 1e-5f);

        float p0 = 0.f, p1 = 0.f, p2 = 0.f;
        #pragma unroll
        for (int i = 0; i < 16; i++) {
            int ca = q * 16 + i;
            float y = (v[i] - mean) * inv * par[PAR_LN2G + ca] + par[PAR_LN2B + ca];
            p0 += y * par[PAR_W3 + ca * 3 + 0];
            p1 += y * par[PAR_W3 + ca * 3 + 1];
            p2 += y * par[PAR_W3 + ca * 3 + 2];
        }
        p0 += __shfl_xor_sync(0xffffffffu, p0, 1);
        p0 += __shfl_xor_sync(0xffffffffu, p0, 2);
        p0 += __shfl_xor_sync(0xffffffffu, p0, 4);
        p1 += __shfl_xor_sync(0xffffffffu, p1, 1);
        p1 += __shfl_xor_sync(0xffffffffu, p1, 2);
        p1 += __shfl_xor_sync(0xffffffffu, p1, 4);
        p2 += __shfl_xor_sync(0xffffffffu, p2, 1);
        p2 += __shfl_xor_sync(0xffffffffu, p2, 2);
        p2 += __shfl_xor_sync(0xffffffffu, p2, 4);
        if (q == 0) {
            int bi = bidx[grow];
            float dots[3] = {p0 + par[PAR_B3 + 0], p1 + par[PAR_B3 + 1], p2 + par[PAR_B3 + 2]};
            #pragma unroll
            for (int j = 0; j < 3; j++) {
                float val = coordp[grow * 3 + j] + 0.01f * tanhf(dots[j]);
                fout[grow * 3 + j] = fminf(fmaxf(val, bmin[bi * 3 + j]), bmax[bi * 3 + j]);
            }
        }
    }
}

// ======== flash: 128 q-rows/CTA, 32 rows/warp (2 m-tiles), streamed exp/PV ========
#define CSTRIDE 80
#define QBUF    10240    // 128 q rows
#define KVB     10240
#define NITER   (32 / KSPLIT)

__device__ __forceinline__ void kv_load128(const __nv_bfloat16* __restrict__ Kh,
                                           const __nv_bfloat16* __restrict__ Vh,
                                           int h, int kb, uint32_t sbase, int tid) {
    #pragma unroll
    for (int i = 0; i < 8; i++) {
        int s = tid + i * 128;
        int row = (s >> 2) & 127, seg = s & 3;
        const __nv_bfloat16* src = ((s < 512) ? Kh : Vh)
            + (((h << 12) + (kb << 7) + row) << 5) + seg * 8;
        uint32_t dst = sbase + ((s < 512) ? 0 : KVB) + row * CSTRIDE + seg * 16;
        cpa16(dst, src);
    }
    asm volatile("cp.async.commit_group;");
}

__global__ void __launch_bounds__(128) flashb_k(const __nv_bfloat16* __restrict__ Qh,
                                                const __nv_bfloat16* __restrict__ Kh,
                                                const __nv_bfloat16* __restrict__ Vh,
                                                float* __restrict__ opart,
                                                float* __restrict__ lpart) {
    __shared__ __align__(16) char smem[QBUF + 4 * KVB];
    const int tid = threadIdx.x, lane = tid & 31, warp = tid >> 5;
    const int h = blockIdx.y, qb = blockIdx.x, sp = blockIdx.z;
    const int kb0 = sp * NITER;

    char* Qs = smem;
    uint32_t Qsa = (uint32_t)__cvta_generic_to_shared(Qs);
    uint32_t kva0 = Qsa + QBUF;
    uint32_t kva1 = Qsa + QBUF + 2 * KVB;

    // load 128 Q rows
    #pragma unroll
    for (int i = 0; i < 4; i++) {
        int s = tid + i * 128;
        int row = s >> 2, seg = s & 3;
        uint4 v = *(const uint4*)(Qh + (((h << 12) + (qb << 7) + row) << 5) + seg * 8);
        *(uint4*)(Qs + row * CSTRIDE + seg * 16) = v;
    }
    kv_load128(Kh, Vh, h, kb0 + 0, kva0, tid);
    kv_load128(Kh, Vh, h, kb0 + 1, kva1, tid);
    __syncthreads();

    // Q fragments: 2 m16 tiles per warp
    uint32_t qa[16];
    {
        int i = lane & 7, sl = lane >> 3;
        #pragma unroll
        for (int mt = 0; mt < 2; mt++) {
            int row = warp * 32 + mt * 16 + ((sl & 1) ? 8 : 0) + i;
            uint32_t a = Qsa + row * CSTRIDE + ((sl >> 1) ? 16 : 0);
            ldsm4(qa[mt * 8 + 0], qa[mt * 8 + 1], qa[mt * 8 + 2], qa[mt * 8 + 3], a);
            ldsm4(qa[mt * 8 + 4], qa[mt * 8 + 5], qa[mt * 8 + 6], qa[mt * 8 + 7], a + 32);
        }
    }

    float l00 = 0.f, l01 = 0.f, l10 = 0.f, l11 = 0.f;
    float o0[4][4], o1[4][4];
    #pragma unroll
    for (int j = 0; j < 4; j++)
        #pragma unroll
        for (int c = 0; c < 4; c++) { o0[j][c] = 0.f; o1[j][c] = 0.f; }

    const int i7 = lane & 7, sel = lane >> 3;
    const uint32_t krow = ((sel >= 2) ? 8 : 0) + i7;
    const uint32_t kcol = (sel & 1) ? 16 : 0;
    const uint32_t vrow = ((sel & 1) ? 8 : 0) + i7;
    const uint32_t vcol = (sel >= 2) ? 16 : 0;

    for (int kb = 0; kb < NITER; kb++) {
        if (kb < NITER - 1) asm volatile("cp.async.wait_group 1;");
        else                asm volatile("cp.async.wait_group 0;");
        __syncthreads();
        uint32_t Kbase = (kb & 1) ? kva1 : kva0;
        uint32_t Vbase = Kbase + KVB;

        // stream 8 substeps of 16 keys: QK -> exp -> PV, K/V frags shared by 2 m-tiles
        #pragma unroll
        for (int ks = 0; ks < 8; ks++) {
            uint32_t a = Kbase + (ks * 16 + krow) * CSTRIDE + kcol;
            uint32_t b0, b1, b2, b3, c0, c1, c2, c3;
            ldsm4(b0, b1, b2, b3, a);
            ldsm4(c0, c1, c2, c3, a + 32);

            float s00[4] = {0.f, 0.f, 0.f, 0.f}, s01[4] = {0.f, 0.f, 0.f, 0.f};
            float s10[4] = {0.f, 0.f, 0.f, 0.f}, s11[4] = {0.f, 0.f, 0.f, 0.f};
            mma16816(s00, qa,      b0, b1); mma16816(s00, qa + 4,  c0, c1);
            mma16816(s01, qa,      b2, b3); mma16816(s01, qa + 4,  c2, c3);
            mma16816(s10, qa + 8,  b0, b1); mma16816(s10, qa + 12, c0, c1);
            mma16816(s11, qa + 8,  b2, b3); mma16816(s11, qa + 12, c2, c3);

            uint32_t e00 = schexp(s00[0]), e01 = schexp(s00[1]);
            uint32_t e02 = schexp(s00[2]), e03 = schexp(s00[3]);
            uint32_t f00 = schexp(s01[0]), f01 = schexp(s01[1]);
            uint32_t f02 = schexp(s01[2]), f03 = schexp(s01[3]);
            uint32_t e10 = schexp(s10[0]), e11 = schexp(s10[1]);
            uint32_t e12 = schexp(s10[2]), e13 = schexp(s10[3]);
            uint32_t f10 = schexp(s11[0]), f11 = schexp(s11[1]);
            uint32_t f12 = schexp(s11[2]), f13 = schexp(s11[3]);

            l00 += (__int_as_float(e00) + __int_as_float(e01))
                 + (__int_as_float(f00) + __int_as_float(f01));
            l01 += (__int_as_float(e02) + __int_as_float(e03))
                 + (__int_as_float(f02) + __int_as_float(f03));
            l10 += (__int_as_float(e10) + __int_as_float(e11))
                 + (__int_as_float(f10) + __int_as_float(f11));
            l11 += (__int_as_float(e12) + __int_as_float(e13))
                 + (__int_as_float(f12) + __int_as_float(f13));

            uint32_t pa0[4], pa1[4];
            pa0[0] = prmt16(e00, e01); pa0[1] = prmt16(e02, e03);
            pa0[2] = prmt16(f00, f01); pa0[3] = prmt16(f02, f03);
            pa1[0] = prmt16(e10, e11); pa1[1] = prmt16(e12, e13);
            pa1[2] = prmt16(f10, f11); pa1[3] = prmt16(f12, f13);

            uint32_t av = Vbase + (ks * 16 + vrow) * CSTRIDE + vcol;
            uint32_t v0, v1, v2, v3, w0, w1, w2, w3;
            ldsm4t(v0, v1, v2, v3, av);
            ldsm4t(w0, w1, w2, w3, av + 32);
            mma16816(o0[0], pa0, v0, v1);
            mma16816(o0[1], pa0, v2, v3);
            mma16816(o0[2], pa0, w0, w1);
            mma16816(o0[3], pa0, w2, w3);
            mma16816(o1[0], pa1, v0, v1);
            mma16816(o1[1], pa1, v2, v3);
            mma16816(o1[2], pa1, w0, w1);
            mma16816(o1[3], pa1, w2, w3);
        }

        __syncthreads();
        if (kb < NITER - 2) kv_load128(Kh, Vh, h, kb0 + kb + 2, (kb & 1) ? kva1 : kva0, tid);
    }

    l00 += __shfl_xor_sync(0xffffffffu, l00, 1);
    l00 += __shfl_xor_sync(0xffffffffu, l00, 2);
    l01 += __shfl_xor_sync(0xffffffffu, l01, 1);
    l01 += __shfl_xor_sync(0xffffffffu, l01, 2);
    l10 += __shfl_xor_sync(0xffffffffu, l10, 1);
    l10 += __shfl_xor_sync(0xffffffffu, l10, 2);
    l11 += __shfl_xor_sync(0xffffffffu, l11, 1);
    l11 += __shfl_xor_sync(0xffffffffu, l11, 2);

    int g = lane >> 2, l2 = (lane & 3) * 2;
    int row0 = (qb << 7) + warp * 32 + g;
    float* op = opart + sp * NATOMS * HDIM;
    #pragma unroll
    for (int j = 0; j < 4; j++) {
        int col = (h << 5) + j * 8 + l2;
        *(float2*)&op[row0 * HDIM + col]        = make_float2(o0[j][0], o0[j][1]);
        *(float2*)&op[(row0 + 8) * HDIM + col]  = make_float2(o0[j][2], o0[j][3]);
        *(float2*)&op[(row0 + 16) * HDIM + col] = make_float2(o1[j][0], o1[j][1]);
        *(float2*)&op[(row0 + 24) * HDIM + col] = make_float2(o1[j][2], o1[j][3]);
    }
    if ((lane & 3) == 0) {
        float* lp = lpart + sp * NHEAD * NATOMS + h * NATOMS;
        lp[row0]      = l00;
        lp[row0 + 8]  = l01;
        lp[row0 + 16] = l10;
        lp[row0 + 24] = l11;
    }
}

// ---------------- host ----------------
extern "C" void kernel_launch(void* const* d_in, const int* in_sizes, int n_in,
                              void* d_out, int out_size) {
    const int*   num_atoms  = (const int*)d_in[0];
    const int*   elems      = (const int*)d_in[1];
    const float* cell       = (const float*)d_in[2];
    const float* coord      = (const float*)d_in[3];
    const float* emb        = (const float*)d_in[4];
    const float* ln_in_g    = (const float*)d_in[5];
    const float* ln_in_b    = (const float*)d_in[6];
    const float* attn_in_w  = (const float*)d_in[7];
    const float* attn_in_b  = (const float*)d_in[8];
    const float* attn_out_w = (const float*)d_in[9];
    const float* attn_out_b = (const float*)d_in[10];
    const float* ce_w1      = (const float*)d_in[11];
    const float* ce_b1      = (const float*)d_in[12];
    const float* ce_w2      = (const float*)d_in[13];
    const float* ce_b2      = (const float*)d_in[14];
    const float* ln_feat_g  = (const float*)d_in[15];
    const float* ln_feat_b  = (const float*)d_in[16];
    const float* op_w1      = (const float*)d_in[17];
    const float* op_b1      = (const float*)d_in[18];
    const float* op_ln1_g   = (const float*)d_in[19];
    const float* op_ln1_b   = (const float*)d_in[20];
    const float* res_w1     = (const float*)d_in[21];
    const float* res_b1     = (const float*)d_in[22];
    const float* res_ln_g   = (const float*)d_in[23];
    const float* res_ln_b   = (const float*)d_in[24];
    const float* res_w2     = (const float*)d_in[25];
    const float* res_b2     = (const float*)d_in[26];
    const float* op_ln2_g   = (const float*)d_in[27];
    const float* op_ln2_b   = (const float*)d_in[28];
    const float* op_w3      = (const float*)d_in[29];
    const float* op_b3      = (const float*)d_in[30];
    float* out = (float*)d_out;

    float* S = nullptr;
    cudaGetSymbolAddress((void**)&S, g_scratch);
    int* bidx = nullptr;
    cudaGetSymbolAddress((void**)&bidx, g_bidx);

    __nv_bfloat16* P = (__nv_bfloat16*)S;
    __nv_bfloat16* xb    = P; P += NATOMS * HDIM;
    __nv_bfloat16* Qh    = P; P += NATOMS * HDIM;
    __nv_bfloat16* Kh    = P; P += NATOMS * HDIM;
    __nv_bfloat16* Vh    = P; P += NATOMS * HDIM;
    __nv_bfloat16* wqkv  = P; P += 128 * 384;
    __nv_bfloat16* wao   = P; P += 128 * 128;
    __nv_bfloat16* wop1  = P; P += FPAD * 128;
    __nv_bfloat16* wr1   = P; P += 128 * 128;
    __nv_bfloat16* wr2   = P; P += 128 * 128;
    float* F = (float*)P;
    float* opart = F; F += KSPLIT * NATOMS * HDIM;
    float* lpart = F; F += KSPLIT * NHEAD * NATOMS;
    float* cf    = F; F += BATCH * HDIM;
    float* bmin  = F; F += BATCH * 3;
    float* bmax  = F; F += BATCH * 3;

    static bool attr_set = false;
    if (!attr_set) {
        cudaFuncSetAttribute(tail_k, cudaFuncAttributeMaxDynamicSharedMemorySize, SMEM_TAIL);
        attr_set = true;
    }

    setup_k<<<1049, 256>>>(elems, emb, ln_in_g, ln_in_b, xb,
                           attn_in_w, attn_out_w, op_w1, res_w1, res_w2,
                           wqkv, wao, wop1, wr1, wr2,
                           cell, ce_w1, ce_b1, ce_w2, ce_b2, cf,
                           num_atoms, bmin, bmax);

    qkv_k<<<dim3(3, 128), 128>>>(xb, wqkv, attn_in_b, Qh, Kh, Vh);

    flashb_k<<<dim3(32, NHEAD, KSPLIT), 128>>>(Qh, Kh, Vh, opart, lpart);

    tail_k<<<128, 256, SMEM_TAIL>>>(opart, lpart,
        wao, attn_out_b, ln_feat_g, ln_feat_b, cf, coord, bidx,
        wop1, op_b1, op_ln1_g, op_ln1_b,
        wr1, res_b1, res_ln_g, res_ln_b,
        wr2, res_b2, op_ln2_g, op_ln2_b,
        op_w3, op_b3, bmin, bmax, out);
}

// round 11
// speedup vs baseline: 7.4640x; 1.0041x over previous
#include <cuda_runtime.h>
#include <cuda_bf16.h>
#include <math.h>
#include <stdint.h>

#define NATOMS 4096
#define HDIM   128
#define BATCH  128
#define NHEAD  4
#define DHEAD  32
#define H3     384
#define FPAD   288
#define KSPLIT 4

// -------- scratch (no allocations allowed) --------
__device__ float g_scratch[8300000];
__device__ int   g_bidx[NATOMS];

// ---------------- helpers ----------------
__device__ __forceinline__ float silu_f(float x) {
    return x / (1.f + __expf(-x));
}
__device__ __forceinline__ void ldsm4(uint32_t& r0, uint32_t& r1, uint32_t& r2, uint32_t& r3, uint32_t addr) {
    asm volatile("ldmatrix.sync.aligned.m8n8.x4.shared.b16 {%0,%1,%2,%3}, [%4];"
                 : "=r"(r0), "=r"(r1), "=r"(r2), "=r"(r3) : "r"(addr));
}
__device__ __forceinline__ void ldsm4t(uint32_t& r0, uint32_t& r1, uint32_t& r2, uint32_t& r3, uint32_t addr) {
    asm volatile("ldmatrix.sync.aligned.m8n8.x4.trans.shared.b16 {%0,%1,%2,%3}, [%4];"
                 : "=r"(r0), "=r"(r1), "=r"(r2), "=r"(r3) : "r"(addr));
}
__device__ __forceinline__ void mma16816(float* d, const uint32_t* a, uint32_t b0, uint32_t b1) {
    asm volatile("mma.sync.aligned.m16n8k16.row.col.f32.bf16.bf16.f32 "
                 "{%0,%1,%2,%3}, {%4,%5,%6,%7}, {%8,%9}, {%0,%1,%2,%3};"
                 : "+f"(d[0]), "+f"(d[1]), "+f"(d[2]), "+f"(d[3])
                 : "r"(a[0]), "r"(a[1]), "r"(a[2]), "r"(a[3]), "r"(b0), "r"(b1));
}
// fp8 e4m3 mma, k32 — fragment layout identical to bf16 k16 with byte-pairs per b16
__device__ __forceinline__ void mma16832(float* d, const uint32_t* a, uint32_t b0, uint32_t b1) {
    asm volatile("mma.sync.aligned.m16n8k32.row.col.f32.e4m3.e4m3.f32 "
                 "{%0,%1,%2,%3}, {%4,%5,%6,%7}, {%8,%9}, {%0,%1,%2,%3};"
                 : "+f"(d[0]), "+f"(d[1]), "+f"(d[2]), "+f"(d[3])
                 : "r"(a[0]), "r"(a[1]), "r"(a[2]), "r"(a[3]), "r"(b0), "r"(b1));
}
__device__ __forceinline__ uint32_t packbf(float lo, float hi) {
    uint32_t r;
    asm volatile("cvt.rn.bf16x2.f32 %0, %1, %2;" : "=r"(r) : "f"(hi), "f"(lo));
    return r;
}
__device__ __forceinline__ uint16_t packe4(float lo, float hi) {
    uint16_t r;
    asm volatile("cvt.rn.satfinite.e4m3x2.f32 %0, %1, %2;" : "=h"(r) : "f"(hi), "f"(lo));
    return r;
}
__device__ __forceinline__ void cpa16(uint32_t dst, const void* src) {
    asm volatile("cp.async.ca.shared.global [%0], [%1], 16;" :: "r"(dst), "l"(src));
}
__device__ __forceinline__ void cpa4(uint32_t dst, const void* src) {
    asm volatile("cp.async.ca.shared.global [%0], [%1], 4;" :: "r"(dst), "l"(src));
}
__device__ __forceinline__ void barh(int id) {
    asm volatile("bar.sync %0, 128;" :: "r"(id) : "memory");
}
// Schraudolph exp2: exp2(x) ~ bits (int)(x*2^23 + C)
__device__ __forceinline__ uint32_t schexp(float x) {
    int i;
    asm("cvt.rni.s32.f32 %0, %1;" : "=r"(i) : "f"(fmaf(x, 8388608.f, 1064876800.f)));
    return (uint32_t)i;
}
__device__ __forceinline__ uint32_t prmt16(uint32_t a, uint32_t b) {
    uint32_t r;
    asm("prmt.b32 %0,%1,%2,0x7632;" : "=r"(r) : "r"(a), "r"(b));
    return r;
}

// ================= fused setup kernel =================
__global__ void __launch_bounds__(256) setup_k(
    const int* __restrict__ elems, const float* __restrict__ emb,
    const float* __restrict__ ln_in_g, const float* __restrict__ ln_in_b,
    __nv_bfloat16* __restrict__ xo,
    const float* __restrict__ aiw, const float* __restrict__ aow,
    const float* __restrict__ opw1, const float* __restrict__ rw1,
    const float* __restrict__ rw2,
    __nv_bfloat16* __restrict__ wqkv, __nv_bfloat16* __restrict__ wao,
    __nv_bfloat16* __restrict__ wop1, __nv_bfloat16* __restrict__ wr1,
    __nv_bfloat16* __restrict__ wr2,
    const float* __restrict__ cell,
    const float* __restrict__ cw1, const float* __restrict__ cb1,
    const float* __restrict__ cw2, const float* __restrict__ cb2,
    float* __restrict__ cf,
    const int* __restrict__ num_atoms,
    float* __restrict__ bmin, float* __restrict__ bmax)
{
    const int b = blockIdx.x, tid = threadIdx.x;

    if (b < 512) {
        int warp = tid >> 5, lane = tid & 31;
        int r = b * 8 + warp;
        int e = elems[r];
        float4 v = *(const float4*)&emb[e * HDIM + lane * 4];
        float s = v.x + v.y + v.z + v.w;
        #pragma unroll
        for (int off = 16; off > 0; off >>= 1) s += __shfl_xor_sync(0xffffffffu, s, off);
        float mean = s * (1.f / 128.f);
        float dx = v.x - mean, dy = v.y - mean, dz = v.z - mean, dw = v.w - mean;
        float sq = dx * dx + dy * dy + dz * dz + dw * dw;
        #pragma unroll
        for (int off = 16; off > 0; off >>= 1) sq += __shfl_xor_sync(0xffffffffu, sq, off);
        float inv = rsqrtf(sq * (1.f / 128.f) + 1e-5f);
        float4 gg = *(const float4*)&ln_in_g[lane * 4];
        float4 bb = *(const float4*)&ln_in_b[lane * 4];
        uint32_t p0 = packbf(dx * inv * gg.x + bb.x, dy * inv * gg.y + bb.y);
        uint32_t p1 = packbf(dz * inv * gg.z + bb.z, dw * inv * gg.w + bb.w);
        *(uint2*)(xo + r * HDIM + lane * 4) = make_uint2(p0, p1);
        return;
    }

    if (b < 1040) {
        int i = (b - 512) * 256 + tid;
        if (i < 49152) wqkv[i] = __float2bfloat16(aiw[i]);
        else if (i < 65536) { int j = i - 49152; wao[j] = __float2bfloat16(aow[j]); }
        else if (i < 102400) {
            int j = i - 65536; int r = j >> 7, c = j & 127;
            wop1[j] = __float2bfloat16(r < 259 ? opw1[r * 128 + c] : 0.f);
        }
        else if (i < 118784) { int j = i - 102400; wr1[j] = __float2bfloat16(rw1[j]); }
        else { int j = i - 118784; wr2[j] = __float2bfloat16(rw2[j]); }
        return;
    }

    if (b < 1048) {
        __shared__ float t1s[16][128];
        int r0 = (b - 1040) * 16;
        #pragma unroll
        for (int i = 0; i < 8; i++) {
            int idx = tid + i * 256;
            int rr = idx >> 7, k = idx & 127;
            int r = r0 + rr;
            float u = cell[r * 3 + 0] * cw1[k] + cell[r * 3 + 1] * cw1[128 + k]
                    + cell[r * 3 + 2] * cw1[256 + k] + cb1[k];
            t1s[rr][k] = silu_f(u);
        }
        __syncthreads();
        int t = tid & 127, half = tid >> 7;
        float acc[8];
        #pragma unroll
        for (int j = 0; j < 8; j++) acc[j] = cb2[t];
        #pragma unroll 4
        for (int k = 0; k < 128; k++) {
            float w = cw2[k * 128 + t];
            #pragma unroll
            for (int j = 0; j < 8; j++) acc[j] += t1s[half * 8 + j][k] * w;
        }
        #pragma unroll
        for (int j = 0; j < 8; j++) cf[(r0 + half * 8 + j) * 128 + t] = acc[j];
        return;
    }

    __shared__ int starts[BATCH + 1];
    if (tid == 0) {
        int acc = 0;
        for (int i = 0; i < BATCH; i++) { starts[i] = acc; acc += num_atoms[i]; }
        starts[BATCH] = acc;
    }
    __syncthreads();
    for (int i = tid; i < NATOMS; i += 256) g_bidx[i] = BATCH - 1;
    __syncthreads();
    if (tid < BATCH) {
        int s = starts[tid], e = starts[tid + 1];
        if (s > NATOMS) s = NATOMS;
        if (e > NATOMS) e = NATOMS;
        for (int i = s; i < e; i++) g_bidx[i] = tid;
        #pragma unroll
        for (int i = 0; i < 3; i++) {
            float a = cell[(3 * tid + i) * 3 + 0];
            float c1 = cell[(3 * tid + i) * 3 + 1];
            float c = cell[(3 * tid + i) * 3 + 2];
            bmin[tid * 3 + i] = fminf(a, fminf(c1, c)) + 1e-6f;
            bmax[tid * 3 + i] = fmaxf(a, fmaxf(c1, c)) - 1e-6f;
        }
    }
}

// ================= QKV GEMM: Q,K -> e4m3 (scaled), V -> bf16 =================
__global__ void __launch_bounds__(128) qkv_k(
    const __nv_bfloat16* __restrict__ A, const __nv_bfloat16* __restrict__ W,
    const float* __restrict__ bias,
    uint8_t* __restrict__ Qf, uint8_t* __restrict__ Kf,
    __nv_bfloat16* __restrict__ Vh)
{
    __shared__ __align__(16) char sA[2 * 32 * 80];
    __shared__ __align__(16) char sW[2 * 32 * 272];
    const int tid = threadIdx.x, lane = tid & 31, warp = tid >> 5;
    const int wr = warp & 1, wc = warp >> 1;
    const int bm = blockIdx.y, nb = blockIdx.x;
    uint32_t aBase = (uint32_t)__cvta_generic_to_shared(sA);
    uint32_t wBase = (uint32_t)__cvta_generic_to_shared(sW);

    #pragma unroll
    for (int p = 0; p < 2; p++) {
        int row = tid >> 2, seg = tid & 3;
        cpa16(aBase + p * 2560 + row * 80 + seg * 16,
              A + (bm * 32 + row) * 128 + p * 32 + seg * 8);
        #pragma unroll
        for (int i = 0; i < 4; i++) {
            int s = tid + i * 128;
            int wrow = s >> 4, wseg = s & 15;
            cpa16(wBase + p * 8704 + wrow * 272 + wseg * 16,
                  W + (p * 32 + wrow) * H3 + nb * 128 + wseg * 8);
        }
        asm volatile("cp.async.commit_group;");
    }

    float acc[8][4];
    #pragma unroll
    for (int j = 0; j < 8; j++)
        #pragma unroll
        for (int c = 0; c < 4; c++) acc[j][c] = 0.f;

    const int i7 = lane & 7, sel = lane >> 3;
    const int arow = wr * 16 + ((sel & 1) ? 8 : 0) + i7;
    const int acol = (sel >> 1) ? 16 : 0;
    const int vrow = ((sel & 1) ? 8 : 0) + i7;
    const int vcol = (sel >= 2) ? 16 : 0;

    for (int ks = 0; ks < 4; ks++) {
        if (ks < 3) asm volatile("cp.async.wait_group 1;");
        else        asm volatile("cp.async.wait_group 0;");
        __syncthreads();
        uint32_t Ab = aBase + (ks & 1) * 2560;
        uint32_t Wb = wBase + (ks & 1) * 8704;
        #pragma unroll
        for (int kh = 0; kh < 2; kh++) {
            uint32_t qa[4];
            ldsm4(qa[0], qa[1], qa[2], qa[3], Ab + arow * 80 + acol + kh * 32);
            #pragma unroll
            for (int j = 0; j < 4; j++) {
                uint32_t r0, r1, r2, r3;
                ldsm4t(r0, r1, r2, r3, Wb + (kh * 16 + vrow) * 272 + wc * 128 + j * 32 + vcol);
                mma16816(acc[2 * j],     qa, r0, r1);
                mma16816(acc[2 * j + 1], qa, r2, r3);
            }
        }
        __syncthreads();
        if (ks + 2 < 4) {
            int p = ks + 2, buf = ks & 1;
            int row = tid >> 2, seg = tid & 3;
            cpa16(aBase + buf * 2560 + row * 80 + seg * 16,
                  A + (bm * 32 + row) * 128 + p * 32 + seg * 8);
            #pragma unroll
            for (int i = 0; i < 4; i++) {
                int s = tid + i * 128;
                int wrow = s >> 4, wseg = s & 15;
                cpa16(wBase + buf * 8704 + wrow * 272 + wseg * 16,
                      W + (p * 32 + wrow) * H3 + nb * 128 + wseg * 8);
            }
            asm volatile("cp.async.commit_group;");
        }
    }

    const int g = lane >> 2, c2 = (lane & 3) * 2;
    int r0 = bm * 32 + wr * 16 + g;
    // sqrt(1/sqrt(32) * log2(e)) applied to BOTH q and k so each stays in good e4m3 range
    const float SC = 0.50507248f;
    if (nb < 2) {
        uint8_t* outp = (nb == 0) ? Qf : Kf;
        #pragma unroll
        for (int t = 0; t < 8; t++) {
            int col = wc * 64 + t * 8 + c2;
            float b0v = bias[nb * 128 + col], b1v = bias[nb * 128 + col + 1];
            int h = col >> 5, d = col & 31;
            *(uint16_t*)(outp + (((h << 12) + r0) << 5) + d) =
                packe4((acc[t][0] + b0v) * SC, (acc[t][1] + b1v) * SC);
            *(uint16_t*)(outp + (((h << 12) + r0 + 8) << 5) + d) =
                packe4((acc[t][2] + b0v) * SC, (acc[t][3] + b1v) * SC);
        }
    } else {
        #pragma unroll
        for (int t = 0; t < 8; t++) {
            int col = wc * 64 + t * 8 + c2;
            float b0v = bias[256 + col], b1v = bias[256 + col + 1];
            int h = col >> 5, d = col & 31;
            *(uint32_t*)(Vh + (((h << 12) + r0) << 5) + d) =
                packbf(acc[t][0] + b0v, acc[t][1] + b1v);
            *(uint32_t*)(Vh + (((h << 12) + r0 + 8) << 5) + d) =
                packbf(acc[t][2] + b0v, acc[t][3] + b1v);
        }
    }
}

// ================= fused tail (unchanged from R10) ==========
#define WSTR 272
#define ASTR 592
#define SM_WAO   0
#define SM_WOP1  (128 * WSTR)
#define SM_WR1   (SM_WOP1 + 288 * WSTR)
#define SM_WR2   (SM_WR1 + 128 * WSTR)
#define SM_ACT   (SM_WR2 + 128 * WSTR)
#define SM_STAGE (SM_ACT + 32 * ASTR)
#define SM_PAR   (SM_STAGE + 32 * 136 * 4)
#define PAR_AOBB 0
#define PAR_OPB1 128
#define PAR_RB1  256
#define PAR_RB2  384
#define PAR_LNFG 512
#define PAR_LNFB 772
#define PAR_LN1G 1032
#define PAR_LN1B 1160
#define PAR_RLNG 1288
#define PAR_RLNB 1416
#define PAR_LN2G 1544
#define PAR_LN2B 1672
#define PAR_W3   1800
#define PAR_B3   2184
#define SMEM_TAIL (SM_PAR + 2192 * 4)

__global__ void __launch_bounds__(256) tail_k(
    const float* __restrict__ opart, const float* __restrict__ lpart,
    const __nv_bfloat16* __restrict__ wao, const float* __restrict__ aob_bias,
    const float* __restrict__ lnf_g, const float* __restrict__ lnf_b,
    const float* __restrict__ cf, const float* __restrict__ coordp,
    const int* __restrict__ bidx,
    const __nv_bfloat16* __restrict__ wop1, const float* __restrict__ op_b1,
    const float* __restrict__ ln1_g, const float* __restrict__ ln1_b,
    const __nv_bfloat16* __restrict__ wr1, const float* __restrict__ r_b1,
    const float* __restrict__ rln_g, const float* __restrict__ rln_b,
    const __nv_bfloat16* __restrict__ wr2, const float* __restrict__ r_b2,
    const float* __restrict__ ln2_g, const float* __restrict__ ln2_b,
    const float* __restrict__ w3, const float* __restrict__ b3,
    const float* __restrict__ bmin, const float* __restrict__ bmax,
    float* __restrict__ fout)
{
    extern __shared__ __align__(16) char dsm[];
    const int tid = threadIdx.x, lane = tid & 31, warp = tid >> 5;
    const int hb = warp >> 2;
    const int wc = warp & 3;
    const int bm = blockIdx.x;
    uint32_t base = (uint32_t)__cvta_generic_to_shared(dsm);
    uint32_t aAct = base + SM_ACT + hb * 16 * ASTR;
    float* sSh = (float*)(dsm + SM_STAGE) + hb * 16 * 136;
    const float* par = (const float*)(dsm + SM_PAR);

    #pragma unroll
    for (int i = 0; i < 8; i++) {
        int s = tid + i * 256;
        int row = s >> 4, seg = s & 15;
        cpa16(base + SM_WAO + row * WSTR + seg * 16, wao + row * 128 + seg * 8);
    }
    #pragma unroll
    for (int i = 0; i < 18; i++) {
        int s = tid + i * 256;
        int row = s >> 4, seg = s & 15;
        cpa16(base + SM_WOP1 + row * WSTR + seg * 16, wop1 + row * 128 + seg * 8);
    }
    #pragma unroll
    for (int i = 0; i < 8; i++) {
        int s = tid + i * 256;
        int row = s >> 4, seg = s & 15;
        cpa16(base + SM_WR1 + row * WSTR + seg * 16, wr1 + row * 128 + seg * 8);
    }
    #pragma unroll
    for (int i = 0; i < 8; i++) {
        int s = tid + i * 256;
        int row = s >> 4, seg = s & 15;
        cpa16(base + SM_WR2 + row * WSTR + seg * 16, wr2 + row * 128 + seg * 8);
    }
    {
        int t = tid;
        if (t < 32)       cpa16(base + SM_PAR + (PAR_AOBB + t * 4) * 4,         aob_bias + t * 4);
        else if (t < 64)  cpa16(base + SM_PAR + (PAR_OPB1 + (t - 32) * 4) * 4,  op_b1 + (t - 32) * 4);
        else if (t < 96)  cpa16(base + SM_PAR + (PAR_RB1 + (t - 64) * 4) * 4,   r_b1 + (t - 64) * 4);
        else if (t < 128) cpa16(base + SM_PAR + (PAR_RB2 + (t - 96) * 4) * 4,   r_b2 + (t - 96) * 4);
        else if (t < 160) cpa16(base + SM_PAR + (PAR_LN1G + (t - 128) * 4) * 4, ln1_g + (t - 128) * 4);
        else if (t < 192) cpa16(base + SM_PAR + (PAR_LN1B + (t - 160) * 4) * 4, ln1_b + (t - 160) * 4);
        else if (t < 224) cpa16(base + SM_PAR + (PAR_RLNG + (t - 192) * 4) * 4, rln_g + (t - 192) * 4);
        else              cpa16(base + SM_PAR + (PAR_RLNB + (t - 224) * 4) * 4, rln_b + (t - 224) * 4);

        if (t < 32)       cpa16(base + SM_PAR + (PAR_LN2G + t * 4) * 4,          ln2_g + t * 4);
        else if (t < 64)  cpa16(base + SM_PAR + (PAR_LN2B + (t - 32) * 4) * 4,   ln2_b + (t - 32) * 4);
        else if (t < 160) cpa16(base + SM_PAR + (PAR_W3 + (t - 64) * 4) * 4,     w3 + (t - 64) * 4);
        else if (t < 224) cpa16(base + SM_PAR + (PAR_LNFG + (t - 160) * 4) * 4,  lnf_g + (t - 160) * 4);

        if (t < 64)       cpa16(base + SM_PAR + (PAR_LNFB + t * 4) * 4,          lnf_b + t * 4);
        else if (t < 67)  cpa4(base + SM_PAR + (PAR_LNFG + 256 + (t - 64)) * 4,  lnf_g + 256 + (t - 64));
        else if (t < 70)  cpa4(base + SM_PAR + (PAR_LNFB + 256 + (t - 67)) * 4,  lnf_b + 256 + (t - 67));
        else if (t < 73)  cpa4(base + SM_PAR + (PAR_B3 + (t - 70)) * 4,          b3 + (t - 70));
    }
    asm volatile("cp.async.commit_group;");

    {
        int r = tid >> 3, q = tid & 7;
        int grow = bm * 32 + r;
        int h = q >> 1;
        float L = 0.f;
        #pragma unroll
        for (int sp = 0; sp < KSPLIT; sp++)
            L += lpart[sp * NHEAD * NATOMS + h * NATOMS + grow];
        float inv = 1.f / L;
        const float* o0p = opart + grow * 128 + q * 16;
        uint32_t pk[8];
        #pragma unroll
        for (int i = 0; i < 4; i++) {
            float4 a = *(const float4*)&o0p[4 * i];
            #pragma unroll
            for (int sp = 1; sp < KSPLIT; sp++) {
                float4 b = *(const float4*)&o0p[sp * NATOMS * HDIM + 4 * i];
                a.x += b.x; a.y += b.y; a.z += b.z; a.w += b.w;
            }
            pk[2 * i]     = packbf(a.x * inv, a.y * inv);
            pk[2 * i + 1] = packbf(a.z * inv, a.w * inv);
        }
        uint4* dst = (uint4*)(dsm + SM_ACT + r * ASTR + q * 32);
        dst[0] = *(uint4*)&pk[0];
        dst[1] = *(uint4*)&pk[4];
    }

    asm volatile("cp.async.wait_group 0;");
    __syncthreads();

    const int i7 = lane & 7, sel = lane >> 3;
    const int arow = ((sel & 1) ? 8 : 0) + i7;
    const int acol = (sel >> 1) ? 16 : 0;
    const int vrow = ((sel & 1) ? 8 : 0) + i7;
    const int vcol = (sel >= 2) ? 16 : 0;
    const int htid = tid & 127;
    const int row = htid >> 3, q = htid & 7;
    const int grow = bm * 32 + hb * 16 + row;
    const int sr0 = lane >> 2;
    const int c2 = (lane & 3) * 2;
    const int barid = hb + 1;

    float acc[4][4];
    uint32_t hkeep[8];

    auto do_gemm = [&](int wOff, int ksteps) {
        #pragma unroll
        for (int j = 0; j < 4; j++)
            #pragma unroll
            for (int c = 0; c < 4; c++) acc[j][c] = 0.f;
        for (int ks = 0; ks < ksteps; ks++) {
            #pragma unroll
            for (int kh = 0; kh < 2; kh++) {
                uint32_t qa[4];
                ldsm4(qa[0], qa[1], qa[2], qa[3], aAct + arow * ASTR + ks * 64 + kh * 32 + acol);
                #pragma unroll
                for (int j = 0; j < 2; j++) {
                    uint32_t r0, r1, r2, r3;
                    ldsm4t(r0, r1, r2, r3,
                           base + wOff + (ks * 32 + kh * 16 + vrow) * WSTR + wc * 64 + j * 32 + vcol);
                    mma16816(acc[2 * j],     qa, r0, r1);
                    mma16816(acc[2 * j + 1], qa, r2, r3);
                }
            }
        }
    };

    auto stage = [&](const float* bias) {
        #pragma unroll
        for (int t = 0; t < 4; t++) {
            int col = wc * 32 + t * 8 + c2;
            float a0 = bias[col], a1 = bias[col + 1];
            sSh[sr0 * 136 + col] = acc[t][0] + a0;       sSh[sr0 * 136 + col + 1] = acc[t][1] + a1;
            sSh[(sr0 + 8) * 136 + col] = acc[t][2] + a0; sSh[(sr0 + 8) * 136 + col + 1] = acc[t][3] + a1;
        }
    };

    do_gemm(SM_WAO, 4);
    stage(par + PAR_AOBB);
    barh(barid);
    {
        int bi = bidx[grow];
        float xv[16], cv[16];
        #pragma unroll
        for (int i = 0; i < 4; i++) {
            float4 f = *(const float4*)&sSh[row * 136 + q * 16 + i * 4];
            xv[4 * i] = f.x; xv[4 * i + 1] = f.y; xv[4 * i + 2] = f.z; xv[4 * i + 3] = f.w;
            float4 c = *(const float4*)&cf[bi * 128 + q * 16 + i * 4];
            cv[4 * i] = c.x; cv[4 * i + 1] = c.y; cv[4 * i + 2] = c.z; cv[4 * i + 3] = c.w;
        }
        float c0 = 0.f, c1 = 0.f, c2v = 0.f;
        float s = 0.f;
        #pragma unroll
        for (int i = 0; i < 16; i++) s += xv[i] + cv[i];
        if (q == 0) {
            c0 = coordp[grow * 3 + 0]; c1 = coordp[grow * 3 + 1]; c2v = coordp[grow * 3 + 2];
            s += c0 + c1 + c2v;
        }
        s += __shfl_xor_sync(0xffffffffu, s, 1);
        s += __shfl_xor_sync(0xffffffffu, s, 2);
        s += __shfl_xor_sync(0xffffffffu, s, 4);
        float mean = s * (1.f / 259.f);
        float sq = 0.f;
        #pragma unroll
        for (int i = 0; i < 16; i++) {
            float d0 = xv[i] - mean, d1 = cv[i] - mean;
            sq += d0 * d0 + d1 * d1;
        }
        if (q == 0) {
            float d0 = c0 - mean, d1 = c1 - mean, d2 = c2v - mean;
            sq += d0 * d0 + d1 * d1 + d2 * d2;
        }
        sq += __shfl_xor_sync(0xffffffffu, sq, 1);
        sq += __shfl_xor_sync(0xffffffffu, sq, 2);
        sq += __shfl_xor_sync(0xffffffffu, sq, 4);
        float inv = rsqrtf(sq * (1.f / 259.f) + 1e-5f);

        uint32_t pk[8];
        #pragma unroll
        for (int i = 0; i < 8; i++) {
            int ca = q * 16 + 2 * i;
            pk[i] = packbf((xv[2 * i] - mean) * inv * par[PAR_LNFG + ca] + par[PAR_LNFB + ca],
                           (xv[2 * i + 1] - mean) * inv * par[PAR_LNFG + ca + 1] + par[PAR_LNFB + ca + 1]);
        }
        uint4* dst = (uint4*)(dsm + SM_ACT + (hb * 16 + row) * ASTR + q * 32);
        dst[0] = *(uint4*)&pk[0]; dst[1] = *(uint4*)&pk[4];
        #pragma unroll
        for (int i = 0; i < 8; i++) {
            int ca = 128 + q * 16 + 2 * i;
            pk[i] = packbf((cv[2 * i] - mean) * inv * par[PAR_LNFG + ca] + par[PAR_LNFB + ca],
                           (cv[2 * i + 1] - mean) * inv * par[PAR_LNFG + ca + 1] + par[PAR_LNFB + ca + 1]);
        }
        dst = (uint4*)(dsm + SM_ACT + (hb * 16 + row) * ASTR + 256 + q * 32);
        dst[0] = *(uint4*)&pk[0]; dst[1] = *(uint4*)&pk[4];
        uint32_t tp0 = 0, tp1 = 0;
        if (q == 0) {
            tp0 = packbf((c0 - mean) * inv * par[PAR_LNFG + 256] + par[PAR_LNFB + 256],
                         (c1 - mean) * inv * par[PAR_LNFG + 257] + par[PAR_LNFB + 257]);
            tp1 = packbf((c2v - mean) * inv * par[PAR_LNFG + 258] + par[PAR_LNFB + 258], 0.f);
        }
        *(uint2*)(dsm + SM_ACT + (hb * 16 + row) * ASTR + 512 + q * 8) = make_uint2(tp0, tp1);
    }
    barh(barid);

    do_gemm(SM_WOP1, 9);
    stage(par + PAR_OPB1);
    barh(barid);
    {
        float v[16];
        #pragma unroll
        for (int i = 0; i < 4; i++) {
            float4 f = *(const float4*)&sSh[row * 136 + q * 16 + i * 4];
            v[4 * i] = f.x; v[4 * i + 1] = f.y; v[4 * i + 2] = f.z; v[4 * i + 3] = f.w;
        }
        float s = 0.f;
        #pragma unroll
        for (int i = 0; i < 16; i++) s += v[i];
        s += __shfl_xor_sync(0xffffffffu, s, 1);
        s += __shfl_xor_sync(0xffffffffu, s, 2);
        s += __shfl_xor_sync(0xffffffffu, s, 4);
        float mean = s * (1.f / 128.f);
        float sq = 0.f;
        #pragma unroll
        for (int i = 0; i < 16; i++) { float d = v[i] - mean; sq += d * d; }
        sq += __shfl_xor_sync(0xffffffffu, sq, 1);
        sq += __shfl_xor_sync(0xffffffffu, sq, 2);
        sq += __shfl_xor_sync(0xffffffffu, sq, 4);
        float inv = rsqrtf(sq * (1.f / 128.f) + 1e-5f);
        #pragma unroll
        for (int i = 0; i < 8; i++) {
            int ca = q * 16 + 2 * i;
            float y0 = silu_f((v[2 * i] - mean) * inv * par[PAR_LN1G + ca] + par[PAR_LN1B + ca]);
            float y1 = silu_f((v[2 * i + 1] - mean) * inv * par[PAR_LN1G + ca + 1] + par[PAR_LN1B + ca + 1]);
            hkeep[i] = packbf(y0, y1);
        }
        uint4* dst = (uint4*)(dsm + SM_ACT + (hb * 16 + row) * ASTR + q * 32);
        dst[0] = *(uint4*)&hkeep[0]; dst[1] = *(uint4*)&hkeep[4];
    }
    barh(barid);

    do_gemm(SM_WR1, 4);
    stage(par + PAR_RB1);
    barh(barid);
    {
        float v[16];
        #pragma unroll
        for (int i = 0; i < 4; i++) {
            float4 f = *(const float4*)&sSh[row * 136 + q * 16 + i * 4];
            v[4 * i] = f.x; v[4 * i + 1] = f.y; v[4 * i + 2] = f.z; v[4 * i + 3] = f.w;
        }
        float s = 0.f;
        #pragma unroll
        for (int i = 0; i < 16; i++) s += v[i];
        s += __shfl_xor_sync(0xffffffffu, s, 1);
        s += __shfl_xor_sync(0xffffffffu, s, 2);
        s += __shfl_xor_sync(0xffffffffu, s, 4);
        float mean = s * (1.f / 128.f);
        float sq = 0.f;
        #pragma unroll
        for (int i = 0; i < 16; i++) { float d = v[i] - mean; sq += d * d; }
        sq += __shfl_xor_sync(0xffffffffu, sq, 1);
        sq += __shfl_xor_sync(0xffffffffu, sq, 2);
        sq += __shfl_xor_sync(0xffffffffu, sq, 4);
        float inv = rsqrtf(sq * (1.f / 128.f) + 1e-5f);
        uint32_t pk[8];
        #pragma unroll
        for (int i = 0; i < 8; i++) {
            int ca = q * 16 + 2 * i;
            float y0 = silu_f((v[2 * i] - mean) * inv * par[PAR_RLNG + ca] + par[PAR_RLNB + ca]);
            float y1 = silu_f((v[2 * i + 1] - mean) * inv * par[PAR_RLNG + ca + 1] + par[PAR_RLNB + ca + 1]);
            pk[i] = packbf(y0, y1);
        }
        uint4* dst = (uint4*)(dsm + SM_ACT + (hb * 16 + row) * ASTR + q * 32);
        dst[0] = *(uint4*)&pk[0]; dst[1] = *(uint4*)&pk[4];
    }
    barh(barid);

    do_gemm(SM_WR2, 4);
    stage(par + PAR_RB2);
    barh(barid);
    {
        float v[16];
        #pragma unroll
        for (int i = 0; i < 4; i++) {
            float4 f = *(const float4*)&sSh[row * 136 + q * 16 + i * 4];
            v[4 * i] = f.x; v[4 * i + 1] = f.y; v[4 * i + 2] = f.z; v[4 * i + 3] = f.w;
        }
        #pragma unroll
        for (int i = 0; i < 8; i++) {
            __nv_bfloat162 hh = *(__nv_bfloat162*)&hkeep[i];
            v[2 * i]     += __bfloat162float(hh.x);
            v[2 * i + 1] += __bfloat162float(hh.y);
        }
        float s = 0.f;
        #pragma unroll
        for (int i = 0; i < 16; i++) s += v[i];
        s += __shfl_xor_sync(0xffffffffu, s, 1);
        s += __shfl_xor_sync(0xffffffffu, s, 2);
        s += __shfl_xor_sync(0xffffffffu, s, 4);
        float mean = s * (1.f / 128.f);
        float sq = 0.f;
        #pragma unroll
        for (int i = 0; i < 16; i++) { float d = v[i] - mean; sq += d * d; }
        sq += __shfl_xor_sync(0xffffffffu, sq, 1);
        sq += __shfl_xor_sync(0xffffffffu, sq, 2);
        sq += __shfl_xor_sync(0xffffffffu, sq, 4);
        float inv = rsqrtf(sq * (1.f / 128.f) + 1e-5f);

        float p0 = 0.f, p1 = 0.f, p2 = 0.f;
        #pragma unroll
        for (int i = 0; i < 16; i++) {
            int ca = q * 16 + i;
            float y = (v[i] - mean) * inv * par[PAR_LN2G + ca] + par[PAR_LN2B + ca];
            p0 += y * par[PAR_W3 + ca * 3 + 0];
            p1 += y * par[PAR_W3 + ca * 3 + 1];
            p2 += y * par[PAR_W3 + ca * 3 + 2];
        }
        p0 += __shfl_xor_sync(0xffffffffu, p0, 1);
        p0 += __shfl_xor_sync(0xffffffffu, p0, 2);
        p0 += __shfl_xor_sync(0xffffffffu, p0, 4);
        p1 += __shfl_xor_sync(0xffffffffu, p1, 1);
        p1 += __shfl_xor_sync(0xffffffffu, p1, 2);
        p1 += __shfl_xor_sync(0xffffffffu, p1, 4);
        p2 += __shfl_xor_sync(0xffffffffu, p2, 1);
        p2 += __shfl_xor_sync(0xffffffffu, p2, 2);
        p2 += __shfl_xor_sync(0xffffffffu, p2, 4);
        if (q == 0) {
            int bi = bidx[grow];
            float dots[3] = {p0 + par[PAR_B3 + 0], p1 + par[PAR_B3 + 1], p2 + par[PAR_B3 + 2]};
            #pragma unroll
            for (int j = 0; j < 3; j++) {
                float val = coordp[grow * 3 + j] + 0.01f * tanhf(dots[j]);
                fout[grow * 3 + j] = fminf(fmaxf(val, bmin[bi * 3 + j]), bmax[bi * 3 + j]);
            }
        }
    }
}

// ======== flash: fp8 QK (m16n8k32), bf16 PV, 128 q-rows/CTA, K-split ========
#define QSTRIDE 48       // 32 fp8 + pad
#define VSTRIDE 80       // 32 bf16 + pad
#define QBUF    6144     // 128 rows * 48
#define KB8     6144     // K tile fp8: 128 * 48
#define VB16    10240    // V tile bf16: 128 * 80
#define KVPAIR  (KB8 + VB16)
#define NITER   (32 / KSPLIT)

__device__ __forceinline__ void kv_load128(const uint8_t* __restrict__ Kf,
                                           const __nv_bfloat16* __restrict__ Vh,
                                           int h, int kb, uint32_t sbase, int tid) {
    // K: 128 rows x 32B fp8
    #pragma unroll
    for (int i = 0; i < 2; i++) {
        cpa16(sbase + tid * QSTRIDE + i * 16,
              Kf + (((h << 12) + (kb << 7) + tid) << 5) + i * 16);
    }
    // V: 128 rows x 64B bf16
    #pragma unroll
    for (int i = 0; i < 4; i++) {
        cpa16(sbase + KB8 + tid * VSTRIDE + i * 16,
              Vh + (((h << 12) + (kb << 7) + tid) << 5) + i * 8);
    }
    asm volatile("cp.async.commit_group;");
}

__global__ void __launch_bounds__(128) flashb_k(const uint8_t* __restrict__ Qf,
                                                const uint8_t* __restrict__ Kf,
                                                const __nv_bfloat16* __restrict__ Vh,
                                                float* __restrict__ opart,
                                                float* __restrict__ lpart) {
    __shared__ __align__(16) char smem[QBUF + 2 * KVPAIR];
    const int tid = threadIdx.x, lane = tid & 31, warp = tid >> 5;
    const int h = blockIdx.y, qb = blockIdx.x, sp = blockIdx.z;
    const int kb0 = sp * NITER;

    uint32_t Qsa = (uint32_t)__cvta_generic_to_shared(smem);
    uint32_t kva0 = Qsa + QBUF;
    uint32_t kva1 = Qsa + QBUF + KVPAIR;

    // load 128 Q rows (fp8, 32B each)
    #pragma unroll
    for (int i = 0; i < 2; i++) {
        int s = tid + i * 128;
        int row = s >> 1, seg = s & 1;
        uint4 v = *(const uint4*)(Qf + (((h << 12) + (qb << 7) + row) << 5) + seg * 16);
        *(uint4*)(smem + row * QSTRIDE + seg * 16) = v;
    }
    kv_load128(Kf, Vh, h, kb0 + 0, kva0, tid);
    kv_load128(Kf, Vh, h, kb0 + 1, kva1, tid);
    __syncthreads();

    // Q fragments: 2 m16-tiles per warp, k32 each (4 regs per tile)
    uint32_t qa[8];
    {
        int i = lane & 7, sl = lane >> 3;
        #pragma unroll
        for (int mt = 0; mt < 2; mt++) {
            int row = warp * 32 + mt * 16 + ((sl & 1) ? 8 : 0) + i;
            uint32_t a = Qsa + row * QSTRIDE + ((sl >> 1) ? 16 : 0);
            ldsm4(qa[mt * 4 + 0], qa[mt * 4 + 1], qa[mt * 4 + 2], qa[mt * 4 + 3], a);
        }
    }

    float l00 = 0.f, l01 = 0.f, l10 = 0.f, l11 = 0.f;
    float o0[4][4], o1[4][4];
    #pragma unroll
    for (int j = 0; j < 4; j++)
        #pragma unroll
        for (int c = 0; c < 4; c++) { o0[j][c] = 0.f; o1[j][c] = 0.f; }

    const int i7 = lane & 7, sel = lane >> 3;
    const uint32_t krow = ((sel >= 2) ? 8 : 0) + i7;
    const uint32_t kcol = (sel & 1) ? 16 : 0;
    const uint32_t vrow = ((sel & 1) ? 8 : 0) + i7;
    const uint32_t vcol = (sel >= 2) ? 16 : 0;

    for (int kb = 0; kb < NITER; kb++) {
        if (kb < NITER - 1) asm volatile("cp.async.wait_group 1;");
        else                asm volatile("cp.async.wait_group 0;");
        __syncthreads();
        uint32_t Kbase = (kb & 1) ? kva1 : kva0;
        uint32_t Vbase = Kbase + KB8;

        #pragma unroll
        for (int ks = 0; ks < 8; ks++) {
            // K fragments: one ldsm covers both n8 tiles x full k32 (fp8)
            uint32_t a = Kbase + (ks * 16 + krow) * QSTRIDE + kcol;
            uint32_t b0, b1, b2, b3;
            ldsm4(b0, b1, b2, b3, a);

            float s00[4] = {0.f, 0.f, 0.f, 0.f}, s01[4] = {0.f, 0.f, 0.f, 0.f};
            float s10[4] = {0.f, 0.f, 0.f, 0.f}, s11[4] = {0.f, 0.f, 0.f, 0.f};
            mma16832(s00, qa,     b0, b1);
            mma16832(s01, qa,     b2, b3);
            mma16832(s10, qa + 4, b0, b1);
            mma16832(s11, qa + 4, b2, b3);

            uint32_t e00 = schexp(s00[0]), e01 = schexp(s00[1]);
            uint32_t e02 = schexp(s00[2]), e03 = schexp(s00[3]);
            uint32_t f00 = schexp(s01[0]), f01 = schexp(s01[1]);
            uint32_t f02 = schexp(s01[2]), f03 = schexp(s01[3]);
            uint32_t e10 = schexp(s10[0]), e11 = schexp(s10[1]);
            uint32_t e12 = schexp(s10[2]), e13 = schexp(s10[3]);
            uint32_t f10 = schexp(s11[0]), f11 = schexp(s11[1]);
            uint32_t f12 = schexp(s11[2]), f13 = schexp(s11[3]);

            l00 += (__int_as_float(e00) + __int_as_float(e01))
                 + (__int_as_float(f00) + __int_as_float(f01));
            l01 += (__int_as_float(e02) + __int_as_float(e03))
                 + (__int_as_float(f02) + __int_as_float(f03));
            l10 += (__int_as_float(e10) + __int_as_float(e11))
                 + (__int_as_float(f10) + __int_as_float(f11));
            l11 += (__int_as_float(e12) + __int_as_float(e13))
                 + (__int_as_float(f12) + __int_as_float(f13));

            uint32_t pa0[4], pa1[4];
            pa0[0] = prmt16(e00, e01); pa0[1] = prmt16(e02, e03);
            pa0[2] = prmt16(f00, f01); pa0[3] = prmt16(f02, f03);
            pa1[0] = prmt16(e10, e11); pa1[1] = prmt16(e12, e13);
            pa1[2] = prmt16(f10, f11); pa1[3] = prmt16(f12, f13);

            uint32_t av = Vbase + (ks * 16 + vrow) * VSTRIDE + vcol;
            uint32_t v0, v1, v2, v3, w0, w1, w2, w3;
            ldsm4t(v0, v1, v2, v3, av);
            ldsm4t(w0, w1, w2, w3, av + 32);
            mma16816(o0[0], pa0, v0, v1);
            mma16816(o0[1], pa0, v2, v3);
            mma16816(o0[2], pa0, w0, w1);
            mma16816(o0[3], pa0, w2, w3);
            mma16816(o1[0], pa1, v0, v1);
            mma16816(o1[1], pa1, v2, v3);
            mma16816(o1[2], pa1, w0, w1);
            mma16816(o1[3], pa1, w2, w3);
        }

        __syncthreads();
        if (kb < NITER - 2) kv_load128(Kf, Vh, h, kb0 + kb + 2, (kb & 1) ? kva1 : kva0, tid);
    }

    l00 += __shfl_xor_sync(0xffffffffu, l00, 1);
    l00 += __shfl_xor_sync(0xffffffffu, l00, 2);
    l01 += __shfl_xor_sync(0xffffffffu, l01, 1);
    l01 += __shfl_xor_sync(0xffffffffu, l01, 2);
    l10 += __shfl_xor_sync(0xffffffffu, l10, 1);
    l10 += __shfl_xor_sync(0xffffffffu, l10, 2);
    l11 += __shfl_xor_sync(0xffffffffu, l11, 1);
    l11 += __shfl_xor_sync(0xffffffffu, l11, 2);

    int g = lane >> 2, l2 = (lane & 3) * 2;
    int row0 = (qb << 7) + warp * 32 + g;
    float* op = opart + sp * NATOMS * HDIM;
    #pragma unroll
    for (int j = 0; j < 4; j++) {
        int col = (h << 5) + j * 8 + l2;
        *(float2*)&op[row0 * HDIM + col]        = make_float2(o0[j][0], o0[j][1]);
        *(float2*)&op[(row0 + 8) * HDIM + col]  = make_float2(o0[j][2], o0[j][3]);
        *(float2*)&op[(row0 + 16) * HDIM + col] = make_float2(o1[j][0], o1[j][1]);
        *(float2*)&op[(row0 + 24) * HDIM + col] = make_float2(o1[j][2], o1[j][3]);
    }
    if ((lane & 3) == 0) {
        float* lp = lpart + sp * NHEAD * NATOMS + h * NATOMS;
        lp[row0]      = l00;
        lp[row0 + 8]  = l01;
        lp[row0 + 16] = l10;
        lp[row0 + 24] = l11;
    }
}

// ---------------- host ----------------
extern "C" void kernel_launch(void* const* d_in, const int* in_sizes, int n_in,
                              void* d_out, int out_size) {
    const int*   num_atoms  = (const int*)d_in[0];
    const int*   elems      = (const int*)d_in[1];
    const float* cell       = (const float*)d_in[2];
    const float* coord      = (const float*)d_in[3];
    const float* emb        = (const float*)d_in[4];
    const float* ln_in_g    = (const float*)d_in[5];
    const float* ln_in_b    = (const float*)d_in[6];
    const float* attn_in_w  = (const float*)d_in[7];
    const float* attn_in_b  = (const float*)d_in[8];
    const float* attn_out_w = (const float*)d_in[9];
    const float* attn_out_b = (const float*)d_in[10];
    const float* ce_w1      = (const float*)d_in[11];
    const float* ce_b1      = (const float*)d_in[12];
    const float* ce_w2      = (const float*)d_in[13];
    const float* ce_b2      = (const float*)d_in[14];
    const float* ln_feat_g  = (const float*)d_in[15];
    const float* ln_feat_b  = (const float*)d_in[16];
    const float* op_w1      = (const float*)d_in[17];
    const float* op_b1      = (const float*)d_in[18];
    const float* op_ln1_g   = (const float*)d_in[19];
    const float* op_ln1_b   = (const float*)d_in[20];
    const float* res_w1     = (const float*)d_in[21];
    const float* res_b1     = (const float*)d_in[22];
    const float* res_ln_g   = (const float*)d_in[23];
    const float* res_ln_b   = (const float*)d_in[24];
    const float* res_w2     = (const float*)d_in[25];
    const float* res_b2     = (const float*)d_in[26];
    const float* op_ln2_g   = (const float*)d_in[27];
    const float* op_ln2_b   = (const float*)d_in[28];
    const float* op_w3      = (const float*)d_in[29];
    const float* op_b3      = (const float*)d_in[30];
    float* out = (float*)d_out;

    float* S = nullptr;
    cudaGetSymbolAddress((void**)&S, g_scratch);
    int* bidx = nullptr;
    cudaGetSymbolAddress((void**)&bidx, g_bidx);

    __nv_bfloat16* P = (__nv_bfloat16*)S;
    __nv_bfloat16* xb    = P; P += NATOMS * HDIM;
    __nv_bfloat16* Vh    = P; P += NATOMS * HDIM;
    __nv_bfloat16* wqkv  = P; P += 128 * 384;
    __nv_bfloat16* wao   = P; P += 128 * 128;
    __nv_bfloat16* wop1  = P; P += FPAD * 128;
    __nv_bfloat16* wr1   = P; P += 128 * 128;
    __nv_bfloat16* wr2   = P; P += 128 * 128;
    uint8_t* U = (uint8_t*)P;
    uint8_t* Qf = U; U += NATOMS * HDIM;      // fp8, 512KB
    uint8_t* Kf = U; U += NATOMS * HDIM;
    // align to 16
    U = (uint8_t*)(((uintptr_t)U + 15) & ~(uintptr_t)15);
    float* F = (float*)U;
    float* opart = F; F += KSPLIT * NATOMS * HDIM;
    float* lpart = F; F += KSPLIT * NHEAD * NATOMS;
    float* cf    = F; F += BATCH * HDIM;
    float* bmin  = F; F += BATCH * 3;
    float* bmax  = F; F += BATCH * 3;

    static bool attr_set = false;
    if (!attr_set) {
        cudaFuncSetAttribute(tail_k, cudaFuncAttributeMaxDynamicSharedMemorySize, SMEM_TAIL);
        attr_set = true;
    }

    setup_k<<<1049, 256>>>(elems, emb, ln_in_g, ln_in_b, xb,
                           attn_in_w, attn_out_w, op_w1, res_w1, res_w2,
                           wqkv, wao, wop1, wr1, wr2,
                           cell, ce_w1, ce_b1, ce_w2, ce_b2, cf,
                           num_atoms, bmin, bmax);

    qkv_k<<<dim3(3, 128), 128>>>(xb, wqkv, attn_in_b, Qf, Kf, Vh);

    flashb_k<<<dim3(32, NHEAD, KSPLIT), 128>>>(Qf, Kf, Vh, opart, lpart);

    tail_k<<<128, 256, SMEM_TAIL>>>(opart, lpart,
        wao, attn_out_b, ln_feat_g, ln_feat_b, cf, coord, bidx,
        wop1, op_b1, op_ln1_g, op_ln1_b,
        wr1, res_b1, res_ln_g, res_ln_b,
        wr2, res_b2, op_ln2_g, op_ln2_b,
        op_w3, op_b3, bmin, bmax, out);
}

// round 12
// speedup vs baseline: 7.6535x; 1.0254x over previous
#include <cuda_runtime.h>
#include <cuda_bf16.h>
#include <math.h>
#include <stdint.h>

#define NATOMS 4096
#define HDIM   128
#define BATCH  128
#define NHEAD  4
#define DHEAD  32
#define H3     384
#define FPAD   288
#define KSPLIT 4

// -------- scratch (no allocations allowed) --------
__device__ float g_scratch[8300000];
__device__ int   g_bidx[NATOMS];

// ---------------- helpers ----------------
__device__ __forceinline__ float silu_f(float x) {
    return x / (1.f + __expf(-x));
}
__device__ __forceinline__ void ldsm4(uint32_t& r0, uint32_t& r1, uint32_t& r2, uint32_t& r3, uint32_t addr) {
    asm volatile("ldmatrix.sync.aligned.m8n8.x4.shared.b16 {%0,%1,%2,%3}, [%4];"
                 : "=r"(r0), "=r"(r1), "=r"(r2), "=r"(r3) : "r"(addr));
}
__device__ __forceinline__ void ldsm4t(uint32_t& r0, uint32_t& r1, uint32_t& r2, uint32_t& r3, uint32_t addr) {
    asm volatile("ldmatrix.sync.aligned.m8n8.x4.trans.shared.b16 {%0,%1,%2,%3}, [%4];"
                 : "=r"(r0), "=r"(r1), "=r"(r2), "=r"(r3) : "r"(addr));
}
__device__ __forceinline__ void mma16816(float* d, const uint32_t* a, uint32_t b0, uint32_t b1) {
    asm volatile("mma.sync.aligned.m16n8k16.row.col.f32.bf16.bf16.f32 "
                 "{%0,%1,%2,%3}, {%4,%5,%6,%7}, {%8,%9}, {%0,%1,%2,%3};"
                 : "+f"(d[0]), "+f"(d[1]), "+f"(d[2]), "+f"(d[3])
                 : "r"(a[0]), "r"(a[1]), "r"(a[2]), "r"(a[3]), "r"(b0), "r"(b1));
}
__device__ __forceinline__ void mma16832(float* d, const uint32_t* a, uint32_t b0, uint32_t b1) {
    asm volatile("mma.sync.aligned.m16n8k32.row.col.f32.e4m3.e4m3.f32 "
                 "{%0,%1,%2,%3}, {%4,%5,%6,%7}, {%8,%9}, {%0,%1,%2,%3};"
                 : "+f"(d[0]), "+f"(d[1]), "+f"(d[2]), "+f"(d[3])
                 : "r"(a[0]), "r"(a[1]), "r"(a[2]), "r"(a[3]), "r"(b0), "r"(b1));
}
__device__ __forceinline__ uint32_t packbf(float lo, float hi) {
    uint32_t r;
    asm volatile("cvt.rn.bf16x2.f32 %0, %1, %2;" : "=r"(r) : "f"(hi), "f"(lo));
    return r;
}
__device__ __forceinline__ uint16_t packe4(float lo, float hi) {
    uint16_t r;
    asm volatile("cvt.rn.satfinite.e4m3x2.f32 %0, %1, %2;" : "=h"(r) : "f"(hi), "f"(lo));
    return r;
}
__device__ __forceinline__ void cpa16(uint32_t dst, const void* src) {
    asm volatile("cp.async.ca.shared.global [%0], [%1], 16;" :: "r"(dst), "l"(src));
}
__device__ __forceinline__ void cpa4(uint32_t dst, const void* src) {
    asm volatile("cp.async.ca.shared.global [%0], [%1], 4;" :: "r"(dst), "l"(src));
}
__device__ __forceinline__ void barh(int id) {
    asm volatile("bar.sync %0, 256;" :: "r"(id) : "memory");
}
__device__ __forceinline__ uint32_t schexp(float x) {
    int i;
    asm("cvt.rni.s32.f32 %0, %1;" : "=r"(i) : "f"(fmaf(x, 8388608.f, 1064876800.f)));
    return (uint32_t)i;
}
__device__ __forceinline__ uint32_t prmt16(uint32_t a, uint32_t b) {
    uint32_t r;
    asm("prmt.b32 %0,%1,%2,0x7632;" : "=r"(r) : "r"(a), "r"(b));
    return r;
}

// ================= fused setup kernel =================
__global__ void __launch_bounds__(256) setup_k(
    const int* __restrict__ elems, const float* __restrict__ emb,
    const float* __restrict__ ln_in_g, const float* __restrict__ ln_in_b,
    __nv_bfloat16* __restrict__ xo,
    const float* __restrict__ aiw, const float* __restrict__ aow,
    const float* __restrict__ opw1, const float* __restrict__ rw1,
    const float* __restrict__ rw2,
    __nv_bfloat16* __restrict__ wqkv, __nv_bfloat16* __restrict__ wao,
    __nv_bfloat16* __restrict__ wop1, __nv_bfloat16* __restrict__ wr1,
    __nv_bfloat16* __restrict__ wr2,
    const float* __restrict__ cell,
    const float* __restrict__ cw1, const float* __restrict__ cb1,
    const float* __restrict__ cw2, const float* __restrict__ cb2,
    float* __restrict__ cf,
    const int* __restrict__ num_atoms,
    float* __restrict__ bmin, float* __restrict__ bmax)
{
    const int b = blockIdx.x, tid = threadIdx.x;

    if (b < 512) {
        int warp = tid >> 5, lane = tid & 31;
        int r = b * 8 + warp;
        int e = elems[r];
        float4 v = *(const float4*)&emb[e * HDIM + lane * 4];
        float s = v.x + v.y + v.z + v.w;
        #pragma unroll
        for (int off = 16; off > 0; off >>= 1) s += __shfl_xor_sync(0xffffffffu, s, off);
        float mean = s * (1.f / 128.f);
        float dx = v.x - mean, dy = v.y - mean, dz = v.z - mean, dw = v.w - mean;
        float sq = dx * dx + dy * dy + dz * dz + dw * dw;
        #pragma unroll
        for (int off = 16; off > 0; off >>= 1) sq += __shfl_xor_sync(0xffffffffu, sq, off);
        float inv = rsqrtf(sq * (1.f / 128.f) + 1e-5f);
        float4 gg = *(const float4*)&ln_in_g[lane * 4];
        float4 bb = *(const float4*)&ln_in_b[lane * 4];
        uint32_t p0 = packbf(dx * inv * gg.x + bb.x, dy * inv * gg.y + bb.y);
        uint32_t p1 = packbf(dz * inv * gg.z + bb.z, dw * inv * gg.w + bb.w);
        *(uint2*)(xo + r * HDIM + lane * 4) = make_uint2(p0, p1);
        return;
    }

    if (b < 1040) {
        int i = (b - 512) * 256 + tid;
        if (i < 49152) wqkv[i] = __float2bfloat16(aiw[i]);
        else if (i < 65536) { int j = i - 49152; wao[j] = __float2bfloat16(aow[j]); }
        else if (i < 102400) {
            int j = i - 65536; int r = j >> 7, c = j & 127;
            wop1[j] = __float2bfloat16(r < 259 ? opw1[r * 128 + c] : 0.f);
        }
        else if (i < 118784) { int j = i - 102400; wr1[j] = __float2bfloat16(rw1[j]); }
        else { int j = i - 118784; wr2[j] = __float2bfloat16(rw2[j]); }
        return;
    }

    if (b < 1048) {
        __shared__ float t1s[16][128];
        int r0 = (b - 1040) * 16;
        #pragma unroll
        for (int i = 0; i < 8; i++) {
            int idx = tid + i * 256;
            int rr = idx >> 7, k = idx & 127;
            int r = r0 + rr;
            float u = cell[r * 3 + 0] * cw1[k] + cell[r * 3 + 1] * cw1[128 + k]
                    + cell[r * 3 + 2] * cw1[256 + k] + cb1[k];
            t1s[rr][k] = silu_f(u);
        }
        __syncthreads();
        int t = tid & 127, half = tid >> 7;
        float acc[8];
        #pragma unroll
        for (int j = 0; j < 8; j++) acc[j] = cb2[t];
        #pragma unroll 4
        for (int k = 0; k < 128; k++) {
            float w = cw2[k * 128 + t];
            #pragma unroll
            for (int j = 0; j < 8; j++) acc[j] += t1s[half * 8 + j][k] * w;
        }
        #pragma unroll
        for (int j = 0; j < 8; j++) cf[(r0 + half * 8 + j) * 128 + t] = acc[j];
        return;
    }

    __shared__ int starts[BATCH + 1];
    if (tid == 0) {
        int acc = 0;
        for (int i = 0; i < BATCH; i++) { starts[i] = acc; acc += num_atoms[i]; }
        starts[BATCH] = acc;
    }
    __syncthreads();
    for (int i = tid; i < NATOMS; i += 256) g_bidx[i] = BATCH - 1;
    __syncthreads();
    if (tid < BATCH) {
        int s = starts[tid], e = starts[tid + 1];
        if (s > NATOMS) s = NATOMS;
        if (e > NATOMS) e = NATOMS;
        for (int i = s; i < e; i++) g_bidx[i] = tid;
        #pragma unroll
        for (int i = 0; i < 3; i++) {
            float a = cell[(3 * tid + i) * 3 + 0];
            float c1 = cell[(3 * tid + i) * 3 + 1];
            float c = cell[(3 * tid + i) * 3 + 2];
            bmin[tid * 3 + i] = fminf(a, fminf(c1, c)) + 1e-6f;
            bmax[tid * 3 + i] = fmaxf(a, fmaxf(c1, c)) - 1e-6f;
        }
    }
}

// ================= QKV GEMM: Q,K -> e4m3 (scaled), V -> bf16 =================
__global__ void __launch_bounds__(128) qkv_k(
    const __nv_bfloat16* __restrict__ A, const __nv_bfloat16* __restrict__ W,
    const float* __restrict__ bias,
    uint8_t* __restrict__ Qf, uint8_t* __restrict__ Kf,
    __nv_bfloat16* __restrict__ Vh)
{
    __shared__ __align__(16) char sA[2 * 32 * 80];
    __shared__ __align__(16) char sW[2 * 32 * 272];
    const int tid = threadIdx.x, lane = tid & 31, warp = tid >> 5;
    const int wr = warp & 1, wc = warp >> 1;
    const int bm = blockIdx.y, nb = blockIdx.x;
    uint32_t aBase = (uint32_t)__cvta_generic_to_shared(sA);
    uint32_t wBase = (uint32_t)__cvta_generic_to_shared(sW);

    #pragma unroll
    for (int p = 0; p < 2; p++) {
        int row = tid >> 2, seg = tid & 3;
        cpa16(aBase + p * 2560 + row * 80 + seg * 16,
              A + (bm * 32 + row) * 128 + p * 32 + seg * 8);
        #pragma unroll
        for (int i = 0; i < 4; i++) {
            int s = tid + i * 128;
            int wrow = s >> 4, wseg = s & 15;
            cpa16(wBase + p * 8704 + wrow * 272 + wseg * 16,
                  W + (p * 32 + wrow) * H3 + nb * 128 + wseg * 8);
        }
        asm volatile("cp.async.commit_group;");
    }

    float acc[8][4];
    #pragma unroll
    for (int j = 0; j < 8; j++)
        #pragma unroll
        for (int c = 0; c < 4; c++) acc[j][c] = 0.f;

    const int i7 = lane & 7, sel = lane >> 3;
    const int arow = wr * 16 + ((sel & 1) ? 8 : 0) + i7;
    const int acol = (sel >> 1) ? 16 : 0;
    const int vrow = ((sel & 1) ? 8 : 0) + i7;
    const int vcol = (sel >= 2) ? 16 : 0;

    for (int ks = 0; ks < 4; ks++) {
        if (ks < 3) asm volatile("cp.async.wait_group 1;");
        else        asm volatile("cp.async.wait_group 0;");
        __syncthreads();
        uint32_t Ab = aBase + (ks & 1) * 2560;
        uint32_t Wb = wBase + (ks & 1) * 8704;
        #pragma unroll
        for (int kh = 0; kh < 2; kh++) {
            uint32_t qa[4];
            ldsm4(qa[0], qa[1], qa[2], qa[3], Ab + arow * 80 + acol + kh * 32);
            #pragma unroll
            for (int j = 0; j < 4; j++) {
                uint32_t r0, r1, r2, r3;
                ldsm4t(r0, r1, r2, r3, Wb + (kh * 16 + vrow) * 272 + wc * 128 + j * 32 + vcol);
                mma16816(acc[2 * j],     qa, r0, r1);
                mma16816(acc[2 * j + 1], qa, r2, r3);
            }
        }
        __syncthreads();
        if (ks + 2 < 4) {
            int p = ks + 2, buf = ks & 1;
            int row = tid >> 2, seg = tid & 3;
            cpa16(aBase + buf * 2560 + row * 80 + seg * 16,
                  A + (bm * 32 + row) * 128 + p * 32 + seg * 8);
            #pragma unroll
            for (int i = 0; i < 4; i++) {
                int s = tid + i * 128;
                int wrow = s >> 4, wseg = s & 15;
                cpa16(wBase + buf * 8704 + wrow * 272 + wseg * 16,
                      W + (p * 32 + wrow) * H3 + nb * 128 + wseg * 8);
            }
            asm volatile("cp.async.commit_group;");
        }
    }

    const int g = lane >> 2, c2 = (lane & 3) * 2;
    int r0 = bm * 32 + wr * 16 + g;
    const float SC = 0.50507248f;   // sqrt(scale * log2e)
    if (nb < 2) {
        uint8_t* outp = (nb == 0) ? Qf : Kf;
        #pragma unroll
        for (int t = 0; t < 8; t++) {
            int col = wc * 64 + t * 8 + c2;
            float b0v = bias[nb * 128 + col], b1v = bias[nb * 128 + col + 1];
            int h = col >> 5, d = col & 31;
            *(uint16_t*)(outp + (((h << 12) + r0) << 5) + d) =
                packe4((acc[t][0] + b0v) * SC, (acc[t][1] + b1v) * SC);
            *(uint16_t*)(outp + (((h << 12) + r0 + 8) << 5) + d) =
                packe4((acc[t][2] + b0v) * SC, (acc[t][3] + b1v) * SC);
        }
    } else {
        #pragma unroll
        for (int t = 0; t < 8; t++) {
            int col = wc * 64 + t * 8 + c2;
            float b0v = bias[256 + col], b1v = bias[256 + col + 1];
            int h = col >> 5, d = col & 31;
            *(uint32_t*)(Vh + (((h << 12) + r0) << 5) + d) =
                packbf(acc[t][0] + b0v, acc[t][1] + b1v);
            *(uint32_t*)(Vh + (((h << 12) + r0 + 8) << 5) + d) =
                packbf(acc[t][2] + b0v, acc[t][3] + b1v);
        }
    }
}

// ================= fused tail: 512 threads (two 256-thread halves of 8 warps) ==========
#define WSTR 272
#define ASTR 592
#define SM_WAO   0
#define SM_WOP1  (128 * WSTR)
#define SM_WR1   (SM_WOP1 + 288 * WSTR)
#define SM_WR2   (SM_WR1 + 128 * WSTR)
#define SM_ACT   (SM_WR2 + 128 * WSTR)
#define SM_STAGE (SM_ACT + 32 * ASTR)
#define SM_PAR   (SM_STAGE + 32 * 136 * 4)
#define PAR_AOBB 0
#define PAR_OPB1 128
#define PAR_RB1  256
#define PAR_RB2  384
#define PAR_LNFG 512
#define PAR_LNFB 772
#define PAR_LN1G 1032
#define PAR_LN1B 1160
#define PAR_RLNG 1288
#define PAR_RLNB 1416
#define PAR_LN2G 1544
#define PAR_LN2B 1672
#define PAR_W3   1800
#define PAR_B3   2184
#define SMEM_TAIL (SM_PAR + 2192 * 4)

__global__ void __launch_bounds__(512) tail_k(
    const float* __restrict__ opart, const float* __restrict__ lpart,
    const __nv_bfloat16* __restrict__ wao, const float* __restrict__ aob_bias,
    const float* __restrict__ lnf_g, const float* __restrict__ lnf_b,
    const float* __restrict__ cf, const float* __restrict__ coordp,
    const int* __restrict__ bidx,
    const __nv_bfloat16* __restrict__ wop1, const float* __restrict__ op_b1,
    const float* __restrict__ ln1_g, const float* __restrict__ ln1_b,
    const __nv_bfloat16* __restrict__ wr1, const float* __restrict__ r_b1,
    const float* __restrict__ rln_g, const float* __restrict__ rln_b,
    const __nv_bfloat16* __restrict__ wr2, const float* __restrict__ r_b2,
    const float* __restrict__ ln2_g, const float* __restrict__ ln2_b,
    const float* __restrict__ w3, const float* __restrict__ b3,
    const float* __restrict__ bmin, const float* __restrict__ bmax,
    float* __restrict__ fout)
{
    extern __shared__ __align__(16) char dsm[];
    const int tid = threadIdx.x, lane = tid & 31, warp = tid >> 5;
    const int hb = warp >> 3;            // half 0/1: rows hb*16..hb*16+15
    const int wc = warp & 7;             // 8 warps per half, n = 16 cols each
    const int bm = blockIdx.x;
    uint32_t base = (uint32_t)__cvta_generic_to_shared(dsm);
    uint32_t aAct = base + SM_ACT + hb * 16 * ASTR;
    float* sSh = (float*)(dsm + SM_STAGE) + hb * 16 * 136;
    const float* par = (const float*)(dsm + SM_PAR);

    // ---- weight loads (512 threads) ----
    #pragma unroll
    for (int i = 0; i < 4; i++) {
        int s = tid + i * 512;
        int row = s >> 4, seg = s & 15;
        cpa16(base + SM_WAO + row * WSTR + seg * 16, wao + row * 128 + seg * 8);
    }
    #pragma unroll
    for (int i = 0; i < 9; i++) {
        int s = tid + i * 512;
        int row = s >> 4, seg = s & 15;
        cpa16(base + SM_WOP1 + row * WSTR + seg * 16, wop1 + row * 128 + seg * 8);
    }
    #pragma unroll
    for (int i = 0; i < 4; i++) {
        int s = tid + i * 512;
        int row = s >> 4, seg = s & 15;
        cpa16(base + SM_WR1 + row * WSTR + seg * 16, wr1 + row * 128 + seg * 8);
    }
    #pragma unroll
    for (int i = 0; i < 4; i++) {
        int s = tid + i * 512;
        int row = s >> 4, seg = s & 15;
        cpa16(base + SM_WR2 + row * WSTR + seg * 16, wr2 + row * 128 + seg * 8);
    }
    if (tid < 256) {
        int t = tid;
        if (t < 32)       cpa16(base + SM_PAR + (PAR_AOBB + t * 4) * 4,         aob_bias + t * 4);
        else if (t < 64)  cpa16(base + SM_PAR + (PAR_OPB1 + (t - 32) * 4) * 4,  op_b1 + (t - 32) * 4);
        else if (t < 96)  cpa16(base + SM_PAR + (PAR_RB1 + (t - 64) * 4) * 4,   r_b1 + (t - 64) * 4);
        else if (t < 128) cpa16(base + SM_PAR + (PAR_RB2 + (t - 96) * 4) * 4,   r_b2 + (t - 96) * 4);
        else if (t < 160) cpa16(base + SM_PAR + (PAR_LN1G + (t - 128) * 4) * 4, ln1_g + (t - 128) * 4);
        else if (t < 192) cpa16(base + SM_PAR + (PAR_LN1B + (t - 160) * 4) * 4, ln1_b + (t - 160) * 4);
        else if (t < 224) cpa16(base + SM_PAR + (PAR_RLNG + (t - 192) * 4) * 4, rln_g + (t - 192) * 4);
        else              cpa16(base + SM_PAR + (PAR_RLNB + (t - 224) * 4) * 4, rln_b + (t - 224) * 4);

        if (t < 32)       cpa16(base + SM_PAR + (PAR_LN2G + t * 4) * 4,          ln2_g + t * 4);
        else if (t < 64)  cpa16(base + SM_PAR + (PAR_LN2B + (t - 32) * 4) * 4,   ln2_b + (t - 32) * 4);
        else if (t < 160) cpa16(base + SM_PAR + (PAR_W3 + (t - 64) * 4) * 4,     w3 + (t - 64) * 4);
        else if (t < 224) cpa16(base + SM_PAR + (PAR_LNFG + (t - 160) * 4) * 4,  lnf_g + (t - 160) * 4);

        if (t < 64)       cpa16(base + SM_PAR + (PAR_LNFB + t * 4) * 4,          lnf_b + t * 4);
        else if (t < 67)  cpa4(base + SM_PAR + (PAR_LNFG + 256 + (t - 64)) * 4,  lnf_g + 256 + (t - 64));
        else if (t < 70)  cpa4(base + SM_PAR + (PAR_LNFB + 256 + (t - 67)) * 4,  lnf_b + 256 + (t - 67));
        else if (t < 73)  cpa4(base + SM_PAR + (PAR_B3 + (t - 70)) * 4,          b3 + (t - 70));
    }
    asm volatile("cp.async.commit_group;");

    // ---- combine flash K-split partials: 32 rows x 16 threads (8 cols each) ----
    {
        int r = tid >> 4, q = tid & 15;
        int grow = bm * 32 + r;
        int h = q >> 2;
        float L = 0.f;
        #pragma unroll
        for (int sp = 0; sp < KSPLIT; sp++)
            L += lpart[sp * NHEAD * NATOMS + h * NATOMS + grow];
        float inv = 1.f / L;
        const float* o0p = opart + grow * 128 + q * 8;
        uint32_t pk[4];
        #pragma unroll
        for (int i = 0; i < 2; i++) {
            float4 a = *(const float4*)&o0p[4 * i];
            #pragma unroll
            for (int sp = 1; sp < KSPLIT; sp++) {
                float4 b = *(const float4*)&o0p[sp * NATOMS * HDIM + 4 * i];
                a.x += b.x; a.y += b.y; a.z += b.z; a.w += b.w;
            }
            pk[2 * i]     = packbf(a.x * inv, a.y * inv);
            pk[2 * i + 1] = packbf(a.z * inv, a.w * inv);
        }
        *(uint4*)(dsm + SM_ACT + r * ASTR + q * 16) = *(uint4*)&pk[0];
    }

    asm volatile("cp.async.wait_group 0;");
    __syncthreads();

    const int i7 = lane & 7, sel = lane >> 3;
    const int arow = ((sel & 1) ? 8 : 0) + i7;
    const int acol = (sel >> 1) ? 16 : 0;
    const int vrow = ((sel & 1) ? 8 : 0) + i7;
    const int vcol = (sel >= 2) ? 16 : 0;
    const int htid = tid & 255;
    const int row = htid >> 4, q = htid & 15;    // LN: 16 threads per row, 8 cols each
    const int grow = bm * 32 + hb * 16 + row;
    const int sr0 = lane >> 2;
    const int c2 = (lane & 3) * 2;
    const int barid = hb + 1;

    float acc[2][4];
    uint32_t hkeep[4];

    auto do_gemm = [&](int wOff, int ksteps) {
        #pragma unroll
        for (int j = 0; j < 2; j++)
            #pragma unroll
            for (int c = 0; c < 4; c++) acc[j][c] = 0.f;
        for (int ks = 0; ks < ksteps; ks++) {
            #pragma unroll
            for (int kh = 0; kh < 2; kh++) {
                uint32_t qa[4];
                ldsm4(qa[0], qa[1], qa[2], qa[3], aAct + arow * ASTR + ks * 64 + kh * 32 + acol);
                uint32_t r0, r1, r2, r3;
                ldsm4t(r0, r1, r2, r3,
                       base + wOff + (ks * 32 + kh * 16 + vrow) * WSTR + wc * 32 + vcol);
                mma16816(acc[0], qa, r0, r1);
                mma16816(acc[1], qa, r2, r3);
            }
        }
    };

    auto stage = [&](const float* bias) {
        #pragma unroll
        for (int t = 0; t < 2; t++) {
            int col = wc * 16 + t * 8 + c2;
            float a0 = bias[col], a1 = bias[col + 1];
            sSh[sr0 * 136 + col] = acc[t][0] + a0;       sSh[sr0 * 136 + col + 1] = acc[t][1] + a1;
            sSh[(sr0 + 8) * 136 + col] = acc[t][2] + a0; sSh[(sr0 + 8) * 136 + col + 1] = acc[t][3] + a1;
        }
    };

    // ============ stage 0: xa = aob @ wao + b ; comb-LN(259) ============
    do_gemm(SM_WAO, 4);
    stage(par + PAR_AOBB);
    barh(barid);
    {
        int bi = bidx[grow];
        float xv[8], cv[8];
        #pragma unroll
        for (int i = 0; i < 2; i++) {
            float4 f = *(const float4*)&sSh[row * 136 + q * 8 + i * 4];
            xv[4 * i] = f.x; xv[4 * i + 1] = f.y; xv[4 * i + 2] = f.z; xv[4 * i + 3] = f.w;
            float4 c = *(const float4*)&cf[bi * 128 + q * 8 + i * 4];
            cv[4 * i] = c.x; cv[4 * i + 1] = c.y; cv[4 * i + 2] = c.z; cv[4 * i + 3] = c.w;
        }
        float c0 = 0.f, c1 = 0.f, c2v = 0.f;
        float s = 0.f;
        #pragma unroll
        for (int i = 0; i < 8; i++) s += xv[i] + cv[i];
        if (q == 0) {
            c0 = coordp[grow * 3 + 0]; c1 = coordp[grow * 3 + 1]; c2v = coordp[grow * 3 + 2];
            s += c0 + c1 + c2v;
        }
        s += __shfl_xor_sync(0xffffffffu, s, 1);
        s += __shfl_xor_sync(0xffffffffu, s, 2);
        s += __shfl_xor_sync(0xffffffffu, s, 4);
        s += __shfl_xor_sync(0xffffffffu, s, 8);
        float mean = s * (1.f / 259.f);
        float sq = 0.f;
        #pragma unroll
        for (int i = 0; i < 8; i++) {
            float d0 = xv[i] - mean, d1 = cv[i] - mean;
            sq += d0 * d0 + d1 * d1;
        }
        if (q == 0) {
            float d0 = c0 - mean, d1 = c1 - mean, d2 = c2v - mean;
            sq += d0 * d0 + d1 * d1 + d2 * d2;
        }
        sq += __shfl_xor_sync(0xffffffffu, sq, 1);
        sq += __shfl_xor_sync(0xffffffffu, sq, 2);
        sq += __shfl_xor_sync(0xffffffffu, sq, 4);
        sq += __shfl_xor_sync(0xffffffffu, sq, 8);
        float inv = rsqrtf(sq * (1.f / 259.f) + 1e-5f);

        uint32_t pk[4];
        #pragma unroll
        for (int i = 0; i < 4; i++) {
            int ca = q * 8 + 2 * i;
            pk[i] = packbf((xv[2 * i] - mean) * inv * par[PAR_LNFG + ca] + par[PAR_LNFB + ca],
                           (xv[2 * i + 1] - mean) * inv * par[PAR_LNFG + ca + 1] + par[PAR_LNFB + ca + 1]);
        }
        *(uint4*)(dsm + SM_ACT + (hb * 16 + row) * ASTR + q * 16) = *(uint4*)&pk[0];
        #pragma unroll
        for (int i = 0; i < 4; i++) {
            int ca = 128 + q * 8 + 2 * i;
            pk[i] = packbf((cv[2 * i] - mean) * inv * par[PAR_LNFG + ca] + par[PAR_LNFB + ca],
                           (cv[2 * i + 1] - mean) * inv * par[PAR_LNFG + ca + 1] + par[PAR_LNFB + ca + 1]);
        }
        *(uint4*)(dsm + SM_ACT + (hb * 16 + row) * ASTR + 256 + q * 16) = *(uint4*)&pk[0];
        // tail cols 256..287 (bytes 512..575): q0 writes 8B, q>=2 zero 4B each
        if (q == 0) {
            uint32_t tp0 = packbf((c0 - mean) * inv * par[PAR_LNFG + 256] + par[PAR_LNFB + 256],
                                  (c1 - mean) * inv * par[PAR_LNFG + 257] + par[PAR_LNFB + 257]);
            uint32_t tp1 = packbf((c2v - mean) * inv * par[PAR_LNFG + 258] + par[PAR_LNFB + 258], 0.f);
            *(uint2*)(dsm + SM_ACT + (hb * 16 + row) * ASTR + 512) = make_uint2(tp0, tp1);
        } else if (q >= 2) {
            *(uint32_t*)(dsm + SM_ACT + (hb * 16 + row) * ASTR + 512 + q * 4) = 0u;
        }
    }
    barh(barid);

    // ============ stage 1: h0 = comb @ wop1 ; LN + SiLU ============
    do_gemm(SM_WOP1, 9);
    stage(par + PAR_OPB1);
    barh(barid);
    {
        float v[8];
        #pragma unroll
        for (int i = 0; i < 2; i++) {
            float4 f = *(const float4*)&sSh[row * 136 + q * 8 + i * 4];
            v[4 * i] = f.x; v[4 * i + 1] = f.y; v[4 * i + 2] = f.z; v[4 * i + 3] = f.w;
        }
        float s = 0.f;
        #pragma unroll
        for (int i = 0; i < 8; i++) s += v[i];
        s += __shfl_xor_sync(0xffffffffu, s, 1);
        s += __shfl_xor_sync(0xffffffffu, s, 2);
        s += __shfl_xor_sync(0xffffffffu, s, 4);
        s += __shfl_xor_sync(0xffffffffu, s, 8);
        float mean = s * (1.f / 128.f);
        float sq = 0.f;
        #pragma unroll
        for (int i = 0; i < 8; i++) { float d = v[i] - mean; sq += d * d; }
        sq += __shfl_xor_sync(0xffffffffu, sq, 1);
        sq += __shfl_xor_sync(0xffffffffu, sq, 2);
        sq += __shfl_xor_sync(0xffffffffu, sq, 4);
        sq += __shfl_xor_sync(0xffffffffu, sq, 8);
        float inv = rsqrtf(sq * (1.f / 128.f) + 1e-5f);
        #pragma unroll
        for (int i = 0; i < 4; i++) {
            int ca = q * 8 + 2 * i;
            float y0 = silu_f((v[2 * i] - mean) * inv * par[PAR_LN1G + ca] + par[PAR_LN1B + ca]);
            float y1 = silu_f((v[2 * i + 1] - mean) * inv * par[PAR_LN1G + ca + 1] + par[PAR_LN1B + ca + 1]);
            hkeep[i] = packbf(y0, y1);
        }
        *(uint4*)(dsm + SM_ACT + (hb * 16 + row) * ASTR + q * 16) = *(uint4*)&hkeep[0];
    }
    barh(barid);

    // ============ stage 2: t = h1 @ wr1 ; LN + SiLU ============
    do_gemm(SM_WR1, 4);
    stage(par + PAR_RB1);
    barh(barid);
    {
        float v[8];
        #pragma unroll
        for (int i = 0; i < 2; i++) {
            float4 f = *(const float4*)&sSh[row * 136 + q * 8 + i * 4];
            v[4 * i] = f.x; v[4 * i + 1] = f.y; v[4 * i + 2] = f.z; v[4 * i + 3] = f.w;
        }
        float s = 0.f;
        #pragma unroll
        for (int i = 0; i < 8; i++) s += v[i];
        s += __shfl_xor_sync(0xffffffffu, s, 1);
        s += __shfl_xor_sync(0xffffffffu, s, 2);
        s += __shfl_xor_sync(0xffffffffu, s, 4);
        s += __shfl_xor_sync(0xffffffffu, s, 8);
        float mean = s * (1.f / 128.f);
        float sq = 0.f;
        #pragma unroll
        for (int i = 0; i < 8; i++) { float d = v[i] - mean; sq += d * d; }
        sq += __shfl_xor_sync(0xffffffffu, sq, 1);
        sq += __shfl_xor_sync(0xffffffffu, sq, 2);
        sq += __shfl_xor_sync(0xffffffffu, sq, 4);
        sq += __shfl_xor_sync(0xffffffffu, sq, 8);
        float inv = rsqrtf(sq * (1.f / 128.f) + 1e-5f);
        uint32_t pk[4];
        #pragma unroll
        for (int i = 0; i < 4; i++) {
            int ca = q * 8 + 2 * i;
            float y0 = silu_f((v[2 * i] - mean) * inv * par[PAR_RLNG + ca] + par[PAR_RLNB + ca]);
            float y1 = silu_f((v[2 * i + 1] - mean) * inv * par[PAR_RLNG + ca + 1] + par[PAR_RLNB + ca + 1]);
            pk[i] = packbf(y0, y1);
        }
        *(uint4*)(dsm + SM_ACT + (hb * 16 + row) * ASTR + q * 16) = *(uint4*)&pk[0];
    }
    barh(barid);

    // ============ stage 3: hfin = t2 @ wr2 + b + h1 ; LN ; proj/tanh/clamp ============
    do_gemm(SM_WR2, 4);
    stage(par + PAR_RB2);
    barh(barid);
    {
        float v[8];
        #pragma unroll
        for (int i = 0; i < 2; i++) {
            float4 f = *(const float4*)&sSh[row * 136 + q * 8 + i * 4];
            v[4 * i] = f.x; v[4 * i + 1] = f.y; v[4 * i + 2] = f.z; v[4 * i + 3] = f.w;
        }
        #pragma unroll
        for (int i = 0; i < 4; i++) {
            __nv_bfloat162 hh = *(__nv_bfloat162*)&hkeep[i];
            v[2 * i]     += __bfloat162float(hh.x);
            v[2 * i + 1] += __bfloat162float(hh.y);
        }
        float s = 0.f;
        #pragma unroll
        for (int i = 0; i < 8; i++) s += v[i];
        s += __shfl_xor_sync(0xffffffffu, s, 1);
        s += __shfl_xor_sync(0xffffffffu, s, 2);
        s += __shfl_xor_sync(0xffffffffu, s, 4);
        s += __shfl_xor_sync(0xffffffffu, s, 8);
        float mean = s * (1.f / 128.f);
        float sq = 0.f;
        #pragma unroll
        for (int i = 0; i < 8; i++) { float d = v[i] - mean; sq += d * d; }
        sq += __shfl_xor_sync(0xffffffffu, sq, 1);
        sq += __shfl_xor_sync(0xffffffffu, sq, 2);
        sq += __shfl_xor_sync(0xffffffffu, sq, 4);
        sq += __shfl_xor_sync(0xffffffffu, sq, 8);
        float inv = rsqrtf(sq * (1.f / 128.f) + 1e-5f);

        float p0 = 0.f, p1 = 0.f, p2 = 0.f;
        #pragma unroll
        for (int i = 0; i < 8; i++) {
            int ca = q * 8 + i;
            float y = (v[i] - mean) * inv * par[PAR_LN2G + ca] + par[PAR_LN2B + ca];
            p0 += y * par[PAR_W3 + ca * 3 + 0];
            p1 += y * par[PAR_W3 + ca * 3 + 1];
            p2 += y * par[PAR_W3 + ca * 3 + 2];
        }
        #pragma unroll
        for (int off = 8; off > 0; off >>= 1) {
            p0 += __shfl_xor_sync(0xffffffffu, p0, off);
            p1 += __shfl_xor_sync(0xffffffffu, p1, off);
            p2 += __shfl_xor_sync(0xffffffffu, p2, off);
        }
        if (q == 0) {
            int bi = bidx[grow];
            float dots[3] = {p0 + par[PAR_B3 + 0], p1 + par[PAR_B3 + 1], p2 + par[PAR_B3 + 2]};
            #pragma unroll
            for (int j = 0; j < 3; j++) {
                float val = coordp[grow * 3 + j] + 0.01f * tanhf(dots[j]);
                fout[grow * 3 + j] = fminf(fmaxf(val, bmin[bi * 3 + j]), bmax[bi * 3 + j]);
            }
        }
    }
}

// ======== flash: fp8 QK, 64 q-rows/CTA (1 m-tile/warp), KSPLIT=4 -> 1024 CTAs ========
#define QSTRIDE 48
#define VSTRIDE 80
#define QBUF    3072     // 64 rows * 48
#define KB8     6144
#define VB16    10240
#define KVPAIR  (KB8 + VB16)
#define NITER   (32 / KSPLIT)

__device__ __forceinline__ void kv_load128(const uint8_t* __restrict__ Kf,
                                           const __nv_bfloat16* __restrict__ Vh,
                                           int h, int kb, uint32_t sbase, int tid) {
    #pragma unroll
    for (int i = 0; i < 2; i++) {
        cpa16(sbase + tid * QSTRIDE + i * 16,
              Kf + (((h << 12) + (kb << 7) + tid) << 5) + i * 16);
    }
    #pragma unroll
    for (int i = 0; i < 4; i++) {
        cpa16(sbase + KB8 + tid * VSTRIDE + i * 16,
              Vh + (((h << 12) + (kb << 7) + tid) << 5) + i * 8);
    }
    asm volatile("cp.async.commit_group;");
}

__global__ void __launch_bounds__(128) flashb_k(const uint8_t* __restrict__ Qf,
                                                const uint8_t* __restrict__ Kf,
                                                const __nv_bfloat16* __restrict__ Vh,
                                                float* __restrict__ opart,
                                                float* __restrict__ lpart) {
    __shared__ __align__(16) char smem[QBUF + 2 * KVPAIR];
    const int tid = threadIdx.x, lane = tid & 31, warp = tid >> 5;
    const int h = blockIdx.y, qb = blockIdx.x, sp = blockIdx.z;
    const int kb0 = sp * NITER;

    uint32_t Qsa = (uint32_t)__cvta_generic_to_shared(smem);
    uint32_t kva0 = Qsa + QBUF;
    uint32_t kva1 = Qsa + QBUF + KVPAIR;

    // load 64 Q rows (fp8, 32B each): 128 transfers of 16B
    {
        int row = tid >> 1, seg = tid & 1;
        uint4 v = *(const uint4*)(Qf + (((h << 12) + (qb << 6) + row) << 5) + seg * 16);
        *(uint4*)(smem + row * QSTRIDE + seg * 16) = v;
    }
    kv_load128(Kf, Vh, h, kb0 + 0, kva0, tid);
    kv_load128(Kf, Vh, h, kb0 + 1, kva1, tid);
    __syncthreads();

    // Q fragments: 1 m16-tile per warp, k32 fp8 (4 regs)
    uint32_t qa[4];
    {
        int i = lane & 7, sl = lane >> 3;
        int row = warp * 16 + ((sl & 1) ? 8 : 0) + i;
        uint32_t a = Qsa + row * QSTRIDE + ((sl >> 1) ? 16 : 0);
        ldsm4(qa[0], qa[1], qa[2], qa[3], a);
    }

    float l0 = 0.f, l1 = 0.f;
    float o[4][4];
    #pragma unroll
    for (int j = 0; j < 4; j++)
        #pragma unroll
        for (int c = 0; c < 4; c++) o[j][c] = 0.f;

    const int i7 = lane & 7, sel = lane >> 3;
    const uint32_t krow = ((sel >= 2) ? 8 : 0) + i7;
    const uint32_t kcol = (sel & 1) ? 16 : 0;
    const uint32_t vrow = ((sel & 1) ? 8 : 0) + i7;
    const uint32_t vcol = (sel >= 2) ? 16 : 0;

    for (int kb = 0; kb < NITER; kb++) {
        if (kb < NITER - 1) asm volatile("cp.async.wait_group 1;");
        else                asm volatile("cp.async.wait_group 0;");
        __syncthreads();
        uint32_t Kbase = (kb & 1) ? kva1 : kva0;
        uint32_t Vbase = Kbase + KB8;

        #pragma unroll
        for (int ks = 0; ks < 8; ks++) {
            uint32_t a = Kbase + (ks * 16 + krow) * QSTRIDE + kcol;
            uint32_t b0, b1, b2, b3;
            ldsm4(b0, b1, b2, b3, a);

            float s0[4] = {0.f, 0.f, 0.f, 0.f}, s1[4] = {0.f, 0.f, 0.f, 0.f};
            mma16832(s0, qa, b0, b1);
            mma16832(s1, qa, b2, b3);

            uint32_t e00 = schexp(s0[0]), e01 = schexp(s0[1]);
            uint32_t e02 = schexp(s0[2]), e03 = schexp(s0[3]);
            uint32_t f00 = schexp(s1[0]), f01 = schexp(s1[1]);
            uint32_t f02 = schexp(s1[2]), f03 = schexp(s1[3]);

            l0 += (__int_as_float(e00) + __int_as_float(e01))
                + (__int_as_float(f00) + __int_as_float(f01));
            l1 += (__int_as_float(e02) + __int_as_float(e03))
                + (__int_as_float(f02) + __int_as_float(f03));

            uint32_t pa[4];
            pa[0] = prmt16(e00, e01);
            pa[1] = prmt16(e02, e03);
            pa[2] = prmt16(f00, f01);
            pa[3] = prmt16(f02, f03);

            uint32_t av = Vbase + (ks * 16 + vrow) * VSTRIDE + vcol;
            uint32_t v0, v1, v2, v3, w0, w1, w2, w3;
            ldsm4t(v0, v1, v2, v3, av);
            ldsm4t(w0, w1, w2, w3, av + 32);
            mma16816(o[0], pa, v0, v1);
            mma16816(o[1], pa, v2, v3);
            mma16816(o[2], pa, w0, w1);
            mma16816(o[3], pa, w2, w3);
        }

        __syncthreads();
        if (kb < NITER - 2) kv_load128(Kf, Vh, h, kb0 + kb + 2, (kb & 1) ? kva1 : kva0, tid);
    }

    l0 += __shfl_xor_sync(0xffffffffu, l0, 1);
    l0 += __shfl_xor_sync(0xffffffffu, l0, 2);
    l1 += __shfl_xor_sync(0xffffffffu, l1, 1);
    l1 += __shfl_xor_sync(0xffffffffu, l1, 2);
    int g = lane >> 2, l2 = (lane & 3) * 2;
    int row0 = (qb << 6) + warp * 16 + g;
    float* op = opart + sp * NATOMS * HDIM;
    #pragma unroll
    for (int j = 0; j < 4; j++) {
        int col = (h << 5) + j * 8 + l2;
        *(float2*)&op[row0 * HDIM + col]       = make_float2(o[j][0], o[j][1]);
        *(float2*)&op[(row0 + 8) * HDIM + col] = make_float2(o[j][2], o[j][3]);
    }
    if ((lane & 3) == 0) {
        float* lp = lpart + sp * NHEAD * NATOMS + h * NATOMS;
        lp[row0]     = l0;
        lp[row0 + 8] = l1;
    }
}

// ---------------- host ----------------
extern "C" void kernel_launch(void* const* d_in, const int* in_sizes, int n_in,
                              void* d_out, int out_size) {
    const int*   num_atoms  = (const int*)d_in[0];
    const int*   elems      = (const int*)d_in[1];
    const float* cell       = (const float*)d_in[2];
    const float* coord      = (const float*)d_in[3];
    const float* emb        = (const float*)d_in[4];
    const float* ln_in_g    = (const float*)d_in[5];
    const float* ln_in_b    = (const float*)d_in[6];
    const float* attn_in_w  = (const float*)d_in[7];
    const float* attn_in_b  = (const float*)d_in[8];
    const float* attn_out_w = (const float*)d_in[9];
    const float* attn_out_b = (const float*)d_in[10];
    const float* ce_w1      = (const float*)d_in[11];
    const float* ce_b1      = (const float*)d_in[12];
    const float* ce_w2      = (const float*)d_in[13];
    const float* ce_b2      = (const float*)d_in[14];
    const float* ln_feat_g  = (const float*)d_in[15];
    const float* ln_feat_b  = (const float*)d_in[16];
    const float* op_w1      = (const float*)d_in[17];
    const float* op_b1      = (const float*)d_in[18];
    const float* op_ln1_g   = (const float*)d_in[19];
    const float* op_ln1_b   = (const float*)d_in[20];
    const float* res_w1     = (const float*)d_in[21];
    const float* res_b1     = (const float*)d_in[22];
    const float* res_ln_g   = (const float*)d_in[23];
    const float* res_ln_b   = (const float*)d_in[24];
    const float* res_w2     = (const float*)d_in[25];
    const float* res_b2     = (const float*)d_in[26];
    const float* op_ln2_g   = (const float*)d_in[27];
    const float* op_ln2_b   = (const float*)d_in[28];
    const float* op_w3      = (const float*)d_in[29];
    const float* op_b3      = (const float*)d_in[30];
    float* out = (float*)d_out;

    float* S = nullptr;
    cudaGetSymbolAddress((void**)&S, g_scratch);
    int* bidx = nullptr;
    cudaGetSymbolAddress((void**)&bidx, g_bidx);

    __nv_bfloat16* P = (__nv_bfloat16*)S;
    __nv_bfloat16* xb    = P; P += NATOMS * HDIM;
    __nv_bfloat16* Vh    = P; P += NATOMS * HDIM;
    __nv_bfloat16* wqkv  = P; P += 128 * 384;
    __nv_bfloat16* wao   = P; P += 128 * 128;
    __nv_bfloat16* wop1  = P; P += FPAD * 128;
    __nv_bfloat16* wr1   = P; P += 128 * 128;
    __nv_bfloat16* wr2   = P; P += 128 * 128;
    uint8_t* U = (uint8_t*)P;
    uint8_t* Qf = U; U += NATOMS * HDIM;
    uint8_t* Kf = U; U += NATOMS * HDIM;
    U = (uint8_t*)(((uintptr_t)U + 15) & ~(uintptr_t)15);
    float* F = (float*)U;
    float* opart = F; F += KSPLIT * NATOMS * HDIM;
    float* lpart = F; F += KSPLIT * NHEAD * NATOMS;
    float* cf    = F; F += BATCH * HDIM;
    float* bmin  = F; F += BATCH * 3;
    float* bmax  = F; F += BATCH * 3;

    static bool attr_set = false;
    if (!attr_set) {
        cudaFuncSetAttribute(tail_k, cudaFuncAttributeMaxDynamicSharedMemorySize, SMEM_TAIL);
        attr_set = true;
    }

    setup_k<<<1049, 256>>>(elems, emb, ln_in_g, ln_in_b, xb,
                           attn_in_w, attn_out_w, op_w1, res_w1, res_w2,
                           wqkv, wao, wop1, wr1, wr2,
                           cell, ce_w1, ce_b1, ce_w2, ce_b2, cf,
                           num_atoms, bmin, bmax);

    qkv_k<<<dim3(3, 128), 128>>>(xb, wqkv, attn_in_b, Qf, Kf, Vh);

    flashb_k<<<dim3(64, NHEAD, KSPLIT), 128>>>(Qf, Kf, Vh, opart, lpart);

    tail_k<<<128, 512, SMEM_TAIL>>>(opart, lpart,
        wao, attn_out_b, ln_feat_g, ln_feat_b, cf, coord, bidx,
        wop1, op_b1, op_ln1_g, op_ln1_b,
        wr1, res_b1, res_ln_g, res_ln_b,
        wr2, res_b2, op_ln2_g, op_ln2_b,
        op_w3, op_b3, bmin, bmax, out);
}